// round 7
// baseline (speedup 1.0000x reference)
#include <cuda_runtime.h>
#include <cuda_bf16.h>
#include <math.h>
#include <stdint.h>

#define BS   16
#define NP   128
#define MNP  2048
#define D    768
#define NH   12
#define HD   64
#define DFF  2048
#define NLAYERS 2
#define TOPK 32
#define NC   751
#define NTOK (BS*NP)    // 2048
#define NMEM (BS*MNP)   // 32768
#define EPS  1e-5f

// ----------------------------------------------------------------------------
// Scratch (static device globals; no runtime allocation)
// ----------------------------------------------------------------------------
__device__ float g_x   [NTOK*(long)D];
__device__ float g_tmp [NTOK*(long)D];
__device__ float g_q   [NTOK*(long)D];
__device__ float g_qk  [NTOK*(long)(2*D)];
__device__ float g_v   [NTOK*(long)D];
__device__ float g_attn[NTOK*(long)D];
__device__ float g_Z   [(long)NH*NTOK*D];       // 75.5 MB
__device__ float g_sims[NTOK*(long)MNP];
__device__ int   g_idx [NTOK*TOPK];
__device__ float g_minv[NMEM];
__device__ float g_bnscale[D];
__device__ float g_bnshift[D];

// bf16 hi/lo split buffers
#define OFF_L1    0L
#define OFF_L3    1179648L
#define OFF_SAIN  2359296L
#define OFF_SAOUT 5898240L
#define OFF_FF1   7077888L
#define OFF_FF2   10223616L
#define OFF_CLS   13369344L
#define WTOTAL    13946112L
__device__ __nv_bfloat16 g_whi[WTOTAL], g_wlo[WTOTAL];
__device__ __nv_bfloat16 g_w2thi[(long)NLAYERS*NH*D*HD], g_w2tlo[(long)NLAYERS*NH*D*HD];
__device__ __nv_bfloat16 g_xhi [NTOK*(long)D], g_xlo [NTOK*(long)D];   // x
__device__ __nv_bfloat16 g_xqhi[NTOK*(long)D], g_xqlo[NTOK*(long)D];   // x+qpos
__device__ __nv_bfloat16 g_qhi [NTOK*(long)D], g_qlo [NTOK*(long)D];   // q proj
__device__ __nv_bfloat16 g_agghi[(long)NH*NTOK*D], g_agglo[(long)NH*NTOK*D];
__device__ __nv_bfloat16 g_h1hi[NTOK*(long)DFF], g_h1lo[NTOK*(long)DFF];
__device__ __nv_bfloat16 g_sahi[NTOK*(long)D], g_salo[NTOK*(long)D];
__device__ __nv_bfloat16 g_cihi[NTOK*(long)D], g_cilo[NTOK*(long)D];

// ----------------------------------------------------------------------------
// Helpers
// ----------------------------------------------------------------------------
__device__ __forceinline__ uint32_t smem_u32(const void* p) {
    uint32_t a;
    asm("{ .reg .u64 t; cvta.to.shared.u64 t, %1; cvt.u32.u64 %0, t; }"
        : "=r"(a) : "l"(p));
    return a;
}

#define CP_ASYNC16(dst, src) \
    asm volatile("cp.async.ca.shared.global [%0], [%1], 16;" \
                 :: "r"(dst), "l"(src) : "memory")
#define CP_COMMIT() asm volatile("cp.async.commit_group;" ::: "memory")
#define CP_WAIT(n)  asm volatile("cp.async.wait_group %0;" :: "n"(n) : "memory")

__device__ __forceinline__ void mma_bf16(float c[4],
    uint32_t a0, uint32_t a1, uint32_t a2, uint32_t a3,
    uint32_t b0, uint32_t b1)
{
    asm("mma.sync.aligned.m16n8k16.row.col.f32.bf16.bf16.f32 "
        "{%0,%1,%2,%3}, {%4,%5,%6,%7}, {%8,%9}, {%0,%1,%2,%3};"
        : "+f"(c[0]), "+f"(c[1]), "+f"(c[2]), "+f"(c[3])
        : "r"(a0), "r"(a1), "r"(a2), "r"(a3), "r"(b0), "r"(b1));
}

__device__ __forceinline__ void split1(float v, __nv_bfloat16& h, __nv_bfloat16& l) {
    __nv_bfloat16 hb = __float2bfloat16_rn(v);
    h = hb;
    l = __float2bfloat16_rn(v - __bfloat162float(hb));
}

// ----------------------------------------------------------------------------
// Split kernels (fp32 -> bf16 hi/lo)
// ----------------------------------------------------------------------------
__global__ void __launch_bounds__(256) split_kernel(
    const float* __restrict__ src,
    __nv_bfloat16* __restrict__ hi, __nv_bfloat16* __restrict__ lo, long n)
{
    long i = blockIdx.x * 256L + threadIdx.x;
    long stride = (long)gridDim.x * 256;
    for (; i < n; i += stride) {
        __nv_bfloat16 h, l;
        split1(src[i], h, l);
        hi[i] = h; lo[i] = l;
    }
}

// W2 transpose-split: out[l][h][n][k] = l2_w[l][h*64+k][n]
__global__ void __launch_bounds__(256) w2t_split_kernel(
    const float* __restrict__ l2w,
    __nv_bfloat16* __restrict__ hi, __nv_bfloat16* __restrict__ lo)
{
    long n = (long)NLAYERS * NH * D * HD;
    long i = blockIdx.x * 256L + threadIdx.x;
    long stride = (long)gridDim.x * 256;
    for (; i < n; i += stride) {
        int k = (int)(i & 63);
        long t = i >> 6;
        int nn = (int)(t % D);
        long t2 = t / D;
        int h = (int)(t2 % NH);
        int l = (int)(t2 / NH);
        float v = l2w[((long)l * D + h * HD + k) * D + nn];
        __nv_bfloat16 hh, ll;
        split1(v, hh, ll);
        hi[i] = hh; lo[i] = ll;
    }
}

__global__ void __launch_bounds__(256) split_affine_kernel(
    const float* __restrict__ src, const float* __restrict__ scale,
    const float* __restrict__ shift,
    __nv_bfloat16* __restrict__ hi, __nv_bfloat16* __restrict__ lo, long n)
{
    long i = blockIdx.x * 256L + threadIdx.x;
    long stride = (long)gridDim.x * 256;
    for (; i < n; i += stride) {
        int k = (int)(i % D);
        __nv_bfloat16 h, l;
        split1(src[i] * scale[k] + shift[k], h, l);
        hi[i] = h; lo[i] = l;
    }
}

// ----------------------------------------------------------------------------
// bf16x3 tensor-core GEMM, generalized strides + batch (blockIdx.z):
// C[M,N] = (Ah+Al)[M,K] @ (Bh+Bl)[N,K]^T  (3-term)
// EPI: 0 = (+bias) fp32 ; 1 = gelu(+bias) -> bf16 split ; 3 = (+bias) fp32 + split
// ----------------------------------------------------------------------------
template<int BN, int EPI>
__global__ void __launch_bounds__(128) hgemm_kernel(
    const __nv_bfloat16* __restrict__ Ah, const __nv_bfloat16* __restrict__ Al,
    const __nv_bfloat16* __restrict__ Bh, const __nv_bfloat16* __restrict__ Bl,
    const float* __restrict__ bias,
    float* __restrict__ C,
    __nv_bfloat16* __restrict__ Chi, __nv_bfloat16* __restrict__ Clo,
    int M, int N, int K, int ldA, int ldB, int ldC,
    long zA, long zB, long zC, long zBias)
{
    constexpr int BM = 128;
    constexpr int NT = BN / 16;
    constexpr int ROWS = BM + BN;
    extern __shared__ __align__(16) __nv_bfloat16 smem[];

    const int bz = blockIdx.z;
    Ah += bz * zA; Al += bz * zA;
    Bh += bz * zB; Bl += bz * zB;
    if (bias) bias += bz * zBias;
    C += bz * zC;
    if (EPI == 1 || EPI == 3) { Chi += bz * zC; Clo += bz * zC; }

    const int tid  = threadIdx.x;
    const int wid  = tid >> 5;
    const int lane = tid & 31;
    const int wm   = wid & 1;
    const int wn   = wid >> 1;
    const int qm   = lane >> 2;
    const int qk   = lane & 3;
    const int bm = blockIdx.y * BM;
    const int bn = blockIdx.x * BN;
    const uint32_t sbase = smem_u32(smem);

    float acc[4][NT][4];
#pragma unroll
    for (int mt = 0; mt < 4; mt++)
#pragma unroll
        for (int nt = 0; nt < NT; nt++)
#pragma unroll
            for (int r = 0; r < 4; r++) acc[mt][nt][r] = 0.f;

    auto loadStage = [&](int s, int k0) {
        const uint32_t pH = sbase + (uint32_t)(s * 2 + 0) * ROWS * 80;
        const uint32_t pL = sbase + (uint32_t)(s * 2 + 1) * ROWS * 80;
#pragma unroll
        for (int c = tid; c < BM * 4; c += 128) {
            int row = c >> 2, kc = c & 3;
            long gofs = (long)(bm + row) * ldA + k0;
            CP_ASYNC16(pH + row * 80 + kc * 16, (const char*)(Ah + gofs) + kc * 16);
            CP_ASYNC16(pL + row * 80 + kc * 16, (const char*)(Al + gofs) + kc * 16);
        }
#pragma unroll
        for (int c = tid; c < BN * 4; c += 128) {
            int row = c >> 2, kc = c & 3;
            int n = bn + row;
            uint32_t dh = pH + (BM + row) * 80 + kc * 16;
            uint32_t dl = pL + (BM + row) * 80 + kc * 16;
            if (n < N) {
                long gofs = (long)n * ldB + k0;
                CP_ASYNC16(dh, (const char*)(Bh + gofs) + kc * 16);
                CP_ASYNC16(dl, (const char*)(Bl + gofs) + kc * 16);
            } else {
                uint32_t z = 0;
                asm volatile("st.shared.v4.b32 [%0], {%1,%1,%1,%1};" :: "r"(dh), "r"(z) : "memory");
                asm volatile("st.shared.v4.b32 [%0], {%1,%1,%1,%1};" :: "r"(dl), "r"(z) : "memory");
            }
        }
    };

    auto compute = [&](int s) {
        const uint32_t* SH = (const uint32_t*)smem + (long)(s * 2 + 0) * ROWS * 20;
        const uint32_t* SL = (const uint32_t*)smem + (long)(s * 2 + 1) * ROWS * 20;
#pragma unroll
        for (int kc = 0; kc < 2; kc++) {
            const int w = kc * 8 + qk;
            uint32_t ah[4][4], al[4][4];
#pragma unroll
            for (int mt = 0; mt < 4; mt++) {
                int r = wm * 64 + mt * 16 + qm;
                ah[mt][0] = SH[r * 20 + w];
                ah[mt][1] = SH[(r + 8) * 20 + w];
                ah[mt][2] = SH[r * 20 + w + 4];
                ah[mt][3] = SH[(r + 8) * 20 + w + 4];
                al[mt][0] = SL[r * 20 + w];
                al[mt][1] = SL[(r + 8) * 20 + w];
                al[mt][2] = SL[r * 20 + w + 4];
                al[mt][3] = SL[(r + 8) * 20 + w + 4];
            }
#pragma unroll
            for (int nt = 0; nt < NT; nt++) {
                int rb = BM + wn * (BN / 2) + nt * 8 + qm;
                uint32_t bh0 = SH[rb * 20 + w], bh1 = SH[rb * 20 + w + 4];
                uint32_t bl0 = SL[rb * 20 + w], bl1 = SL[rb * 20 + w + 4];
#pragma unroll
                for (int mt = 0; mt < 4; mt++) {
                    mma_bf16(acc[mt][nt], ah[mt][0], ah[mt][1], ah[mt][2], ah[mt][3], bh0, bh1);
                    mma_bf16(acc[mt][nt], ah[mt][0], ah[mt][1], ah[mt][2], ah[mt][3], bl0, bl1);
                    mma_bf16(acc[mt][nt], al[mt][0], al[mt][1], al[mt][2], al[mt][3], bh0, bh1);
                }
            }
        }
    };

    const int niter = K >> 5;
    loadStage(0, 0); CP_COMMIT();
    for (int i = 0; i < niter; i++) {
        if (i + 1 < niter) { loadStage((i + 1) & 1, (i + 1) << 5); CP_COMMIT(); CP_WAIT(1); }
        else               { CP_WAIT(0); }
        __syncthreads();
        compute(i & 1);
        __syncthreads();
    }

#pragma unroll
    for (int mt = 0; mt < 4; mt++) {
        int r0 = bm + wm * 64 + mt * 16 + qm;
#pragma unroll
        for (int nt = 0; nt < NT; nt++) {
            int c0 = bn + wn * (BN / 2) + nt * 8 + qk * 2;
            float v0 = acc[mt][nt][0], v1 = acc[mt][nt][1];
            float v2 = acc[mt][nt][2], v3 = acc[mt][nt][3];
            if (bias) {
                float b0 = (c0 < N) ? bias[c0] : 0.f;
                float b1 = (c0 + 1 < N) ? bias[c0 + 1] : 0.f;
                v0 += b0; v1 += b1; v2 += b0; v3 += b1;
            }
            if (EPI == 1) {
                v0 = 0.5f * v0 * (1.f + erff(v0 * 0.70710678118654752f));
                v1 = 0.5f * v1 * (1.f + erff(v1 * 0.70710678118654752f));
                v2 = 0.5f * v2 * (1.f + erff(v2 * 0.70710678118654752f));
                v3 = 0.5f * v3 * (1.f + erff(v3 * 0.70710678118654752f));
            }
            if (EPI == 1 || EPI == 3) {
                __nv_bfloat162 h2, l2;
                split1(v0, h2.x, l2.x); split1(v1, h2.y, l2.y);
                *(__nv_bfloat162*)(Chi + (long)r0 * ldC + c0) = h2;
                *(__nv_bfloat162*)(Clo + (long)r0 * ldC + c0) = l2;
                split1(v2, h2.x, l2.x); split1(v3, h2.y, l2.y);
                *(__nv_bfloat162*)(Chi + (long)(r0 + 8) * ldC + c0) = h2;
                *(__nv_bfloat162*)(Clo + (long)(r0 + 8) * ldC + c0) = l2;
            }
            if (EPI == 0 || EPI == 3) {
                if (c0 < N) {
                    C[(long)r0 * ldC + c0] = v0;
                    C[(long)(r0 + 8) * ldC + c0] = v2;
                }
                if (c0 + 1 < N) {
                    C[(long)r0 * ldC + c0 + 1] = v1;
                    C[(long)(r0 + 8) * ldC + c0 + 1] = v3;
                }
            }
        }
    }
}

// ----------------------------------------------------------------------------
// FP32 scalar GEMM (exact path for sims -> top-k selection stability).
// ----------------------------------------------------------------------------
__global__ void __launch_bounds__(256) f32_gemm_kernel(
    const float* __restrict__ A, const float* __restrict__ B,
    float* __restrict__ C, int M, int N, int K,
    long sA, long sB, long sC)
{
    constexpr int BM = 128, BN = 128, BK = 8;
    int bz = blockIdx.z;
    A += bz * sA; B += bz * sB; C += bz * sC;
    int bm = blockIdx.y * BM, bn = blockIdx.x * BN;

    __shared__ float As[BK][BM + 4];
    __shared__ float Bs[BK][BN + 4];

    int tid = threadIdx.x;
    int tx = tid & 15, ty = tid >> 4;

    float acc[8][8];
#pragma unroll
    for (int i = 0; i < 8; i++)
#pragma unroll
        for (int j = 0; j < 8; j++) acc[i][j] = 0.f;

    for (int k0 = 0; k0 < K; k0 += BK) {
#pragma unroll
        for (int l = 0; l < 4; l++) {
            int lin = tid + l * 256;
            int kk = lin & 7, r = lin >> 3;
            int m = bm + r;
            As[kk][r] = (m < M) ? A[(long)m * K + k0 + kk] : 0.f;
        }
#pragma unroll
        for (int l = 0; l < 4; l++) {
            int lin = tid + l * 256;
            int kk = lin & 7, r = lin >> 3;
            int n = bn + r;
            Bs[kk][r] = (n < N) ? B[(long)n * K + k0 + kk] : 0.f;
        }
        __syncthreads();
#pragma unroll
        for (int k = 0; k < BK; k++) {
            float a[8], b[8];
            *(float4*)&a[0] = *(const float4*)&As[k][ty * 8];
            *(float4*)&a[4] = *(const float4*)&As[k][ty * 8 + 4];
            *(float4*)&b[0] = *(const float4*)&Bs[k][tx * 8];
            *(float4*)&b[4] = *(const float4*)&Bs[k][tx * 8 + 4];
#pragma unroll
            for (int i = 0; i < 8; i++)
#pragma unroll
                for (int j = 0; j < 8; j++)
                    acc[i][j] = fmaf(a[i], b[j], acc[i][j]);
        }
        __syncthreads();
    }
#pragma unroll
    for (int i = 0; i < 8; i++) {
        int m = bm + ty * 8 + i;
        if (m >= M) continue;
#pragma unroll
        for (int j = 0; j < 8; j++) {
            int n = bn + tx * 8 + j;
            if (n < N) C[(long)m * N + n] = acc[i][j];
        }
    }
}

// ----------------------------------------------------------------------------
// LayerNorm + fused bf16 splits of x and x+qpos.
// ----------------------------------------------------------------------------
__global__ void __launch_bounds__(256) ln_kernel(
    const float* __restrict__ x, const float* __restrict__ add,
    const float* __restrict__ g, const float* __restrict__ b,
    const float* __restrict__ qpos,
    float* __restrict__ out,
    __nv_bfloat16* __restrict__ ohi, __nv_bfloat16* __restrict__ olo,
    __nv_bfloat16* __restrict__ oqhi, __nv_bfloat16* __restrict__ oqlo)
{
    int row = blockIdx.x, tid = threadIdx.x;
    const float* xr = x + (long)row * D;
    float vals[3];
    float s = 0.f, sq = 0.f;
#pragma unroll
    for (int i = 0; i < 3; i++) {
        int c = tid + i * 256;
        float v = xr[c];
        if (add) v += add[(long)row * D + c];
        vals[i] = v; s += v; sq += v * v;
    }
    __shared__ float rs[256], rq[256];
    rs[tid] = s; rq[tid] = sq;
    __syncthreads();
    for (int o = 128; o > 0; o >>= 1) {
        if (tid < o) { rs[tid] += rs[tid + o]; rq[tid] += rq[tid + o]; }
        __syncthreads();
    }
    float mu = rs[0] * (1.f / D);
    float var = rq[0] * (1.f / D) - mu * mu;
    float rstd = rsqrtf(var + EPS);
#pragma unroll
    for (int i = 0; i < 3; i++) {
        int c = tid + i * 256;
        long o = (long)row * D + c;
        float v = (vals[i] - mu) * rstd * g[c] + b[c];
        out[o] = v;
        __nv_bfloat16 h, l;
        split1(v, h, l);
        ohi[o] = h; olo[o] = l;
        split1(v + qpos[o], h, l);
        oqhi[o] = h; oqlo[o] = l;
    }
}

__global__ void __launch_bounds__(256) rownorm_kernel(
    const float* __restrict__ m, float* __restrict__ minv)
{
    int row = blockIdx.x, tid = threadIdx.x;
    float s = 0.f;
#pragma unroll
    for (int i = 0; i < 3; i++) {
        float v = m[(long)row * D + tid + i * 256];
        s += v * v;
    }
    __shared__ float rs[256];
    rs[tid] = s; __syncthreads();
    for (int o = 128; o > 0; o >>= 1) {
        if (tid < o) rs[tid] += rs[tid + o];
        __syncthreads();
    }
    if (tid == 0) minv[row] = rsqrtf(rs[0]);
}

// ----------------------------------------------------------------------------
// Top-32 per query row (iterative block argmax over smem copy).
// ----------------------------------------------------------------------------
__global__ void __launch_bounds__(256) topk_kernel(
    const float* __restrict__ sims, const float* __restrict__ minv,
    int* __restrict__ idx_out)
{
    int row = blockIdx.x;
    int b = row / NP;
    int tid = threadIdx.x;
    __shared__ float s[MNP];
    __shared__ float rmax[256];
    __shared__ int   rarg[256];
    for (int i = tid; i < MNP; i += 256)
        s[i] = sims[(long)row * MNP + i] * minv[b * MNP + i];
    __syncthreads();
    for (int t = 0; t < TOPK; t++) {
        float best = -INFINITY; int bi = 0x7fffffff;
        for (int i = tid; i < MNP; i += 256) {
            float v = s[i];
            if (v > best) { best = v; bi = i; }
        }
        rmax[tid] = best; rarg[tid] = bi;
        __syncthreads();
        for (int o = 128; o > 0; o >>= 1) {
            if (tid < o) {
                float ov = rmax[tid + o]; int oi = rarg[tid + o];
                if (ov > rmax[tid] || (ov == rmax[tid] && oi < rarg[tid])) {
                    rmax[tid] = ov; rarg[tid] = oi;
                }
            }
            __syncthreads();
        }
        if (tid == 0) {
            idx_out[row * TOPK + t] = rarg[0];
            s[rarg[0]] = -INFINITY;
        }
        __syncthreads();
    }
}

// ----------------------------------------------------------------------------
// Fused cross-attention core: scores via Z·m̃ gather, softmax, memory-domain
// aggregation. Block per query (128 threads). Writes Agg bf16 hi/lo.
// ----------------------------------------------------------------------------
#define XATTN_SMEM ((9216 + 9216 + 768 + 768 + 384 + 16 + 32) * 4)

__global__ void __launch_bounds__(128) xattn_kernel(
    const float* __restrict__ qf,      // [2048][768]
    const float* __restrict__ Z,       // [12][2048][768]
    const float* __restrict__ memory,  // [16*2048][768]
    const float* __restrict__ kpos,    // [16*2048][768]
    const float* __restrict__ l2b,     // [768]
    const int*   __restrict__ idx,     // [2048][32]
    __nv_bfloat16* __restrict__ agghi, // [12][2048][768]
    __nv_bfloat16* __restrict__ agglo)
{
    extern __shared__ float ssm[];
    float* Zs  = ssm;            // 12*768
    float* agg = Zs + 9216;      // 12*768
    float* qv  = agg + 9216;     // 768
    float* row = qv + 768;       // 768
    float* sc  = row + 768;      // 12*32
    float* qb  = sc + 384;       // 16
    int*   ids = (int*)(qb + 16);// 32

    const int qi = blockIdx.x;
    const int b  = qi >> 7;
    const int tid = threadIdx.x;
    const int warp = tid >> 5, lane = tid & 31;

    // load q row + Z rows + zero agg
    for (int c = tid; c < D; c += 128) qv[c] = qf[(long)qi * D + c];
    {
        const float* Zg = Z + (long)qi * D;
        for (int i = tid; i < 2304; i += 128) {
            int h = i / 192, o = (i % 192) * 4;
            *(float4*)&Zs[h * D + o] = *(const float4*)&Zg[(long)h * NTOK * D + o];
        }
    }
    for (int i = tid; i < 9216; i += 128) agg[i] = 0.f;
    if (tid < TOPK) ids[tid] = idx[qi * TOPK + tid];
    __syncthreads();

    // qb[h] = q_h . b2_h
    for (int h = warp; h < NH; h += 4) {
        float s = qv[h * HD + lane] * l2b[h * HD + lane]
                + qv[h * HD + 32 + lane] * l2b[h * HD + 32 + lane];
#pragma unroll
        for (int o = 16; o > 0; o >>= 1) s += __shfl_xor_sync(0xffffffffu, s, o);
        if (lane == 0) qb[h] = s;
    }
    __syncthreads();

    // scores: s[h][j] = (Z[h] . (mem+kpos)[ix_j] + qb[h]) / 8
    for (int j = 0; j < TOPK; j++) {
        long base = ((long)b * MNP + ids[j]) * D;
        for (int c = tid; c < D; c += 128) row[c] = memory[base + c] + kpos[base + c];
        __syncthreads();
#pragma unroll
        for (int t = 0; t < 3; t++) {
            int h = warp * 3 + t;
            float s = 0.f;
#pragma unroll
            for (int c = lane; c < D; c += 32) s = fmaf(Zs[h * D + c], row[c], s);
#pragma unroll
            for (int o = 16; o > 0; o >>= 1) s += __shfl_xor_sync(0xffffffffu, s, o);
            if (lane == 0) sc[h * TOPK + j] = (s + qb[h]) * 0.125f;
        }
        __syncthreads();
    }

    // softmax per head
    if (tid < NH) {
        float m = -INFINITY;
        for (int j = 0; j < TOPK; j++) m = fmaxf(m, sc[tid * TOPK + j]);
        float sum = 0.f;
        for (int j = 0; j < TOPK; j++) {
            float e = expf(sc[tid * TOPK + j] - m);
            sc[tid * TOPK + j] = e; sum += e;
        }
        float inv = 1.f / sum;
        for (int j = 0; j < TOPK; j++) sc[tid * TOPK + j] *= inv;
    }
    __syncthreads();

    // aggregate: agg[h] = sum_j p[h][j] * mem[ix_j]
    for (int j = 0; j < TOPK; j++) {
        long base = ((long)b * MNP + ids[j]) * D;
        for (int c = tid; c < D; c += 128) row[c] = memory[base + c];
        __syncthreads();
#pragma unroll
        for (int t = 0; t < 3; t++) {
            int h = warp * 3 + t;
            float p = sc[h * TOPK + j];
#pragma unroll
            for (int c = lane; c < D; c += 32)
                agg[h * D + c] = fmaf(p, row[c], agg[h * D + c]);
        }
        __syncthreads();
    }

    // write split
    for (int i = tid; i < 9216; i += 128) {
        int h = i / D, c = i % D;
        __nv_bfloat16 hh, ll;
        split1(agg[i], hh, ll);
        long o = (long)h * NTOK * D + (long)qi * D + c;
        agghi[o] = hh; agglo[o] = ll;
    }
}

// ----------------------------------------------------------------------------
// Dense self-attention over NP=128 keys -> bf16 split out
// ----------------------------------------------------------------------------
__global__ void __launch_bounds__(128) self_attn_kernel(
    const float* __restrict__ qk, const float* __restrict__ v,
    __nv_bfloat16* __restrict__ ohi, __nv_bfloat16* __restrict__ olo)
{
    int row = blockIdx.x;
    int b = row >> 7;
    int h = blockIdx.y;
    int tid = threadIdx.x;

    __shared__ float qv[HD];
    __shared__ float sc[NP];
    __shared__ float red[128];

    const float* qr = qk + (long)row * (2 * D) + h * HD;
    if (tid < HD) qv[tid] = qr[tid];
    __syncthreads();

    const float* kr = qk + (long)(b * NP + tid) * (2 * D) + D + h * HD;
    float s = 0.f;
#pragma unroll
    for (int d = 0; d < HD; d++) s = fmaf(qv[d], kr[d], s);
    s *= 0.125f;

    red[tid] = s; __syncthreads();
    for (int o = 64; o > 0; o >>= 1) {
        if (tid < o) red[tid] = fmaxf(red[tid], red[tid + o]);
        __syncthreads();
    }
    float m = red[0]; __syncthreads();
    float e = expf(s - m);
    sc[tid] = e;
    red[tid] = e; __syncthreads();
    for (int o = 64; o > 0; o >>= 1) {
        if (tid < o) red[tid] += red[tid + o];
        __syncthreads();
    }
    float inv = 1.f / red[0];

    if (tid < HD) {
        float acc = 0.f;
        for (int j = 0; j < NP; j++)
            acc = fmaf(sc[j], v[(long)(b * NP + j) * D + h * HD + tid], acc);
        long o = (long)row * D + h * HD + tid;
        __nv_bfloat16 hh, ll;
        split1(acc * inv, hh, ll);
        ohi[o] = hh; olo[o] = ll;
    }
}

// ----------------------------------------------------------------------------
// BatchNorm stats -> fused scale/shift
// ----------------------------------------------------------------------------
__global__ void __launch_bounds__(256) bn_stats_kernel(
    const float* __restrict__ x, const float* __restrict__ g,
    const float* __restrict__ b, float* __restrict__ scale,
    float* __restrict__ shift)
{
    int f = blockIdx.x, tid = threadIdx.x;
    float s = 0.f, sq = 0.f;
    for (int r = tid; r < NTOK; r += 256) {
        float v = x[(long)r * D + f];
        s += v; sq += v * v;
    }
    __shared__ float rs[256], rq[256];
    rs[tid] = s; rq[tid] = sq;
    __syncthreads();
    for (int o = 128; o > 0; o >>= 1) {
        if (tid < o) { rs[tid] += rs[tid + o]; rq[tid] += rq[tid + o]; }
        __syncthreads();
    }
    if (tid == 0) {
        float mu = rs[0] * (1.f / NTOK);
        float var = rq[0] * (1.f / NTOK) - mu * mu;
        float rstd = rsqrtf(var + EPS);
        float sc = rstd * g[f];
        scale[f] = sc;
        shift[f] = b[f] - mu * sc;
    }
}

// ----------------------------------------------------------------------------
// Host orchestration
// ----------------------------------------------------------------------------
#define SMEM128 (2 * 2 * 256 * 80)
#define SMEM64  (2 * 2 * 192 * 80)

extern "C" void kernel_launch(void* const* d_in, const int* in_sizes, int n_in,
                              void* d_out, int out_size)
{
    const float* tgt      = (const float*)d_in[0];
    const float* memory   = (const float*)d_in[1];
    const float* qpos     = (const float*)d_in[2];
    const float* kpos     = (const float*)d_in[3];
    const float* norm0_g  = (const float*)d_in[4];
    const float* norm0_b  = (const float*)d_in[5];
    const float* l1_w     = (const float*)d_in[6];
    const float* l1_b     = (const float*)d_in[7];
    const float* l2_w     = (const float*)d_in[8];
    const float* l2_b     = (const float*)d_in[9];
    const float* l3_w     = (const float*)d_in[10];
    const float* l3_b     = (const float*)d_in[11];
    const float* n1_g     = (const float*)d_in[12];
    const float* n1_b     = (const float*)d_in[13];
    const float* n2_g     = (const float*)d_in[14];
    const float* n2_b     = (const float*)d_in[15];
    const float* n3_g     = (const float*)d_in[16];
    const float* n3_b     = (const float*)d_in[17];
    const float* sa_in_w  = (const float*)d_in[18];
    const float* sa_in_b  = (const float*)d_in[19];
    const float* sa_out_w = (const float*)d_in[20];
    const float* sa_out_b = (const float*)d_in[21];
    const float* ff1_w    = (const float*)d_in[22];
    const float* ff1_b    = (const float*)d_in[23];
    const float* ff2_w    = (const float*)d_in[24];
    const float* ff2_b    = (const float*)d_in[25];
    const float* bn_g     = (const float*)d_in[26];
    const float* bn_b     = (const float*)d_in[27];
    const float* cls_w    = (const float*)d_in[28];

    float *x, *tmp, *q, *qk, *v, *attn, *Z, *sims, *minv, *bnsc, *bnsh;
    int* idx;
    __nv_bfloat16 *whi, *wlo, *w2th, *w2tl;
    __nv_bfloat16 *xhi, *xlo, *xqhi, *xqlo, *qhi, *qlo, *agghi, *agglo;
    __nv_bfloat16 *h1hi, *h1lo, *sahi, *salo, *cihi, *cilo;
    cudaGetSymbolAddress((void**)&x,    g_x);
    cudaGetSymbolAddress((void**)&tmp,  g_tmp);
    cudaGetSymbolAddress((void**)&q,    g_q);
    cudaGetSymbolAddress((void**)&qk,   g_qk);
    cudaGetSymbolAddress((void**)&v,    g_v);
    cudaGetSymbolAddress((void**)&attn, g_attn);
    cudaGetSymbolAddress((void**)&Z,    g_Z);
    cudaGetSymbolAddress((void**)&sims, g_sims);
    cudaGetSymbolAddress((void**)&idx,  g_idx);
    cudaGetSymbolAddress((void**)&minv, g_minv);
    cudaGetSymbolAddress((void**)&bnsc, g_bnscale);
    cudaGetSymbolAddress((void**)&bnsh, g_bnshift);
    cudaGetSymbolAddress((void**)&whi,  g_whi);
    cudaGetSymbolAddress((void**)&wlo,  g_wlo);
    cudaGetSymbolAddress((void**)&w2th, g_w2thi);
    cudaGetSymbolAddress((void**)&w2tl, g_w2tlo);
    cudaGetSymbolAddress((void**)&xhi,  g_xhi);
    cudaGetSymbolAddress((void**)&xlo,  g_xlo);
    cudaGetSymbolAddress((void**)&xqhi, g_xqhi);
    cudaGetSymbolAddress((void**)&xqlo, g_xqlo);
    cudaGetSymbolAddress((void**)&qhi,  g_qhi);
    cudaGetSymbolAddress((void**)&qlo,  g_qlo);
    cudaGetSymbolAddress((void**)&agghi, g_agghi);
    cudaGetSymbolAddress((void**)&agglo, g_agglo);
    cudaGetSymbolAddress((void**)&h1hi, g_h1hi);
    cudaGetSymbolAddress((void**)&h1lo, g_h1lo);
    cudaGetSymbolAddress((void**)&sahi, g_sahi);
    cudaGetSymbolAddress((void**)&salo, g_salo);
    cudaGetSymbolAddress((void**)&cihi, g_cihi);
    cudaGetSymbolAddress((void**)&cilo, g_cilo);

    // smem attrs (no-ops after first call; cheap)
    cudaFuncSetAttribute(hgemm_kernel<128,0>, cudaFuncAttributeMaxDynamicSharedMemorySize, SMEM128);
    cudaFuncSetAttribute(hgemm_kernel<128,1>, cudaFuncAttributeMaxDynamicSharedMemorySize, SMEM128);
    cudaFuncSetAttribute(hgemm_kernel<128,3>, cudaFuncAttributeMaxDynamicSharedMemorySize, SMEM128);
    cudaFuncSetAttribute(hgemm_kernel<64,0>,  cudaFuncAttributeMaxDynamicSharedMemorySize, SMEM64);
    cudaFuncSetAttribute(xattn_kernel, cudaFuncAttributeMaxDynamicSharedMemorySize, XATTN_SMEM);

    // ---- weight splits ----
    split_kernel<<<2048, 256>>>(l1_w,     whi + OFF_L1,    wlo + OFF_L1,    (long)NLAYERS*D*D);
    split_kernel<<<2048, 256>>>(l3_w,     whi + OFF_L3,    wlo + OFF_L3,    (long)NLAYERS*D*D);
    split_kernel<<<2048, 256>>>(sa_in_w,  whi + OFF_SAIN,  wlo + OFF_SAIN,  (long)NLAYERS*3*D*D);
    split_kernel<<<2048, 256>>>(sa_out_w, whi + OFF_SAOUT, wlo + OFF_SAOUT, (long)NLAYERS*D*D);
    split_kernel<<<2048, 256>>>(ff1_w,    whi + OFF_FF1,   wlo + OFF_FF1,   (long)NLAYERS*DFF*D);
    split_kernel<<<2048, 256>>>(ff2_w,    whi + OFF_FF2,   wlo + OFF_FF2,   (long)NLAYERS*D*DFF);
    split_kernel<<<2048, 256>>>(cls_w,    whi + OFF_CLS,   wlo + OFF_CLS,   (long)NC*D);
    w2t_split_kernel<<<2048, 256>>>(l2_w, w2th, w2tl);

    rownorm_kernel<<<NMEM, 256>>>(memory, minv);
    ln_kernel<<<NTOK, 256>>>(tgt, nullptr, norm0_g, norm0_b, qpos,
                             x, xhi, xlo, xqhi, xqlo);

    for (int l = 0; l < NLAYERS; l++) {
        long wdd = (long)l * D * D;
        const __nv_bfloat16* l1h = whi + OFF_L1 + wdd;   const __nv_bfloat16* l1l = wlo + OFF_L1 + wdd;
        const __nv_bfloat16* l3h = whi + OFF_L3 + wdd;   const __nv_bfloat16* l3l = wlo + OFF_L3 + wdd;
        const __nv_bfloat16* sih = whi + OFF_SAIN + (long)l*3*D*D;
        const __nv_bfloat16* sil = wlo + OFF_SAIN + (long)l*3*D*D;
        const __nv_bfloat16* soh = whi + OFF_SAOUT + wdd;
        const __nv_bfloat16* sol = wlo + OFF_SAOUT + wdd;
        const __nv_bfloat16* f1h = whi + OFF_FF1 + (long)l*DFF*D;
        const __nv_bfloat16* f1l = wlo + OFF_FF1 + (long)l*DFF*D;
        const __nv_bfloat16* f2h = whi + OFF_FF2 + (long)l*D*DFF;
        const __nv_bfloat16* f2l = wlo + OFF_FF2 + (long)l*D*DFF;
        const __nv_bfloat16* w2h = w2th + (long)l*NH*D*HD;
        const __nv_bfloat16* w2l = w2tl + (long)l*NH*D*HD;
        const float* l1bb = l1_b + (long)l * D;
        const float* l2bb = l2_b + (long)l * D;
        const float* l3bb = l3_b + (long)l * D;
        const float* sab  = sa_in_b + (long)l * 3 * D;
        const float* sob  = sa_out_b + (long)l * D;
        const float* f1b  = ff1_b + (long)l * DFF;
        const float* f2b  = ff2_b + (long)l * D;

        // sims[b] = x[b] @ memory[b]^T  (FP32 exact, selection stability)
        f32_gemm_kernel<<<dim3(MNP / 128, 1, BS), 256>>>(
            x, memory, sims, NP, MNP, D,
            (long)NP * D, (long)MNP * D, (long)NP * MNP);

        topk_kernel<<<NTOK, 256>>>(sims, minv, idx);

        // q = (x + qpos) @ l1^T + b1  -> fp32 + split
        hgemm_kernel<128,3><<<dim3(D/128, NTOK/128, 1), 128, SMEM128>>>(
            xqhi, xqlo, l1h, l1l, l1bb, q, qhi, qlo,
            NTOK, D, D, D, D, D, 0, 0, 0, 0);

        // Z_h = Q_h @ W2T_h^T  (batched over heads)
        hgemm_kernel<128,0><<<dim3(D/128, NTOK/128, NH), 128, SMEM128>>>(
            qhi, qlo, w2h, w2l, nullptr, Z, nullptr, nullptr,
            NTOK, D, HD, D, HD, D,
            (long)HD, (long)D*HD, (long)NTOK*D, 0);

        // fused scores/softmax/aggregate
        xattn_kernel<<<NTOK, 128, XATTN_SMEM>>>(
            q, Z, memory, kpos, l2bb, idx, agghi, agglo);

        // out_h = Agg_h @ W3_h^T + b3_h  (batched over heads)
        hgemm_kernel<64,0><<<dim3(1, NTOK/128, NH), 128, SMEM64>>>(
            agghi, agglo, l3h, l3l, l3bb, attn, nullptr, nullptr,
            NTOK, HD, D, D, D, D,
            (long)NTOK*D, (long)HD*D, (long)HD, (long)HD);

        ln_kernel<<<NTOK, 256>>>(x, attn, n1_g + (long)l * D, n1_b + (long)l * D,
                                 qpos, x, xhi, xlo, xqhi, xqlo);

        // self-attn projections
        hgemm_kernel<128,0><<<dim3((2*D)/128, NTOK/128, 1), 128, SMEM128>>>(
            xqhi, xqlo, sih, sil, sab, qk, nullptr, nullptr,
            NTOK, 2*D, D, D, D, 2*D, 0, 0, 0, 0);
        hgemm_kernel<64,0><<<dim3(D/64, NTOK/128, 1), 128, SMEM64>>>(
            xhi, xlo, sih + (long)2*D*D, sil + (long)2*D*D, sab + 2*D,
            v, nullptr, nullptr, NTOK, D, D, D, D, D, 0, 0, 0, 0);

        self_attn_kernel<<<dim3(NTOK, NH), 128>>>(qk, v, sahi, salo);

        hgemm_kernel<64,0><<<dim3(D/64, NTOK/128, 1), 128, SMEM64>>>(
            sahi, salo, soh, sol, sob, tmp, nullptr, nullptr,
            NTOK, D, D, D, D, D, 0, 0, 0, 0);

        ln_kernel<<<NTOK, 256>>>(x, tmp, n2_g + (long)l * D, n2_b + (long)l * D,
                                 qpos, x, xhi, xlo, xqhi, xqlo);

        // FFN
        hgemm_kernel<128,1><<<dim3(DFF/128, NTOK/128, 1), 128, SMEM128>>>(
            xhi, xlo, f1h, f1l, f1b, nullptr, h1hi, h1lo,
            NTOK, DFF, D, D, D, DFF, 0, 0, 0, 0);
        hgemm_kernel<64,0><<<dim3(D/64, NTOK/128, 1), 128, SMEM64>>>(
            h1hi, h1lo, f2h, f2l, f2b, tmp, nullptr, nullptr,
            NTOK, D, DFF, DFF, DFF, D, 0, 0, 0, 0);

        ln_kernel<<<NTOK, 256>>>(x, tmp, n3_g + (long)l * D, n3_b + (long)l * D,
                                 qpos, x, xhi, xlo, xqhi, xqlo);
    }

    bn_stats_kernel<<<D, 256>>>(x, bn_g, bn_b, bnsc, bnsh);
    split_affine_kernel<<<2048, 256>>>(x, bnsc, bnsh, cihi, cilo, (long)NTOK * D);

    float* out = (float*)d_out;
    long xsz = (long)NTOK * D;
    long csz = (long)NTOK * NC;

    if ((long)out_size >= xsz + csz) {
        cudaMemcpyAsync(out, x, sizeof(float) * xsz, cudaMemcpyDeviceToDevice, 0);
        hgemm_kernel<64,0><<<dim3((NC+63)/64, NTOK/128, 1), 128, SMEM64>>>(
            cihi, cilo, whi + OFF_CLS, wlo + OFF_CLS, nullptr,
            out + xsz, nullptr, nullptr, NTOK, NC, D, D, D, NC, 0, 0, 0, 0);
    } else if ((long)out_size == csz) {
        hgemm_kernel<64,0><<<dim3((NC+63)/64, NTOK/128, 1), 128, SMEM64>>>(
            cihi, cilo, whi + OFF_CLS, wlo + OFF_CLS, nullptr,
            out, nullptr, nullptr, NTOK, NC, D, D, D, NC, 0, 0, 0, 0);
    } else {
        cudaMemcpyAsync(out, x, sizeof(float) * ((long)out_size < xsz ? out_size : xsz),
                        cudaMemcpyDeviceToDevice, 0);
    }
}

// round 8
// speedup vs baseline: 1.1159x; 1.1159x over previous
#include <cuda_runtime.h>
#include <cuda_bf16.h>
#include <math.h>
#include <stdint.h>

#define BS   16
#define NP   128
#define MNP  2048
#define D    768
#define NH   12
#define HD   64
#define DFF  2048
#define NLAYERS 2
#define TOPK 32
#define NC   751
#define NTOK (BS*NP)    // 2048
#define NMEM (BS*MNP)   // 32768
#define EPS  1e-5f

// ----------------------------------------------------------------------------
// Scratch (static device globals; no runtime allocation)
// ----------------------------------------------------------------------------
__device__ float g_x   [NTOK*(long)D];
__device__ float g_tmp [NTOK*(long)D];
__device__ float g_q   [NTOK*(long)D];
__device__ float g_qk  [NTOK*(long)(2*D)];
__device__ float g_v   [NTOK*(long)D];
__device__ float g_attn[NTOK*(long)D];
__device__ float g_K   [NMEM*(long)D];
__device__ float g_V   [NMEM*(long)D];
__device__ float g_sims[NTOK*(long)MNP];
__device__ int   g_idx [NTOK*TOPK];
__device__ float g_minv[NMEM];
__device__ float g_bnscale[D];
__device__ float g_bnshift[D];

// bf16 hi/lo split buffers
#define OFF_L1    0L
#define OFF_L2    1179648L
#define OFF_L3    2359296L
#define OFF_SAIN  3538944L
#define OFF_SAOUT 7077888L
#define OFF_FF1   8257536L
#define OFF_FF2   11403264L
#define OFF_CLS   14548992L
#define WTOTAL    15125760L
__device__ __nv_bfloat16 g_whi[WTOTAL], g_wlo[WTOTAL];
__device__ __nv_bfloat16 g_mkhi[NMEM*(long)D], g_mklo[NMEM*(long)D];   // mem+kpos
__device__ __nv_bfloat16 g_mhi [NMEM*(long)D], g_mlo [NMEM*(long)D];   // mem
__device__ __nv_bfloat16 g_xhi [NTOK*(long)D], g_xlo [NTOK*(long)D];   // x
__device__ __nv_bfloat16 g_xqhi[NTOK*(long)D], g_xqlo[NTOK*(long)D];   // x+qpos
__device__ __nv_bfloat16 g_h1hi[NTOK*(long)DFF], g_h1lo[NTOK*(long)DFF];
__device__ __nv_bfloat16 g_sahi[NTOK*(long)D], g_salo[NTOK*(long)D];   // self-attn out
__device__ __nv_bfloat16 g_cihi[NTOK*(long)D], g_cilo[NTOK*(long)D];   // cls input

// ----------------------------------------------------------------------------
// Helpers
// ----------------------------------------------------------------------------
__device__ __forceinline__ uint32_t smem_u32(const void* p) {
    uint32_t a;
    asm("{ .reg .u64 t; cvta.to.shared.u64 t, %1; cvt.u32.u64 %0, t; }"
        : "=r"(a) : "l"(p));
    return a;
}

#define CP_ASYNC16(dst, src) \
    asm volatile("cp.async.ca.shared.global [%0], [%1], 16;" \
                 :: "r"(dst), "l"(src) : "memory")
#define CP_COMMIT() asm volatile("cp.async.commit_group;" ::: "memory")
#define CP_WAIT(n)  asm volatile("cp.async.wait_group %0;" :: "n"(n) : "memory")

__device__ __forceinline__ void ldsm_x4(uint32_t& r0, uint32_t& r1,
                                        uint32_t& r2, uint32_t& r3, uint32_t addr)
{
    asm volatile("ldmatrix.sync.aligned.m8n8.x4.shared.b16 {%0,%1,%2,%3}, [%4];"
        : "=r"(r0), "=r"(r1), "=r"(r2), "=r"(r3) : "r"(addr));
}

__device__ __forceinline__ void mma_bf16(float c[4],
    uint32_t a0, uint32_t a1, uint32_t a2, uint32_t a3,
    uint32_t b0, uint32_t b1)
{
    asm("mma.sync.aligned.m16n8k16.row.col.f32.bf16.bf16.f32 "
        "{%0,%1,%2,%3}, {%4,%5,%6,%7}, {%8,%9}, {%0,%1,%2,%3};"
        : "+f"(c[0]), "+f"(c[1]), "+f"(c[2]), "+f"(c[3])
        : "r"(a0), "r"(a1), "r"(a2), "r"(a3), "r"(b0), "r"(b1));
}

__device__ __forceinline__ void split1(float v, __nv_bfloat16& h, __nv_bfloat16& l) {
    __nv_bfloat16 hb = __float2bfloat16_rn(v);
    h = hb;
    l = __float2bfloat16_rn(v - __bfloat162float(hb));
}

// ----------------------------------------------------------------------------
// Split kernels (fp32 -> bf16 hi/lo)
// ----------------------------------------------------------------------------
__global__ void __launch_bounds__(256) split_kernel(
    const float* __restrict__ src,
    __nv_bfloat16* __restrict__ hi, __nv_bfloat16* __restrict__ lo, long n)
{
    long i = blockIdx.x * 256L + threadIdx.x;
    long stride = (long)gridDim.x * 256;
    for (; i < n; i += stride) {
        __nv_bfloat16 h, l;
        split1(src[i], h, l);
        hi[i] = h; lo[i] = l;
    }
}

__global__ void __launch_bounds__(256) split_add_kernel(
    const float* __restrict__ a, const float* __restrict__ b,
    __nv_bfloat16* __restrict__ hi, __nv_bfloat16* __restrict__ lo, long n)
{
    long i = blockIdx.x * 256L + threadIdx.x;
    long stride = (long)gridDim.x * 256;
    for (; i < n; i += stride) {
        __nv_bfloat16 h, l;
        split1(a[i] + b[i], h, l);
        hi[i] = h; lo[i] = l;
    }
}

__global__ void __launch_bounds__(256) split_affine_kernel(
    const float* __restrict__ src, const float* __restrict__ scale,
    const float* __restrict__ shift,
    __nv_bfloat16* __restrict__ hi, __nv_bfloat16* __restrict__ lo, long n)
{
    long i = blockIdx.x * 256L + threadIdx.x;
    long stride = (long)gridDim.x * 256;
    for (; i < n; i += stride) {
        int k = (int)(i % D);
        __nv_bfloat16 h, l;
        split1(src[i] * scale[k] + shift[k], h, l);
        hi[i] = h; lo[i] = l;
    }
}

// ----------------------------------------------------------------------------
// bf16x3 tensor-core GEMM with ldmatrix fragment loads.
// C[M,N] = (Ah+Al)[M,K] @ (Bh+Bl)[N,K]^T  (3-term: AhBh + AhBl + AlBh)
// 256 threads = 8 warps; warp tile 64 x (BN/4). BM=128, BK=32, double-buffered.
// EPI: 0 = (+bias) fp32 ; 1 = gelu(+bias) -> bf16 split
// M % 128 == 0, K % 32 == 0; N arbitrary (B rows zero-filled, stores guarded).
// ----------------------------------------------------------------------------
template<int BN, int EPI>
__global__ void __launch_bounds__(256) hgemm_kernel(
    const __nv_bfloat16* __restrict__ Ah, const __nv_bfloat16* __restrict__ Al,
    const __nv_bfloat16* __restrict__ Bh, const __nv_bfloat16* __restrict__ Bl,
    const float* __restrict__ bias,
    float* __restrict__ C,
    __nv_bfloat16* __restrict__ Chi, __nv_bfloat16* __restrict__ Clo,
    int M, int N, int K)
{
    constexpr int BM = 128;
    constexpr int NT = BN / 32;          // n8-tiles per warp (4 col-warps)
    constexpr int ROWS = BM + BN;
    extern __shared__ __align__(16) __nv_bfloat16 smem[];

    const int tid  = threadIdx.x;
    const int wid  = tid >> 5;
    const int lane = tid & 31;
    const int wm   = wid & 1;            // 2 row-halves of 64
    const int wn   = wid >> 1;           // 4 col groups of BN/4
    const int qm   = lane >> 2;
    const int qk   = lane & 3;
    const int bm = blockIdx.y * BM;
    const int bn = blockIdx.x * BN;
    const uint32_t sbase = smem_u32(smem);

    float acc[4][NT][4];
#pragma unroll
    for (int mt = 0; mt < 4; mt++)
#pragma unroll
        for (int nt = 0; nt < NT; nt++)
#pragma unroll
            for (int r = 0; r < 4; r++) acc[mt][nt][r] = 0.f;

    auto loadStage = [&](int s, int k0) {
        const uint32_t pH = sbase + (uint32_t)(s * 2 + 0) * ROWS * 80;
        const uint32_t pL = sbase + (uint32_t)(s * 2 + 1) * ROWS * 80;
#pragma unroll
        for (int c = tid; c < BM * 4; c += 256) {
            int row = c >> 2, kc = c & 3;
            long gofs = (long)(bm + row) * K + k0;
            CP_ASYNC16(pH + row * 80 + kc * 16, (const char*)(Ah + gofs) + kc * 16);
            CP_ASYNC16(pL + row * 80 + kc * 16, (const char*)(Al + gofs) + kc * 16);
        }
#pragma unroll
        for (int c = tid; c < BN * 4; c += 256) {
            int row = c >> 2, kc = c & 3;
            int n = bn + row;
            uint32_t dh = pH + (BM + row) * 80 + kc * 16;
            uint32_t dl = pL + (BM + row) * 80 + kc * 16;
            if (n < N) {
                long gofs = (long)n * K + k0;
                CP_ASYNC16(dh, (const char*)(Bh + gofs) + kc * 16);
                CP_ASYNC16(dl, (const char*)(Bl + gofs) + kc * 16);
            } else {
                uint32_t z = 0;
                asm volatile("st.shared.v4.b32 [%0], {%1,%1,%1,%1};" :: "r"(dh), "r"(z) : "memory");
                asm volatile("st.shared.v4.b32 [%0], {%1,%1,%1,%1};" :: "r"(dl), "r"(z) : "memory");
            }
        }
    };

    auto compute = [&](int s) {
        const uint32_t baseH = sbase + (uint32_t)(s * 2 + 0) * ROWS * 80;
        const uint32_t baseL = sbase + (uint32_t)(s * 2 + 1) * ROWS * 80;
#pragma unroll
        for (int kc = 0; kc < 2; kc++) {
            uint32_t ah[4][4], al[4][4], bh[NT][2], bl[NT][2];
            // A fragments: ldmatrix x4 per m16 tile (mats: m0k0, m8k0, m0k8, m8k8)
            const int arow = wm * 64 + (lane & 15);
            const uint32_t acol = kc * 32 + ((lane & 16) ? 16 : 0);
#pragma unroll
            for (int mt = 0; mt < 4; mt++) {
                uint32_t ro = (uint32_t)(arow + mt * 16) * 80 + acol;
                ldsm_x4(ah[mt][0], ah[mt][1], ah[mt][2], ah[mt][3], baseH + ro);
                ldsm_x4(al[mt][0], al[mt][1], al[mt][2], al[mt][3], baseL + ro);
            }
            // B fragments: ldmatrix x4 covers two adjacent n8 tiles (b0,b1 each)
            const int brow = BM + wn * (BN / 4) + (lane & 7) + ((lane & 16) ? 8 : 0);
            const uint32_t bcol = kc * 32 + ((lane & 8) ? 16 : 0);
#pragma unroll
            for (int np = 0; np < NT / 2; np++) {
                uint32_t ro = (uint32_t)(brow + np * 16) * 80 + bcol;
                ldsm_x4(bh[2*np][0], bh[2*np][1], bh[2*np+1][0], bh[2*np+1][1], baseH + ro);
                ldsm_x4(bl[2*np][0], bl[2*np][1], bl[2*np+1][0], bl[2*np+1][1], baseL + ro);
            }
#pragma unroll
            for (int mt = 0; mt < 4; mt++)
#pragma unroll
                for (int nt = 0; nt < NT; nt++) {
                    mma_bf16(acc[mt][nt], ah[mt][0], ah[mt][1], ah[mt][2], ah[mt][3],
                             bh[nt][0], bh[nt][1]);
                    mma_bf16(acc[mt][nt], ah[mt][0], ah[mt][1], ah[mt][2], ah[mt][3],
                             bl[nt][0], bl[nt][1]);
                    mma_bf16(acc[mt][nt], al[mt][0], al[mt][1], al[mt][2], al[mt][3],
                             bh[nt][0], bh[nt][1]);
                }
        }
    };

    const int niter = K >> 5;
    loadStage(0, 0); CP_COMMIT();
    for (int i = 0; i < niter; i++) {
        if (i + 1 < niter) { loadStage((i + 1) & 1, (i + 1) << 5); CP_COMMIT(); CP_WAIT(1); }
        else               { CP_WAIT(0); }
        __syncthreads();
        compute(i & 1);
        __syncthreads();
    }

    // Epilogue
#pragma unroll
    for (int mt = 0; mt < 4; mt++) {
        int r0 = bm + wm * 64 + mt * 16 + qm;
#pragma unroll
        for (int nt = 0; nt < NT; nt++) {
            int c0 = bn + wn * (BN / 4) + nt * 8 + qk * 2;
            float v0 = acc[mt][nt][0], v1 = acc[mt][nt][1];
            float v2 = acc[mt][nt][2], v3 = acc[mt][nt][3];
            if (bias) {
                float b0 = (c0 < N) ? bias[c0] : 0.f;
                float b1 = (c0 + 1 < N) ? bias[c0 + 1] : 0.f;
                v0 += b0; v1 += b1; v2 += b0; v3 += b1;
            }
            if (EPI == 1) {
                v0 = 0.5f * v0 * (1.f + erff(v0 * 0.70710678118654752f));
                v1 = 0.5f * v1 * (1.f + erff(v1 * 0.70710678118654752f));
                v2 = 0.5f * v2 * (1.f + erff(v2 * 0.70710678118654752f));
                v3 = 0.5f * v3 * (1.f + erff(v3 * 0.70710678118654752f));
                __nv_bfloat162 h2, l2;
                split1(v0, h2.x, l2.x); split1(v1, h2.y, l2.y);
                *(__nv_bfloat162*)(Chi + (long)r0 * N + c0) = h2;
                *(__nv_bfloat162*)(Clo + (long)r0 * N + c0) = l2;
                split1(v2, h2.x, l2.x); split1(v3, h2.y, l2.y);
                *(__nv_bfloat162*)(Chi + (long)(r0 + 8) * N + c0) = h2;
                *(__nv_bfloat162*)(Clo + (long)(r0 + 8) * N + c0) = l2;
            } else {
                if (c0 < N) {
                    C[(long)r0 * N + c0] = v0;
                    C[(long)(r0 + 8) * N + c0] = v2;
                }
                if (c0 + 1 < N) {
                    C[(long)r0 * N + c0 + 1] = v1;
                    C[(long)(r0 + 8) * N + c0 + 1] = v3;
                }
            }
        }
    }
}

// ----------------------------------------------------------------------------
// FP32 scalar GEMM (exact path for sims -> top-k selection stability).
// ----------------------------------------------------------------------------
__global__ void __launch_bounds__(256) f32_gemm_kernel(
    const float* __restrict__ A, const float* __restrict__ B,
    float* __restrict__ C, int M, int N, int K,
    long sA, long sB, long sC)
{
    constexpr int BM = 128, BN = 128, BK = 8;
    int bz = blockIdx.z;
    A += bz * sA; B += bz * sB; C += bz * sC;
    int bm = blockIdx.y * BM, bn = blockIdx.x * BN;

    __shared__ float As[BK][BM + 4];
    __shared__ float Bs[BK][BN + 4];

    int tid = threadIdx.x;
    int tx = tid & 15, ty = tid >> 4;

    float acc[8][8];
#pragma unroll
    for (int i = 0; i < 8; i++)
#pragma unroll
        for (int j = 0; j < 8; j++) acc[i][j] = 0.f;

    for (int k0 = 0; k0 < K; k0 += BK) {
#pragma unroll
        for (int l = 0; l < 4; l++) {
            int lin = tid + l * 256;
            int kk = lin & 7, r = lin >> 3;
            int m = bm + r;
            As[kk][r] = (m < M) ? A[(long)m * K + k0 + kk] : 0.f;
        }
#pragma unroll
        for (int l = 0; l < 4; l++) {
            int lin = tid + l * 256;
            int kk = lin & 7, r = lin >> 3;
            int n = bn + r;
            Bs[kk][r] = (n < N) ? B[(long)n * K + k0 + kk] : 0.f;
        }
        __syncthreads();
#pragma unroll
        for (int k = 0; k < BK; k++) {
            float a[8], b[8];
            *(float4*)&a[0] = *(const float4*)&As[k][ty * 8];
            *(float4*)&a[4] = *(const float4*)&As[k][ty * 8 + 4];
            *(float4*)&b[0] = *(const float4*)&Bs[k][tx * 8];
            *(float4*)&b[4] = *(const float4*)&Bs[k][tx * 8 + 4];
#pragma unroll
            for (int i = 0; i < 8; i++)
#pragma unroll
                for (int j = 0; j < 8; j++)
                    acc[i][j] = fmaf(a[i], b[j], acc[i][j]);
        }
        __syncthreads();
    }
#pragma unroll
    for (int i = 0; i < 8; i++) {
        int m = bm + ty * 8 + i;
        if (m >= M) continue;
#pragma unroll
        for (int j = 0; j < 8; j++) {
            int n = bn + tx * 8 + j;
            if (n < N) C[(long)m * N + n] = acc[i][j];
        }
    }
}

// ----------------------------------------------------------------------------
// LayerNorm over last dim (D=768) + fused bf16 splits of x and x+qpos.
// ----------------------------------------------------------------------------
__global__ void __launch_bounds__(256) ln_kernel(
    const float* __restrict__ x, const float* __restrict__ add,
    const float* __restrict__ g, const float* __restrict__ b,
    const float* __restrict__ qpos,
    float* __restrict__ out,
    __nv_bfloat16* __restrict__ ohi, __nv_bfloat16* __restrict__ olo,
    __nv_bfloat16* __restrict__ oqhi, __nv_bfloat16* __restrict__ oqlo)
{
    int row = blockIdx.x, tid = threadIdx.x;
    const float* xr = x + (long)row * D;
    float vals[3];
    float s = 0.f, sq = 0.f;
#pragma unroll
    for (int i = 0; i < 3; i++) {
        int c = tid + i * 256;
        float v = xr[c];
        if (add) v += add[(long)row * D + c];
        vals[i] = v; s += v; sq += v * v;
    }
    __shared__ float rs[256], rq[256];
    rs[tid] = s; rq[tid] = sq;
    __syncthreads();
    for (int o = 128; o > 0; o >>= 1) {
        if (tid < o) { rs[tid] += rs[tid + o]; rq[tid] += rq[tid + o]; }
        __syncthreads();
    }
    float mu = rs[0] * (1.f / D);
    float var = rq[0] * (1.f / D) - mu * mu;
    float rstd = rsqrtf(var + EPS);
#pragma unroll
    for (int i = 0; i < 3; i++) {
        int c = tid + i * 256;
        long o = (long)row * D + c;
        float v = (vals[i] - mu) * rstd * g[c] + b[c];
        out[o] = v;
        __nv_bfloat16 h, l;
        split1(v, h, l);
        ohi[o] = h; olo[o] = l;
        split1(v + qpos[o], h, l);
        oqhi[o] = h; oqlo[o] = l;
    }
}

__global__ void __launch_bounds__(256) rownorm_kernel(
    const float* __restrict__ m, float* __restrict__ minv)
{
    int row = blockIdx.x, tid = threadIdx.x;
    float s = 0.f;
#pragma unroll
    for (int i = 0; i < 3; i++) {
        float v = m[(long)row * D + tid + i * 256];
        s += v * v;
    }
    __shared__ float rs[256];
    rs[tid] = s; __syncthreads();
    for (int o = 128; o > 0; o >>= 1) {
        if (tid < o) rs[tid] += rs[tid + o];
        __syncthreads();
    }
    if (tid == 0) minv[row] = rsqrtf(rs[0]);
}

// ----------------------------------------------------------------------------
// Top-32 per query row (iterative block argmax over smem copy).
// ----------------------------------------------------------------------------
__global__ void __launch_bounds__(256) topk_kernel(
    const float* __restrict__ sims, const float* __restrict__ minv,
    int* __restrict__ idx_out)
{
    int row = blockIdx.x;
    int b = row / NP;
    int tid = threadIdx.x;
    __shared__ float s[MNP];
    __shared__ float rmax[256];
    __shared__ int   rarg[256];
    for (int i = tid; i < MNP; i += 256)
        s[i] = sims[(long)row * MNP + i] * minv[b * MNP + i];
    __syncthreads();
    for (int t = 0; t < TOPK; t++) {
        float best = -INFINITY; int bi = 0x7fffffff;
        for (int i = tid; i < MNP; i += 256) {
            float v = s[i];
            if (v > best) { best = v; bi = i; }
        }
        rmax[tid] = best; rarg[tid] = bi;
        __syncthreads();
        for (int o = 128; o > 0; o >>= 1) {
            if (tid < o) {
                float ov = rmax[tid + o]; int oi = rarg[tid + o];
                if (ov > rmax[tid] || (ov == rmax[tid] && oi < rarg[tid])) {
                    rmax[tid] = ov; rarg[tid] = oi;
                }
            }
            __syncthreads();
        }
        if (tid == 0) {
            idx_out[row * TOPK + t] = rarg[0];
            s[rarg[0]] = -INFINITY;
        }
        __syncthreads();
    }
}

// ----------------------------------------------------------------------------
// Sparse cross-attention (32 gathered keys per query,head)
// ----------------------------------------------------------------------------
__global__ void __launch_bounds__(128) cross_attn_kernel(
    const float* __restrict__ q, const float* __restrict__ K,
    const float* __restrict__ V, const int* __restrict__ idx,
    float* __restrict__ out)
{
    int row = blockIdx.x;
    int b = row >> 7;
    int warp = threadIdx.x >> 5, lane = threadIdx.x & 31;
    int h = blockIdx.y * 4 + warp;

    __shared__ float qv[4][HD];
    __shared__ float ps[4][TOPK];
    __shared__ int   id[4][TOPK];

    const float* qr = q + (long)row * D + h * HD;
    qv[warp][lane] = qr[lane];
    qv[warp][lane + 32] = qr[lane + 32];
    int ix = idx[row * TOPK + lane];
    id[warp][lane] = ix;
    __syncwarp();

    const float* kr = K + ((long)(b * MNP + ix)) * D + h * HD;
    float s = 0.f;
#pragma unroll
    for (int d = 0; d < HD; d++) s = fmaf(qv[warp][d], kr[d], s);
    s *= 0.125f;

    float m = s;
#pragma unroll
    for (int o = 16; o > 0; o >>= 1) m = fmaxf(m, __shfl_xor_sync(0xffffffffu, m, o));
    float e = expf(s - m);
    float sum = e;
#pragma unroll
    for (int o = 16; o > 0; o >>= 1) sum += __shfl_xor_sync(0xffffffffu, sum, o);
    ps[warp][lane] = e / sum;
    __syncwarp();

    float acc0 = 0.f, acc1 = 0.f;
#pragma unroll
    for (int j = 0; j < TOPK; j++) {
        const float* vr = V + ((long)(b * MNP + id[warp][j])) * D + h * HD;
        float p = ps[warp][j];
        acc0 = fmaf(p, vr[lane], acc0);
        acc1 = fmaf(p, vr[lane + 32], acc1);
    }
    float* orow = out + (long)row * D + h * HD;
    orow[lane] = acc0;
    orow[lane + 32] = acc1;
}

// ----------------------------------------------------------------------------
// Dense self-attention over NP=128 keys -> writes bf16 hi/lo split directly.
// ----------------------------------------------------------------------------
__global__ void __launch_bounds__(128) self_attn_kernel(
    const float* __restrict__ qk, const float* __restrict__ v,
    __nv_bfloat16* __restrict__ ohi, __nv_bfloat16* __restrict__ olo)
{
    int row = blockIdx.x;
    int b = row >> 7;
    int h = blockIdx.y;
    int tid = threadIdx.x;

    __shared__ float qv[HD];
    __shared__ float sc[NP];
    __shared__ float red[128];

    const float* qr = qk + (long)row * (2 * D) + h * HD;
    if (tid < HD) qv[tid] = qr[tid];
    __syncthreads();

    const float* kr = qk + (long)(b * NP + tid) * (2 * D) + D + h * HD;
    float s = 0.f;
#pragma unroll
    for (int d = 0; d < HD; d++) s = fmaf(qv[d], kr[d], s);
    s *= 0.125f;

    red[tid] = s; __syncthreads();
    for (int o = 64; o > 0; o >>= 1) {
        if (tid < o) red[tid] = fmaxf(red[tid], red[tid + o]);
        __syncthreads();
    }
    float m = red[0]; __syncthreads();
    float e = expf(s - m);
    sc[tid] = e;
    red[tid] = e; __syncthreads();
    for (int o = 64; o > 0; o >>= 1) {
        if (tid < o) red[tid] += red[tid + o];
        __syncthreads();
    }
    float inv = 1.f / red[0];

    if (tid < HD) {
        float acc = 0.f;
        for (int j = 0; j < NP; j++)
            acc = fmaf(sc[j], v[(long)(b * NP + j) * D + h * HD + tid], acc);
        long o = (long)row * D + h * HD + tid;
        __nv_bfloat16 hh, ll;
        split1(acc * inv, hh, ll);
        ohi[o] = hh; olo[o] = ll;
    }
}

// ----------------------------------------------------------------------------
// BatchNorm stats -> fused scale/shift
// ----------------------------------------------------------------------------
__global__ void __launch_bounds__(256) bn_stats_kernel(
    const float* __restrict__ x, const float* __restrict__ g,
    const float* __restrict__ b, float* __restrict__ scale,
    float* __restrict__ shift)
{
    int f = blockIdx.x, tid = threadIdx.x;
    float s = 0.f, sq = 0.f;
    for (int r = tid; r < NTOK; r += 256) {
        float v = x[(long)r * D + f];
        s += v; sq += v * v;
    }
    __shared__ float rs[256], rq[256];
    rs[tid] = s; rq[tid] = sq;
    __syncthreads();
    for (int o = 128; o > 0; o >>= 1) {
        if (tid < o) { rs[tid] += rs[tid + o]; rq[tid] += rq[tid + o]; }
        __syncthreads();
    }
    if (tid == 0) {
        float mu = rs[0] * (1.f / NTOK);
        float var = rq[0] * (1.f / NTOK) - mu * mu;
        float rstd = rsqrtf(var + EPS);
        float sc = rstd * g[f];
        scale[f] = sc;
        shift[f] = b[f] - mu * sc;
    }
}

// ----------------------------------------------------------------------------
// Host orchestration
// ----------------------------------------------------------------------------
#define SMEM128 (2 * 2 * 256 * 80)   // 81920
#define SMEM64  (2 * 2 * 192 * 80)   // 61440

static void launch_hgemm(int bn_tile, int epi,
    const __nv_bfloat16* Ah, const __nv_bfloat16* Al,
    const __nv_bfloat16* Bh, const __nv_bfloat16* Bl,
    const float* bias, float* C, __nv_bfloat16* Chi, __nv_bfloat16* Clo,
    int M, int N, int K)
{
    if (bn_tile == 128) {
        dim3 grid((N + 127) / 128, M / 128);
        if (epi == 0)
            hgemm_kernel<128,0><<<grid, 256, SMEM128>>>(Ah, Al, Bh, Bl, bias, C, Chi, Clo, M, N, K);
        else
            hgemm_kernel<128,1><<<grid, 256, SMEM128>>>(Ah, Al, Bh, Bl, bias, C, Chi, Clo, M, N, K);
    } else {
        dim3 grid((N + 63) / 64, M / 128);
        hgemm_kernel<64,0><<<grid, 256, SMEM64>>>(Ah, Al, Bh, Bl, bias, C, Chi, Clo, M, N, K);
    }
}

extern "C" void kernel_launch(void* const* d_in, const int* in_sizes, int n_in,
                              void* d_out, int out_size)
{
    const float* tgt      = (const float*)d_in[0];
    const float* memory   = (const float*)d_in[1];
    const float* qpos     = (const float*)d_in[2];
    const float* kpos     = (const float*)d_in[3];
    const float* norm0_g  = (const float*)d_in[4];
    const float* norm0_b  = (const float*)d_in[5];
    const float* l1_w     = (const float*)d_in[6];
    const float* l1_b     = (const float*)d_in[7];
    const float* l2_w     = (const float*)d_in[8];
    const float* l2_b     = (const float*)d_in[9];
    const float* l3_w     = (const float*)d_in[10];
    const float* l3_b     = (const float*)d_in[11];
    const float* n1_g     = (const float*)d_in[12];
    const float* n1_b     = (const float*)d_in[13];
    const float* n2_g     = (const float*)d_in[14];
    const float* n2_b     = (const float*)d_in[15];
    const float* n3_g     = (const float*)d_in[16];
    const float* n3_b     = (const float*)d_in[17];
    const float* sa_in_w  = (const float*)d_in[18];
    const float* sa_in_b  = (const float*)d_in[19];
    const float* sa_out_w = (const float*)d_in[20];
    const float* sa_out_b = (const float*)d_in[21];
    const float* ff1_w    = (const float*)d_in[22];
    const float* ff1_b    = (const float*)d_in[23];
    const float* ff2_w    = (const float*)d_in[24];
    const float* ff2_b    = (const float*)d_in[25];
    const float* bn_g     = (const float*)d_in[26];
    const float* bn_b     = (const float*)d_in[27];
    const float* cls_w    = (const float*)d_in[28];

    float *x, *tmp, *q, *qk, *v, *attn, *Kb, *Vb, *sims, *minv, *bnsc, *bnsh;
    int* idx;
    __nv_bfloat16 *whi, *wlo, *mkhi, *mklo, *mhi, *mlo;
    __nv_bfloat16 *xhi, *xlo, *xqhi, *xqlo, *h1hi, *h1lo, *sahi, *salo, *cihi, *cilo;
    cudaGetSymbolAddress((void**)&x,    g_x);
    cudaGetSymbolAddress((void**)&tmp,  g_tmp);
    cudaGetSymbolAddress((void**)&q,    g_q);
    cudaGetSymbolAddress((void**)&qk,   g_qk);
    cudaGetSymbolAddress((void**)&v,    g_v);
    cudaGetSymbolAddress((void**)&attn, g_attn);
    cudaGetSymbolAddress((void**)&Kb,   g_K);
    cudaGetSymbolAddress((void**)&Vb,   g_V);
    cudaGetSymbolAddress((void**)&sims, g_sims);
    cudaGetSymbolAddress((void**)&idx,  g_idx);
    cudaGetSymbolAddress((void**)&minv, g_minv);
    cudaGetSymbolAddress((void**)&bnsc, g_bnscale);
    cudaGetSymbolAddress((void**)&bnsh, g_bnshift);
    cudaGetSymbolAddress((void**)&whi,  g_whi);
    cudaGetSymbolAddress((void**)&wlo,  g_wlo);
    cudaGetSymbolAddress((void**)&mkhi, g_mkhi);
    cudaGetSymbolAddress((void**)&mklo, g_mklo);
    cudaGetSymbolAddress((void**)&mhi,  g_mhi);
    cudaGetSymbolAddress((void**)&mlo,  g_mlo);
    cudaGetSymbolAddress((void**)&xhi,  g_xhi);
    cudaGetSymbolAddress((void**)&xlo,  g_xlo);
    cudaGetSymbolAddress((void**)&xqhi, g_xqhi);
    cudaGetSymbolAddress((void**)&xqlo, g_xqlo);
    cudaGetSymbolAddress((void**)&h1hi, g_h1hi);
    cudaGetSymbolAddress((void**)&h1lo, g_h1lo);
    cudaGetSymbolAddress((void**)&sahi, g_sahi);
    cudaGetSymbolAddress((void**)&salo, g_salo);
    cudaGetSymbolAddress((void**)&cihi, g_cihi);
    cudaGetSymbolAddress((void**)&cilo, g_cilo);

    cudaFuncSetAttribute(hgemm_kernel<128,0>, cudaFuncAttributeMaxDynamicSharedMemorySize, SMEM128);
    cudaFuncSetAttribute(hgemm_kernel<128,1>, cudaFuncAttributeMaxDynamicSharedMemorySize, SMEM128);
    cudaFuncSetAttribute(hgemm_kernel<64,0>,  cudaFuncAttributeMaxDynamicSharedMemorySize, SMEM64);

    // ---- one-time (per call) splits ----
    split_kernel<<<4096, 256>>>(l1_w,     whi + OFF_L1,    wlo + OFF_L1,    (long)NLAYERS*D*D);
    split_kernel<<<4096, 256>>>(l2_w,     whi + OFF_L2,    wlo + OFF_L2,    (long)NLAYERS*D*D);
    split_kernel<<<4096, 256>>>(l3_w,     whi + OFF_L3,    wlo + OFF_L3,    (long)NLAYERS*D*D);
    split_kernel<<<4096, 256>>>(sa_in_w,  whi + OFF_SAIN,  wlo + OFF_SAIN,  (long)NLAYERS*3*D*D);
    split_kernel<<<4096, 256>>>(sa_out_w, whi + OFF_SAOUT, wlo + OFF_SAOUT, (long)NLAYERS*D*D);
    split_kernel<<<4096, 256>>>(ff1_w,    whi + OFF_FF1,   wlo + OFF_FF1,   (long)NLAYERS*DFF*D);
    split_kernel<<<4096, 256>>>(ff2_w,    whi + OFF_FF2,   wlo + OFF_FF2,   (long)NLAYERS*D*DFF);
    split_kernel<<<4096, 256>>>(cls_w,    whi + OFF_CLS,   wlo + OFF_CLS,   (long)NC*D);
    split_add_kernel<<<8192, 256>>>(memory, kpos, mkhi, mklo, (long)NMEM*D);
    split_kernel<<<8192, 256>>>(memory, mhi, mlo, (long)NMEM*D);

    rownorm_kernel<<<NMEM, 256>>>(memory, minv);
    ln_kernel<<<NTOK, 256>>>(tgt, nullptr, norm0_g, norm0_b, qpos,
                             x, xhi, xlo, xqhi, xqlo);

    for (int l = 0; l < NLAYERS; l++) {
        long wdd = (long)l * D * D;
        const __nv_bfloat16* l1h = whi + OFF_L1 + wdd;  const __nv_bfloat16* l1l = wlo + OFF_L1 + wdd;
        const __nv_bfloat16* l2h = whi + OFF_L2 + wdd;  const __nv_bfloat16* l2l = wlo + OFF_L2 + wdd;
        const __nv_bfloat16* l3h = whi + OFF_L3 + wdd;  const __nv_bfloat16* l3l = wlo + OFF_L3 + wdd;
        const __nv_bfloat16* sih = whi + OFF_SAIN + (long)l*3*D*D;
        const __nv_bfloat16* sil = wlo + OFF_SAIN + (long)l*3*D*D;
        const __nv_bfloat16* soh = whi + OFF_SAOUT + wdd;
        const __nv_bfloat16* sol = wlo + OFF_SAOUT + wdd;
        const __nv_bfloat16* f1h = whi + OFF_FF1 + (long)l*DFF*D;
        const __nv_bfloat16* f1l = wlo + OFF_FF1 + (long)l*DFF*D;
        const __nv_bfloat16* f2h = whi + OFF_FF2 + (long)l*D*DFF;
        const __nv_bfloat16* f2l = wlo + OFF_FF2 + (long)l*D*DFF;
        const float* l1bb = l1_b + (long)l * D;
        const float* l2bb = l2_b + (long)l * D;
        const float* l3bb = l3_b + (long)l * D;
        const float* sab  = sa_in_b + (long)l * 3 * D;
        const float* sob  = sa_out_b + (long)l * D;
        const float* f1b  = ff1_b + (long)l * DFF;
        const float* f2b  = ff2_b + (long)l * D;

        // sims[b] = x[b] @ memory[b]^T  — FP32 EXACT (top-k selection stability)
        f32_gemm_kernel<<<dim3(MNP / 128, 1, BS), 256>>>(
            x, memory, sims, NP, MNP, D,
            (long)NP * D, (long)MNP * D, (long)NP * MNP);

        topk_kernel<<<NTOK, 256>>>(sims, minv, idx);

        // q = (x + qpos) @ l1_w^T + b
        launch_hgemm(64, 0, xqhi, xqlo, l1h, l1l, l1bb, q, nullptr, nullptr, NTOK, D, D);

        // K = (mem + kpos) @ l2_w^T + b ; V = mem @ l3_w^T + b
        launch_hgemm(128, 0, mkhi, mklo, l2h, l2l, l2bb, Kb, nullptr, nullptr, NMEM, D, D);
        launch_hgemm(128, 0, mhi,  mlo,  l3h, l3l, l3bb, Vb, nullptr, nullptr, NMEM, D, D);

        cross_attn_kernel<<<dim3(NTOK, NH / 4), 128>>>(q, Kb, Vb, idx, attn);

        ln_kernel<<<NTOK, 256>>>(x, attn, n1_g + (long)l * D, n1_b + (long)l * D,
                                 qpos, x, xhi, xlo, xqhi, xqlo);

        // self-attn projections: [q;k] = (x+qpos) @ [wq;wk]^T ; v = x @ wv^T
        launch_hgemm(128, 0, xqhi, xqlo, sih, sil, sab, qk, nullptr, nullptr, NTOK, 2 * D, D);
        launch_hgemm(64, 0, xhi, xlo, sih + (long)2*D*D, sil + (long)2*D*D, sab + 2*D,
                     v, nullptr, nullptr, NTOK, D, D);

        self_attn_kernel<<<dim3(NTOK, NH), 128>>>(qk, v, sahi, salo);

        launch_hgemm(64, 0, sahi, salo, soh, sol, sob, tmp, nullptr, nullptr, NTOK, D, D);

        ln_kernel<<<NTOK, 256>>>(x, tmp, n2_g + (long)l * D, n2_b + (long)l * D,
                                 qpos, x, xhi, xlo, xqhi, xqlo);

        // FFN: h1 = gelu(x @ ff1^T + b1) -> bf16 split ; tmp = h1 @ ff2^T + b2
        launch_hgemm(128, 1, xhi, xlo, f1h, f1l, f1b, nullptr, h1hi, h1lo, NTOK, DFF, D);
        launch_hgemm(64, 0, h1hi, h1lo, f2h, f2l, f2b, tmp, nullptr, nullptr, NTOK, D, DFF);

        ln_kernel<<<NTOK, 256>>>(x, tmp, n3_g + (long)l * D, n3_b + (long)l * D,
                                 qpos, x, xhi, xlo, xqhi, xqlo);
    }

    bn_stats_kernel<<<D, 256>>>(x, bn_g, bn_b, bnsc, bnsh);
    split_affine_kernel<<<2048, 256>>>(x, bnsc, bnsh, cihi, cilo, (long)NTOK * D);

    float* out = (float*)d_out;
    long xsz = (long)NTOK * D;
    long csz = (long)NTOK * NC;

    if ((long)out_size >= xsz + csz) {
        cudaMemcpyAsync(out, x, sizeof(float) * xsz, cudaMemcpyDeviceToDevice, 0);
        launch_hgemm(64, 0, cihi, cilo, whi + OFF_CLS, wlo + OFF_CLS, nullptr,
                     out + xsz, nullptr, nullptr, NTOK, NC, D);
    } else if ((long)out_size == csz) {
        launch_hgemm(64, 0, cihi, cilo, whi + OFF_CLS, wlo + OFF_CLS, nullptr,
                     out, nullptr, nullptr, NTOK, NC, D);
    } else {
        cudaMemcpyAsync(out, x, sizeof(float) * ((long)out_size < xsz ? out_size : xsz),
                        cudaMemcpyDeviceToDevice, 0);
    }
}

// round 9
// speedup vs baseline: 1.1875x; 1.0642x over previous
#include <cuda_runtime.h>
#include <cuda_bf16.h>
#include <math.h>
#include <stdint.h>

#define BS   16
#define NP   128
#define MNP  2048
#define D    768
#define NH   12
#define HD   64
#define DFF  2048
#define NLAYERS 2
#define TOPK 32
#define CN   40          // coarse candidates for exact rescore
#define NC   751
#define NTOK (BS*NP)    // 2048
#define NMEM (BS*MNP)   // 32768
#define EPS  1e-5f

// ----------------------------------------------------------------------------
// Scratch (static device globals; no runtime allocation)
// ----------------------------------------------------------------------------
__device__ float g_x   [NTOK*(long)D];
__device__ float g_tmp [NTOK*(long)D];
__device__ float g_q   [NTOK*(long)D];
__device__ float g_qk  [NTOK*(long)(2*D)];
__device__ float g_v   [NTOK*(long)D];
__device__ float g_attn[NTOK*(long)D];
__device__ float g_K   [NMEM*(long)D];
__device__ float g_V   [NMEM*(long)D];
__device__ float g_sims[NTOK*(long)MNP];
__device__ int   g_idx [NTOK*TOPK];
__device__ float g_minv[NMEM];
__device__ float g_bnscale[D];
__device__ float g_bnshift[D];

// bf16 hi/lo split buffers
#define OFF_L1    0L
#define OFF_L2    1179648L
#define OFF_L3    2359296L
#define OFF_SAIN  3538944L
#define OFF_SAOUT 7077888L
#define OFF_FF1   8257536L
#define OFF_FF2   11403264L
#define OFF_CLS   14548992L
#define WTOTAL    15125760L
__device__ __nv_bfloat16 g_whi[WTOTAL], g_wlo[WTOTAL];
__device__ __nv_bfloat16 g_mkhi[NMEM*(long)D], g_mklo[NMEM*(long)D];   // mem+kpos
__device__ __nv_bfloat16 g_mhi [NMEM*(long)D], g_mlo [NMEM*(long)D];   // mem
__device__ __nv_bfloat16 g_xhi [NTOK*(long)D], g_xlo [NTOK*(long)D];   // x
__device__ __nv_bfloat16 g_xqhi[NTOK*(long)D], g_xqlo[NTOK*(long)D];   // x+qpos
__device__ __nv_bfloat16 g_h1hi[NTOK*(long)DFF], g_h1lo[NTOK*(long)DFF];
__device__ __nv_bfloat16 g_sahi[NTOK*(long)D], g_salo[NTOK*(long)D];   // self-attn out
__device__ __nv_bfloat16 g_cihi[NTOK*(long)D], g_cilo[NTOK*(long)D];   // cls input

// ----------------------------------------------------------------------------
// Helpers
// ----------------------------------------------------------------------------
__device__ __forceinline__ uint32_t smem_u32(const void* p) {
    uint32_t a;
    asm("{ .reg .u64 t; cvta.to.shared.u64 t, %1; cvt.u32.u64 %0, t; }"
        : "=r"(a) : "l"(p));
    return a;
}

#define CP_ASYNC16(dst, src) \
    asm volatile("cp.async.ca.shared.global [%0], [%1], 16;" \
                 :: "r"(dst), "l"(src) : "memory")
#define CP_COMMIT() asm volatile("cp.async.commit_group;" ::: "memory")
#define CP_WAIT(n)  asm volatile("cp.async.wait_group %0;" :: "n"(n) : "memory")

__device__ __forceinline__ void ldsm_x4(uint32_t& r0, uint32_t& r1,
                                        uint32_t& r2, uint32_t& r3, uint32_t addr)
{
    asm volatile("ldmatrix.sync.aligned.m8n8.x4.shared.b16 {%0,%1,%2,%3}, [%4];"
        : "=r"(r0), "=r"(r1), "=r"(r2), "=r"(r3) : "r"(addr));
}

__device__ __forceinline__ void mma_bf16(float c[4],
    uint32_t a0, uint32_t a1, uint32_t a2, uint32_t a3,
    uint32_t b0, uint32_t b1)
{
    asm("mma.sync.aligned.m16n8k16.row.col.f32.bf16.bf16.f32 "
        "{%0,%1,%2,%3}, {%4,%5,%6,%7}, {%8,%9}, {%0,%1,%2,%3};"
        : "+f"(c[0]), "+f"(c[1]), "+f"(c[2]), "+f"(c[3])
        : "r"(a0), "r"(a1), "r"(a2), "r"(a3), "r"(b0), "r"(b1));
}

__device__ __forceinline__ void split1(float v, __nv_bfloat16& h, __nv_bfloat16& l) {
    __nv_bfloat16 hb = __float2bfloat16_rn(v);
    h = hb;
    l = __float2bfloat16_rn(v - __bfloat162float(hb));
}

// ----------------------------------------------------------------------------
// Split kernels (fp32 -> bf16 hi/lo)
// ----------------------------------------------------------------------------
__global__ void __launch_bounds__(256) split_kernel(
    const float* __restrict__ src,
    __nv_bfloat16* __restrict__ hi, __nv_bfloat16* __restrict__ lo, long n)
{
    long i = blockIdx.x * 256L + threadIdx.x;
    long stride = (long)gridDim.x * 256;
    for (; i < n; i += stride) {
        __nv_bfloat16 h, l;
        split1(src[i], h, l);
        hi[i] = h; lo[i] = l;
    }
}

__global__ void __launch_bounds__(256) split_add_kernel(
    const float* __restrict__ a, const float* __restrict__ b,
    __nv_bfloat16* __restrict__ hi, __nv_bfloat16* __restrict__ lo, long n)
{
    long i = blockIdx.x * 256L + threadIdx.x;
    long stride = (long)gridDim.x * 256;
    for (; i < n; i += stride) {
        __nv_bfloat16 h, l;
        split1(a[i] + b[i], h, l);
        hi[i] = h; lo[i] = l;
    }
}

__global__ void __launch_bounds__(256) split_affine_kernel(
    const float* __restrict__ src, const float* __restrict__ scale,
    const float* __restrict__ shift,
    __nv_bfloat16* __restrict__ hi, __nv_bfloat16* __restrict__ lo, long n)
{
    long i = blockIdx.x * 256L + threadIdx.x;
    long stride = (long)gridDim.x * 256;
    for (; i < n; i += stride) {
        int k = (int)(i % D);
        __nv_bfloat16 h, l;
        split1(src[i] * scale[k] + shift[k], h, l);
        hi[i] = h; lo[i] = l;
    }
}

// ----------------------------------------------------------------------------
// bf16x3 tensor-core GEMM with ldmatrix fragment loads + batch strides.
// C[M,N] = (Ah+Al)[M,K] @ (Bh+Bl)[N,K]^T  (3-term: AhBh + AhBl + AlBh)
// 256 threads = 8 warps; warp tile 64 x (BN/4). BM=128, BK=32, double-buffered.
// EPI: 0 = (+bias) fp32 ; 1 = gelu(+bias) -> bf16 split
// M % 128 == 0, K % 32 == 0; N arbitrary (B rows zero-filled, stores guarded).
// ----------------------------------------------------------------------------
template<int BN, int EPI>
__global__ void __launch_bounds__(256) hgemm_kernel(
    const __nv_bfloat16* __restrict__ Ah, const __nv_bfloat16* __restrict__ Al,
    const __nv_bfloat16* __restrict__ Bh, const __nv_bfloat16* __restrict__ Bl,
    const float* __restrict__ bias,
    float* __restrict__ C,
    __nv_bfloat16* __restrict__ Chi, __nv_bfloat16* __restrict__ Clo,
    int M, int N, int K, long zA, long zB, long zC)
{
    constexpr int BM = 128;
    constexpr int NT = BN / 32;          // n8-tiles per warp (4 col-warps)
    constexpr int ROWS = BM + BN;
    extern __shared__ __align__(16) __nv_bfloat16 smem[];

    const int bz = blockIdx.z;
    Ah += bz * zA; Al += bz * zA;
    Bh += bz * zB; Bl += bz * zB;
    C  += bz * zC;
    if (EPI == 1) { Chi += bz * zC; Clo += bz * zC; }

    const int tid  = threadIdx.x;
    const int wid  = tid >> 5;
    const int lane = tid & 31;
    const int wm   = wid & 1;            // 2 row-halves of 64
    const int wn   = wid >> 1;           // 4 col groups of BN/4
    const int qm   = lane >> 2;
    const int qk   = lane & 3;
    const int bm = blockIdx.y * BM;
    const int bn = blockIdx.x * BN;
    const uint32_t sbase = smem_u32(smem);

    float acc[4][NT][4];
#pragma unroll
    for (int mt = 0; mt < 4; mt++)
#pragma unroll
        for (int nt = 0; nt < NT; nt++)
#pragma unroll
            for (int r = 0; r < 4; r++) acc[mt][nt][r] = 0.f;

    auto loadStage = [&](int s, int k0) {
        const uint32_t pH = sbase + (uint32_t)(s * 2 + 0) * ROWS * 80;
        const uint32_t pL = sbase + (uint32_t)(s * 2 + 1) * ROWS * 80;
#pragma unroll
        for (int c = tid; c < BM * 4; c += 256) {
            int row = c >> 2, kc = c & 3;
            long gofs = (long)(bm + row) * K + k0;
            CP_ASYNC16(pH + row * 80 + kc * 16, (const char*)(Ah + gofs) + kc * 16);
            CP_ASYNC16(pL + row * 80 + kc * 16, (const char*)(Al + gofs) + kc * 16);
        }
#pragma unroll
        for (int c = tid; c < BN * 4; c += 256) {
            int row = c >> 2, kc = c & 3;
            int n = bn + row;
            uint32_t dh = pH + (BM + row) * 80 + kc * 16;
            uint32_t dl = pL + (BM + row) * 80 + kc * 16;
            if (n < N) {
                long gofs = (long)n * K + k0;
                CP_ASYNC16(dh, (const char*)(Bh + gofs) + kc * 16);
                CP_ASYNC16(dl, (const char*)(Bl + gofs) + kc * 16);
            } else {
                uint32_t z = 0;
                asm volatile("st.shared.v4.b32 [%0], {%1,%1,%1,%1};" :: "r"(dh), "r"(z) : "memory");
                asm volatile("st.shared.v4.b32 [%0], {%1,%1,%1,%1};" :: "r"(dl), "r"(z) : "memory");
            }
        }
    };

    auto compute = [&](int s) {
        const uint32_t baseH = sbase + (uint32_t)(s * 2 + 0) * ROWS * 80;
        const uint32_t baseL = sbase + (uint32_t)(s * 2 + 1) * ROWS * 80;
#pragma unroll
        for (int kc = 0; kc < 2; kc++) {
            uint32_t ah[4][4], al[4][4], bh[NT][2], bl[NT][2];
            const int arow = wm * 64 + (lane & 15);
            const uint32_t acol = kc * 32 + ((lane & 16) ? 16 : 0);
#pragma unroll
            for (int mt = 0; mt < 4; mt++) {
                uint32_t ro = (uint32_t)(arow + mt * 16) * 80 + acol;
                ldsm_x4(ah[mt][0], ah[mt][1], ah[mt][2], ah[mt][3], baseH + ro);
                ldsm_x4(al[mt][0], al[mt][1], al[mt][2], al[mt][3], baseL + ro);
            }
            const int brow = BM + wn * (BN / 4) + (lane & 7) + ((lane & 16) ? 8 : 0);
            const uint32_t bcol = kc * 32 + ((lane & 8) ? 16 : 0);
#pragma unroll
            for (int np = 0; np < NT / 2; np++) {
                uint32_t ro = (uint32_t)(brow + np * 16) * 80 + bcol;
                ldsm_x4(bh[2*np][0], bh[2*np][1], bh[2*np+1][0], bh[2*np+1][1], baseH + ro);
                ldsm_x4(bl[2*np][0], bl[2*np][1], bl[2*np+1][0], bl[2*np+1][1], baseL + ro);
            }
#pragma unroll
            for (int mt = 0; mt < 4; mt++)
#pragma unroll
                for (int nt = 0; nt < NT; nt++) {
                    mma_bf16(acc[mt][nt], ah[mt][0], ah[mt][1], ah[mt][2], ah[mt][3],
                             bh[nt][0], bh[nt][1]);
                    mma_bf16(acc[mt][nt], ah[mt][0], ah[mt][1], ah[mt][2], ah[mt][3],
                             bl[nt][0], bl[nt][1]);
                    mma_bf16(acc[mt][nt], al[mt][0], al[mt][1], al[mt][2], al[mt][3],
                             bh[nt][0], bh[nt][1]);
                }
        }
    };

    const int niter = K >> 5;
    loadStage(0, 0); CP_COMMIT();
    for (int i = 0; i < niter; i++) {
        if (i + 1 < niter) { loadStage((i + 1) & 1, (i + 1) << 5); CP_COMMIT(); CP_WAIT(1); }
        else               { CP_WAIT(0); }
        __syncthreads();
        compute(i & 1);
        __syncthreads();
    }

    // Epilogue
#pragma unroll
    for (int mt = 0; mt < 4; mt++) {
        int r0 = bm + wm * 64 + mt * 16 + qm;
#pragma unroll
        for (int nt = 0; nt < NT; nt++) {
            int c0 = bn + wn * (BN / 4) + nt * 8 + qk * 2;
            float v0 = acc[mt][nt][0], v1 = acc[mt][nt][1];
            float v2 = acc[mt][nt][2], v3 = acc[mt][nt][3];
            if (bias) {
                float b0 = (c0 < N) ? bias[c0] : 0.f;
                float b1 = (c0 + 1 < N) ? bias[c0 + 1] : 0.f;
                v0 += b0; v1 += b1; v2 += b0; v3 += b1;
            }
            if (EPI == 1) {
                v0 = 0.5f * v0 * (1.f + erff(v0 * 0.70710678118654752f));
                v1 = 0.5f * v1 * (1.f + erff(v1 * 0.70710678118654752f));
                v2 = 0.5f * v2 * (1.f + erff(v2 * 0.70710678118654752f));
                v3 = 0.5f * v3 * (1.f + erff(v3 * 0.70710678118654752f));
                __nv_bfloat162 h2, l2;
                split1(v0, h2.x, l2.x); split1(v1, h2.y, l2.y);
                *(__nv_bfloat162*)(Chi + (long)r0 * N + c0) = h2;
                *(__nv_bfloat162*)(Clo + (long)r0 * N + c0) = l2;
                split1(v2, h2.x, l2.x); split1(v3, h2.y, l2.y);
                *(__nv_bfloat162*)(Chi + (long)(r0 + 8) * N + c0) = h2;
                *(__nv_bfloat162*)(Clo + (long)(r0 + 8) * N + c0) = l2;
            } else {
                if (c0 < N) {
                    C[(long)r0 * N + c0] = v0;
                    C[(long)(r0 + 8) * N + c0] = v2;
                }
                if (c0 + 1 < N) {
                    C[(long)r0 * N + c0 + 1] = v1;
                    C[(long)(r0 + 8) * N + c0 + 1] = v3;
                }
            }
        }
    }
}

// ----------------------------------------------------------------------------
// LayerNorm over last dim (D=768) + fused bf16 splits of x and x+qpos.
// ----------------------------------------------------------------------------
__global__ void __launch_bounds__(256) ln_kernel(
    const float* __restrict__ x, const float* __restrict__ add,
    const float* __restrict__ g, const float* __restrict__ b,
    const float* __restrict__ qpos,
    float* __restrict__ out,
    __nv_bfloat16* __restrict__ ohi, __nv_bfloat16* __restrict__ olo,
    __nv_bfloat16* __restrict__ oqhi, __nv_bfloat16* __restrict__ oqlo)
{
    int row = blockIdx.x, tid = threadIdx.x;
    const float* xr = x + (long)row * D;
    float vals[3];
    float s = 0.f, sq = 0.f;
#pragma unroll
    for (int i = 0; i < 3; i++) {
        int c = tid + i * 256;
        float v = xr[c];
        if (add) v += add[(long)row * D + c];
        vals[i] = v; s += v; sq += v * v;
    }
    __shared__ float rs[256], rq[256];
    rs[tid] = s; rq[tid] = sq;
    __syncthreads();
    for (int o = 128; o > 0; o >>= 1) {
        if (tid < o) { rs[tid] += rs[tid + o]; rq[tid] += rq[tid + o]; }
        __syncthreads();
    }
    float mu = rs[0] * (1.f / D);
    float var = rq[0] * (1.f / D) - mu * mu;
    float rstd = rsqrtf(var + EPS);
#pragma unroll
    for (int i = 0; i < 3; i++) {
        int c = tid + i * 256;
        long o = (long)row * D + c;
        float v = (vals[i] - mu) * rstd * g[c] + b[c];
        out[o] = v;
        __nv_bfloat16 h, l;
        split1(v, h, l);
        ohi[o] = h; olo[o] = l;
        split1(v + qpos[o], h, l);
        oqhi[o] = h; oqlo[o] = l;
    }
}

__global__ void __launch_bounds__(256) rownorm_kernel(
    const float* __restrict__ m, float* __restrict__ minv)
{
    int row = blockIdx.x, tid = threadIdx.x;
    float s = 0.f;
#pragma unroll
    for (int i = 0; i < 3; i++) {
        float v = m[(long)row * D + tid + i * 256];
        s += v * v;
    }
    __shared__ float rs[256];
    rs[tid] = s; __syncthreads();
    for (int o = 128; o > 0; o >>= 1) {
        if (tid < o) rs[tid] += rs[tid + o];
        __syncthreads();
    }
    if (tid == 0) minv[row] = rsqrtf(rs[0]);
}

// ----------------------------------------------------------------------------
// Top-32 with coarse-then-exact selection:
// phase 1: top-CN (40) by coarse tensor-core sims (scaled by minv)
// phase 2: exact fp32 rescore of the 40 candidates (x row cached in smem)
// phase 3: exact top-32 of the 40 (ties -> lowest index)
// ----------------------------------------------------------------------------
__global__ void __launch_bounds__(256) topk_kernel(
    const float* __restrict__ sims, const float* __restrict__ minv,
    const float* __restrict__ x, const float* __restrict__ memory,
    int* __restrict__ idx_out)
{
    int row = blockIdx.x;
    int b = row >> 7;     // / NP
    int tid = threadIdx.x;
    int warp = tid >> 5, lane = tid & 31;
    __shared__ float s[MNP];
    __shared__ float rmax[256];
    __shared__ int   rarg[256];
    __shared__ float xrow[D];
    __shared__ int   cand[CN];
    __shared__ float cval[CN];

    for (int i = tid; i < MNP; i += 256)
        s[i] = sims[(long)row * MNP + i] * minv[b * MNP + i];
    for (int c = tid; c < D; c += 256)
        xrow[c] = x[(long)row * D + c];
    __syncthreads();

    // phase 1: coarse top-CN
    for (int t = 0; t < CN; t++) {
        float best = -INFINITY; int bi = 0x7fffffff;
        for (int i = tid; i < MNP; i += 256) {
            float v = s[i];
            if (v > best) { best = v; bi = i; }
        }
        rmax[tid] = best; rarg[tid] = bi;
        __syncthreads();
        for (int o = 128; o > 0; o >>= 1) {
            if (tid < o) {
                float ov = rmax[tid + o]; int oi = rarg[tid + o];
                if (ov > rmax[tid] || (ov == rmax[tid] && oi < rarg[tid])) {
                    rmax[tid] = ov; rarg[tid] = oi;
                }
            }
            __syncthreads();
        }
        if (tid == 0) {
            cand[t] = rarg[0];
            s[rarg[0]] = -INFINITY;
        }
        __syncthreads();
    }

    // phase 2: exact fp32 rescore (warp j handles candidates j, j+8, ...)
    for (int j = warp; j < CN; j += 8) {
        int ix = cand[j];
        const float* mr = memory + ((long)(b * MNP + ix)) * D;
        float acc = 0.f;
        for (int c = lane; c < D; c += 32) acc = fmaf(xrow[c], mr[c], acc);
#pragma unroll
        for (int o = 16; o > 0; o >>= 1) acc += __shfl_xor_sync(0xffffffffu, acc, o);
        if (lane == 0) cval[j] = acc * minv[b * MNP + ix];
    }
    __syncthreads();

    // phase 3: exact top-32 of CN (warp 0)
    if (warp == 0) {
        for (int t = 0; t < TOPK; t++) {
            float v = -INFINITY; int myi = 0x7fffffff, myj = -1;
            for (int j = lane; j < CN; j += 32) {
                float cv = cval[j];
                if (cv > v || (cv == v && cand[j] < myi)) { v = cv; myi = cand[j]; myj = j; }
            }
#pragma unroll
            for (int o = 16; o > 0; o >>= 1) {
                float ov = __shfl_xor_sync(0xffffffffu, v, o);
                int   oi = __shfl_xor_sync(0xffffffffu, myi, o);
                int   oj = __shfl_xor_sync(0xffffffffu, myj, o);
                if (ov > v || (ov == v && oi < myi)) { v = ov; myi = oi; myj = oj; }
            }
            if (lane == 0) {
                idx_out[row * TOPK + t] = myi;
                cval[myj] = -INFINITY;
            }
            __syncwarp();
        }
    }
}

// ----------------------------------------------------------------------------
// Sparse cross-attention (32 gathered keys per query,head)
// ----------------------------------------------------------------------------
__global__ void __launch_bounds__(128) cross_attn_kernel(
    const float* __restrict__ q, const float* __restrict__ K,
    const float* __restrict__ V, const int* __restrict__ idx,
    float* __restrict__ out)
{
    int row = blockIdx.x;
    int b = row >> 7;
    int warp = threadIdx.x >> 5, lane = threadIdx.x & 31;
    int h = blockIdx.y * 4 + warp;

    __shared__ float qv[4][HD];
    __shared__ float ps[4][TOPK];
    __shared__ int   id[4][TOPK];

    const float* qr = q + (long)row * D + h * HD;
    qv[warp][lane] = qr[lane];
    qv[warp][lane + 32] = qr[lane + 32];
    int ix = idx[row * TOPK + lane];
    id[warp][lane] = ix;
    __syncwarp();

    const float* kr = K + ((long)(b * MNP + ix)) * D + h * HD;
    float s = 0.f;
#pragma unroll
    for (int d = 0; d < HD; d++) s = fmaf(qv[warp][d], kr[d], s);
    s *= 0.125f;

    float m = s;
#pragma unroll
    for (int o = 16; o > 0; o >>= 1) m = fmaxf(m, __shfl_xor_sync(0xffffffffu, m, o));
    float e = expf(s - m);
    float sum = e;
#pragma unroll
    for (int o = 16; o > 0; o >>= 1) sum += __shfl_xor_sync(0xffffffffu, sum, o);
    ps[warp][lane] = e / sum;
    __syncwarp();

    float acc0 = 0.f, acc1 = 0.f;
#pragma unroll
    for (int j = 0; j < TOPK; j++) {
        const float* vr = V + ((long)(b * MNP + id[warp][j])) * D + h * HD;
        float p = ps[warp][j];
        acc0 = fmaf(p, vr[lane], acc0);
        acc1 = fmaf(p, vr[lane + 32], acc1);
    }
    float* orow = out + (long)row * D + h * HD;
    orow[lane] = acc0;
    orow[lane + 32] = acc1;
}

// ----------------------------------------------------------------------------
// Dense self-attention over NP=128 keys -> writes bf16 hi/lo split directly.
// ----------------------------------------------------------------------------
__global__ void __launch_bounds__(128) self_attn_kernel(
    const float* __restrict__ qk, const float* __restrict__ v,
    __nv_bfloat16* __restrict__ ohi, __nv_bfloat16* __restrict__ olo)
{
    int row = blockIdx.x;
    int b = row >> 7;
    int h = blockIdx.y;
    int tid = threadIdx.x;

    __shared__ float qv[HD];
    __shared__ float sc[NP];
    __shared__ float red[128];

    const float* qr = qk + (long)row * (2 * D) + h * HD;
    if (tid < HD) qv[tid] = qr[tid];
    __syncthreads();

    const float* kr = qk + (long)(b * NP + tid) * (2 * D) + D + h * HD;
    float s = 0.f;
#pragma unroll
    for (int d = 0; d < HD; d++) s = fmaf(qv[d], kr[d], s);
    s *= 0.125f;

    red[tid] = s; __syncthreads();
    for (int o = 64; o > 0; o >>= 1) {
        if (tid < o) red[tid] = fmaxf(red[tid], red[tid + o]);
        __syncthreads();
    }
    float m = red[0]; __syncthreads();
    float e = expf(s - m);
    sc[tid] = e;
    red[tid] = e; __syncthreads();
    for (int o = 64; o > 0; o >>= 1) {
        if (tid < o) red[tid] += red[tid + o];
        __syncthreads();
    }
    float inv = 1.f / red[0];

    if (tid < HD) {
        float acc = 0.f;
        for (int j = 0; j < NP; j++)
            acc = fmaf(sc[j], v[(long)(b * NP + j) * D + h * HD + tid], acc);
        long o = (long)row * D + h * HD + tid;
        __nv_bfloat16 hh, ll;
        split1(acc * inv, hh, ll);
        ohi[o] = hh; olo[o] = ll;
    }
}

// ----------------------------------------------------------------------------
// BatchNorm stats -> fused scale/shift
// ----------------------------------------------------------------------------
__global__ void __launch_bounds__(256) bn_stats_kernel(
    const float* __restrict__ x, const float* __restrict__ g,
    const float* __restrict__ b, float* __restrict__ scale,
    float* __restrict__ shift)
{
    int f = blockIdx.x, tid = threadIdx.x;
    float s = 0.f, sq = 0.f;
    for (int r = tid; r < NTOK; r += 256) {
        float v = x[(long)r * D + f];
        s += v; sq += v * v;
    }
    __shared__ float rs[256], rq[256];
    rs[tid] = s; rq[tid] = sq;
    __syncthreads();
    for (int o = 128; o > 0; o >>= 1) {
        if (tid < o) { rs[tid] += rs[tid + o]; rq[tid] += rq[tid + o]; }
        __syncthreads();
    }
    if (tid == 0) {
        float mu = rs[0] * (1.f / NTOK);
        float var = rq[0] * (1.f / NTOK) - mu * mu;
        float rstd = rsqrtf(var + EPS);
        float sc = rstd * g[f];
        scale[f] = sc;
        shift[f] = b[f] - mu * sc;
    }
}

// ----------------------------------------------------------------------------
// Host orchestration
// ----------------------------------------------------------------------------
#define SMEM128 (2 * 2 * 256 * 80)   // 81920
#define SMEM64  (2 * 2 * 192 * 80)   // 61440

static void launch_hgemm(int bn_tile, int epi,
    const __nv_bfloat16* Ah, const __nv_bfloat16* Al,
    const __nv_bfloat16* Bh, const __nv_bfloat16* Bl,
    const float* bias, float* C, __nv_bfloat16* Chi, __nv_bfloat16* Clo,
    int M, int N, int K)
{
    if (bn_tile == 128) {
        dim3 grid((N + 127) / 128, M / 128);
        if (epi == 0)
            hgemm_kernel<128,0><<<grid, 256, SMEM128>>>(Ah, Al, Bh, Bl, bias, C, Chi, Clo, M, N, K, 0, 0, 0);
        else
            hgemm_kernel<128,1><<<grid, 256, SMEM128>>>(Ah, Al, Bh, Bl, bias, C, Chi, Clo, M, N, K, 0, 0, 0);
    } else {
        dim3 grid((N + 63) / 64, M / 128);
        hgemm_kernel<64,0><<<grid, 256, SMEM64>>>(Ah, Al, Bh, Bl, bias, C, Chi, Clo, M, N, K, 0, 0, 0);
    }
}

extern "C" void kernel_launch(void* const* d_in, const int* in_sizes, int n_in,
                              void* d_out, int out_size)
{
    const float* tgt      = (const float*)d_in[0];
    const float* memory   = (const float*)d_in[1];
    const float* qpos     = (const float*)d_in[2];
    const float* kpos     = (const float*)d_in[3];
    const float* norm0_g  = (const float*)d_in[4];
    const float* norm0_b  = (const float*)d_in[5];
    const float* l1_w     = (const float*)d_in[6];
    const float* l1_b     = (const float*)d_in[7];
    const float* l2_w     = (const float*)d_in[8];
    const float* l2_b     = (const float*)d_in[9];
    const float* l3_w     = (const float*)d_in[10];
    const float* l3_b     = (const float*)d_in[11];
    const float* n1_g     = (const float*)d_in[12];
    const float* n1_b     = (const float*)d_in[13];
    const float* n2_g     = (const float*)d_in[14];
    const float* n2_b     = (const float*)d_in[15];
    const float* n3_g     = (const float*)d_in[16];
    const float* n3_b     = (const float*)d_in[17];
    const float* sa_in_w  = (const float*)d_in[18];
    const float* sa_in_b  = (const float*)d_in[19];
    const float* sa_out_w = (const float*)d_in[20];
    const float* sa_out_b = (const float*)d_in[21];
    const float* ff1_w    = (const float*)d_in[22];
    const float* ff1_b    = (const float*)d_in[23];
    const float* ff2_w    = (const float*)d_in[24];
    const float* ff2_b    = (const float*)d_in[25];
    const float* bn_g     = (const float*)d_in[26];
    const float* bn_b     = (const float*)d_in[27];
    const float* cls_w    = (const float*)d_in[28];

    float *x, *tmp, *q, *qk, *v, *attn, *Kb, *Vb, *sims, *minv, *bnsc, *bnsh;
    int* idx;
    __nv_bfloat16 *whi, *wlo, *mkhi, *mklo, *mhi, *mlo;
    __nv_bfloat16 *xhi, *xlo, *xqhi, *xqlo, *h1hi, *h1lo, *sahi, *salo, *cihi, *cilo;
    cudaGetSymbolAddress((void**)&x,    g_x);
    cudaGetSymbolAddress((void**)&tmp,  g_tmp);
    cudaGetSymbolAddress((void**)&q,    g_q);
    cudaGetSymbolAddress((void**)&qk,   g_qk);
    cudaGetSymbolAddress((void**)&v,    g_v);
    cudaGetSymbolAddress((void**)&attn, g_attn);
    cudaGetSymbolAddress((void**)&Kb,   g_K);
    cudaGetSymbolAddress((void**)&Vb,   g_V);
    cudaGetSymbolAddress((void**)&sims, g_sims);
    cudaGetSymbolAddress((void**)&idx,  g_idx);
    cudaGetSymbolAddress((void**)&minv, g_minv);
    cudaGetSymbolAddress((void**)&bnsc, g_bnscale);
    cudaGetSymbolAddress((void**)&bnsh, g_bnshift);
    cudaGetSymbolAddress((void**)&whi,  g_whi);
    cudaGetSymbolAddress((void**)&wlo,  g_wlo);
    cudaGetSymbolAddress((void**)&mkhi, g_mkhi);
    cudaGetSymbolAddress((void**)&mklo, g_mklo);
    cudaGetSymbolAddress((void**)&mhi,  g_mhi);
    cudaGetSymbolAddress((void**)&mlo,  g_mlo);
    cudaGetSymbolAddress((void**)&xhi,  g_xhi);
    cudaGetSymbolAddress((void**)&xlo,  g_xlo);
    cudaGetSymbolAddress((void**)&xqhi, g_xqhi);
    cudaGetSymbolAddress((void**)&xqlo, g_xqlo);
    cudaGetSymbolAddress((void**)&h1hi, g_h1hi);
    cudaGetSymbolAddress((void**)&h1lo, g_h1lo);
    cudaGetSymbolAddress((void**)&sahi, g_sahi);
    cudaGetSymbolAddress((void**)&salo, g_salo);
    cudaGetSymbolAddress((void**)&cihi, g_cihi);
    cudaGetSymbolAddress((void**)&cilo, g_cilo);

    cudaFuncSetAttribute(hgemm_kernel<128,0>, cudaFuncAttributeMaxDynamicSharedMemorySize, SMEM128);
    cudaFuncSetAttribute(hgemm_kernel<128,1>, cudaFuncAttributeMaxDynamicSharedMemorySize, SMEM128);
    cudaFuncSetAttribute(hgemm_kernel<64,0>,  cudaFuncAttributeMaxDynamicSharedMemorySize, SMEM64);

    // ---- one-time (per call) splits ----
    split_kernel<<<4096, 256>>>(l1_w,     whi + OFF_L1,    wlo + OFF_L1,    (long)NLAYERS*D*D);
    split_kernel<<<4096, 256>>>(l2_w,     whi + OFF_L2,    wlo + OFF_L2,    (long)NLAYERS*D*D);
    split_kernel<<<4096, 256>>>(l3_w,     whi + OFF_L3,    wlo + OFF_L3,    (long)NLAYERS*D*D);
    split_kernel<<<4096, 256>>>(sa_in_w,  whi + OFF_SAIN,  wlo + OFF_SAIN,  (long)NLAYERS*3*D*D);
    split_kernel<<<4096, 256>>>(sa_out_w, whi + OFF_SAOUT, wlo + OFF_SAOUT, (long)NLAYERS*D*D);
    split_kernel<<<4096, 256>>>(ff1_w,    whi + OFF_FF1,   wlo + OFF_FF1,   (long)NLAYERS*DFF*D);
    split_kernel<<<4096, 256>>>(ff2_w,    whi + OFF_FF2,   wlo + OFF_FF2,   (long)NLAYERS*D*DFF);
    split_kernel<<<4096, 256>>>(cls_w,    whi + OFF_CLS,   wlo + OFF_CLS,   (long)NC*D);
    split_add_kernel<<<8192, 256>>>(memory, kpos, mkhi, mklo, (long)NMEM*D);
    split_kernel<<<8192, 256>>>(memory, mhi, mlo, (long)NMEM*D);

    rownorm_kernel<<<NMEM, 256>>>(memory, minv);
    ln_kernel<<<NTOK, 256>>>(tgt, nullptr, norm0_g, norm0_b, qpos,
                             x, xhi, xlo, xqhi, xqlo);

    for (int l = 0; l < NLAYERS; l++) {
        long wdd = (long)l * D * D;
        const __nv_bfloat16* l1h = whi + OFF_L1 + wdd;  const __nv_bfloat16* l1l = wlo + OFF_L1 + wdd;
        const __nv_bfloat16* l2h = whi + OFF_L2 + wdd;  const __nv_bfloat16* l2l = wlo + OFF_L2 + wdd;
        const __nv_bfloat16* l3h = whi + OFF_L3 + wdd;  const __nv_bfloat16* l3l = wlo + OFF_L3 + wdd;
        const __nv_bfloat16* sih = whi + OFF_SAIN + (long)l*3*D*D;
        const __nv_bfloat16* sil = wlo + OFF_SAIN + (long)l*3*D*D;
        const __nv_bfloat16* soh = whi + OFF_SAOUT + wdd;
        const __nv_bfloat16* sol = wlo + OFF_SAOUT + wdd;
        const __nv_bfloat16* f1h = whi + OFF_FF1 + (long)l*DFF*D;
        const __nv_bfloat16* f1l = wlo + OFF_FF1 + (long)l*DFF*D;
        const __nv_bfloat16* f2h = whi + OFF_FF2 + (long)l*D*DFF;
        const __nv_bfloat16* f2l = wlo + OFF_FF2 + (long)l*D*DFF;
        const float* l1bb = l1_b + (long)l * D;
        const float* l2bb = l2_b + (long)l * D;
        const float* l3bb = l3_b + (long)l * D;
        const float* sab  = sa_in_b + (long)l * 3 * D;
        const float* sob  = sa_out_b + (long)l * D;
        const float* f1b  = ff1_b + (long)l * DFF;
        const float* f2b  = ff2_b + (long)l * D;

        // coarse sims[b] = x[b] @ memory[b]^T  (bf16x3 tensor cores, batched)
        {
            dim3 grid(MNP / 128, 1, BS);
            hgemm_kernel<128,0><<<grid, 256, SMEM128>>>(
                xhi, xlo, mhi, mlo, nullptr, sims, nullptr, nullptr,
                NP, MNP, D, (long)NP * D, (long)MNP * D, (long)NP * MNP);
        }

        // exact top-32 via coarse top-40 + fp32 rescore
        topk_kernel<<<NTOK, 256>>>(sims, minv, x, memory, idx);

        // q = (x + qpos) @ l1_w^T + b
        launch_hgemm(64, 0, xqhi, xqlo, l1h, l1l, l1bb, q, nullptr, nullptr, NTOK, D, D);

        // K = (mem + kpos) @ l2_w^T + b ; V = mem @ l3_w^T + b
        launch_hgemm(128, 0, mkhi, mklo, l2h, l2l, l2bb, Kb, nullptr, nullptr, NMEM, D, D);
        launch_hgemm(128, 0, mhi,  mlo,  l3h, l3l, l3bb, Vb, nullptr, nullptr, NMEM, D, D);

        cross_attn_kernel<<<dim3(NTOK, NH / 4), 128>>>(q, Kb, Vb, idx, attn);

        ln_kernel<<<NTOK, 256>>>(x, attn, n1_g + (long)l * D, n1_b + (long)l * D,
                                 qpos, x, xhi, xlo, xqhi, xqlo);

        // self-attn projections: [q;k] = (x+qpos) @ [wq;wk]^T ; v = x @ wv^T
        launch_hgemm(128, 0, xqhi, xqlo, sih, sil, sab, qk, nullptr, nullptr, NTOK, 2 * D, D);
        launch_hgemm(64, 0, xhi, xlo, sih + (long)2*D*D, sil + (long)2*D*D, sab + 2*D,
                     v, nullptr, nullptr, NTOK, D, D);

        self_attn_kernel<<<dim3(NTOK, NH), 128>>>(qk, v, sahi, salo);

        launch_hgemm(64, 0, sahi, salo, soh, sol, sob, tmp, nullptr, nullptr, NTOK, D, D);

        ln_kernel<<<NTOK, 256>>>(x, tmp, n2_g + (long)l * D, n2_b + (long)l * D,
                                 qpos, x, xhi, xlo, xqhi, xqlo);

        // FFN: h1 = gelu(x @ ff1^T + b1) -> bf16 split ; tmp = h1 @ ff2^T + b2
        launch_hgemm(128, 1, xhi, xlo, f1h, f1l, f1b, nullptr, h1hi, h1lo, NTOK, DFF, D);
        launch_hgemm(64, 0, h1hi, h1lo, f2h, f2l, f2b, tmp, nullptr, nullptr, NTOK, D, DFF);

        ln_kernel<<<NTOK, 256>>>(x, tmp, n3_g + (long)l * D, n3_b + (long)l * D,
                                 qpos, x, xhi, xlo, xqhi, xqlo);
    }

    bn_stats_kernel<<<D, 256>>>(x, bn_g, bn_b, bnsc, bnsh);
    split_affine_kernel<<<2048, 256>>>(x, bnsc, bnsh, cihi, cilo, (long)NTOK * D);

    float* out = (float*)d_out;
    long xsz = (long)NTOK * D;
    long csz = (long)NTOK * NC;

    if ((long)out_size >= xsz + csz) {
        cudaMemcpyAsync(out, x, sizeof(float) * xsz, cudaMemcpyDeviceToDevice, 0);
        launch_hgemm(64, 0, cihi, cilo, whi + OFF_CLS, wlo + OFF_CLS, nullptr,
                     out + xsz, nullptr, nullptr, NTOK, NC, D);
    } else if ((long)out_size == csz) {
        launch_hgemm(64, 0, cihi, cilo, whi + OFF_CLS, wlo + OFF_CLS, nullptr,
                     out, nullptr, nullptr, NTOK, NC, D);
    } else {
        cudaMemcpyAsync(out, x, sizeof(float) * ((long)out_size < xsz ? out_size : xsz),
                        cudaMemcpyDeviceToDevice, 0);
    }
}

// round 12
// speedup vs baseline: 1.5609x; 1.3144x over previous
#include <cuda_runtime.h>
#include <cuda_bf16.h>
#include <cuda_fp16.h>
#include <math.h>
#include <stdint.h>

#define BS   16
#define NP   128
#define MNP  2048
#define D    768
#define NH   12
#define HD   64
#define DFF  2048
#define NLAYERS 2
#define TOPK 32
#define CN   40
#define NC   751
#define NTOK (BS*NP)
#define NMEM (BS*MNP)
#define EPS  1e-5f

// ----------------------------------------------------------------------------
// Scratch
// ----------------------------------------------------------------------------
__device__ float g_x   [NTOK*(long)D];
__device__ float g_tmp [NTOK*(long)D];
__device__ float g_q   [NTOK*(long)D];
__device__ float g_qk  [NTOK*(long)(2*D)];
__device__ float g_v   [NTOK*(long)D];
__device__ float g_attn[NTOK*(long)D];
__device__ float g_Z   [(long)NH*NTOK*D];
__device__ float g_sims[NTOK*(long)MNP];
__device__ int   g_idx [NTOK*TOPK];
__device__ float g_minv[NMEM];
__device__ float g_bnscale[D];
__device__ float g_bnshift[D];

// bf16 weight splits (same offset table R7 validated)
#define OFF_L1    0L
#define OFF_L3    1179648L
#define OFF_SAIN  2359296L
#define OFF_SAOUT 5898240L
#define OFF_FF1   7077888L
#define OFF_FF2   10223616L
#define OFF_CLS   13369344L
#define WTOTAL    13946112L
__device__ __nv_bfloat16 g_whi[WTOTAL], g_wlo[WTOTAL];
__device__ __nv_bfloat16 g_w2thi[(long)NLAYERS*NH*D*HD], g_w2tlo[(long)NLAYERS*NH*D*HD];
__device__ __nv_bfloat16 g_xhi [NTOK*(long)D], g_xlo [NTOK*(long)D];
__device__ __nv_bfloat16 g_xqhi[NTOK*(long)D], g_xqlo[NTOK*(long)D];
__device__ __nv_bfloat16 g_qhi [NTOK*(long)D], g_qlo [NTOK*(long)D];
__device__ __nv_bfloat16 g_agghi[(long)NH*NTOK*D], g_agglo[(long)NH*NTOK*D];
__device__ __nv_bfloat16 g_h1hi[NTOK*(long)DFF], g_h1lo[NTOK*(long)DFF];
__device__ __nv_bfloat16 g_sahi[NTOK*(long)D], g_salo[NTOK*(long)D];
__device__ __nv_bfloat16 g_cihi[NTOK*(long)D], g_cilo[NTOK*(long)D];

// fp16 coarse-sims buffers
__device__ __half g_mf16 [NMEM*(long)D];
__device__ __half g_xf16 [NTOK*(long)D];

// ----------------------------------------------------------------------------
// Helpers
// ----------------------------------------------------------------------------
__device__ __forceinline__ uint32_t smem_u32(const void* p) {
    uint32_t a;
    asm("{ .reg .u64 t; cvta.to.shared.u64 t, %1; cvt.u32.u64 %0, t; }"
        : "=r"(a) : "l"(p));
    return a;
}

#define CP_ASYNC16(dst, src) \
    asm volatile("cp.async.ca.shared.global [%0], [%1], 16;" \
                 :: "r"(dst), "l"(src) : "memory")
#define CP_COMMIT() asm volatile("cp.async.commit_group;" ::: "memory")
#define CP_WAIT(n)  asm volatile("cp.async.wait_group %0;" :: "n"(n) : "memory")

__device__ __forceinline__ void ldsm_x4(uint32_t& r0, uint32_t& r1,
                                        uint32_t& r2, uint32_t& r3, uint32_t addr)
{
    asm volatile("ldmatrix.sync.aligned.m8n8.x4.shared.b16 {%0,%1,%2,%3}, [%4];"
        : "=r"(r0), "=r"(r1), "=r"(r2), "=r"(r3) : "r"(addr));
}

__device__ __forceinline__ void mma_bf16(float c[4],
    uint32_t a0, uint32_t a1, uint32_t a2, uint32_t a3,
    uint32_t b0, uint32_t b1)
{
    asm("mma.sync.aligned.m16n8k16.row.col.f32.bf16.bf16.f32 "
        "{%0,%1,%2,%3}, {%4,%5,%6,%7}, {%8,%9}, {%0,%1,%2,%3};"
        : "+f"(c[0]), "+f"(c[1]), "+f"(c[2]), "+f"(c[3])
        : "r"(a0), "r"(a1), "r"(a2), "r"(a3), "r"(b0), "r"(b1));
}

__device__ __forceinline__ void mma_f16(float c[4],
    uint32_t a0, uint32_t a1, uint32_t a2, uint32_t a3,
    uint32_t b0, uint32_t b1)
{
    asm("mma.sync.aligned.m16n8k16.row.col.f32.f16.f16.f32 "
        "{%0,%1,%2,%3}, {%4,%5,%6,%7}, {%8,%9}, {%0,%1,%2,%3};"
        : "+f"(c[0]), "+f"(c[1]), "+f"(c[2]), "+f"(c[3])
        : "r"(a0), "r"(a1), "r"(a2), "r"(a3), "r"(b0), "r"(b1));
}

__device__ __forceinline__ void split1(float v, __nv_bfloat16& h, __nv_bfloat16& l) {
    __nv_bfloat16 hb = __float2bfloat16_rn(v);
    h = hb;
    l = __float2bfloat16_rn(v - __bfloat162float(hb));
}

// ----------------------------------------------------------------------------
// Convert / split kernels
// ----------------------------------------------------------------------------
__global__ void __launch_bounds__(256) split_kernel(
    const float* __restrict__ src,
    __nv_bfloat16* __restrict__ hi, __nv_bfloat16* __restrict__ lo, long n)
{
    long i = blockIdx.x * 256L + threadIdx.x;
    long stride = (long)gridDim.x * 256;
    for (; i < n; i += stride) {
        __nv_bfloat16 h, l;
        split1(src[i], h, l);
        hi[i] = h; lo[i] = l;
    }
}

// W2 transpose-split: out[l][h][n][k] = l2_w[l][h*64+k][n]
__global__ void __launch_bounds__(256) w2t_split_kernel(
    const float* __restrict__ l2w,
    __nv_bfloat16* __restrict__ hi, __nv_bfloat16* __restrict__ lo)
{
    long n = (long)NLAYERS * NH * D * HD;
    long i = blockIdx.x * 256L + threadIdx.x;
    long stride = (long)gridDim.x * 256;
    for (; i < n; i += stride) {
        int k = (int)(i & 63);
        long t = i >> 6;
        int nn = (int)(t % D);
        long t2 = t / D;
        int h = (int)(t2 % NH);
        int l = (int)(t2 / NH);
        float v = l2w[((long)l * D + h * HD + k) * D + nn];
        __nv_bfloat16 hh, ll;
        split1(v, hh, ll);
        hi[i] = hh; lo[i] = ll;
    }
}

__global__ void __launch_bounds__(256) conv_kernel(
    const float* __restrict__ src, __half* __restrict__ dst, long n)
{
    long i = blockIdx.x * 256L + threadIdx.x;
    long stride = (long)gridDim.x * 256;
    for (; i < n; i += stride) dst[i] = __float2half_rn(src[i]);
}

__global__ void __launch_bounds__(256) split_affine_kernel(
    const float* __restrict__ src, const float* __restrict__ scale,
    const float* __restrict__ shift,
    __nv_bfloat16* __restrict__ hi, __nv_bfloat16* __restrict__ lo, long n)
{
    long i = blockIdx.x * 256L + threadIdx.x;
    long stride = (long)gridDim.x * 256;
    for (; i < n; i += stride) {
        int k = (int)(i % D);
        __nv_bfloat16 h, l;
        split1(src[i] * scale[k] + shift[k], h, l);
        hi[i] = h; lo[i] = l;
    }
}

// ----------------------------------------------------------------------------
// bf16x3 tensor-core GEMM, ldmatrix, generalized strides + batch.
// C[M,N] = (Ah+Al)[M,K] @ (Bh+Bl)[N,K]^T (+bias)
// EPI: 0 fp32 ; 1 gelu->split ; 3 fp32+split
// ----------------------------------------------------------------------------
template<int BN, int EPI>
__global__ void __launch_bounds__(256) hgemm_kernel(
    const __nv_bfloat16* __restrict__ Ah, const __nv_bfloat16* __restrict__ Al,
    const __nv_bfloat16* __restrict__ Bh, const __nv_bfloat16* __restrict__ Bl,
    const float* __restrict__ bias,
    float* __restrict__ C,
    __nv_bfloat16* __restrict__ Chi, __nv_bfloat16* __restrict__ Clo,
    int M, int N, int K, int ldA, int ldB, int ldC,
    long zA, long zB, long zC, long zBias)
{
    constexpr int BM = 128;
    constexpr int NT = BN / 32;
    constexpr int ROWS = BM + BN;
    extern __shared__ __align__(16) __nv_bfloat16 smem[];

    const int bz = blockIdx.z;
    Ah += bz * zA; Al += bz * zA;
    Bh += bz * zB; Bl += bz * zB;
    if (bias) bias += bz * zBias;
    C  += bz * zC;
    if (EPI == 1 || EPI == 3) { Chi += bz * zC; Clo += bz * zC; }

    const int tid  = threadIdx.x;
    const int wid  = tid >> 5;
    const int lane = tid & 31;
    const int wm   = wid & 1;
    const int wn   = wid >> 1;
    const int qm   = lane >> 2;
    const int qk   = lane & 3;
    const int bm = blockIdx.y * BM;
    const int bn = blockIdx.x * BN;
    const uint32_t sbase = smem_u32(smem);

    float acc[4][NT][4];
#pragma unroll
    for (int mt = 0; mt < 4; mt++)
#pragma unroll
        for (int nt = 0; nt < NT; nt++)
#pragma unroll
            for (int r = 0; r < 4; r++) acc[mt][nt][r] = 0.f;

    auto loadStage = [&](int s, int k0) {
        const uint32_t pH = sbase + (uint32_t)(s * 2 + 0) * ROWS * 80;
        const uint32_t pL = sbase + (uint32_t)(s * 2 + 1) * ROWS * 80;
#pragma unroll
        for (int c = tid; c < BM * 4; c += 256) {
            int row = c >> 2, kc = c & 3;
            long gofs = (long)(bm + row) * ldA + k0;
            CP_ASYNC16(pH + row * 80 + kc * 16, (const char*)(Ah + gofs) + kc * 16);
            CP_ASYNC16(pL + row * 80 + kc * 16, (const char*)(Al + gofs) + kc * 16);
        }
#pragma unroll
        for (int c = tid; c < BN * 4; c += 256) {
            int row = c >> 2, kc = c & 3;
            int n = bn + row;
            uint32_t dh = pH + (BM + row) * 80 + kc * 16;
            uint32_t dl = pL + (BM + row) * 80 + kc * 16;
            if (n < N) {
                long gofs = (long)n * ldB + k0;
                CP_ASYNC16(dh, (const char*)(Bh + gofs) + kc * 16);
                CP_ASYNC16(dl, (const char*)(Bl + gofs) + kc * 16);
            } else {
                uint32_t z = 0;
                asm volatile("st.shared.v4.b32 [%0], {%1,%1,%1,%1};" :: "r"(dh), "r"(z) : "memory");
                asm volatile("st.shared.v4.b32 [%0], {%1,%1,%1,%1};" :: "r"(dl), "r"(z) : "memory");
            }
        }
    };

    auto compute = [&](int s) {
        const uint32_t baseH = sbase + (uint32_t)(s * 2 + 0) * ROWS * 80;
        const uint32_t baseL = sbase + (uint32_t)(s * 2 + 1) * ROWS * 80;
#pragma unroll
        for (int kc = 0; kc < 2; kc++) {
            uint32_t ah[4][4], al[4][4], bh[NT][2], bl[NT][2];
            const int arow = wm * 64 + (lane & 15);
            const uint32_t acol = kc * 32 + ((lane & 16) ? 16 : 0);
#pragma unroll
            for (int mt = 0; mt < 4; mt++) {
                uint32_t ro = (uint32_t)(arow + mt * 16) * 80 + acol;
                ldsm_x4(ah[mt][0], ah[mt][1], ah[mt][2], ah[mt][3], baseH + ro);
                ldsm_x4(al[mt][0], al[mt][1], al[mt][2], al[mt][3], baseL + ro);
            }
            const int brow = BM + wn * (BN / 4) + (lane & 7) + ((lane & 16) ? 8 : 0);
            const uint32_t bcol = kc * 32 + ((lane & 8) ? 16 : 0);
#pragma unroll
            for (int np = 0; np < NT / 2; np++) {
                uint32_t ro = (uint32_t)(brow + np * 16) * 80 + bcol;
                ldsm_x4(bh[2*np][0], bh[2*np][1], bh[2*np+1][0], bh[2*np+1][1], baseH + ro);
                ldsm_x4(bl[2*np][0], bl[2*np][1], bl[2*np+1][0], bl[2*np+1][1], baseL + ro);
            }
#pragma unroll
            for (int mt = 0; mt < 4; mt++)
#pragma unroll
                for (int nt = 0; nt < NT; nt++) {
                    mma_bf16(acc[mt][nt], ah[mt][0], ah[mt][1], ah[mt][2], ah[mt][3],
                             bh[nt][0], bh[nt][1]);
                    mma_bf16(acc[mt][nt], ah[mt][0], ah[mt][1], ah[mt][2], ah[mt][3],
                             bl[nt][0], bl[nt][1]);
                    mma_bf16(acc[mt][nt], al[mt][0], al[mt][1], al[mt][2], al[mt][3],
                             bh[nt][0], bh[nt][1]);
                }
        }
    };

    const int niter = K >> 5;
    loadStage(0, 0); CP_COMMIT();
    for (int i = 0; i < niter; i++) {
        if (i + 1 < niter) { loadStage((i + 1) & 1, (i + 1) << 5); CP_COMMIT(); CP_WAIT(1); }
        else               { CP_WAIT(0); }
        __syncthreads();
        compute(i & 1);
        __syncthreads();
    }

#pragma unroll
    for (int mt = 0; mt < 4; mt++) {
        int r0 = bm + wm * 64 + mt * 16 + qm;
#pragma unroll
        for (int nt = 0; nt < NT; nt++) {
            int c0 = bn + wn * (BN / 4) + nt * 8 + qk * 2;
            float v0 = acc[mt][nt][0], v1 = acc[mt][nt][1];
            float v2 = acc[mt][nt][2], v3 = acc[mt][nt][3];
            if (bias) {
                float b0 = (c0 < N) ? bias[c0] : 0.f;
                float b1 = (c0 + 1 < N) ? bias[c0 + 1] : 0.f;
                v0 += b0; v1 += b1; v2 += b0; v3 += b1;
            }
            if (EPI == 1) {
                v0 = 0.5f * v0 * (1.f + erff(v0 * 0.70710678118654752f));
                v1 = 0.5f * v1 * (1.f + erff(v1 * 0.70710678118654752f));
                v2 = 0.5f * v2 * (1.f + erff(v2 * 0.70710678118654752f));
                v3 = 0.5f * v3 * (1.f + erff(v3 * 0.70710678118654752f));
            }
            if (EPI == 1 || EPI == 3) {
                __nv_bfloat162 h2, l2;
                split1(v0, h2.x, l2.x); split1(v1, h2.y, l2.y);
                *(__nv_bfloat162*)(Chi + (long)r0 * ldC + c0) = h2;
                *(__nv_bfloat162*)(Clo + (long)r0 * ldC + c0) = l2;
                split1(v2, h2.x, l2.x); split1(v3, h2.y, l2.y);
                *(__nv_bfloat162*)(Chi + (long)(r0 + 8) * ldC + c0) = h2;
                *(__nv_bfloat162*)(Clo + (long)(r0 + 8) * ldC + c0) = l2;
            }
            if (EPI == 0 || EPI == 3) {
                if (c0 < N) {
                    C[(long)r0 * ldC + c0] = v0;
                    C[(long)(r0 + 8) * ldC + c0] = v2;
                }
                if (c0 + 1 < N) {
                    C[(long)r0 * ldC + c0 + 1] = v1;
                    C[(long)(r0 + 8) * ldC + c0 + 1] = v3;
                }
            }
        }
    }
}

// ----------------------------------------------------------------------------
// Single-pass fp16 tensor-core GEMM (coarse sims only).
// ----------------------------------------------------------------------------
__global__ void __launch_bounds__(256) fgemm_kernel(
    const __half* __restrict__ A, const __half* __restrict__ B,
    float* __restrict__ C,
    int M, int N, int K, long zA, long zB, long zC)
{
    constexpr int BM = 128, BN = 128, NT = 4, ROWS = BM + BN;
    extern __shared__ __align__(16) __half fsmem[];

    const int bz = blockIdx.z;
    A += bz * zA; B += bz * zB; C += bz * zC;

    const int tid  = threadIdx.x;
    const int wid  = tid >> 5;
    const int lane = tid & 31;
    const int wm   = wid & 1;
    const int wn   = wid >> 1;
    const int qm   = lane >> 2;
    const int qk   = lane & 3;
    const int bm = blockIdx.y * BM;
    const int bn = blockIdx.x * BN;
    const uint32_t sbase = smem_u32(fsmem);

    float acc[4][NT][4];
#pragma unroll
    for (int mt = 0; mt < 4; mt++)
#pragma unroll
        for (int nt = 0; nt < NT; nt++)
#pragma unroll
            for (int r = 0; r < 4; r++) acc[mt][nt][r] = 0.f;

    auto loadStage = [&](int s, int k0) {
        const uint32_t p = sbase + (uint32_t)s * ROWS * 80;
#pragma unroll
        for (int c = tid; c < BM * 4; c += 256) {
            int row = c >> 2, kc = c & 3;
            long gofs = (long)(bm + row) * K + k0;
            CP_ASYNC16(p + row * 80 + kc * 16, (const char*)(A + gofs) + kc * 16);
        }
#pragma unroll
        for (int c = tid; c < BN * 4; c += 256) {
            int row = c >> 2, kc = c & 3;
            long gofs = (long)(bn + row) * K + k0;
            CP_ASYNC16(p + (BM + row) * 80 + kc * 16, (const char*)(B + gofs) + kc * 16);
        }
    };

    auto compute = [&](int s) {
        const uint32_t base = sbase + (uint32_t)s * ROWS * 80;
#pragma unroll
        for (int kc = 0; kc < 2; kc++) {
            uint32_t a[4][4], b[NT][2];
            const int arow = wm * 64 + (lane & 15);
            const uint32_t acol = kc * 32 + ((lane & 16) ? 16 : 0);
#pragma unroll
            for (int mt = 0; mt < 4; mt++) {
                uint32_t ro = (uint32_t)(arow + mt * 16) * 80 + acol;
                ldsm_x4(a[mt][0], a[mt][1], a[mt][2], a[mt][3], base + ro);
            }
            const int brow = BM + wn * 32 + (lane & 7) + ((lane & 16) ? 8 : 0);
            const uint32_t bcol = kc * 32 + ((lane & 8) ? 16 : 0);
#pragma unroll
            for (int np = 0; np < NT / 2; np++) {
                uint32_t ro = (uint32_t)(brow + np * 16) * 80 + bcol;
                ldsm_x4(b[2*np][0], b[2*np][1], b[2*np+1][0], b[2*np+1][1], base + ro);
            }
#pragma unroll
            for (int mt = 0; mt < 4; mt++)
#pragma unroll
                for (int nt = 0; nt < NT; nt++)
                    mma_f16(acc[mt][nt], a[mt][0], a[mt][1], a[mt][2], a[mt][3],
                            b[nt][0], b[nt][1]);
        }
    };

    const int niter = K >> 5;
    loadStage(0, 0); CP_COMMIT();
    for (int i = 0; i < niter; i++) {
        if (i + 1 < niter) { loadStage((i + 1) & 1, (i + 1) << 5); CP_COMMIT(); CP_WAIT(1); }
        else               { CP_WAIT(0); }
        __syncthreads();
        compute(i & 1);
        __syncthreads();
    }

#pragma unroll
    for (int mt = 0; mt < 4; mt++) {
        int r0 = bm + wm * 64 + mt * 16 + qm;
#pragma unroll
        for (int nt = 0; nt < NT; nt++) {
            int c0 = bn + wn * 32 + nt * 8 + qk * 2;
            C[(long)r0 * N + c0]           = acc[mt][nt][0];
            C[(long)r0 * N + c0 + 1]       = acc[mt][nt][1];
            C[(long)(r0 + 8) * N + c0]     = acc[mt][nt][2];
            C[(long)(r0 + 8) * N + c0 + 1] = acc[mt][nt][3];
        }
    }
}

// ----------------------------------------------------------------------------
// LayerNorm + fused bf16 splits of x and x+qpos + fp16 x copy.
// ----------------------------------------------------------------------------
__global__ void __launch_bounds__(256) ln_kernel(
    const float* __restrict__ x, const float* __restrict__ add,
    const float* __restrict__ g, const float* __restrict__ b,
    const float* __restrict__ qpos,
    float* __restrict__ out,
    __nv_bfloat16* __restrict__ ohi, __nv_bfloat16* __restrict__ olo,
    __nv_bfloat16* __restrict__ oqhi, __nv_bfloat16* __restrict__ oqlo,
    __half* __restrict__ oxf16)
{
    int row = blockIdx.x, tid = threadIdx.x;
    const float* xr = x + (long)row * D;
    float vals[3];
    float s = 0.f, sq = 0.f;
#pragma unroll
    for (int i = 0; i < 3; i++) {
        int c = tid + i * 256;
        float v = xr[c];
        if (add) v += add[(long)row * D + c];
        vals[i] = v; s += v; sq += v * v;
    }
    __shared__ float rs[256], rq[256];
    rs[tid] = s; rq[tid] = sq;
    __syncthreads();
    for (int o = 128; o > 0; o >>= 1) {
        if (tid < o) { rs[tid] += rs[tid + o]; rq[tid] += rq[tid + o]; }
        __syncthreads();
    }
    float mu = rs[0] * (1.f / D);
    float var = rq[0] * (1.f / D) - mu * mu;
    float rstd = rsqrtf(var + EPS);
#pragma unroll
    for (int i = 0; i < 3; i++) {
        int c = tid + i * 256;
        long o = (long)row * D + c;
        float v = (vals[i] - mu) * rstd * g[c] + b[c];
        out[o] = v;
        oxf16[o] = __float2half_rn(v);
        __nv_bfloat16 h, l;
        split1(v, h, l);
        ohi[o] = h; olo[o] = l;
        split1(v + qpos[o], h, l);
        oqhi[o] = h; oqlo[o] = l;
    }
}

__global__ void __launch_bounds__(256) rownorm_kernel(
    const float* __restrict__ m, float* __restrict__ minv)
{
    int row = blockIdx.x, tid = threadIdx.x;
    float s = 0.f;
#pragma unroll
    for (int i = 0; i < 3; i++) {
        float v = m[(long)row * D + tid + i * 256];
        s += v * v;
    }
    __shared__ float rs[256];
    rs[tid] = s; __syncthreads();
    for (int o = 128; o > 0; o >>= 1) {
        if (tid < o) rs[tid] += rs[tid + o];
        __syncthreads();
    }
    if (tid == 0) minv[row] = rsqrtf(rs[0]);
}

// ----------------------------------------------------------------------------
// Top-32: coarse top-40 (fp16 sims) + exact fp32 rescore of the 40.
// ----------------------------------------------------------------------------
__global__ void __launch_bounds__(256) topk_kernel(
    const float* __restrict__ sims, const float* __restrict__ minv,
    const float* __restrict__ x, const float* __restrict__ memory,
    int* __restrict__ idx_out)
{
    int row = blockIdx.x;
    int b = row >> 7;
    int tid = threadIdx.x;
    int warp = tid >> 5, lane = tid & 31;
    __shared__ float s[MNP];
    __shared__ float rmax[256];
    __shared__ int   rarg[256];
    __shared__ float xrow[D];
    __shared__ int   cand[CN];
    __shared__ float cval[CN];

    for (int i = tid; i < MNP; i += 256)
        s[i] = sims[(long)row * MNP + i] * minv[b * MNP + i];
    for (int c = tid; c < D; c += 256)
        xrow[c] = x[(long)row * D + c];
    __syncthreads();

    for (int t = 0; t < CN; t++) {
        float best = -INFINITY; int bi = 0x7fffffff;
        for (int i = tid; i < MNP; i += 256) {
            float v = s[i];
            if (v > best) { best = v; bi = i; }
        }
        rmax[tid] = best; rarg[tid] = bi;
        __syncthreads();
        for (int o = 128; o > 0; o >>= 1) {
            if (tid < o) {
                float ov = rmax[tid + o]; int oi = rarg[tid + o];
                if (ov > rmax[tid] || (ov == rmax[tid] && oi < rarg[tid])) {
                    rmax[tid] = ov; rarg[tid] = oi;
                }
            }
            __syncthreads();
        }
        if (tid == 0) {
            cand[t] = rarg[0];
            s[rarg[0]] = -INFINITY;
        }
        __syncthreads();
    }

    for (int j = warp; j < CN; j += 8) {
        int ix = cand[j];
        const float* mr = memory + ((long)(b * MNP + ix)) * D;
        float acc = 0.f;
        for (int c = lane; c < D; c += 32) acc = fmaf(xrow[c], mr[c], acc);
#pragma unroll
        for (int o = 16; o > 0; o >>= 1) acc += __shfl_xor_sync(0xffffffffu, acc, o);
        if (lane == 0) cval[j] = acc * minv[b * MNP + ix];
    }
    __syncthreads();

    if (warp == 0) {
        for (int t = 0; t < TOPK; t++) {
            float v = -INFINITY; int myi = 0x7fffffff, myj = -1;
            for (int j = lane; j < CN; j += 32) {
                float cv = cval[j];
                if (cv > v || (cv == v && cand[j] < myi)) { v = cv; myi = cand[j]; myj = j; }
            }
#pragma unroll
            for (int o = 16; o > 0; o >>= 1) {
                float ov = __shfl_xor_sync(0xffffffffu, v, o);
                int   oi = __shfl_xor_sync(0xffffffffu, myi, o);
                int   oj = __shfl_xor_sync(0xffffffffu, myj, o);
                if (ov > v || (ov == v && oi < myi)) { v = ov; myi = oi; myj = oj; }
            }
            if (lane == 0) {
                idx_out[row * TOPK + t] = myi;
                cval[myj] = -INFINITY;
            }
            __syncwarp();
        }
    }
}

// ----------------------------------------------------------------------------
// Fused cross-attention: per-query block, Z in registers (stride-32 cols),
// scores over 32 gathered (mem+kpos) rows, per-head softmax, memory-domain
// aggregation (reusing the register file), bf16 split output.
// ----------------------------------------------------------------------------
__global__ void __launch_bounds__(128) xattn_kernel(
    const float* __restrict__ qf,      // [2048][768]
    const float* __restrict__ Z,       // [12][2048][768]
    const float* __restrict__ memory,  // [32768][768]
    const float* __restrict__ kpos,    // [32768][768]
    const float* __restrict__ l2b,     // [768]
    const int*   __restrict__ idx,     // [2048][32]
    __nv_bfloat16* __restrict__ agghi, // [12][2048][768]
    __nv_bfloat16* __restrict__ agglo)
{
    __shared__ float row[D];
    __shared__ float qrow[D];
    __shared__ float sc[NH][TOPK];
    __shared__ float qb[NH];
    __shared__ int   ids[TOPK];

    const int qi = blockIdx.x;
    const int b = qi >> 7;
    const int tid = threadIdx.x;
    const int warp = tid >> 5, lane = tid & 31;
    const int h0 = warp * 3;

    for (int k = 0; k < 6; k++)
        qrow[tid + 128 * k] = qf[(long)qi * D + tid + 128 * k];
    if (tid < TOPK) ids[tid] = idx[qi * TOPK + tid];
    __syncthreads();

    // qb[h] = q_h . b2_h
#pragma unroll
    for (int t = 0; t < 3; t++) {
        int h = h0 + t;
        float s = qrow[h * HD + lane] * l2b[h * HD + lane]
                + qrow[h * HD + 32 + lane] * l2b[h * HD + 32 + lane];
#pragma unroll
        for (int o = 16; o > 0; o >>= 1) s += __shfl_xor_sync(0xffffffffu, s, o);
        if (lane == 0) qb[h] = s;
    }

    // Z rows for this warp's 3 heads -> registers (stride-32 columns)
    float reg[3][24];
#pragma unroll
    for (int t = 0; t < 3; t++) {
        const float* zp = Z + ((long)(h0 + t) * NTOK + qi) * D;
#pragma unroll
        for (int i = 0; i < 24; i++) reg[t][i] = zp[lane + 32 * i];
    }

    // scores
    for (int j = 0; j < TOPK; j++) {
        long base = ((long)(b * MNP + ids[j])) * D;
        for (int k = 0; k < 6; k++) {
            int c = tid + 128 * k;
            row[c] = memory[base + c] + kpos[base + c];
        }
        __syncthreads();
#pragma unroll
        for (int t = 0; t < 3; t++) {
            float s = 0.f;
#pragma unroll
            for (int i = 0; i < 24; i++) s = fmaf(reg[t][i], row[lane + 32 * i], s);
#pragma unroll
            for (int o = 16; o > 0; o >>= 1) s += __shfl_xor_sync(0xffffffffu, s, o);
            if (lane == 0) sc[h0 + t][j] = (s + qb[h0 + t]) * 0.125f;
        }
        __syncthreads();
    }

    // softmax per head
    if (tid < NH) {
        float m = -INFINITY;
        for (int j = 0; j < TOPK; j++) m = fmaxf(m, sc[tid][j]);
        float sum = 0.f;
        for (int j = 0; j < TOPK; j++) {
            float e = expf(sc[tid][j] - m);
            sc[tid][j] = e; sum += e;
        }
        float inv = 1.f / sum;
        for (int j = 0; j < TOPK; j++) sc[tid][j] *= inv;
    }
    __syncthreads();

    // aggregate (reuse register file)
#pragma unroll
    for (int t = 0; t < 3; t++)
#pragma unroll
        for (int i = 0; i < 24; i++) reg[t][i] = 0.f;

    for (int j = 0; j < TOPK; j++) {
        long base = ((long)(b * MNP + ids[j])) * D;
        for (int k = 0; k < 6; k++)
            row[tid + 128 * k] = memory[base + tid + 128 * k];
        __syncthreads();
#pragma unroll
        for (int t = 0; t < 3; t++) {
            float p = sc[h0 + t][j];
#pragma unroll
            for (int i = 0; i < 24; i++)
                reg[t][i] = fmaf(p, row[lane + 32 * i], reg[t][i]);
        }
        __syncthreads();
    }

    // write splits
#pragma unroll
    for (int t = 0; t < 3; t++) {
        long o0 = ((long)(h0 + t) * NTOK + qi) * D;
#pragma unroll
        for (int i = 0; i < 24; i++) {
            __nv_bfloat16 h, l;
            split1(reg[t][i], h, l);
            agghi[o0 + lane + 32 * i] = h;
            agglo[o0 + lane + 32 * i] = l;
        }
    }
}

// ----------------------------------------------------------------------------
// Dense self-attention over NP=128 keys -> bf16 split out
// ----------------------------------------------------------------------------
__global__ void __launch_bounds__(128) self_attn_kernel(
    const float* __restrict__ qk, const float* __restrict__ v,
    __nv_bfloat16* __restrict__ ohi, __nv_bfloat16* __restrict__ olo)
{
    int row = blockIdx.x;
    int b = row >> 7;
    int h = blockIdx.y;
    int tid = threadIdx.x;

    __shared__ float qv[HD];
    __shared__ float sc[NP];
    __shared__ float red[128];

    const float* qr = qk + (long)row * (2 * D) + h * HD;
    if (tid < HD) qv[tid] = qr[tid];
    __syncthreads();

    const float* kr = qk + (long)(b * NP + tid) * (2 * D) + D + h * HD;
    float s = 0.f;
#pragma unroll
    for (int d = 0; d < HD; d++) s = fmaf(qv[d], kr[d], s);
    s *= 0.125f;

    red[tid] = s; __syncthreads();
    for (int o = 64; o > 0; o >>= 1) {
        if (tid < o) red[tid] = fmaxf(red[tid], red[tid + o]);
        __syncthreads();
    }
    float m = red[0]; __syncthreads();
    float e = expf(s - m);
    sc[tid] = e;
    red[tid] = e; __syncthreads();
    for (int o = 64; o > 0; o >>= 1) {
        if (tid < o) red[tid] += red[tid + o];
        __syncthreads();
    }
    float inv = 1.f / red[0];

    if (tid < HD) {
        float acc = 0.f;
        for (int j = 0; j < NP; j++)
            acc = fmaf(sc[j], v[(long)(b * NP + j) * D + h * HD + tid], acc);
        long o = (long)row * D + h * HD + tid;
        __nv_bfloat16 hh, ll;
        split1(acc * inv, hh, ll);
        ohi[o] = hh; olo[o] = ll;
    }
}

// ----------------------------------------------------------------------------
// BatchNorm stats -> fused scale/shift
// ----------------------------------------------------------------------------
__global__ void __launch_bounds__(256) bn_stats_kernel(
    const float* __restrict__ x, const float* __restrict__ g,
    const float* __restrict__ b, float* __restrict__ scale,
    float* __restrict__ shift)
{
    int f = blockIdx.x, tid = threadIdx.x;
    float s = 0.f, sq = 0.f;
    for (int r = tid; r < NTOK; r += 256) {
        float v = x[(long)r * D + f];
        s += v; sq += v * v;
    }
    __shared__ float rs[256], rq[256];
    rs[tid] = s; rq[tid] = sq;
    __syncthreads();
    for (int o = 128; o > 0; o >>= 1) {
        if (tid < o) { rs[tid] += rs[tid + o]; rq[tid] += rq[tid + o]; }
        __syncthreads();
    }
    if (tid == 0) {
        float mu = rs[0] * (1.f / NTOK);
        float var = rq[0] * (1.f / NTOK) - mu * mu;
        float rstd = rsqrtf(var + EPS);
        float sc = rstd * g[f];
        scale[f] = sc;
        shift[f] = b[f] - mu * sc;
    }
}

// ----------------------------------------------------------------------------
// Host orchestration
// ----------------------------------------------------------------------------
#define SMEM128 (2 * 2 * 256 * 80)   // 81920
#define SMEM64  (2 * 2 * 192 * 80)   // 61440
#define SMEMF   (2 * 256 * 80)       // 40960

extern "C" void kernel_launch(void* const* d_in, const int* in_sizes, int n_in,
                              void* d_out, int out_size)
{
    const float* tgt      = (const float*)d_in[0];
    const float* memory   = (const float*)d_in[1];
    const float* qpos     = (const float*)d_in[2];
    const float* kpos     = (const float*)d_in[3];
    const float* norm0_g  = (const float*)d_in[4];
    const float* norm0_b  = (const float*)d_in[5];
    const float* l1_w     = (const float*)d_in[6];
    const float* l1_b     = (const float*)d_in[7];
    const float* l2_w     = (const float*)d_in[8];
    const float* l2_b     = (const float*)d_in[9];
    const float* l3_w     = (const float*)d_in[10];
    const float* l3_b     = (const float*)d_in[11];
    const float* n1_g     = (const float*)d_in[12];
    const float* n1_b     = (const float*)d_in[13];
    const float* n2_g     = (const float*)d_in[14];
    const float* n2_b     = (const float*)d_in[15];
    const float* n3_g     = (const float*)d_in[16];
    const float* n3_b     = (const float*)d_in[17];
    const float* sa_in_w  = (const float*)d_in[18];
    const float* sa_in_b  = (const float*)d_in[19];
    const float* sa_out_w = (const float*)d_in[20];
    const float* sa_out_b = (const float*)d_in[21];
    const float* ff1_w    = (const float*)d_in[22];
    const float* ff1_b    = (const float*)d_in[23];
    const float* ff2_w    = (const float*)d_in[24];
    const float* ff2_b    = (const float*)d_in[25];
    const float* bn_g     = (const float*)d_in[26];
    const float* bn_b     = (const float*)d_in[27];
    const float* cls_w    = (const float*)d_in[28];

    float *x, *tmp, *q, *qk, *v, *attn, *Z, *sims, *minv, *bnsc, *bnsh;
    int* idx;
    __nv_bfloat16 *whi, *wlo, *w2th, *w2tl;
    __nv_bfloat16 *xhi, *xlo, *xqhi, *xqlo, *qhi, *qlo, *agghi, *agglo;
    __nv_bfloat16 *h1hi, *h1lo, *sahi, *salo, *cihi, *cilo;
    __half *mf16, *xf16;
    cudaGetSymbolAddress((void**)&x,    g_x);
    cudaGetSymbolAddress((void**)&tmp,  g_tmp);
    cudaGetSymbolAddress((void**)&q,    g_q);
    cudaGetSymbolAddress((void**)&qk,   g_qk);
    cudaGetSymbolAddress((void**)&v,    g_v);
    cudaGetSymbolAddress((void**)&attn, g_attn);
    cudaGetSymbolAddress((void**)&Z,    g_Z);
    cudaGetSymbolAddress((void**)&sims, g_sims);
    cudaGetSymbolAddress((void**)&idx,  g_idx);
    cudaGetSymbolAddress((void**)&minv, g_minv);
    cudaGetSymbolAddress((void**)&bnsc, g_bnscale);
    cudaGetSymbolAddress((void**)&bnsh, g_bnshift);
    cudaGetSymbolAddress((void**)&whi,  g_whi);
    cudaGetSymbolAddress((void**)&wlo,  g_wlo);
    cudaGetSymbolAddress((void**)&w2th, g_w2thi);
    cudaGetSymbolAddress((void**)&w2tl, g_w2tlo);
    cudaGetSymbolAddress((void**)&xhi,  g_xhi);
    cudaGetSymbolAddress((void**)&xlo,  g_xlo);
    cudaGetSymbolAddress((void**)&xqhi, g_xqhi);
    cudaGetSymbolAddress((void**)&xqlo, g_xqlo);
    cudaGetSymbolAddress((void**)&qhi,  g_qhi);
    cudaGetSymbolAddress((void**)&qlo,  g_qlo);
    cudaGetSymbolAddress((void**)&agghi, g_agghi);
    cudaGetSymbolAddress((void**)&agglo, g_agglo);
    cudaGetSymbolAddress((void**)&h1hi, g_h1hi);
    cudaGetSymbolAddress((void**)&h1lo, g_h1lo);
    cudaGetSymbolAddress((void**)&sahi, g_sahi);
    cudaGetSymbolAddress((void**)&salo, g_salo);
    cudaGetSymbolAddress((void**)&cihi, g_cihi);
    cudaGetSymbolAddress((void**)&cilo, g_cilo);
    cudaGetSymbolAddress((void**)&mf16, g_mf16);
    cudaGetSymbolAddress((void**)&xf16, g_xf16);

    cudaFuncSetAttribute(hgemm_kernel<128,0>, cudaFuncAttributeMaxDynamicSharedMemorySize, SMEM128);
    cudaFuncSetAttribute(hgemm_kernel<128,1>, cudaFuncAttributeMaxDynamicSharedMemorySize, SMEM128);
    cudaFuncSetAttribute(hgemm_kernel<128,3>, cudaFuncAttributeMaxDynamicSharedMemorySize, SMEM128);
    cudaFuncSetAttribute(hgemm_kernel<64,0>,  cudaFuncAttributeMaxDynamicSharedMemorySize, SMEM64);

    // ---- one-time conversions ----
    split_kernel<<<2048, 256>>>(l1_w,     whi + OFF_L1,    wlo + OFF_L1,    (long)NLAYERS*D*D);
    split_kernel<<<2048, 256>>>(l3_w,     whi + OFF_L3,    wlo + OFF_L3,    (long)NLAYERS*D*D);
    split_kernel<<<2048, 256>>>(sa_in_w,  whi + OFF_SAIN,  wlo + OFF_SAIN,  (long)NLAYERS*3*D*D);
    split_kernel<<<2048, 256>>>(sa_out_w, whi + OFF_SAOUT, wlo + OFF_SAOUT, (long)NLAYERS*D*D);
    split_kernel<<<2048, 256>>>(ff1_w,    whi + OFF_FF1,   wlo + OFF_FF1,   (long)NLAYERS*DFF*D);
    split_kernel<<<2048, 256>>>(ff2_w,    whi + OFF_FF2,   wlo + OFF_FF2,   (long)NLAYERS*D*DFF);
    split_kernel<<<2048, 256>>>(cls_w,    whi + OFF_CLS,   wlo + OFF_CLS,   (long)NC*D);
    w2t_split_kernel<<<2048, 256>>>(l2_w, w2th, w2tl);
    conv_kernel<<<8192, 256>>>(memory, mf16, (long)NMEM*D);

    rownorm_kernel<<<NMEM, 256>>>(memory, minv);
    ln_kernel<<<NTOK, 256>>>(tgt, nullptr, norm0_g, norm0_b, qpos,
                             x, xhi, xlo, xqhi, xqlo, xf16);

    for (int l = 0; l < NLAYERS; l++) {
        long wdd = (long)l * D * D;
        const __nv_bfloat16* l1h = whi + OFF_L1 + wdd;   const __nv_bfloat16* l1l = wlo + OFF_L1 + wdd;
        const __nv_bfloat16* l3h = whi + OFF_L3 + wdd;   const __nv_bfloat16* l3l = wlo + OFF_L3 + wdd;
        const __nv_bfloat16* sih = whi + OFF_SAIN + (long)l*3*D*D;
        const __nv_bfloat16* sil = wlo + OFF_SAIN + (long)l*3*D*D;
        const __nv_bfloat16* soh = whi + OFF_SAOUT + wdd;
        const __nv_bfloat16* sol = wlo + OFF_SAOUT + wdd;
        const __nv_bfloat16* f1h = whi + OFF_FF1 + (long)l*DFF*D;
        const __nv_bfloat16* f1l = wlo + OFF_FF1 + (long)l*DFF*D;
        const __nv_bfloat16* f2h = whi + OFF_FF2 + (long)l*D*DFF;
        const __nv_bfloat16* f2l = wlo + OFF_FF2 + (long)l*D*DFF;
        const __nv_bfloat16* w2h = w2th + (long)l*NH*D*HD;
        const __nv_bfloat16* w2l = w2tl + (long)l*NH*D*HD;
        const float* l1bb = l1_b + (long)l * D;
        const float* l2bb = l2_b + (long)l * D;
        const float* l3bb = l3_b + (long)l * D;
        const float* sab  = sa_in_b + (long)l * 3 * D;
        const float* sob  = sa_out_b + (long)l * D;
        const float* f1b  = ff1_b + (long)l * DFF;
        const float* f2b  = ff2_b + (long)l * D;

        // coarse sims (fp16, batched)
        fgemm_kernel<<<dim3(MNP/128, 1, BS), 256, SMEMF>>>(
            xf16, mf16, sims, NP, MNP, D,
            (long)NP*D, (long)MNP*D, (long)NP*MNP);

        // exact top-32 (coarse top-40 + fp32 rescore)
        topk_kernel<<<NTOK, 256>>>(sims, minv, x, memory, idx);

        // q = (x+qpos) @ l1^T + b1  -> fp32 + bf16 splits
        hgemm_kernel<128,3><<<dim3(D/128, NTOK/128, 1), 256, SMEM128>>>(
            xqhi, xqlo, l1h, l1l, l1bb, q, qhi, qlo,
            NTOK, D, D, D, D, D, 0, 0, 0, 0);

        // Z_h = Q_h @ W2T_h^T  (batched over heads, K=64)
        hgemm_kernel<128,0><<<dim3(D/128, NTOK/128, NH), 256, SMEM128>>>(
            qhi, qlo, w2h, w2l, nullptr, Z, nullptr, nullptr,
            NTOK, D, HD, D, HD, D,
            (long)HD, (long)D*HD, (long)NTOK*D, 0);

        // fused scores / softmax / memory-domain aggregation
        xattn_kernel<<<NTOK, 128>>>(q, Z, memory, kpos, l2bb, idx, agghi, agglo);

        // attn_h = Agg_h @ W3_h^T + b3_h  (batched over heads)
        hgemm_kernel<64,0><<<dim3(1, NTOK/128, NH), 256, SMEM64>>>(
            agghi, agglo, l3h, l3l, l3bb, attn, nullptr, nullptr,
            NTOK, HD, D, D, D, D,
            (long)NTOK*D, (long)HD*D, (long)HD, (long)HD);

        ln_kernel<<<NTOK, 256>>>(x, attn, n1_g + (long)l * D, n1_b + (long)l * D,
                                 qpos, x, xhi, xlo, xqhi, xqlo, xf16);

        // self-attn projections (bf16x3)
        hgemm_kernel<128,0><<<dim3((2*D)/128, NTOK/128, 1), 256, SMEM128>>>(
            xqhi, xqlo, sih, sil, sab, qk, nullptr, nullptr,
            NTOK, 2*D, D, D, D, 2*D, 0, 0, 0, 0);
        hgemm_kernel<64,0><<<dim3(D/64, NTOK/128, 1), 256, SMEM64>>>(
            xhi, xlo, sih + (long)2*D*D, sil + (long)2*D*D, sab + 2*D,
            v, nullptr, nullptr, NTOK, D, D, D, D, D, 0, 0, 0, 0);

        self_attn_kernel<<<dim3(NTOK, NH), 128>>>(qk, v, sahi, salo);

        hgemm_kernel<64,0><<<dim3(D/64, NTOK/128, 1), 256, SMEM64>>>(
            sahi, salo, soh, sol, sob, tmp, nullptr, nullptr,
            NTOK, D, D, D, D, D, 0, 0, 0, 0);

        ln_kernel<<<NTOK, 256>>>(x, tmp, n2_g + (long)l * D, n2_b + (long)l * D,
                                 qpos, x, xhi, xlo, xqhi, xqlo, xf16);

        // FFN (bf16x3)
        hgemm_kernel<128,1><<<dim3(DFF/128, NTOK/128, 1), 256, SMEM128>>>(
            xhi, xlo, f1h, f1l, f1b, nullptr, h1hi, h1lo,
            NTOK, DFF, D, D, D, DFF, 0, 0, 0, 0);
        hgemm_kernel<64,0><<<dim3(D/64, NTOK/128, 1), 256, SMEM64>>>(
            h1hi, h1lo, f2h, f2l, f2b, tmp, nullptr, nullptr,
            NTOK, D, DFF, DFF, DFF, D, 0, 0, 0, 0);

        ln_kernel<<<NTOK, 256>>>(x, tmp, n3_g + (long)l * D, n3_b + (long)l * D,
                                 qpos, x, xhi, xlo, xqhi, xqlo, xf16);
    }

    bn_stats_kernel<<<D, 256>>>(x, bn_g, bn_b, bnsc, bnsh);
    split_affine_kernel<<<2048, 256>>>(x, bnsc, bnsh, cihi, cilo, (long)NTOK * D);

    float* out = (float*)d_out;
    long xsz = (long)NTOK * D;
    long csz = (long)NTOK * NC;

    if ((long)out_size >= xsz + csz) {
        cudaMemcpyAsync(out, x, sizeof(float) * xsz, cudaMemcpyDeviceToDevice, 0);
        hgemm_kernel<64,0><<<dim3((NC+63)/64, NTOK/128, 1), 256, SMEM64>>>(
            cihi, cilo, whi + OFF_CLS, wlo + OFF_CLS, nullptr,
            out + xsz, nullptr, nullptr, NTOK, NC, D, D, D, NC, 0, 0, 0, 0);
    } else if ((long)out_size == csz) {
        hgemm_kernel<64,0><<<dim3((NC+63)/64, NTOK/128, 1), 256, SMEM64>>>(
            cihi, cilo, whi + OFF_CLS, wlo + OFF_CLS, nullptr,
            out, nullptr, nullptr, NTOK, NC, D, D, D, NC, 0, 0, 0, 0);
    } else {
        cudaMemcpyAsync(out, x, sizeof(float) * ((long)out_size < xsz ? out_size : xsz),
                        cudaMemcpyDeviceToDevice, 0);
    }
}

// round 13
// speedup vs baseline: 1.6749x; 1.0730x over previous
#include <cuda_runtime.h>
#include <cuda_bf16.h>
#include <cuda_fp16.h>
#include <math.h>
#include <stdint.h>

#define BS   16
#define NP   128
#define MNP  2048
#define D    768
#define NH   12
#define HD   64
#define DFF  2048
#define NLAYERS 2
#define TOPK 32
#define COVER 48
#define NC   751
#define NTOK (BS*NP)
#define NMEM (BS*MNP)
#define EPS  1e-5f

// ----------------------------------------------------------------------------
// Scratch
// ----------------------------------------------------------------------------
__device__ float g_x   [NTOK*(long)D];
__device__ float g_tmp [NTOK*(long)D];
__device__ float g_q   [NTOK*(long)D];
__device__ float g_qk  [NTOK*(long)(2*D)];
__device__ float g_v   [NTOK*(long)D];
__device__ float g_attn[NTOK*(long)D];
__device__ float g_Z   [(long)NH*NTOK*D];
__device__ float g_sims[NTOK*(long)MNP];
__device__ int   g_idx [NTOK*TOPK];
__device__ float g_minv[NMEM];
__device__ float g_bnscale[D];
__device__ float g_bnshift[D];

#define OFF_L1    0L
#define OFF_L3    1179648L
#define OFF_SAIN  2359296L
#define OFF_SAOUT 5898240L
#define OFF_FF1   7077888L
#define OFF_FF2   10223616L
#define OFF_CLS   13369344L
#define WTOTAL    13946112L
__device__ __nv_bfloat16 g_whi[WTOTAL], g_wlo[WTOTAL];
__device__ __nv_bfloat16 g_w2thi[(long)NLAYERS*NH*D*HD], g_w2tlo[(long)NLAYERS*NH*D*HD];
__device__ __nv_bfloat16 g_xhi [NTOK*(long)D], g_xlo [NTOK*(long)D];
__device__ __nv_bfloat16 g_xqhi[NTOK*(long)D], g_xqlo[NTOK*(long)D];
__device__ __nv_bfloat16 g_qhi [NTOK*(long)D], g_qlo [NTOK*(long)D];
__device__ __nv_bfloat16 g_agghi[(long)NH*NTOK*D], g_agglo[(long)NH*NTOK*D];
__device__ __nv_bfloat16 g_h1hi[NTOK*(long)DFF], g_h1lo[NTOK*(long)DFF];
__device__ __nv_bfloat16 g_sahi[NTOK*(long)D], g_salo[NTOK*(long)D];
__device__ __nv_bfloat16 g_cihi[NTOK*(long)D], g_cilo[NTOK*(long)D];

__device__ __half g_mf16 [NMEM*(long)D];
__device__ __half g_xf16 [NTOK*(long)D];

// ----------------------------------------------------------------------------
// Helpers
// ----------------------------------------------------------------------------
__device__ __forceinline__ uint32_t smem_u32(const void* p) {
    uint32_t a;
    asm("{ .reg .u64 t; cvta.to.shared.u64 t, %1; cvt.u32.u64 %0, t; }"
        : "=r"(a) : "l"(p));
    return a;
}

#define CP_ASYNC16(dst, src) \
    asm volatile("cp.async.ca.shared.global [%0], [%1], 16;" \
                 :: "r"(dst), "l"(src) : "memory")
#define CP_COMMIT() asm volatile("cp.async.commit_group;" ::: "memory")
#define CP_WAIT(n)  asm volatile("cp.async.wait_group %0;" :: "n"(n) : "memory")

__device__ __forceinline__ void ldsm_x4(uint32_t& r0, uint32_t& r1,
                                        uint32_t& r2, uint32_t& r3, uint32_t addr)
{
    asm volatile("ldmatrix.sync.aligned.m8n8.x4.shared.b16 {%0,%1,%2,%3}, [%4];"
        : "=r"(r0), "=r"(r1), "=r"(r2), "=r"(r3) : "r"(addr));
}

__device__ __forceinline__ void mma_bf16(float c[4],
    uint32_t a0, uint32_t a1, uint32_t a2, uint32_t a3,
    uint32_t b0, uint32_t b1)
{
    asm("mma.sync.aligned.m16n8k16.row.col.f32.bf16.bf16.f32 "
        "{%0,%1,%2,%3}, {%4,%5,%6,%7}, {%8,%9}, {%0,%1,%2,%3};"
        : "+f"(c[0]), "+f"(c[1]), "+f"(c[2]), "+f"(c[3])
        : "r"(a0), "r"(a1), "r"(a2), "r"(a3), "r"(b0), "r"(b1));
}

__device__ __forceinline__ void mma_f16(float c[4],
    uint32_t a0, uint32_t a1, uint32_t a2, uint32_t a3,
    uint32_t b0, uint32_t b1)
{
    asm("mma.sync.aligned.m16n8k16.row.col.f32.f16.f16.f32 "
        "{%0,%1,%2,%3}, {%4,%5,%6,%7}, {%8,%9}, {%0,%1,%2,%3};"
        : "+f"(c[0]), "+f"(c[1]), "+f"(c[2]), "+f"(c[3])
        : "r"(a0), "r"(a1), "r"(a2), "r"(a3), "r"(b0), "r"(b1));
}

__device__ __forceinline__ void split1(float v, __nv_bfloat16& h, __nv_bfloat16& l) {
    __nv_bfloat16 hb = __float2bfloat16_rn(v);
    h = hb;
    l = __float2bfloat16_rn(v - __bfloat162float(hb));
}

// ----------------------------------------------------------------------------
// Convert / split kernels
// ----------------------------------------------------------------------------
__global__ void __launch_bounds__(256) split_kernel(
    const float* __restrict__ src,
    __nv_bfloat16* __restrict__ hi, __nv_bfloat16* __restrict__ lo, long n)
{
    long i = blockIdx.x * 256L + threadIdx.x;
    long stride = (long)gridDim.x * 256;
    for (; i < n; i += stride) {
        __nv_bfloat16 h, l;
        split1(src[i], h, l);
        hi[i] = h; lo[i] = l;
    }
}

__global__ void __launch_bounds__(256) w2t_split_kernel(
    const float* __restrict__ l2w,
    __nv_bfloat16* __restrict__ hi, __nv_bfloat16* __restrict__ lo)
{
    long n = (long)NLAYERS * NH * D * HD;
    long i = blockIdx.x * 256L + threadIdx.x;
    long stride = (long)gridDim.x * 256;
    for (; i < n; i += stride) {
        int k = (int)(i & 63);
        long t = i >> 6;
        int nn = (int)(t % D);
        long t2 = t / D;
        int h = (int)(t2 % NH);
        int l = (int)(t2 / NH);
        float v = l2w[((long)l * D + h * HD + k) * D + nn];
        __nv_bfloat16 hh, ll;
        split1(v, hh, ll);
        hi[i] = hh; lo[i] = ll;
    }
}

__global__ void __launch_bounds__(256) conv_kernel(
    const float* __restrict__ src, __half* __restrict__ dst, long n)
{
    long i = blockIdx.x * 256L + threadIdx.x;
    long stride = (long)gridDim.x * 256;
    for (; i < n; i += stride) dst[i] = __float2half_rn(src[i]);
}

__global__ void __launch_bounds__(256) split_affine_kernel(
    const float* __restrict__ src, const float* __restrict__ scale,
    const float* __restrict__ shift,
    __nv_bfloat16* __restrict__ hi, __nv_bfloat16* __restrict__ lo, long n)
{
    long i = blockIdx.x * 256L + threadIdx.x;
    long stride = (long)gridDim.x * 256;
    for (; i < n; i += stride) {
        int k = (int)(i % D);
        __nv_bfloat16 h, l;
        split1(src[i] * scale[k] + shift[k], h, l);
        hi[i] = h; lo[i] = l;
    }
}

// ----------------------------------------------------------------------------
// bf16x3 tensor-core GEMM (unchanged from R12)
// ----------------------------------------------------------------------------
template<int BN, int EPI>
__global__ void __launch_bounds__(256) hgemm_kernel(
    const __nv_bfloat16* __restrict__ Ah, const __nv_bfloat16* __restrict__ Al,
    const __nv_bfloat16* __restrict__ Bh, const __nv_bfloat16* __restrict__ Bl,
    const float* __restrict__ bias,
    float* __restrict__ C,
    __nv_bfloat16* __restrict__ Chi, __nv_bfloat16* __restrict__ Clo,
    int M, int N, int K, int ldA, int ldB, int ldC,
    long zA, long zB, long zC, long zBias)
{
    constexpr int BM = 128;
    constexpr int NT = BN / 32;
    constexpr int ROWS = BM + BN;
    extern __shared__ __align__(16) __nv_bfloat16 smem[];

    const int bz = blockIdx.z;
    Ah += bz * zA; Al += bz * zA;
    Bh += bz * zB; Bl += bz * zB;
    if (bias) bias += bz * zBias;
    C  += bz * zC;
    if (EPI == 1 || EPI == 3) { Chi += bz * zC; Clo += bz * zC; }

    const int tid  = threadIdx.x;
    const int wid  = tid >> 5;
    const int lane = tid & 31;
    const int wm   = wid & 1;
    const int wn   = wid >> 1;
    const int qm   = lane >> 2;
    const int qk   = lane & 3;
    const int bm = blockIdx.y * BM;
    const int bn = blockIdx.x * BN;
    const uint32_t sbase = smem_u32(smem);

    float acc[4][NT][4];
#pragma unroll
    for (int mt = 0; mt < 4; mt++)
#pragma unroll
        for (int nt = 0; nt < NT; nt++)
#pragma unroll
            for (int r = 0; r < 4; r++) acc[mt][nt][r] = 0.f;

    auto loadStage = [&](int s, int k0) {
        const uint32_t pH = sbase + (uint32_t)(s * 2 + 0) * ROWS * 80;
        const uint32_t pL = sbase + (uint32_t)(s * 2 + 1) * ROWS * 80;
#pragma unroll
        for (int c = tid; c < BM * 4; c += 256) {
            int row = c >> 2, kc = c & 3;
            long gofs = (long)(bm + row) * ldA + k0;
            CP_ASYNC16(pH + row * 80 + kc * 16, (const char*)(Ah + gofs) + kc * 16);
            CP_ASYNC16(pL + row * 80 + kc * 16, (const char*)(Al + gofs) + kc * 16);
        }
#pragma unroll
        for (int c = tid; c < BN * 4; c += 256) {
            int row = c >> 2, kc = c & 3;
            int n = bn + row;
            uint32_t dh = pH + (BM + row) * 80 + kc * 16;
            uint32_t dl = pL + (BM + row) * 80 + kc * 16;
            if (n < N) {
                long gofs = (long)n * ldB + k0;
                CP_ASYNC16(dh, (const char*)(Bh + gofs) + kc * 16);
                CP_ASYNC16(dl, (const char*)(Bl + gofs) + kc * 16);
            } else {
                uint32_t z = 0;
                asm volatile("st.shared.v4.b32 [%0], {%1,%1,%1,%1};" :: "r"(dh), "r"(z) : "memory");
                asm volatile("st.shared.v4.b32 [%0], {%1,%1,%1,%1};" :: "r"(dl), "r"(z) : "memory");
            }
        }
    };

    auto compute = [&](int s) {
        const uint32_t baseH = sbase + (uint32_t)(s * 2 + 0) * ROWS * 80;
        const uint32_t baseL = sbase + (uint32_t)(s * 2 + 1) * ROWS * 80;
#pragma unroll
        for (int kc = 0; kc < 2; kc++) {
            uint32_t ah[4][4], al[4][4], bh[NT][2], bl[NT][2];
            const int arow = wm * 64 + (lane & 15);
            const uint32_t acol = kc * 32 + ((lane & 16) ? 16 : 0);
#pragma unroll
            for (int mt = 0; mt < 4; mt++) {
                uint32_t ro = (uint32_t)(arow + mt * 16) * 80 + acol;
                ldsm_x4(ah[mt][0], ah[mt][1], ah[mt][2], ah[mt][3], baseH + ro);
                ldsm_x4(al[mt][0], al[mt][1], al[mt][2], al[mt][3], baseL + ro);
            }
            const int brow = BM + wn * (BN / 4) + (lane & 7) + ((lane & 16) ? 8 : 0);
            const uint32_t bcol = kc * 32 + ((lane & 8) ? 16 : 0);
#pragma unroll
            for (int np = 0; np < NT / 2; np++) {
                uint32_t ro = (uint32_t)(brow + np * 16) * 80 + bcol;
                ldsm_x4(bh[2*np][0], bh[2*np][1], bh[2*np+1][0], bh[2*np+1][1], baseH + ro);
                ldsm_x4(bl[2*np][0], bl[2*np][1], bl[2*np+1][0], bl[2*np+1][1], baseL + ro);
            }
#pragma unroll
            for (int mt = 0; mt < 4; mt++)
#pragma unroll
                for (int nt = 0; nt < NT; nt++) {
                    mma_bf16(acc[mt][nt], ah[mt][0], ah[mt][1], ah[mt][2], ah[mt][3],
                             bh[nt][0], bh[nt][1]);
                    mma_bf16(acc[mt][nt], ah[mt][0], ah[mt][1], ah[mt][2], ah[mt][3],
                             bl[nt][0], bl[nt][1]);
                    mma_bf16(acc[mt][nt], al[mt][0], al[mt][1], al[mt][2], al[mt][3],
                             bh[nt][0], bh[nt][1]);
                }
        }
    };

    const int niter = K >> 5;
    loadStage(0, 0); CP_COMMIT();
    for (int i = 0; i < niter; i++) {
        if (i + 1 < niter) { loadStage((i + 1) & 1, (i + 1) << 5); CP_COMMIT(); CP_WAIT(1); }
        else               { CP_WAIT(0); }
        __syncthreads();
        compute(i & 1);
        __syncthreads();
    }

#pragma unroll
    for (int mt = 0; mt < 4; mt++) {
        int r0 = bm + wm * 64 + mt * 16 + qm;
#pragma unroll
        for (int nt = 0; nt < NT; nt++) {
            int c0 = bn + wn * (BN / 4) + nt * 8 + qk * 2;
            float v0 = acc[mt][nt][0], v1 = acc[mt][nt][1];
            float v2 = acc[mt][nt][2], v3 = acc[mt][nt][3];
            if (bias) {
                float b0 = (c0 < N) ? bias[c0] : 0.f;
                float b1 = (c0 + 1 < N) ? bias[c0 + 1] : 0.f;
                v0 += b0; v1 += b1; v2 += b0; v3 += b1;
            }
            if (EPI == 1) {
                v0 = 0.5f * v0 * (1.f + erff(v0 * 0.70710678118654752f));
                v1 = 0.5f * v1 * (1.f + erff(v1 * 0.70710678118654752f));
                v2 = 0.5f * v2 * (1.f + erff(v2 * 0.70710678118654752f));
                v3 = 0.5f * v3 * (1.f + erff(v3 * 0.70710678118654752f));
            }
            if (EPI == 1 || EPI == 3) {
                __nv_bfloat162 h2, l2;
                split1(v0, h2.x, l2.x); split1(v1, h2.y, l2.y);
                *(__nv_bfloat162*)(Chi + (long)r0 * ldC + c0) = h2;
                *(__nv_bfloat162*)(Clo + (long)r0 * ldC + c0) = l2;
                split1(v2, h2.x, l2.x); split1(v3, h2.y, l2.y);
                *(__nv_bfloat162*)(Chi + (long)(r0 + 8) * ldC + c0) = h2;
                *(__nv_bfloat162*)(Clo + (long)(r0 + 8) * ldC + c0) = l2;
            }
            if (EPI == 0 || EPI == 3) {
                if (c0 < N) {
                    C[(long)r0 * ldC + c0] = v0;
                    C[(long)(r0 + 8) * ldC + c0] = v2;
                }
                if (c0 + 1 < N) {
                    C[(long)r0 * ldC + c0 + 1] = v1;
                    C[(long)(r0 + 8) * ldC + c0 + 1] = v3;
                }
            }
        }
    }
}

// ----------------------------------------------------------------------------
// Single-pass fp16 tensor-core GEMM (coarse sims only) — unchanged
// ----------------------------------------------------------------------------
__global__ void __launch_bounds__(256) fgemm_kernel(
    const __half* __restrict__ A, const __half* __restrict__ B,
    float* __restrict__ C,
    int M, int N, int K, long zA, long zB, long zC)
{
    constexpr int BM = 128, BN = 128, NT = 4, ROWS = BM + BN;
    extern __shared__ __align__(16) __half fsmem[];

    const int bz = blockIdx.z;
    A += bz * zA; B += bz * zB; C += bz * zC;

    const int tid  = threadIdx.x;
    const int wid  = tid >> 5;
    const int lane = tid & 31;
    const int wm   = wid & 1;
    const int wn   = wid >> 1;
    const int qm   = lane >> 2;
    const int qk   = lane & 3;
    const int bm = blockIdx.y * BM;
    const int bn = blockIdx.x * BN;
    const uint32_t sbase = smem_u32(fsmem);

    float acc[4][NT][4];
#pragma unroll
    for (int mt = 0; mt < 4; mt++)
#pragma unroll
        for (int nt = 0; nt < NT; nt++)
#pragma unroll
            for (int r = 0; r < 4; r++) acc[mt][nt][r] = 0.f;

    auto loadStage = [&](int s, int k0) {
        const uint32_t p = sbase + (uint32_t)s * ROWS * 80;
#pragma unroll
        for (int c = tid; c < BM * 4; c += 256) {
            int row = c >> 2, kc = c & 3;
            long gofs = (long)(bm + row) * K + k0;
            CP_ASYNC16(p + row * 80 + kc * 16, (const char*)(A + gofs) + kc * 16);
        }
#pragma unroll
        for (int c = tid; c < BN * 4; c += 256) {
            int row = c >> 2, kc = c & 3;
            long gofs = (long)(bn + row) * K + k0;
            CP_ASYNC16(p + (BM + row) * 80 + kc * 16, (const char*)(B + gofs) + kc * 16);
        }
    };

    auto compute = [&](int s) {
        const uint32_t base = sbase + (uint32_t)s * ROWS * 80;
#pragma unroll
        for (int kc = 0; kc < 2; kc++) {
            uint32_t a[4][4], b[NT][2];
            const int arow = wm * 64 + (lane & 15);
            const uint32_t acol = kc * 32 + ((lane & 16) ? 16 : 0);
#pragma unroll
            for (int mt = 0; mt < 4; mt++) {
                uint32_t ro = (uint32_t)(arow + mt * 16) * 80 + acol;
                ldsm_x4(a[mt][0], a[mt][1], a[mt][2], a[mt][3], base + ro);
            }
            const int brow = BM + wn * 32 + (lane & 7) + ((lane & 16) ? 8 : 0);
            const uint32_t bcol = kc * 32 + ((lane & 8) ? 16 : 0);
#pragma unroll
            for (int np = 0; np < NT / 2; np++) {
                uint32_t ro = (uint32_t)(brow + np * 16) * 80 + bcol;
                ldsm_x4(b[2*np][0], b[2*np][1], b[2*np+1][0], b[2*np+1][1], base + ro);
            }
#pragma unroll
            for (int mt = 0; mt < 4; mt++)
#pragma unroll
                for (int nt = 0; nt < NT; nt++)
                    mma_f16(acc[mt][nt], a[mt][0], a[mt][1], a[mt][2], a[mt][3],
                            b[nt][0], b[nt][1]);
        }
    };

    const int niter = K >> 5;
    loadStage(0, 0); CP_COMMIT();
    for (int i = 0; i < niter; i++) {
        if (i + 1 < niter) { loadStage((i + 1) & 1, (i + 1) << 5); CP_COMMIT(); CP_WAIT(1); }
        else               { CP_WAIT(0); }
        __syncthreads();
        compute(i & 1);
        __syncthreads();
    }

#pragma unroll
    for (int mt = 0; mt < 4; mt++) {
        int r0 = bm + wm * 64 + mt * 16 + qm;
#pragma unroll
        for (int nt = 0; nt < NT; nt++) {
            int c0 = bn + wn * 32 + nt * 8 + qk * 2;
            C[(long)r0 * N + c0]           = acc[mt][nt][0];
            C[(long)r0 * N + c0 + 1]       = acc[mt][nt][1];
            C[(long)(r0 + 8) * N + c0]     = acc[mt][nt][2];
            C[(long)(r0 + 8) * N + c0 + 1] = acc[mt][nt][3];
        }
    }
}

// ----------------------------------------------------------------------------
// LayerNorm + fused splits (unchanged)
// ----------------------------------------------------------------------------
__global__ void __launch_bounds__(256) ln_kernel(
    const float* __restrict__ x, const float* __restrict__ add,
    const float* __restrict__ g, const float* __restrict__ b,
    const float* __restrict__ qpos,
    float* __restrict__ out,
    __nv_bfloat16* __restrict__ ohi, __nv_bfloat16* __restrict__ olo,
    __nv_bfloat16* __restrict__ oqhi, __nv_bfloat16* __restrict__ oqlo,
    __half* __restrict__ oxf16)
{
    int row = blockIdx.x, tid = threadIdx.x;
    const float* xr = x + (long)row * D;
    float vals[3];
    float s = 0.f, sq = 0.f;
#pragma unroll
    for (int i = 0; i < 3; i++) {
        int c = tid + i * 256;
        float v = xr[c];
        if (add) v += add[(long)row * D + c];
        vals[i] = v; s += v; sq += v * v;
    }
    __shared__ float rs[256], rq[256];
    rs[tid] = s; rq[tid] = sq;
    __syncthreads();
    for (int o = 128; o > 0; o >>= 1) {
        if (tid < o) { rs[tid] += rs[tid + o]; rq[tid] += rq[tid + o]; }
        __syncthreads();
    }
    float mu = rs[0] * (1.f / D);
    float var = rq[0] * (1.f / D) - mu * mu;
    float rstd = rsqrtf(var + EPS);
#pragma unroll
    for (int i = 0; i < 3; i++) {
        int c = tid + i * 256;
        long o = (long)row * D + c;
        float v = (vals[i] - mu) * rstd * g[c] + b[c];
        out[o] = v;
        oxf16[o] = __float2half_rn(v);
        __nv_bfloat16 h, l;
        split1(v, h, l);
        ohi[o] = h; olo[o] = l;
        split1(v + qpos[o], h, l);
        oqhi[o] = h; oqlo[o] = l;
    }
}

__global__ void __launch_bounds__(256) rownorm_kernel(
    const float* __restrict__ m, float* __restrict__ minv)
{
    int row = blockIdx.x, tid = threadIdx.x;
    float s = 0.f;
#pragma unroll
    for (int i = 0; i < 3; i++) {
        float v = m[(long)row * D + tid + i * 256];
        s += v * v;
    }
    __shared__ float rs[256];
    rs[tid] = s; __syncthreads();
    for (int o = 128; o > 0; o >>= 1) {
        if (tid < o) rs[tid] += rs[tid + o];
        __syncthreads();
    }
    if (tid == 0) minv[row] = rsqrtf(rs[0]);
}

// ----------------------------------------------------------------------------
// Top-32 via histogram threshold: collect all coarse candidates covering the
// coarse top-48, exact fp32 rescore, exact top-32.
// ----------------------------------------------------------------------------
__global__ void __launch_bounds__(256) topk_kernel(
    const float* __restrict__ sims, const float* __restrict__ minv,
    const float* __restrict__ x, const float* __restrict__ memory,
    int* __restrict__ idx_out)
{
    int row = blockIdx.x;
    int b = row >> 7;
    int tid = threadIdx.x;
    int warp = tid >> 5, lane = tid & 31;

    __shared__ float s[MNP];
    __shared__ float xrow[D];
    __shared__ int   hist[1024];
    __shared__ int   pcount[256];
    __shared__ int   cnt;
    __shared__ uint32_t s_tu;
    __shared__ int   cand[1024];
    __shared__ float cval[1024];

    for (int i = tid; i < MNP; i += 256)
        s[i] = sims[(long)row * MNP + i] * minv[b * MNP + i];
    for (int c = tid; c < D; c += 256)
        xrow[c] = x[(long)row * D + c];
    for (int i = tid; i < 1024; i += 256) hist[i] = 0;
    if (tid == 0) cnt = 0;
    __syncthreads();

    auto mapu = [](float f) -> uint32_t {
        uint32_t u = __float_as_uint(f);
        return (u & 0x80000000u) ? ~u : (u | 0x80000000u);
    };

    for (int i = tid; i < MNP; i += 256)
        atomicAdd(&hist[mapu(s[i]) >> 22], 1);
    __syncthreads();

    // suffix counts per 4-bin group
    int local = hist[tid*4] + hist[tid*4+1] + hist[tid*4+2] + hist[tid*4+3];
    pcount[tid] = local;
    __syncthreads();
    for (int off = 1; off < 256; off <<= 1) {
        int v = (tid + off < 256) ? pcount[tid + off] : 0;
        __syncthreads();
        pcount[tid] += v;
        __syncthreads();
    }
    // unique group t with suffix >= COVER and next-group suffix < COVER
    {
        int c0 = pcount[tid];
        int c1 = (tid + 1 < 256) ? pcount[tid + 1] : 0;
        if (c0 >= COVER && c1 < COVER) {
            int acc = c1;
            int chosen = tid * 4;
            for (int k = 3; k >= 0; k--) {
                acc += hist[tid*4 + k];
                if (acc >= COVER) { chosen = tid*4 + k; break; }
            }
            s_tu = (uint32_t)chosen << 22;
        }
    }
    __syncthreads();
    uint32_t tu = s_tu;

    // collect candidates (>= threshold bin edge); guaranteed count >= COVER
    for (int i = tid; i < MNP; i += 256) {
        if (mapu(s[i]) >= tu) {
            int p = atomicAdd(&cnt, 1);
            if (p < 1024) cand[p] = i;
        }
    }
    __syncthreads();
    int n = cnt < 1024 ? cnt : 1024;

    // exact fp32 rescore
    for (int j = warp; j < n; j += 8) {
        int ix = cand[j];
        const float* mr = memory + ((long)(b * MNP + ix)) * D;
        float acc = 0.f;
        for (int c = lane; c < D; c += 32) acc = fmaf(xrow[c], mr[c], acc);
#pragma unroll
        for (int o = 16; o > 0; o >>= 1) acc += __shfl_xor_sync(0xffffffffu, acc, o);
        if (lane == 0) cval[j] = acc * minv[b * MNP + ix];
    }
    __syncthreads();

    // exact top-32 (warp 0), ties -> lowest index
    if (warp == 0) {
        for (int t = 0; t < TOPK; t++) {
            float v = -INFINITY; int myi = 0x7fffffff, myj = -1;
            for (int j = lane; j < n; j += 32) {
                float cv = cval[j];
                if (cv > v || (cv == v && cand[j] < myi)) { v = cv; myi = cand[j]; myj = j; }
            }
#pragma unroll
            for (int o = 16; o > 0; o >>= 1) {
                float ov = __shfl_xor_sync(0xffffffffu, v, o);
                int   oi = __shfl_xor_sync(0xffffffffu, myi, o);
                int   oj = __shfl_xor_sync(0xffffffffu, myj, o);
                if (ov > v || (ov == v && oi < myi)) { v = ov; myi = oi; myj = oj; }
            }
            if (lane == 0) {
                idx_out[row * TOPK + t] = myi;
                cval[myj] = -INFINITY;
            }
            __syncwarp();
        }
    }
}

// ----------------------------------------------------------------------------
// Fused cross-attention with cp.async double-buffered row gathers.
// ----------------------------------------------------------------------------
__global__ void __launch_bounds__(128) xattn_kernel(
    const float* __restrict__ qf,
    const float* __restrict__ Z,
    const float* __restrict__ memory,
    const float* __restrict__ kpos,
    const float* __restrict__ l2b,
    const int*   __restrict__ idx,
    __nv_bfloat16* __restrict__ agghi,
    __nv_bfloat16* __restrict__ agglo)
{
    __shared__ __align__(16) float mrow[2][D];
    __shared__ __align__(16) float krow[2][D];
    __shared__ float qrow[D];
    __shared__ float sc[NH][TOPK];
    __shared__ float qb[NH];
    __shared__ int   ids[TOPK];

    const int qi = blockIdx.x;
    const int b = qi >> 7;
    const int tid = threadIdx.x;
    const int warp = tid >> 5, lane = tid & 31;
    const int h0 = warp * 3;
    const uint32_t mbase = smem_u32(mrow);
    const uint32_t kbase = smem_u32(krow);

    for (int k = 0; k < 6; k++)
        qrow[tid + 128 * k] = qf[(long)qi * D + tid + 128 * k];
    if (tid < TOPK) ids[tid] = idx[qi * TOPK + tid];
    __syncthreads();

    // qb[h] = q_h . b2_h
#pragma unroll
    for (int t = 0; t < 3; t++) {
        int h = h0 + t;
        float s = qrow[h * HD + lane] * l2b[h * HD + lane]
                + qrow[h * HD + 32 + lane] * l2b[h * HD + 32 + lane];
#pragma unroll
        for (int o = 16; o > 0; o >>= 1) s += __shfl_xor_sync(0xffffffffu, s, o);
        if (lane == 0) qb[h] = s;
    }

    // Z rows -> registers
    float reg[3][24];
#pragma unroll
    for (int t = 0; t < 3; t++) {
        const float* zp = Z + ((long)(h0 + t) * NTOK + qi) * D;
#pragma unroll
        for (int i = 0; i < 24; i++) reg[t][i] = zp[lane + 32 * i];
    }

    // prefetch helpers: 768 floats = 192 x 16B, 128 threads
    auto fetch_mk = [&](int buf, int j) {
        long base = ((long)(b * MNP + ids[j])) * D;
        for (int c = tid; c < 192; c += 128) {
            CP_ASYNC16(mbase + (uint32_t)(buf * D + c * 4) * 4, (const char*)(memory + base) + c * 16);
            CP_ASYNC16(kbase + (uint32_t)(buf * D + c * 4) * 4, (const char*)(kpos + base) + c * 16);
        }
    };
    auto fetch_m = [&](int buf, int j) {
        long base = ((long)(b * MNP + ids[j])) * D;
        for (int c = tid; c < 192; c += 128)
            CP_ASYNC16(mbase + (uint32_t)(buf * D + c * 4) * 4, (const char*)(memory + base) + c * 16);
    };

    // ---- scores (double-buffered) ----
    fetch_mk(0, 0); CP_COMMIT();
    for (int j = 0; j < TOPK; j++) {
        int buf = j & 1;
        if (j + 1 < TOPK) { fetch_mk(buf ^ 1, j + 1); CP_COMMIT(); CP_WAIT(1); }
        else              { CP_WAIT(0); }
        __syncthreads();
#pragma unroll
        for (int t = 0; t < 3; t++) {
            float s = 0.f;
#pragma unroll
            for (int i = 0; i < 24; i++)
                s = fmaf(reg[t][i], mrow[buf][lane + 32 * i] + krow[buf][lane + 32 * i], s);
#pragma unroll
            for (int o = 16; o > 0; o >>= 1) s += __shfl_xor_sync(0xffffffffu, s, o);
            if (lane == 0) sc[h0 + t][j] = (s + qb[h0 + t]) * 0.125f;
        }
        __syncthreads();
    }

    // softmax per head
    if (tid < NH) {
        float m = -INFINITY;
        for (int j = 0; j < TOPK; j++) m = fmaxf(m, sc[tid][j]);
        float sum = 0.f;
        for (int j = 0; j < TOPK; j++) {
            float e = expf(sc[tid][j] - m);
            sc[tid][j] = e; sum += e;
        }
        float inv = 1.f / sum;
        for (int j = 0; j < TOPK; j++) sc[tid][j] *= inv;
    }
    __syncthreads();

    // ---- aggregate (double-buffered, reuse register file) ----
#pragma unroll
    for (int t = 0; t < 3; t++)
#pragma unroll
        for (int i = 0; i < 24; i++) reg[t][i] = 0.f;

    fetch_m(0, 0); CP_COMMIT();
    for (int j = 0; j < TOPK; j++) {
        int buf = j & 1;
        if (j + 1 < TOPK) { fetch_m(buf ^ 1, j + 1); CP_COMMIT(); CP_WAIT(1); }
        else              { CP_WAIT(0); }
        __syncthreads();
#pragma unroll
        for (int t = 0; t < 3; t++) {
            float p = sc[h0 + t][j];
#pragma unroll
            for (int i = 0; i < 24; i++)
                reg[t][i] = fmaf(p, mrow[buf][lane + 32 * i], reg[t][i]);
        }
        __syncthreads();
    }

    // write splits
#pragma unroll
    for (int t = 0; t < 3; t++) {
        long o0 = ((long)(h0 + t) * NTOK + qi) * D;
#pragma unroll
        for (int i = 0; i < 24; i++) {
            __nv_bfloat16 h, l;
            split1(reg[t][i], h, l);
            agghi[o0 + lane + 32 * i] = h;
            agglo[o0 + lane + 32 * i] = l;
        }
    }
}

// ----------------------------------------------------------------------------
// Dense self-attention (unchanged)
// ----------------------------------------------------------------------------
__global__ void __launch_bounds__(128) self_attn_kernel(
    const float* __restrict__ qk, const float* __restrict__ v,
    __nv_bfloat16* __restrict__ ohi, __nv_bfloat16* __restrict__ olo)
{
    int row = blockIdx.x;
    int b = row >> 7;
    int h = blockIdx.y;
    int tid = threadIdx.x;

    __shared__ float qv[HD];
    __shared__ float sc[NP];
    __shared__ float red[128];

    const float* qr = qk + (long)row * (2 * D) + h * HD;
    if (tid < HD) qv[tid] = qr[tid];
    __syncthreads();

    const float* kr = qk + (long)(b * NP + tid) * (2 * D) + D + h * HD;
    float s = 0.f;
#pragma unroll
    for (int d = 0; d < HD; d++) s = fmaf(qv[d], kr[d], s);
    s *= 0.125f;

    red[tid] = s; __syncthreads();
    for (int o = 64; o > 0; o >>= 1) {
        if (tid < o) red[tid] = fmaxf(red[tid], red[tid + o]);
        __syncthreads();
    }
    float m = red[0]; __syncthreads();
    float e = expf(s - m);
    sc[tid] = e;
    red[tid] = e; __syncthreads();
    for (int o = 64; o > 0; o >>= 1) {
        if (tid < o) red[tid] += red[tid + o];
        __syncthreads();
    }
    float inv = 1.f / red[0];

    if (tid < HD) {
        float acc = 0.f;
        for (int j = 0; j < NP; j++)
            acc = fmaf(sc[j], v[(long)(b * NP + j) * D + h * HD + tid], acc);
        long o = (long)row * D + h * HD + tid;
        __nv_bfloat16 hh, ll;
        split1(acc * inv, hh, ll);
        ohi[o] = hh; olo[o] = ll;
    }
}

// ----------------------------------------------------------------------------
// BatchNorm stats (unchanged)
// ----------------------------------------------------------------------------
__global__ void __launch_bounds__(256) bn_stats_kernel(
    const float* __restrict__ x, const float* __restrict__ g,
    const float* __restrict__ b, float* __restrict__ scale,
    float* __restrict__ shift)
{
    int f = blockIdx.x, tid = threadIdx.x;
    float s = 0.f, sq = 0.f;
    for (int r = tid; r < NTOK; r += 256) {
        float v = x[(long)r * D + f];
        s += v; sq += v * v;
    }
    __shared__ float rs[256], rq[256];
    rs[tid] = s; rq[tid] = sq;
    __syncthreads();
    for (int o = 128; o > 0; o >>= 1) {
        if (tid < o) { rs[tid] += rs[tid + o]; rq[tid] += rq[tid + o]; }
        __syncthreads();
    }
    if (tid == 0) {
        float mu = rs[0] * (1.f / NTOK);
        float var = rq[0] * (1.f / NTOK) - mu * mu;
        float rstd = rsqrtf(var + EPS);
        float sc = rstd * g[f];
        scale[f] = sc;
        shift[f] = b[f] - mu * sc;
    }
}

// ----------------------------------------------------------------------------
// Host orchestration (unchanged from R12 except kernel signatures)
// ----------------------------------------------------------------------------
#define SMEM128 (2 * 2 * 256 * 80)
#define SMEM64  (2 * 2 * 192 * 80)
#define SMEMF   (2 * 256 * 80)

extern "C" void kernel_launch(void* const* d_in, const int* in_sizes, int n_in,
                              void* d_out, int out_size)
{
    const float* tgt      = (const float*)d_in[0];
    const float* memory   = (const float*)d_in[1];
    const float* qpos     = (const float*)d_in[2];
    const float* kpos     = (const float*)d_in[3];
    const float* norm0_g  = (const float*)d_in[4];
    const float* norm0_b  = (const float*)d_in[5];
    const float* l1_w     = (const float*)d_in[6];
    const float* l1_b     = (const float*)d_in[7];
    const float* l2_w     = (const float*)d_in[8];
    const float* l2_b     = (const float*)d_in[9];
    const float* l3_w     = (const float*)d_in[10];
    const float* l3_b     = (const float*)d_in[11];
    const float* n1_g     = (const float*)d_in[12];
    const float* n1_b     = (const float*)d_in[13];
    const float* n2_g     = (const float*)d_in[14];
    const float* n2_b     = (const float*)d_in[15];
    const float* n3_g     = (const float*)d_in[16];
    const float* n3_b     = (const float*)d_in[17];
    const float* sa_in_w  = (const float*)d_in[18];
    const float* sa_in_b  = (const float*)d_in[19];
    const float* sa_out_w = (const float*)d_in[20];
    const float* sa_out_b = (const float*)d_in[21];
    const float* ff1_w    = (const float*)d_in[22];
    const float* ff1_b    = (const float*)d_in[23];
    const float* ff2_w    = (const float*)d_in[24];
    const float* ff2_b    = (const float*)d_in[25];
    const float* bn_g     = (const float*)d_in[26];
    const float* bn_b     = (const float*)d_in[27];
    const float* cls_w    = (const float*)d_in[28];

    float *x, *tmp, *q, *qk, *v, *attn, *Z, *sims, *minv, *bnsc, *bnsh;
    int* idx;
    __nv_bfloat16 *whi, *wlo, *w2th, *w2tl;
    __nv_bfloat16 *xhi, *xlo, *xqhi, *xqlo, *qhi, *qlo, *agghi, *agglo;
    __nv_bfloat16 *h1hi, *h1lo, *sahi, *salo, *cihi, *cilo;
    __half *mf16, *xf16;
    cudaGetSymbolAddress((void**)&x,    g_x);
    cudaGetSymbolAddress((void**)&tmp,  g_tmp);
    cudaGetSymbolAddress((void**)&q,    g_q);
    cudaGetSymbolAddress((void**)&qk,   g_qk);
    cudaGetSymbolAddress((void**)&v,    g_v);
    cudaGetSymbolAddress((void**)&attn, g_attn);
    cudaGetSymbolAddress((void**)&Z,    g_Z);
    cudaGetSymbolAddress((void**)&sims, g_sims);
    cudaGetSymbolAddress((void**)&idx,  g_idx);
    cudaGetSymbolAddress((void**)&minv, g_minv);
    cudaGetSymbolAddress((void**)&bnsc, g_bnscale);
    cudaGetSymbolAddress((void**)&bnsh, g_bnshift);
    cudaGetSymbolAddress((void**)&whi,  g_whi);
    cudaGetSymbolAddress((void**)&wlo,  g_wlo);
    cudaGetSymbolAddress((void**)&w2th, g_w2thi);
    cudaGetSymbolAddress((void**)&w2tl, g_w2tlo);
    cudaGetSymbolAddress((void**)&xhi,  g_xhi);
    cudaGetSymbolAddress((void**)&xlo,  g_xlo);
    cudaGetSymbolAddress((void**)&xqhi, g_xqhi);
    cudaGetSymbolAddress((void**)&xqlo, g_xqlo);
    cudaGetSymbolAddress((void**)&qhi,  g_qhi);
    cudaGetSymbolAddress((void**)&qlo,  g_qlo);
    cudaGetSymbolAddress((void**)&agghi, g_agghi);
    cudaGetSymbolAddress((void**)&agglo, g_agglo);
    cudaGetSymbolAddress((void**)&h1hi, g_h1hi);
    cudaGetSymbolAddress((void**)&h1lo, g_h1lo);
    cudaGetSymbolAddress((void**)&sahi, g_sahi);
    cudaGetSymbolAddress((void**)&salo, g_salo);
    cudaGetSymbolAddress((void**)&cihi, g_cihi);
    cudaGetSymbolAddress((void**)&cilo, g_cilo);
    cudaGetSymbolAddress((void**)&mf16, g_mf16);
    cudaGetSymbolAddress((void**)&xf16, g_xf16);

    cudaFuncSetAttribute(hgemm_kernel<128,0>, cudaFuncAttributeMaxDynamicSharedMemorySize, SMEM128);
    cudaFuncSetAttribute(hgemm_kernel<128,1>, cudaFuncAttributeMaxDynamicSharedMemorySize, SMEM128);
    cudaFuncSetAttribute(hgemm_kernel<128,3>, cudaFuncAttributeMaxDynamicSharedMemorySize, SMEM128);
    cudaFuncSetAttribute(hgemm_kernel<64,0>,  cudaFuncAttributeMaxDynamicSharedMemorySize, SMEM64);

    split_kernel<<<2048, 256>>>(l1_w,     whi + OFF_L1,    wlo + OFF_L1,    (long)NLAYERS*D*D);
    split_kernel<<<2048, 256>>>(l3_w,     whi + OFF_L3,    wlo + OFF_L3,    (long)NLAYERS*D*D);
    split_kernel<<<2048, 256>>>(sa_in_w,  whi + OFF_SAIN,  wlo + OFF_SAIN,  (long)NLAYERS*3*D*D);
    split_kernel<<<2048, 256>>>(sa_out_w, whi + OFF_SAOUT, wlo + OFF_SAOUT, (long)NLAYERS*D*D);
    split_kernel<<<2048, 256>>>(ff1_w,    whi + OFF_FF1,   wlo + OFF_FF1,   (long)NLAYERS*DFF*D);
    split_kernel<<<2048, 256>>>(ff2_w,    whi + OFF_FF2,   wlo + OFF_FF2,   (long)NLAYERS*D*DFF);
    split_kernel<<<2048, 256>>>(cls_w,    whi + OFF_CLS,   wlo + OFF_CLS,   (long)NC*D);
    w2t_split_kernel<<<2048, 256>>>(l2_w, w2th, w2tl);
    conv_kernel<<<8192, 256>>>(memory, mf16, (long)NMEM*D);

    rownorm_kernel<<<NMEM, 256>>>(memory, minv);
    ln_kernel<<<NTOK, 256>>>(tgt, nullptr, norm0_g, norm0_b, qpos,
                             x, xhi, xlo, xqhi, xqlo, xf16);

    for (int l = 0; l < NLAYERS; l++) {
        long wdd = (long)l * D * D;
        const __nv_bfloat16* l1h = whi + OFF_L1 + wdd;   const __nv_bfloat16* l1l = wlo + OFF_L1 + wdd;
        const __nv_bfloat16* l3h = whi + OFF_L3 + wdd;   const __nv_bfloat16* l3l = wlo + OFF_L3 + wdd;
        const __nv_bfloat16* sih = whi + OFF_SAIN + (long)l*3*D*D;
        const __nv_bfloat16* sil = wlo + OFF_SAIN + (long)l*3*D*D;
        const __nv_bfloat16* soh = whi + OFF_SAOUT + wdd;
        const __nv_bfloat16* sol = wlo + OFF_SAOUT + wdd;
        const __nv_bfloat16* f1h = whi + OFF_FF1 + (long)l*DFF*D;
        const __nv_bfloat16* f1l = wlo + OFF_FF1 + (long)l*DFF*D;
        const __nv_bfloat16* f2h = whi + OFF_FF2 + (long)l*D*DFF;
        const __nv_bfloat16* f2l = wlo + OFF_FF2 + (long)l*D*DFF;
        const __nv_bfloat16* w2h = w2th + (long)l*NH*D*HD;
        const __nv_bfloat16* w2l = w2tl + (long)l*NH*D*HD;
        const float* l1bb = l1_b + (long)l * D;
        const float* l2bb = l2_b + (long)l * D;
        const float* l3bb = l3_b + (long)l * D;
        const float* sab  = sa_in_b + (long)l * 3 * D;
        const float* sob  = sa_out_b + (long)l * D;
        const float* f1b  = ff1_b + (long)l * DFF;
        const float* f2b  = ff2_b + (long)l * D;

        fgemm_kernel<<<dim3(MNP/128, 1, BS), 256, SMEMF>>>(
            xf16, mf16, sims, NP, MNP, D,
            (long)NP*D, (long)MNP*D, (long)NP*MNP);

        topk_kernel<<<NTOK, 256>>>(sims, minv, x, memory, idx);

        hgemm_kernel<128,3><<<dim3(D/128, NTOK/128, 1), 256, SMEM128>>>(
            xqhi, xqlo, l1h, l1l, l1bb, q, qhi, qlo,
            NTOK, D, D, D, D, D, 0, 0, 0, 0);

        hgemm_kernel<128,0><<<dim3(D/128, NTOK/128, NH), 256, SMEM128>>>(
            qhi, qlo, w2h, w2l, nullptr, Z, nullptr, nullptr,
            NTOK, D, HD, D, HD, D,
            (long)HD, (long)D*HD, (long)NTOK*D, 0);

        xattn_kernel<<<NTOK, 128>>>(q, Z, memory, kpos, l2bb, idx, agghi, agglo);

        hgemm_kernel<64,0><<<dim3(1, NTOK/128, NH), 256, SMEM64>>>(
            agghi, agglo, l3h, l3l, l3bb, attn, nullptr, nullptr,
            NTOK, HD, D, D, D, D,
            (long)NTOK*D, (long)HD*D, (long)HD, (long)HD);

        ln_kernel<<<NTOK, 256>>>(x, attn, n1_g + (long)l * D, n1_b + (long)l * D,
                                 qpos, x, xhi, xlo, xqhi, xqlo, xf16);

        hgemm_kernel<128,0><<<dim3((2*D)/128, NTOK/128, 1), 256, SMEM128>>>(
            xqhi, xqlo, sih, sil, sab, qk, nullptr, nullptr,
            NTOK, 2*D, D, D, D, 2*D, 0, 0, 0, 0);
        hgemm_kernel<64,0><<<dim3(D/64, NTOK/128, 1), 256, SMEM64>>>(
            xhi, xlo, sih + (long)2*D*D, sil + (long)2*D*D, sab + 2*D,
            v, nullptr, nullptr, NTOK, D, D, D, D, D, 0, 0, 0, 0);

        self_attn_kernel<<<dim3(NTOK, NH), 128>>>(qk, v, sahi, salo);

        hgemm_kernel<64,0><<<dim3(D/64, NTOK/128, 1), 256, SMEM64>>>(
            sahi, salo, soh, sol, sob, tmp, nullptr, nullptr,
            NTOK, D, D, D, D, D, 0, 0, 0, 0);

        ln_kernel<<<NTOK, 256>>>(x, tmp, n2_g + (long)l * D, n2_b + (long)l * D,
                                 qpos, x, xhi, xlo, xqhi, xqlo, xf16);

        hgemm_kernel<128,1><<<dim3(DFF/128, NTOK/128, 1), 256, SMEM128>>>(
            xhi, xlo, f1h, f1l, f1b, nullptr, h1hi, h1lo,
            NTOK, DFF, D, D, D, DFF, 0, 0, 0, 0);
        hgemm_kernel<64,0><<<dim3(D/64, NTOK/128, 1), 256, SMEM64>>>(
            h1hi, h1lo, f2h, f2l, f2b, tmp, nullptr, nullptr,
            NTOK, D, DFF, DFF, DFF, D, 0, 0, 0, 0);

        ln_kernel<<<NTOK, 256>>>(x, tmp, n3_g + (long)l * D, n3_b + (long)l * D,
                                 qpos, x, xhi, xlo, xqhi, xqlo, xf16);
    }

    bn_stats_kernel<<<D, 256>>>(x, bn_g, bn_b, bnsc, bnsh);
    split_affine_kernel<<<2048, 256>>>(x, bnsc, bnsh, cihi, cilo, (long)NTOK * D);

    float* out = (float*)d_out;
    long xsz = (long)NTOK * D;
    long csz = (long)NTOK * NC;

    if ((long)out_size >= xsz + csz) {
        cudaMemcpyAsync(out, x, sizeof(float) * xsz, cudaMemcpyDeviceToDevice, 0);
        hgemm_kernel<64,0><<<dim3((NC+63)/64, NTOK/128, 1), 256, SMEM64>>>(
            cihi, cilo, whi + OFF_CLS, wlo + OFF_CLS, nullptr,
            out + xsz, nullptr, nullptr, NTOK, NC, D, D, D, NC, 0, 0, 0, 0);
    } else if ((long)out_size == csz) {
        hgemm_kernel<64,0><<<dim3((NC+63)/64, NTOK/128, 1), 256, SMEM64>>>(
            cihi, cilo, whi + OFF_CLS, wlo + OFF_CLS, nullptr,
            out, nullptr, nullptr, NTOK, NC, D, D, D, NC, 0, 0, 0, 0);
    } else {
        cudaMemcpyAsync(out, x, sizeof(float) * ((long)out_size < xsz ? out_size : xsz),
                        cudaMemcpyDeviceToDevice, 0);
    }
}

// round 14
// speedup vs baseline: 2.7707x; 1.6543x over previous
#include <cuda_runtime.h>
#include <cuda_bf16.h>
#include <cuda_fp16.h>
#include <math.h>
#include <stdint.h>

#define BS   16
#define NP   128
#define MNP  2048
#define D    768
#define NH   12
#define HD   64
#define DFF  2048
#define NLAYERS 2
#define TOPK 32
#define COVER 48
#define NC   751
#define NTOK (BS*NP)
#define NMEM (BS*MNP)
#define EPS  1e-5f

// ----------------------------------------------------------------------------
// Scratch
// ----------------------------------------------------------------------------
__device__ float g_x   [NTOK*(long)D];
__device__ float g_tmp [NTOK*(long)D];
__device__ float g_q   [NTOK*(long)D];
__device__ float g_qk  [NTOK*(long)(2*D)];
__device__ float g_v   [NTOK*(long)D];
__device__ float g_attn[NTOK*(long)D];
__device__ float g_Z   [(long)NH*NTOK*D];
__device__ float g_sims[NTOK*(long)MNP];
__device__ int   g_idx [NTOK*TOPK];
__device__ float g_minv[NMEM];
__device__ float g_bnscale[D];
__device__ float g_bnshift[D];

#define OFF_L1    0L
#define OFF_L3    1179648L
#define OFF_SAIN  2359296L
#define OFF_SAOUT 5898240L
#define OFF_FF1   7077888L
#define OFF_FF2   10223616L
#define OFF_CLS   13369344L
#define WTOTAL    13946112L
__device__ __nv_bfloat16 g_whi[WTOTAL], g_wlo[WTOTAL];
__device__ __nv_bfloat16 g_w2thi[(long)NLAYERS*NH*D*HD], g_w2tlo[(long)NLAYERS*NH*D*HD];
__device__ __nv_bfloat16 g_xhi [NTOK*(long)D], g_xlo [NTOK*(long)D];
__device__ __nv_bfloat16 g_xqhi[NTOK*(long)D], g_xqlo[NTOK*(long)D];
__device__ __nv_bfloat16 g_qhi [NTOK*(long)D], g_qlo [NTOK*(long)D];
__device__ __nv_bfloat16 g_agghi[(long)NH*NTOK*D], g_agglo[(long)NH*NTOK*D];
__device__ __nv_bfloat16 g_h1hi[NTOK*(long)DFF], g_h1lo[NTOK*(long)DFF];
__device__ __nv_bfloat16 g_sahi[NTOK*(long)D], g_salo[NTOK*(long)D];
__device__ __nv_bfloat16 g_cihi[NTOK*(long)D], g_cilo[NTOK*(long)D];

__device__ __half g_mf16 [NMEM*(long)D];
__device__ __half g_xf16 [NTOK*(long)D];

// ----------------------------------------------------------------------------
// Helpers
// ----------------------------------------------------------------------------
__device__ __forceinline__ uint32_t smem_u32(const void* p) {
    uint32_t a;
    asm("{ .reg .u64 t; cvta.to.shared.u64 t, %1; cvt.u32.u64 %0, t; }"
        : "=r"(a) : "l"(p));
    return a;
}

#define CP_ASYNC16(dst, src) \
    asm volatile("cp.async.ca.shared.global [%0], [%1], 16;" \
                 :: "r"(dst), "l"(src) : "memory")
#define CP_COMMIT() asm volatile("cp.async.commit_group;" ::: "memory")
#define CP_WAIT(n)  asm volatile("cp.async.wait_group %0;" :: "n"(n) : "memory")

__device__ __forceinline__ void ldsm_x4(uint32_t& r0, uint32_t& r1,
                                        uint32_t& r2, uint32_t& r3, uint32_t addr)
{
    asm volatile("ldmatrix.sync.aligned.m8n8.x4.shared.b16 {%0,%1,%2,%3}, [%4];"
        : "=r"(r0), "=r"(r1), "=r"(r2), "=r"(r3) : "r"(addr));
}

__device__ __forceinline__ void mma_bf16(float c[4],
    uint32_t a0, uint32_t a1, uint32_t a2, uint32_t a3,
    uint32_t b0, uint32_t b1)
{
    asm("mma.sync.aligned.m16n8k16.row.col.f32.bf16.bf16.f32 "
        "{%0,%1,%2,%3}, {%4,%5,%6,%7}, {%8,%9}, {%0,%1,%2,%3};"
        : "+f"(c[0]), "+f"(c[1]), "+f"(c[2]), "+f"(c[3])
        : "r"(a0), "r"(a1), "r"(a2), "r"(a3), "r"(b0), "r"(b1));
}

__device__ __forceinline__ void mma_f16(float c[4],
    uint32_t a0, uint32_t a1, uint32_t a2, uint32_t a3,
    uint32_t b0, uint32_t b1)
{
    asm("mma.sync.aligned.m16n8k16.row.col.f32.f16.f16.f32 "
        "{%0,%1,%2,%3}, {%4,%5,%6,%7}, {%8,%9}, {%0,%1,%2,%3};"
        : "+f"(c[0]), "+f"(c[1]), "+f"(c[2]), "+f"(c[3])
        : "r"(a0), "r"(a1), "r"(a2), "r"(a3), "r"(b0), "r"(b1));
}

__device__ __forceinline__ void split1(float v, __nv_bfloat16& h, __nv_bfloat16& l) {
    __nv_bfloat16 hb = __float2bfloat16_rn(v);
    h = hb;
    l = __float2bfloat16_rn(v - __bfloat162float(hb));
}

// ----------------------------------------------------------------------------
// Convert / split kernels
// ----------------------------------------------------------------------------
__global__ void __launch_bounds__(256) split_kernel(
    const float* __restrict__ src,
    __nv_bfloat16* __restrict__ hi, __nv_bfloat16* __restrict__ lo, long n)
{
    long i = blockIdx.x * 256L + threadIdx.x;
    long stride = (long)gridDim.x * 256;
    for (; i < n; i += stride) {
        __nv_bfloat16 h, l;
        split1(src[i], h, l);
        hi[i] = h; lo[i] = l;
    }
}

__global__ void __launch_bounds__(256) w2t_split_kernel(
    const float* __restrict__ l2w,
    __nv_bfloat16* __restrict__ hi, __nv_bfloat16* __restrict__ lo)
{
    long n = (long)NLAYERS * NH * D * HD;
    long i = blockIdx.x * 256L + threadIdx.x;
    long stride = (long)gridDim.x * 256;
    for (; i < n; i += stride) {
        int k = (int)(i & 63);
        long t = i >> 6;
        int nn = (int)(t % D);
        long t2 = t / D;
        int h = (int)(t2 % NH);
        int l = (int)(t2 / NH);
        float v = l2w[((long)l * D + h * HD + k) * D + nn];
        __nv_bfloat16 hh, ll;
        split1(v, hh, ll);
        hi[i] = hh; lo[i] = ll;
    }
}

// memory -> fp16 copy + row inverse norms, single pass.
__global__ void __launch_bounds__(256) convnorm_kernel(
    const float* __restrict__ m, __half* __restrict__ mf,
    float* __restrict__ minv)
{
    int row = blockIdx.x, tid = threadIdx.x;
    float s = 0.f;
#pragma unroll
    for (int i = 0; i < 3; i++) {
        long o = (long)row * D + tid + i * 256;
        float v = m[o];
        mf[o] = __float2half_rn(v);
        s += v * v;
    }
    __shared__ float rs[256];
    rs[tid] = s; __syncthreads();
    for (int o = 128; o > 0; o >>= 1) {
        if (tid < o) rs[tid] += rs[tid + o];
        __syncthreads();
    }
    if (tid == 0) minv[row] = rsqrtf(rs[0]);
}

__global__ void __launch_bounds__(256) split_affine_kernel(
    const float* __restrict__ src, const float* __restrict__ scale,
    const float* __restrict__ shift,
    __nv_bfloat16* __restrict__ hi, __nv_bfloat16* __restrict__ lo, long n)
{
    long i = blockIdx.x * 256L + threadIdx.x;
    long stride = (long)gridDim.x * 256;
    for (; i < n; i += stride) {
        int k = (int)(i % D);
        __nv_bfloat16 h, l;
        split1(src[i] * scale[k] + shift[k], h, l);
        hi[i] = h; lo[i] = l;
    }
}

// ----------------------------------------------------------------------------
// bf16x3 tensor-core GEMM (unchanged)
// ----------------------------------------------------------------------------
template<int BN, int EPI>
__global__ void __launch_bounds__(256) hgemm_kernel(
    const __nv_bfloat16* __restrict__ Ah, const __nv_bfloat16* __restrict__ Al,
    const __nv_bfloat16* __restrict__ Bh, const __nv_bfloat16* __restrict__ Bl,
    const float* __restrict__ bias,
    float* __restrict__ C,
    __nv_bfloat16* __restrict__ Chi, __nv_bfloat16* __restrict__ Clo,
    int M, int N, int K, int ldA, int ldB, int ldC,
    long zA, long zB, long zC, long zBias)
{
    constexpr int BM = 128;
    constexpr int NT = BN / 32;
    constexpr int ROWS = BM + BN;
    extern __shared__ __align__(16) __nv_bfloat16 smem[];

    const int bz = blockIdx.z;
    Ah += bz * zA; Al += bz * zA;
    Bh += bz * zB; Bl += bz * zB;
    if (bias) bias += bz * zBias;
    C  += bz * zC;
    if (EPI == 1 || EPI == 3) { Chi += bz * zC; Clo += bz * zC; }

    const int tid  = threadIdx.x;
    const int wid  = tid >> 5;
    const int lane = tid & 31;
    const int wm   = wid & 1;
    const int wn   = wid >> 1;
    const int qm   = lane >> 2;
    const int qk   = lane & 3;
    const int bm = blockIdx.y * BM;
    const int bn = blockIdx.x * BN;
    const uint32_t sbase = smem_u32(smem);

    float acc[4][NT][4];
#pragma unroll
    for (int mt = 0; mt < 4; mt++)
#pragma unroll
        for (int nt = 0; nt < NT; nt++)
#pragma unroll
            for (int r = 0; r < 4; r++) acc[mt][nt][r] = 0.f;

    auto loadStage = [&](int s, int k0) {
        const uint32_t pH = sbase + (uint32_t)(s * 2 + 0) * ROWS * 80;
        const uint32_t pL = sbase + (uint32_t)(s * 2 + 1) * ROWS * 80;
#pragma unroll
        for (int c = tid; c < BM * 4; c += 256) {
            int row = c >> 2, kc = c & 3;
            long gofs = (long)(bm + row) * ldA + k0;
            CP_ASYNC16(pH + row * 80 + kc * 16, (const char*)(Ah + gofs) + kc * 16);
            CP_ASYNC16(pL + row * 80 + kc * 16, (const char*)(Al + gofs) + kc * 16);
        }
#pragma unroll
        for (int c = tid; c < BN * 4; c += 256) {
            int row = c >> 2, kc = c & 3;
            int n = bn + row;
            uint32_t dh = pH + (BM + row) * 80 + kc * 16;
            uint32_t dl = pL + (BM + row) * 80 + kc * 16;
            if (n < N) {
                long gofs = (long)n * ldB + k0;
                CP_ASYNC16(dh, (const char*)(Bh + gofs) + kc * 16);
                CP_ASYNC16(dl, (const char*)(Bl + gofs) + kc * 16);
            } else {
                uint32_t z = 0;
                asm volatile("st.shared.v4.b32 [%0], {%1,%1,%1,%1};" :: "r"(dh), "r"(z) : "memory");
                asm volatile("st.shared.v4.b32 [%0], {%1,%1,%1,%1};" :: "r"(dl), "r"(z) : "memory");
            }
        }
    };

    auto compute = [&](int s) {
        const uint32_t baseH = sbase + (uint32_t)(s * 2 + 0) * ROWS * 80;
        const uint32_t baseL = sbase + (uint32_t)(s * 2 + 1) * ROWS * 80;
#pragma unroll
        for (int kc = 0; kc < 2; kc++) {
            uint32_t ah[4][4], al[4][4], bh[NT][2], bl[NT][2];
            const int arow = wm * 64 + (lane & 15);
            const uint32_t acol = kc * 32 + ((lane & 16) ? 16 : 0);
#pragma unroll
            for (int mt = 0; mt < 4; mt++) {
                uint32_t ro = (uint32_t)(arow + mt * 16) * 80 + acol;
                ldsm_x4(ah[mt][0], ah[mt][1], ah[mt][2], ah[mt][3], baseH + ro);
                ldsm_x4(al[mt][0], al[mt][1], al[mt][2], al[mt][3], baseL + ro);
            }
            const int brow = BM + wn * (BN / 4) + (lane & 7) + ((lane & 16) ? 8 : 0);
            const uint32_t bcol = kc * 32 + ((lane & 8) ? 16 : 0);
#pragma unroll
            for (int np = 0; np < NT / 2; np++) {
                uint32_t ro = (uint32_t)(brow + np * 16) * 80 + bcol;
                ldsm_x4(bh[2*np][0], bh[2*np][1], bh[2*np+1][0], bh[2*np+1][1], baseH + ro);
                ldsm_x4(bl[2*np][0], bl[2*np][1], bl[2*np+1][0], bl[2*np+1][1], baseL + ro);
            }
#pragma unroll
            for (int mt = 0; mt < 4; mt++)
#pragma unroll
                for (int nt = 0; nt < NT; nt++) {
                    mma_bf16(acc[mt][nt], ah[mt][0], ah[mt][1], ah[mt][2], ah[mt][3],
                             bh[nt][0], bh[nt][1]);
                    mma_bf16(acc[mt][nt], ah[mt][0], ah[mt][1], ah[mt][2], ah[mt][3],
                             bl[nt][0], bl[nt][1]);
                    mma_bf16(acc[mt][nt], al[mt][0], al[mt][1], al[mt][2], al[mt][3],
                             bh[nt][0], bh[nt][1]);
                }
        }
    };

    const int niter = K >> 5;
    loadStage(0, 0); CP_COMMIT();
    for (int i = 0; i < niter; i++) {
        if (i + 1 < niter) { loadStage((i + 1) & 1, (i + 1) << 5); CP_COMMIT(); CP_WAIT(1); }
        else               { CP_WAIT(0); }
        __syncthreads();
        compute(i & 1);
        __syncthreads();
    }

#pragma unroll
    for (int mt = 0; mt < 4; mt++) {
        int r0 = bm + wm * 64 + mt * 16 + qm;
#pragma unroll
        for (int nt = 0; nt < NT; nt++) {
            int c0 = bn + wn * (BN / 4) + nt * 8 + qk * 2;
            float v0 = acc[mt][nt][0], v1 = acc[mt][nt][1];
            float v2 = acc[mt][nt][2], v3 = acc[mt][nt][3];
            if (bias) {
                float b0 = (c0 < N) ? bias[c0] : 0.f;
                float b1 = (c0 + 1 < N) ? bias[c0 + 1] : 0.f;
                v0 += b0; v1 += b1; v2 += b0; v3 += b1;
            }
            if (EPI == 1) {
                v0 = 0.5f * v0 * (1.f + erff(v0 * 0.70710678118654752f));
                v1 = 0.5f * v1 * (1.f + erff(v1 * 0.70710678118654752f));
                v2 = 0.5f * v2 * (1.f + erff(v2 * 0.70710678118654752f));
                v3 = 0.5f * v3 * (1.f + erff(v3 * 0.70710678118654752f));
            }
            if (EPI == 1 || EPI == 3) {
                __nv_bfloat162 h2, l2;
                split1(v0, h2.x, l2.x); split1(v1, h2.y, l2.y);
                *(__nv_bfloat162*)(Chi + (long)r0 * ldC + c0) = h2;
                *(__nv_bfloat162*)(Clo + (long)r0 * ldC + c0) = l2;
                split1(v2, h2.x, l2.x); split1(v3, h2.y, l2.y);
                *(__nv_bfloat162*)(Chi + (long)(r0 + 8) * ldC + c0) = h2;
                *(__nv_bfloat162*)(Clo + (long)(r0 + 8) * ldC + c0) = l2;
            }
            if (EPI == 0 || EPI == 3) {
                if (c0 < N) {
                    C[(long)r0 * ldC + c0] = v0;
                    C[(long)(r0 + 8) * ldC + c0] = v2;
                }
                if (c0 + 1 < N) {
                    C[(long)r0 * ldC + c0 + 1] = v1;
                    C[(long)(r0 + 8) * ldC + c0 + 1] = v3;
                }
            }
        }
    }
}

// ----------------------------------------------------------------------------
// Single-pass fp16 tensor-core GEMM (coarse sims only) — unchanged
// ----------------------------------------------------------------------------
__global__ void __launch_bounds__(256) fgemm_kernel(
    const __half* __restrict__ A, const __half* __restrict__ B,
    float* __restrict__ C,
    int M, int N, int K, long zA, long zB, long zC)
{
    constexpr int BM = 128, BN = 128, NT = 4, ROWS = BM + BN;
    extern __shared__ __align__(16) __half fsmem[];

    const int bz = blockIdx.z;
    A += bz * zA; B += bz * zB; C += bz * zC;

    const int tid  = threadIdx.x;
    const int wid  = tid >> 5;
    const int lane = tid & 31;
    const int wm   = wid & 1;
    const int wn   = wid >> 1;
    const int qm   = lane >> 2;
    const int qk   = lane & 3;
    const int bm = blockIdx.y * BM;
    const int bn = blockIdx.x * BN;
    const uint32_t sbase = smem_u32(fsmem);

    float acc[4][NT][4];
#pragma unroll
    for (int mt = 0; mt < 4; mt++)
#pragma unroll
        for (int nt = 0; nt < NT; nt++)
#pragma unroll
            for (int r = 0; r < 4; r++) acc[mt][nt][r] = 0.f;

    auto loadStage = [&](int s, int k0) {
        const uint32_t p = sbase + (uint32_t)s * ROWS * 80;
#pragma unroll
        for (int c = tid; c < BM * 4; c += 256) {
            int row = c >> 2, kc = c & 3;
            long gofs = (long)(bm + row) * K + k0;
            CP_ASYNC16(p + row * 80 + kc * 16, (const char*)(A + gofs) + kc * 16);
        }
#pragma unroll
        for (int c = tid; c < BN * 4; c += 256) {
            int row = c >> 2, kc = c & 3;
            long gofs = (long)(bn + row) * K + k0;
            CP_ASYNC16(p + (BM + row) * 80 + kc * 16, (const char*)(B + gofs) + kc * 16);
        }
    };

    auto compute = [&](int s) {
        const uint32_t base = sbase + (uint32_t)s * ROWS * 80;
#pragma unroll
        for (int kc = 0; kc < 2; kc++) {
            uint32_t a[4][4], b[NT][2];
            const int arow = wm * 64 + (lane & 15);
            const uint32_t acol = kc * 32 + ((lane & 16) ? 16 : 0);
#pragma unroll
            for (int mt = 0; mt < 4; mt++) {
                uint32_t ro = (uint32_t)(arow + mt * 16) * 80 + acol;
                ldsm_x4(a[mt][0], a[mt][1], a[mt][2], a[mt][3], base + ro);
            }
            const int brow = BM + wn * 32 + (lane & 7) + ((lane & 16) ? 8 : 0);
            const uint32_t bcol = kc * 32 + ((lane & 8) ? 16 : 0);
#pragma unroll
            for (int np = 0; np < NT / 2; np++) {
                uint32_t ro = (uint32_t)(brow + np * 16) * 80 + bcol;
                ldsm_x4(b[2*np][0], b[2*np][1], b[2*np+1][0], b[2*np+1][1], base + ro);
            }
#pragma unroll
            for (int mt = 0; mt < 4; mt++)
#pragma unroll
                for (int nt = 0; nt < NT; nt++)
                    mma_f16(acc[mt][nt], a[mt][0], a[mt][1], a[mt][2], a[mt][3],
                            b[nt][0], b[nt][1]);
        }
    };

    const int niter = K >> 5;
    loadStage(0, 0); CP_COMMIT();
    for (int i = 0; i < niter; i++) {
        if (i + 1 < niter) { loadStage((i + 1) & 1, (i + 1) << 5); CP_COMMIT(); CP_WAIT(1); }
        else               { CP_WAIT(0); }
        __syncthreads();
        compute(i & 1);
        __syncthreads();
    }

#pragma unroll
    for (int mt = 0; mt < 4; mt++) {
        int r0 = bm + wm * 64 + mt * 16 + qm;
#pragma unroll
        for (int nt = 0; nt < NT; nt++) {
            int c0 = bn + wn * 32 + nt * 8 + qk * 2;
            C[(long)r0 * N + c0]           = acc[mt][nt][0];
            C[(long)r0 * N + c0 + 1]       = acc[mt][nt][1];
            C[(long)(r0 + 8) * N + c0]     = acc[mt][nt][2];
            C[(long)(r0 + 8) * N + c0 + 1] = acc[mt][nt][3];
        }
    }
}

// ----------------------------------------------------------------------------
// LayerNorm + fused splits (unchanged)
// ----------------------------------------------------------------------------
__global__ void __launch_bounds__(256) ln_kernel(
    const float* __restrict__ x, const float* __restrict__ add,
    const float* __restrict__ g, const float* __restrict__ b,
    const float* __restrict__ qpos,
    float* __restrict__ out,
    __nv_bfloat16* __restrict__ ohi, __nv_bfloat16* __restrict__ olo,
    __nv_bfloat16* __restrict__ oqhi, __nv_bfloat16* __restrict__ oqlo,
    __half* __restrict__ oxf16)
{
    int row = blockIdx.x, tid = threadIdx.x;
    const float* xr = x + (long)row * D;
    float vals[3];
    float s = 0.f, sq = 0.f;
#pragma unroll
    for (int i = 0; i < 3; i++) {
        int c = tid + i * 256;
        float v = xr[c];
        if (add) v += add[(long)row * D + c];
        vals[i] = v; s += v; sq += v * v;
    }
    __shared__ float rs[256], rq[256];
    rs[tid] = s; rq[tid] = sq;
    __syncthreads();
    for (int o = 128; o > 0; o >>= 1) {
        if (tid < o) { rs[tid] += rs[tid + o]; rq[tid] += rq[tid + o]; }
        __syncthreads();
    }
    float mu = rs[0] * (1.f / D);
    float var = rq[0] * (1.f / D) - mu * mu;
    float rstd = rsqrtf(var + EPS);
#pragma unroll
    for (int i = 0; i < 3; i++) {
        int c = tid + i * 256;
        long o = (long)row * D + c;
        float v = (vals[i] - mu) * rstd * g[c] + b[c];
        out[o] = v;
        oxf16[o] = __float2half_rn(v);
        __nv_bfloat16 h, l;
        split1(v, h, l);
        ohi[o] = h; olo[o] = l;
        split1(v + qpos[o], h, l);
        oqhi[o] = h; oqlo[o] = l;
    }
}

// ----------------------------------------------------------------------------
// Top-32 via histogram threshold (unchanged from R13)
// ----------------------------------------------------------------------------
__global__ void __launch_bounds__(256) topk_kernel(
    const float* __restrict__ sims, const float* __restrict__ minv,
    const float* __restrict__ x, const float* __restrict__ memory,
    int* __restrict__ idx_out)
{
    int row = blockIdx.x;
    int b = row >> 7;
    int tid = threadIdx.x;
    int warp = tid >> 5, lane = tid & 31;

    __shared__ float s[MNP];
    __shared__ float xrow[D];
    __shared__ int   hist[1024];
    __shared__ int   pcount[256];
    __shared__ int   cnt;
    __shared__ uint32_t s_tu;
    __shared__ int   cand[1024];
    __shared__ float cval[1024];

    for (int i = tid; i < MNP; i += 256)
        s[i] = sims[(long)row * MNP + i] * minv[b * MNP + i];
    for (int c = tid; c < D; c += 256)
        xrow[c] = x[(long)row * D + c];
    for (int i = tid; i < 1024; i += 256) hist[i] = 0;
    if (tid == 0) cnt = 0;
    __syncthreads();

    auto mapu = [](float f) -> uint32_t {
        uint32_t u = __float_as_uint(f);
        return (u & 0x80000000u) ? ~u : (u | 0x80000000u);
    };

    for (int i = tid; i < MNP; i += 256)
        atomicAdd(&hist[mapu(s[i]) >> 22], 1);
    __syncthreads();

    int local = hist[tid*4] + hist[tid*4+1] + hist[tid*4+2] + hist[tid*4+3];
    pcount[tid] = local;
    __syncthreads();
    for (int off = 1; off < 256; off <<= 1) {
        int v = (tid + off < 256) ? pcount[tid + off] : 0;
        __syncthreads();
        pcount[tid] += v;
        __syncthreads();
    }
    {
        int c0 = pcount[tid];
        int c1 = (tid + 1 < 256) ? pcount[tid + 1] : 0;
        if (c0 >= COVER && c1 < COVER) {
            int acc = c1;
            int chosen = tid * 4;
            for (int k = 3; k >= 0; k--) {
                acc += hist[tid*4 + k];
                if (acc >= COVER) { chosen = tid*4 + k; break; }
            }
            s_tu = (uint32_t)chosen << 22;
        }
    }
    __syncthreads();
    uint32_t tu = s_tu;

    for (int i = tid; i < MNP; i += 256) {
        if (mapu(s[i]) >= tu) {
            int p = atomicAdd(&cnt, 1);
            if (p < 1024) cand[p] = i;
        }
    }
    __syncthreads();
    int n = cnt < 1024 ? cnt : 1024;

    for (int j = warp; j < n; j += 8) {
        int ix = cand[j];
        const float* mr = memory + ((long)(b * MNP + ix)) * D;
        float acc = 0.f;
        for (int c = lane; c < D; c += 32) acc = fmaf(xrow[c], mr[c], acc);
#pragma unroll
        for (int o = 16; o > 0; o >>= 1) acc += __shfl_xor_sync(0xffffffffu, acc, o);
        if (lane == 0) cval[j] = acc * minv[b * MNP + ix];
    }
    __syncthreads();

    if (warp == 0) {
        for (int t = 0; t < TOPK; t++) {
            float v = -INFINITY; int myi = 0x7fffffff, myj = -1;
            for (int j = lane; j < n; j += 32) {
                float cv = cval[j];
                if (cv > v || (cv == v && cand[j] < myi)) { v = cv; myi = cand[j]; myj = j; }
            }
#pragma unroll
            for (int o = 16; o > 0; o >>= 1) {
                float ov = __shfl_xor_sync(0xffffffffu, v, o);
                int   oi = __shfl_xor_sync(0xffffffffu, myi, o);
                int   oj = __shfl_xor_sync(0xffffffffu, myj, o);
                if (ov > v || (ov == v && oi < myi)) { v = ov; myi = oi; myj = oj; }
            }
            if (lane == 0) {
                idx_out[row * TOPK + t] = myi;
                cval[myj] = -INFINITY;
            }
            __syncwarp();
        }
    }
}

// ----------------------------------------------------------------------------
// Fused cross-attention with cp.async double-buffered row gathers (unchanged)
// ----------------------------------------------------------------------------
__global__ void __launch_bounds__(128) xattn_kernel(
    const float* __restrict__ qf,
    const float* __restrict__ Z,
    const float* __restrict__ memory,
    const float* __restrict__ kpos,
    const float* __restrict__ l2b,
    const int*   __restrict__ idx,
    __nv_bfloat16* __restrict__ agghi,
    __nv_bfloat16* __restrict__ agglo)
{
    __shared__ __align__(16) float mrow[2][D];
    __shared__ __align__(16) float krow[2][D];
    __shared__ float qrow[D];
    __shared__ float sc[NH][TOPK];
    __shared__ float qb[NH];
    __shared__ int   ids[TOPK];

    const int qi = blockIdx.x;
    const int b = qi >> 7;
    const int tid = threadIdx.x;
    const int warp = tid >> 5, lane = tid & 31;
    const int h0 = warp * 3;
    const uint32_t mbase = smem_u32(mrow);
    const uint32_t kbase = smem_u32(krow);

    for (int k = 0; k < 6; k++)
        qrow[tid + 128 * k] = qf[(long)qi * D + tid + 128 * k];
    if (tid < TOPK) ids[tid] = idx[qi * TOPK + tid];
    __syncthreads();

#pragma unroll
    for (int t = 0; t < 3; t++) {
        int h = h0 + t;
        float s = qrow[h * HD + lane] * l2b[h * HD + lane]
                + qrow[h * HD + 32 + lane] * l2b[h * HD + 32 + lane];
#pragma unroll
        for (int o = 16; o > 0; o >>= 1) s += __shfl_xor_sync(0xffffffffu, s, o);
        if (lane == 0) qb[h] = s;
    }

    float reg[3][24];
#pragma unroll
    for (int t = 0; t < 3; t++) {
        const float* zp = Z + ((long)(h0 + t) * NTOK + qi) * D;
#pragma unroll
        for (int i = 0; i < 24; i++) reg[t][i] = zp[lane + 32 * i];
    }

    auto fetch_mk = [&](int buf, int j) {
        long base = ((long)(b * MNP + ids[j])) * D;
        for (int c = tid; c < 192; c += 128) {
            CP_ASYNC16(mbase + (uint32_t)(buf * D + c * 4) * 4, (const char*)(memory + base) + c * 16);
            CP_ASYNC16(kbase + (uint32_t)(buf * D + c * 4) * 4, (const char*)(kpos + base) + c * 16);
        }
    };
    auto fetch_m = [&](int buf, int j) {
        long base = ((long)(b * MNP + ids[j])) * D;
        for (int c = tid; c < 192; c += 128)
            CP_ASYNC16(mbase + (uint32_t)(buf * D + c * 4) * 4, (const char*)(memory + base) + c * 16);
    };

    fetch_mk(0, 0); CP_COMMIT();
    for (int j = 0; j < TOPK; j++) {
        int buf = j & 1;
        if (j + 1 < TOPK) { fetch_mk(buf ^ 1, j + 1); CP_COMMIT(); CP_WAIT(1); }
        else              { CP_WAIT(0); }
        __syncthreads();
#pragma unroll
        for (int t = 0; t < 3; t++) {
            float s = 0.f;
#pragma unroll
            for (int i = 0; i < 24; i++)
                s = fmaf(reg[t][i], mrow[buf][lane + 32 * i] + krow[buf][lane + 32 * i], s);
#pragma unroll
            for (int o = 16; o > 0; o >>= 1) s += __shfl_xor_sync(0xffffffffu, s, o);
            if (lane == 0) sc[h0 + t][j] = (s + qb[h0 + t]) * 0.125f;
        }
        __syncthreads();
    }

    if (tid < NH) {
        float m = -INFINITY;
        for (int j = 0; j < TOPK; j++) m = fmaxf(m, sc[tid][j]);
        float sum = 0.f;
        for (int j = 0; j < TOPK; j++) {
            float e = expf(sc[tid][j] - m);
            sc[tid][j] = e; sum += e;
        }
        float inv = 1.f / sum;
        for (int j = 0; j < TOPK; j++) sc[tid][j] *= inv;
    }
    __syncthreads();

#pragma unroll
    for (int t = 0; t < 3; t++)
#pragma unroll
        for (int i = 0; i < 24; i++) reg[t][i] = 0.f;

    fetch_m(0, 0); CP_COMMIT();
    for (int j = 0; j < TOPK; j++) {
        int buf = j & 1;
        if (j + 1 < TOPK) { fetch_m(buf ^ 1, j + 1); CP_COMMIT(); CP_WAIT(1); }
        else              { CP_WAIT(0); }
        __syncthreads();
#pragma unroll
        for (int t = 0; t < 3; t++) {
            float p = sc[h0 + t][j];
#pragma unroll
            for (int i = 0; i < 24; i++)
                reg[t][i] = fmaf(p, mrow[buf][lane + 32 * i], reg[t][i]);
        }
        __syncthreads();
    }

#pragma unroll
    for (int t = 0; t < 3; t++) {
        long o0 = ((long)(h0 + t) * NTOK + qi) * D;
#pragma unroll
        for (int i = 0; i < 24; i++) {
            __nv_bfloat16 h, l;
            split1(reg[t][i], h, l);
            agghi[o0 + lane + 32 * i] = h;
            agglo[o0 + lane + 32 * i] = l;
        }
    }
}

// ----------------------------------------------------------------------------
// Self-attention: block per (batch, head). Q/K/V head slices staged in smem
// (K,V pitch 65 for conflict-free lane-strided access). Warp per query.
// ----------------------------------------------------------------------------
#define SA_SMEM ((128*64 + 128*65 + 128*65 + 4*128) * 4)   // 101888 bytes

__global__ void __launch_bounds__(128) self_attn_kernel(
    const float* __restrict__ qk, const float* __restrict__ v,
    __nv_bfloat16* __restrict__ ohi, __nv_bfloat16* __restrict__ olo)
{
    extern __shared__ float ssm[];
    float* Qs = ssm;                    // [128][64]
    float* Ks = Qs + 128 * 64;          // [128][65]
    float* Vs = Ks + 128 * 65;          // [128][65]
    float* Ps = Vs + 128 * 65;          // [4][128]

    const int bh = blockIdx.x;
    const int b = bh / NH, h = bh % NH;
    const int tid = threadIdx.x;
    const int warp = tid >> 5, lane = tid & 31;

    // stage Q, K, V head slices (float4 per 16B chunk)
    for (int i = tid; i < 128 * 16; i += 128) {
        int r = i >> 4, c4 = (i & 15) << 2;
        long tok = (long)(b * NP + r);
        float4 qv = *(const float4*)&qk[tok * 2 * D + h * HD + c4];
        float4 kv = *(const float4*)&qk[tok * 2 * D + D + h * HD + c4];
        float4 vv = *(const float4*)&v[tok * D + h * HD + c4];
        *(float4*)&Qs[r * 64 + c4] = qv;
        Ks[r * 65 + c4 + 0] = kv.x; Ks[r * 65 + c4 + 1] = kv.y;
        Ks[r * 65 + c4 + 2] = kv.z; Ks[r * 65 + c4 + 3] = kv.w;
        Vs[r * 65 + c4 + 0] = vv.x; Vs[r * 65 + c4 + 1] = vv.y;
        Vs[r * 65 + c4 + 2] = vv.z; Vs[r * 65 + c4 + 3] = vv.w;
    }
    __syncthreads();

    // warp w handles queries [w*32, w*32+32)
    for (int qq = 0; qq < 32; qq++) {
        int qi = warp * 32 + qq;
        const float* qrow = &Qs[qi * 64];
        float s[4];
#pragma unroll
        for (int kk = 0; kk < 4; kk++) {
            int k = lane + kk * 32;
            const float* krow = &Ks[k * 65];
            float acc = 0.f;
#pragma unroll
            for (int d = 0; d < HD; d++) acc = fmaf(qrow[d], krow[d], acc);
            s[kk] = acc * 0.125f;
        }
        float m = fmaxf(fmaxf(s[0], s[1]), fmaxf(s[2], s[3]));
#pragma unroll
        for (int o = 16; o > 0; o >>= 1) m = fmaxf(m, __shfl_xor_sync(0xffffffffu, m, o));
        float e[4], sum = 0.f;
#pragma unroll
        for (int kk = 0; kk < 4; kk++) { e[kk] = expf(s[kk] - m); sum += e[kk]; }
#pragma unroll
        for (int o = 16; o > 0; o >>= 1) sum += __shfl_xor_sync(0xffffffffu, sum, o);
        float inv = 1.f / sum;
#pragma unroll
        for (int kk = 0; kk < 4; kk++) Ps[warp * 128 + lane + kk * 32] = e[kk] * inv;
        __syncwarp();

        // aggregate: lane handles dims lane and lane+32
        float a0 = 0.f, a1 = 0.f;
#pragma unroll 8
        for (int k = 0; k < 128; k++) {
            float p = Ps[warp * 128 + k];
            a0 = fmaf(p, Vs[k * 65 + lane], a0);
            a1 = fmaf(p, Vs[k * 65 + lane + 32], a1);
        }
        long o = (long)(b * NP + qi) * D + h * HD + lane;
        __nv_bfloat16 hh, ll;
        split1(a0, hh, ll);
        ohi[o] = hh; olo[o] = ll;
        split1(a1, hh, ll);
        ohi[o + 32] = hh; olo[o + 32] = ll;
        __syncwarp();
    }
}

// ----------------------------------------------------------------------------
// BatchNorm stats (unchanged)
// ----------------------------------------------------------------------------
__global__ void __launch_bounds__(256) bn_stats_kernel(
    const float* __restrict__ x, const float* __restrict__ g,
    const float* __restrict__ b, float* __restrict__ scale,
    float* __restrict__ shift)
{
    int f = blockIdx.x, tid = threadIdx.x;
    float s = 0.f, sq = 0.f;
    for (int r = tid; r < NTOK; r += 256) {
        float v = x[(long)r * D + f];
        s += v; sq += v * v;
    }
    __shared__ float rs[256], rq[256];
    rs[tid] = s; rq[tid] = sq;
    __syncthreads();
    for (int o = 128; o > 0; o >>= 1) {
        if (tid < o) { rs[tid] += rs[tid + o]; rq[tid] += rq[tid + o]; }
        __syncthreads();
    }
    if (tid == 0) {
        float mu = rs[0] * (1.f / NTOK);
        float var = rq[0] * (1.f / NTOK) - mu * mu;
        float rstd = rsqrtf(var + EPS);
        float sc = rstd * g[f];
        scale[f] = sc;
        shift[f] = b[f] - mu * sc;
    }
}

// ----------------------------------------------------------------------------
// Host orchestration
// ----------------------------------------------------------------------------
#define SMEM128 (2 * 2 * 256 * 80)
#define SMEM64  (2 * 2 * 192 * 80)
#define SMEMF   (2 * 256 * 80)

extern "C" void kernel_launch(void* const* d_in, const int* in_sizes, int n_in,
                              void* d_out, int out_size)
{
    const float* tgt      = (const float*)d_in[0];
    const float* memory   = (const float*)d_in[1];
    const float* qpos     = (const float*)d_in[2];
    const float* kpos     = (const float*)d_in[3];
    const float* norm0_g  = (const float*)d_in[4];
    const float* norm0_b  = (const float*)d_in[5];
    const float* l1_w     = (const float*)d_in[6];
    const float* l1_b     = (const float*)d_in[7];
    const float* l2_w     = (const float*)d_in[8];
    const float* l2_b     = (const float*)d_in[9];
    const float* l3_w     = (const float*)d_in[10];
    const float* l3_b     = (const float*)d_in[11];
    const float* n1_g     = (const float*)d_in[12];
    const float* n1_b     = (const float*)d_in[13];
    const float* n2_g     = (const float*)d_in[14];
    const float* n2_b     = (const float*)d_in[15];
    const float* n3_g     = (const float*)d_in[16];
    const float* n3_b     = (const float*)d_in[17];
    const float* sa_in_w  = (const float*)d_in[18];
    const float* sa_in_b  = (const float*)d_in[19];
    const float* sa_out_w = (const float*)d_in[20];
    const float* sa_out_b = (const float*)d_in[21];
    const float* ff1_w    = (const float*)d_in[22];
    const float* ff1_b    = (const float*)d_in[23];
    const float* ff2_w    = (const float*)d_in[24];
    const float* ff2_b    = (const float*)d_in[25];
    const float* bn_g     = (const float*)d_in[26];
    const float* bn_b     = (const float*)d_in[27];
    const float* cls_w    = (const float*)d_in[28];

    float *x, *tmp, *q, *qk, *v, *attn, *Z, *sims, *minv, *bnsc, *bnsh;
    int* idx;
    __nv_bfloat16 *whi, *wlo, *w2th, *w2tl;
    __nv_bfloat16 *xhi, *xlo, *xqhi, *xqlo, *qhi, *qlo, *agghi, *agglo;
    __nv_bfloat16 *h1hi, *h1lo, *sahi, *salo, *cihi, *cilo;
    __half *mf16, *xf16;
    cudaGetSymbolAddress((void**)&x,    g_x);
    cudaGetSymbolAddress((void**)&tmp,  g_tmp);
    cudaGetSymbolAddress((void**)&q,    g_q);
    cudaGetSymbolAddress((void**)&qk,   g_qk);
    cudaGetSymbolAddress((void**)&v,    g_v);
    cudaGetSymbolAddress((void**)&attn, g_attn);
    cudaGetSymbolAddress((void**)&Z,    g_Z);
    cudaGetSymbolAddress((void**)&sims, g_sims);
    cudaGetSymbolAddress((void**)&idx,  g_idx);
    cudaGetSymbolAddress((void**)&minv, g_minv);
    cudaGetSymbolAddress((void**)&bnsc, g_bnscale);
    cudaGetSymbolAddress((void**)&bnsh, g_bnshift);
    cudaGetSymbolAddress((void**)&whi,  g_whi);
    cudaGetSymbolAddress((void**)&wlo,  g_wlo);
    cudaGetSymbolAddress((void**)&w2th, g_w2thi);
    cudaGetSymbolAddress((void**)&w2tl, g_w2tlo);
    cudaGetSymbolAddress((void**)&xhi,  g_xhi);
    cudaGetSymbolAddress((void**)&xlo,  g_xlo);
    cudaGetSymbolAddress((void**)&xqhi, g_xqhi);
    cudaGetSymbolAddress((void**)&xqlo, g_xqlo);
    cudaGetSymbolAddress((void**)&qhi,  g_qhi);
    cudaGetSymbolAddress((void**)&qlo,  g_qlo);
    cudaGetSymbolAddress((void**)&agghi, g_agghi);
    cudaGetSymbolAddress((void**)&agglo, g_agglo);
    cudaGetSymbolAddress((void**)&h1hi, g_h1hi);
    cudaGetSymbolAddress((void**)&h1lo, g_h1lo);
    cudaGetSymbolAddress((void**)&sahi, g_sahi);
    cudaGetSymbolAddress((void**)&salo, g_salo);
    cudaGetSymbolAddress((void**)&cihi, g_cihi);
    cudaGetSymbolAddress((void**)&cilo, g_cilo);
    cudaGetSymbolAddress((void**)&mf16, g_mf16);
    cudaGetSymbolAddress((void**)&xf16, g_xf16);

    cudaFuncSetAttribute(hgemm_kernel<128,0>, cudaFuncAttributeMaxDynamicSharedMemorySize, SMEM128);
    cudaFuncSetAttribute(hgemm_kernel<128,1>, cudaFuncAttributeMaxDynamicSharedMemorySize, SMEM128);
    cudaFuncSetAttribute(hgemm_kernel<64,0>,  cudaFuncAttributeMaxDynamicSharedMemorySize, SMEM64);
    cudaFuncSetAttribute(hgemm_kernel<64,3>,  cudaFuncAttributeMaxDynamicSharedMemorySize, SMEM64);
    cudaFuncSetAttribute(self_attn_kernel,    cudaFuncAttributeMaxDynamicSharedMemorySize, SA_SMEM);

    split_kernel<<<2048, 256>>>(l1_w,     whi + OFF_L1,    wlo + OFF_L1,    (long)NLAYERS*D*D);
    split_kernel<<<2048, 256>>>(l3_w,     whi + OFF_L3,    wlo + OFF_L3,    (long)NLAYERS*D*D);
    split_kernel<<<2048, 256>>>(sa_in_w,  whi + OFF_SAIN,  wlo + OFF_SAIN,  (long)NLAYERS*3*D*D);
    split_kernel<<<2048, 256>>>(sa_out_w, whi + OFF_SAOUT, wlo + OFF_SAOUT, (long)NLAYERS*D*D);
    split_kernel<<<2048, 256>>>(ff1_w,    whi + OFF_FF1,   wlo + OFF_FF1,   (long)NLAYERS*DFF*D);
    split_kernel<<<2048, 256>>>(ff2_w,    whi + OFF_FF2,   wlo + OFF_FF2,   (long)NLAYERS*D*DFF);
    split_kernel<<<2048, 256>>>(cls_w,    whi + OFF_CLS,   wlo + OFF_CLS,   (long)NC*D);
    w2t_split_kernel<<<2048, 256>>>(l2_w, w2th, w2tl);
    convnorm_kernel<<<NMEM, 256>>>(memory, mf16, minv);

    ln_kernel<<<NTOK, 256>>>(tgt, nullptr, norm0_g, norm0_b, qpos,
                             x, xhi, xlo, xqhi, xqlo, xf16);

    for (int l = 0; l < NLAYERS; l++) {
        long wdd = (long)l * D * D;
        const __nv_bfloat16* l1h = whi + OFF_L1 + wdd;   const __nv_bfloat16* l1l = wlo + OFF_L1 + wdd;
        const __nv_bfloat16* l3h = whi + OFF_L3 + wdd;   const __nv_bfloat16* l3l = wlo + OFF_L3 + wdd;
        const __nv_bfloat16* sih = whi + OFF_SAIN + (long)l*3*D*D;
        const __nv_bfloat16* sil = wlo + OFF_SAIN + (long)l*3*D*D;
        const __nv_bfloat16* soh = whi + OFF_SAOUT + wdd;
        const __nv_bfloat16* sol = wlo + OFF_SAOUT + wdd;
        const __nv_bfloat16* f1h = whi + OFF_FF1 + (long)l*DFF*D;
        const __nv_bfloat16* f1l = wlo + OFF_FF1 + (long)l*DFF*D;
        const __nv_bfloat16* f2h = whi + OFF_FF2 + (long)l*D*DFF;
        const __nv_bfloat16* f2l = wlo + OFF_FF2 + (long)l*D*DFF;
        const __nv_bfloat16* w2h = w2th + (long)l*NH*D*HD;
        const __nv_bfloat16* w2l = w2tl + (long)l*NH*D*HD;
        const float* l1bb = l1_b + (long)l * D;
        const float* l2bb = l2_b + (long)l * D;
        const float* l3bb = l3_b + (long)l * D;
        const float* sab  = sa_in_b + (long)l * 3 * D;
        const float* sob  = sa_out_b + (long)l * D;
        const float* f1b  = ff1_b + (long)l * DFF;
        const float* f2b  = ff2_b + (long)l * D;

        fgemm_kernel<<<dim3(MNP/128, 1, BS), 256, SMEMF>>>(
            xf16, mf16, sims, NP, MNP, D,
            (long)NP*D, (long)MNP*D, (long)NP*MNP);

        topk_kernel<<<NTOK, 256>>>(sims, minv, x, memory, idx);

        // q = (x+qpos) @ l1^T + b1  (BN=64 -> 192 blocks)
        hgemm_kernel<64,3><<<dim3(D/64, NTOK/128, 1), 256, SMEM64>>>(
            xqhi, xqlo, l1h, l1l, l1bb, q, qhi, qlo,
            NTOK, D, D, D, D, D, 0, 0, 0, 0);

        hgemm_kernel<128,0><<<dim3(D/128, NTOK/128, NH), 256, SMEM128>>>(
            qhi, qlo, w2h, w2l, nullptr, Z, nullptr, nullptr,
            NTOK, D, HD, D, HD, D,
            (long)HD, (long)D*HD, (long)NTOK*D, 0);

        xattn_kernel<<<NTOK, 128>>>(q, Z, memory, kpos, l2bb, idx, agghi, agglo);

        hgemm_kernel<64,0><<<dim3(1, NTOK/128, NH), 256, SMEM64>>>(
            agghi, agglo, l3h, l3l, l3bb, attn, nullptr, nullptr,
            NTOK, HD, D, D, D, D,
            (long)NTOK*D, (long)HD*D, (long)HD, (long)HD);

        ln_kernel<<<NTOK, 256>>>(x, attn, n1_g + (long)l * D, n1_b + (long)l * D,
                                 qpos, x, xhi, xlo, xqhi, xqlo, xf16);

        hgemm_kernel<128,0><<<dim3((2*D)/128, NTOK/128, 1), 256, SMEM128>>>(
            xqhi, xqlo, sih, sil, sab, qk, nullptr, nullptr,
            NTOK, 2*D, D, D, D, 2*D, 0, 0, 0, 0);
        hgemm_kernel<64,0><<<dim3(D/64, NTOK/128, 1), 256, SMEM64>>>(
            xhi, xlo, sih + (long)2*D*D, sil + (long)2*D*D, sab + 2*D,
            v, nullptr, nullptr, NTOK, D, D, D, D, D, 0, 0, 0, 0);

        self_attn_kernel<<<BS * NH, 128, SA_SMEM>>>(qk, v, sahi, salo);

        hgemm_kernel<64,0><<<dim3(D/64, NTOK/128, 1), 256, SMEM64>>>(
            sahi, salo, soh, sol, sob, tmp, nullptr, nullptr,
            NTOK, D, D, D, D, D, 0, 0, 0, 0);

        ln_kernel<<<NTOK, 256>>>(x, tmp, n2_g + (long)l * D, n2_b + (long)l * D,
                                 qpos, x, xhi, xlo, xqhi, xqlo, xf16);

        hgemm_kernel<128,1><<<dim3(DFF/128, NTOK/128, 1), 256, SMEM128>>>(
            xhi, xlo, f1h, f1l, f1b, nullptr, h1hi, h1lo,
            NTOK, DFF, D, D, D, DFF, 0, 0, 0, 0);
        hgemm_kernel<64,0><<<dim3(D/64, NTOK/128, 1), 256, SMEM64>>>(
            h1hi, h1lo, f2h, f2l, f2b, tmp, nullptr, nullptr,
            NTOK, D, DFF, DFF, DFF, D, 0, 0, 0, 0);

        ln_kernel<<<NTOK, 256>>>(x, tmp, n3_g + (long)l * D, n3_b + (long)l * D,
                                 qpos, x, xhi, xlo, xqhi, xqlo, xf16);
    }

    bn_stats_kernel<<<D, 256>>>(x, bn_g, bn_b, bnsc, bnsh);
    split_affine_kernel<<<2048, 256>>>(x, bnsc, bnsh, cihi, cilo, (long)NTOK * D);

    float* out = (float*)d_out;
    long xsz = (long)NTOK * D;
    long csz = (long)NTOK * NC;

    if ((long)out_size >= xsz + csz) {
        cudaMemcpyAsync(out, x, sizeof(float) * xsz, cudaMemcpyDeviceToDevice, 0);
        hgemm_kernel<64,0><<<dim3((NC+63)/64, NTOK/128, 1), 256, SMEM64>>>(
            cihi, cilo, whi + OFF_CLS, wlo + OFF_CLS, nullptr,
            out + xsz, nullptr, nullptr, NTOK, NC, D, D, D, NC, 0, 0, 0, 0);
    } else if ((long)out_size == csz) {
        hgemm_kernel<64,0><<<dim3((NC+63)/64, NTOK/128, 1), 256, SMEM64>>>(
            cihi, cilo, whi + OFF_CLS, wlo + OFF_CLS, nullptr,
            out, nullptr, nullptr, NTOK, NC, D, D, D, NC, 0, 0, 0, 0);
    } else {
        cudaMemcpyAsync(out, x, sizeof(float) * ((long)out_size < xsz ? out_size : xsz),
                        cudaMemcpyDeviceToDevice, 0);
    }
}

// round 15
// speedup vs baseline: 2.7875x; 1.0061x over previous
#include <cuda_runtime.h>
#include <cuda_bf16.h>
#include <cuda_fp16.h>
#include <math.h>
#include <stdint.h>

#define BS   16
#define NP   128
#define MNP  2048
#define D    768
#define NH   12
#define HD   64
#define DFF  2048
#define NLAYERS 2
#define TOPK 32
#define COVER 48
#define NC   751
#define NTOK (BS*NP)
#define NMEM (BS*MNP)
#define EPS  1e-5f

// ----------------------------------------------------------------------------
// Scratch
// ----------------------------------------------------------------------------
__device__ float g_x   [NTOK*(long)D];
__device__ float g_tmp [NTOK*(long)D];
__device__ float g_q   [NTOK*(long)D];
__device__ float g_qk  [NTOK*(long)(2*D)];
__device__ float g_v   [NTOK*(long)D];
__device__ float g_attn[NTOK*(long)D];
__device__ float g_Z   [(long)NH*NTOK*D];
__device__ float g_sims[NTOK*(long)MNP];
__device__ int   g_idx [NTOK*TOPK];
__device__ float g_minv[NMEM];
__device__ float g_bnscale[D];
__device__ float g_bnshift[D];

#define OFF_L1    0L
#define OFF_L3    1179648L
#define OFF_SAIN  2359296L
#define OFF_SAOUT 5898240L
#define OFF_FF1   7077888L
#define OFF_FF2   10223616L
#define OFF_CLS   13369344L
#define WTOTAL    13946112L
__device__ __nv_bfloat16 g_whi[WTOTAL], g_wlo[WTOTAL];
__device__ __nv_bfloat16 g_w2thi[(long)NLAYERS*NH*D*HD], g_w2tlo[(long)NLAYERS*NH*D*HD];
__device__ __nv_bfloat16 g_xhi [NTOK*(long)D], g_xlo [NTOK*(long)D];
__device__ __nv_bfloat16 g_xqhi[NTOK*(long)D], g_xqlo[NTOK*(long)D];
__device__ __nv_bfloat16 g_qhi [NTOK*(long)D], g_qlo [NTOK*(long)D];
__device__ __nv_bfloat16 g_agghi[(long)NH*NTOK*D], g_agglo[(long)NH*NTOK*D];
__device__ __nv_bfloat16 g_h1hi[NTOK*(long)DFF], g_h1lo[NTOK*(long)DFF];
__device__ __nv_bfloat16 g_sahi[NTOK*(long)D], g_salo[NTOK*(long)D];
__device__ __nv_bfloat16 g_cihi[NTOK*(long)D], g_cilo[NTOK*(long)D];

__device__ __half g_mf16 [NMEM*(long)D];
__device__ __half g_xf16 [NTOK*(long)D];

// ----------------------------------------------------------------------------
// Helpers
// ----------------------------------------------------------------------------
__device__ __forceinline__ uint32_t smem_u32(const void* p) {
    uint32_t a;
    asm("{ .reg .u64 t; cvta.to.shared.u64 t, %1; cvt.u32.u64 %0, t; }"
        : "=r"(a) : "l"(p));
    return a;
}

#define CP_ASYNC16(dst, src) \
    asm volatile("cp.async.ca.shared.global [%0], [%1], 16;" \
                 :: "r"(dst), "l"(src) : "memory")
#define CP_COMMIT() asm volatile("cp.async.commit_group;" ::: "memory")
#define CP_WAIT(n)  asm volatile("cp.async.wait_group %0;" :: "n"(n) : "memory")

__device__ __forceinline__ void ldsm_x4(uint32_t& r0, uint32_t& r1,
                                        uint32_t& r2, uint32_t& r3, uint32_t addr)
{
    asm volatile("ldmatrix.sync.aligned.m8n8.x4.shared.b16 {%0,%1,%2,%3}, [%4];"
        : "=r"(r0), "=r"(r1), "=r"(r2), "=r"(r3) : "r"(addr));
}

__device__ __forceinline__ void mma_bf16(float c[4],
    uint32_t a0, uint32_t a1, uint32_t a2, uint32_t a3,
    uint32_t b0, uint32_t b1)
{
    asm("mma.sync.aligned.m16n8k16.row.col.f32.bf16.bf16.f32 "
        "{%0,%1,%2,%3}, {%4,%5,%6,%7}, {%8,%9}, {%0,%1,%2,%3};"
        : "+f"(c[0]), "+f"(c[1]), "+f"(c[2]), "+f"(c[3])
        : "r"(a0), "r"(a1), "r"(a2), "r"(a3), "r"(b0), "r"(b1));
}

__device__ __forceinline__ void mma_f16(float c[4],
    uint32_t a0, uint32_t a1, uint32_t a2, uint32_t a3,
    uint32_t b0, uint32_t b1)
{
    asm("mma.sync.aligned.m16n8k16.row.col.f32.f16.f16.f32 "
        "{%0,%1,%2,%3}, {%4,%5,%6,%7}, {%8,%9}, {%0,%1,%2,%3};"
        : "+f"(c[0]), "+f"(c[1]), "+f"(c[2]), "+f"(c[3])
        : "r"(a0), "r"(a1), "r"(a2), "r"(a3), "r"(b0), "r"(b1));
}

__device__ __forceinline__ void split1(float v, __nv_bfloat16& h, __nv_bfloat16& l) {
    __nv_bfloat16 hb = __float2bfloat16_rn(v);
    h = hb;
    l = __float2bfloat16_rn(v - __bfloat162float(hb));
}

// ----------------------------------------------------------------------------
// Fused multi-segment weight split (dst offsets == concatenated segment starts)
// ----------------------------------------------------------------------------
struct SplitJobs {
    const float* src[7];
    long cum[8];
};

__global__ void __launch_bounds__(256) multi_split_kernel(
    SplitJobs jobs, __nv_bfloat16* __restrict__ hi, __nv_bfloat16* __restrict__ lo)
{
    long total = jobs.cum[7];
    long i = blockIdx.x * 256L + threadIdx.x;
    long stride = (long)gridDim.x * 256;
    for (; i < total; i += stride) {
        int s = 0;
#pragma unroll
        for (int k = 1; k < 7; k++) if (i >= jobs.cum[k]) s = k;
        float v = jobs.src[s][i - jobs.cum[s]];
        __nv_bfloat16 h, l;
        split1(v, h, l);
        hi[i] = h; lo[i] = l;
    }
}

__global__ void __launch_bounds__(256) w2t_split_kernel(
    const float* __restrict__ l2w,
    __nv_bfloat16* __restrict__ hi, __nv_bfloat16* __restrict__ lo)
{
    long n = (long)NLAYERS * NH * D * HD;
    long i = blockIdx.x * 256L + threadIdx.x;
    long stride = (long)gridDim.x * 256;
    for (; i < n; i += stride) {
        int k = (int)(i & 63);
        long t = i >> 6;
        int nn = (int)(t % D);
        long t2 = t / D;
        int h = (int)(t2 % NH);
        int l = (int)(t2 / NH);
        float v = l2w[((long)l * D + h * HD + k) * D + nn];
        __nv_bfloat16 hh, ll;
        split1(v, hh, ll);
        hi[i] = hh; lo[i] = ll;
    }
}

// memory -> fp16 copy + row inverse norms, single pass.
__global__ void __launch_bounds__(256) convnorm_kernel(
    const float* __restrict__ m, __half* __restrict__ mf,
    float* __restrict__ minv)
{
    int row = blockIdx.x, tid = threadIdx.x;
    float s = 0.f;
#pragma unroll
    for (int i = 0; i < 3; i++) {
        long o = (long)row * D + tid + i * 256;
        float v = m[o];
        mf[o] = __float2half_rn(v);
        s += v * v;
    }
    __shared__ float rs[256];
    rs[tid] = s; __syncthreads();
    for (int o = 128; o > 0; o >>= 1) {
        if (tid < o) rs[tid] += rs[tid + o];
        __syncthreads();
    }
    if (tid == 0) minv[row] = rsqrtf(rs[0]);
}

__global__ void __launch_bounds__(256) split_affine_kernel(
    const float* __restrict__ src, const float* __restrict__ scale,
    const float* __restrict__ shift,
    __nv_bfloat16* __restrict__ hi, __nv_bfloat16* __restrict__ lo, long n)
{
    long i = blockIdx.x * 256L + threadIdx.x;
    long stride = (long)gridDim.x * 256;
    for (; i < n; i += stride) {
        int k = (int)(i % D);
        __nv_bfloat16 h, l;
        split1(src[i] * scale[k] + shift[k], h, l);
        hi[i] = h; lo[i] = l;
    }
}

// ----------------------------------------------------------------------------
// bf16x3 tensor-core GEMM (unchanged)
// ----------------------------------------------------------------------------
template<int BN, int EPI>
__global__ void __launch_bounds__(256) hgemm_kernel(
    const __nv_bfloat16* __restrict__ Ah, const __nv_bfloat16* __restrict__ Al,
    const __nv_bfloat16* __restrict__ Bh, const __nv_bfloat16* __restrict__ Bl,
    const float* __restrict__ bias,
    float* __restrict__ C,
    __nv_bfloat16* __restrict__ Chi, __nv_bfloat16* __restrict__ Clo,
    int M, int N, int K, int ldA, int ldB, int ldC,
    long zA, long zB, long zC, long zBias)
{
    constexpr int BM = 128;
    constexpr int NT = BN / 32;
    constexpr int ROWS = BM + BN;
    extern __shared__ __align__(16) __nv_bfloat16 smem[];

    const int bz = blockIdx.z;
    Ah += bz * zA; Al += bz * zA;
    Bh += bz * zB; Bl += bz * zB;
    if (bias) bias += bz * zBias;
    C  += bz * zC;
    if (EPI == 1 || EPI == 3) { Chi += bz * zC; Clo += bz * zC; }

    const int tid  = threadIdx.x;
    const int wid  = tid >> 5;
    const int lane = tid & 31;
    const int wm   = wid & 1;
    const int wn   = wid >> 1;
    const int qm   = lane >> 2;
    const int qk   = lane & 3;
    const int bm = blockIdx.y * BM;
    const int bn = blockIdx.x * BN;
    const uint32_t sbase = smem_u32(smem);

    float acc[4][NT][4];
#pragma unroll
    for (int mt = 0; mt < 4; mt++)
#pragma unroll
        for (int nt = 0; nt < NT; nt++)
#pragma unroll
            for (int r = 0; r < 4; r++) acc[mt][nt][r] = 0.f;

    auto loadStage = [&](int s, int k0) {
        const uint32_t pH = sbase + (uint32_t)(s * 2 + 0) * ROWS * 80;
        const uint32_t pL = sbase + (uint32_t)(s * 2 + 1) * ROWS * 80;
#pragma unroll
        for (int c = tid; c < BM * 4; c += 256) {
            int row = c >> 2, kc = c & 3;
            long gofs = (long)(bm + row) * ldA + k0;
            CP_ASYNC16(pH + row * 80 + kc * 16, (const char*)(Ah + gofs) + kc * 16);
            CP_ASYNC16(pL + row * 80 + kc * 16, (const char*)(Al + gofs) + kc * 16);
        }
#pragma unroll
        for (int c = tid; c < BN * 4; c += 256) {
            int row = c >> 2, kc = c & 3;
            int n = bn + row;
            uint32_t dh = pH + (BM + row) * 80 + kc * 16;
            uint32_t dl = pL + (BM + row) * 80 + kc * 16;
            if (n < N) {
                long gofs = (long)n * ldB + k0;
                CP_ASYNC16(dh, (const char*)(Bh + gofs) + kc * 16);
                CP_ASYNC16(dl, (const char*)(Bl + gofs) + kc * 16);
            } else {
                uint32_t z = 0;
                asm volatile("st.shared.v4.b32 [%0], {%1,%1,%1,%1};" :: "r"(dh), "r"(z) : "memory");
                asm volatile("st.shared.v4.b32 [%0], {%1,%1,%1,%1};" :: "r"(dl), "r"(z) : "memory");
            }
        }
    };

    auto compute = [&](int s) {
        const uint32_t baseH = sbase + (uint32_t)(s * 2 + 0) * ROWS * 80;
        const uint32_t baseL = sbase + (uint32_t)(s * 2 + 1) * ROWS * 80;
#pragma unroll
        for (int kc = 0; kc < 2; kc++) {
            uint32_t ah[4][4], al[4][4], bh[NT][2], bl[NT][2];
            const int arow = wm * 64 + (lane & 15);
            const uint32_t acol = kc * 32 + ((lane & 16) ? 16 : 0);
#pragma unroll
            for (int mt = 0; mt < 4; mt++) {
                uint32_t ro = (uint32_t)(arow + mt * 16) * 80 + acol;
                ldsm_x4(ah[mt][0], ah[mt][1], ah[mt][2], ah[mt][3], baseH + ro);
                ldsm_x4(al[mt][0], al[mt][1], al[mt][2], al[mt][3], baseL + ro);
            }
            const int brow = BM + wn * (BN / 4) + (lane & 7) + ((lane & 16) ? 8 : 0);
            const uint32_t bcol = kc * 32 + ((lane & 8) ? 16 : 0);
#pragma unroll
            for (int np = 0; np < NT / 2; np++) {
                uint32_t ro = (uint32_t)(brow + np * 16) * 80 + bcol;
                ldsm_x4(bh[2*np][0], bh[2*np][1], bh[2*np+1][0], bh[2*np+1][1], baseH + ro);
                ldsm_x4(bl[2*np][0], bl[2*np][1], bl[2*np+1][0], bl[2*np+1][1], baseL + ro);
            }
#pragma unroll
            for (int mt = 0; mt < 4; mt++)
#pragma unroll
                for (int nt = 0; nt < NT; nt++) {
                    mma_bf16(acc[mt][nt], ah[mt][0], ah[mt][1], ah[mt][2], ah[mt][3],
                             bh[nt][0], bh[nt][1]);
                    mma_bf16(acc[mt][nt], ah[mt][0], ah[mt][1], ah[mt][2], ah[mt][3],
                             bl[nt][0], bl[nt][1]);
                    mma_bf16(acc[mt][nt], al[mt][0], al[mt][1], al[mt][2], al[mt][3],
                             bh[nt][0], bh[nt][1]);
                }
        }
    };

    const int niter = K >> 5;
    loadStage(0, 0); CP_COMMIT();
    for (int i = 0; i < niter; i++) {
        if (i + 1 < niter) { loadStage((i + 1) & 1, (i + 1) << 5); CP_COMMIT(); CP_WAIT(1); }
        else               { CP_WAIT(0); }
        __syncthreads();
        compute(i & 1);
        __syncthreads();
    }

#pragma unroll
    for (int mt = 0; mt < 4; mt++) {
        int r0 = bm + wm * 64 + mt * 16 + qm;
#pragma unroll
        for (int nt = 0; nt < NT; nt++) {
            int c0 = bn + wn * (BN / 4) + nt * 8 + qk * 2;
            float v0 = acc[mt][nt][0], v1 = acc[mt][nt][1];
            float v2 = acc[mt][nt][2], v3 = acc[mt][nt][3];
            if (bias) {
                float b0 = (c0 < N) ? bias[c0] : 0.f;
                float b1 = (c0 + 1 < N) ? bias[c0 + 1] : 0.f;
                v0 += b0; v1 += b1; v2 += b0; v3 += b1;
            }
            if (EPI == 1) {
                v0 = 0.5f * v0 * (1.f + erff(v0 * 0.70710678118654752f));
                v1 = 0.5f * v1 * (1.f + erff(v1 * 0.70710678118654752f));
                v2 = 0.5f * v2 * (1.f + erff(v2 * 0.70710678118654752f));
                v3 = 0.5f * v3 * (1.f + erff(v3 * 0.70710678118654752f));
            }
            if (EPI == 1 || EPI == 3) {
                __nv_bfloat162 h2, l2;
                split1(v0, h2.x, l2.x); split1(v1, h2.y, l2.y);
                *(__nv_bfloat162*)(Chi + (long)r0 * ldC + c0) = h2;
                *(__nv_bfloat162*)(Clo + (long)r0 * ldC + c0) = l2;
                split1(v2, h2.x, l2.x); split1(v3, h2.y, l2.y);
                *(__nv_bfloat162*)(Chi + (long)(r0 + 8) * ldC + c0) = h2;
                *(__nv_bfloat162*)(Clo + (long)(r0 + 8) * ldC + c0) = l2;
            }
            if (EPI == 0 || EPI == 3) {
                if (c0 < N) {
                    C[(long)r0 * ldC + c0] = v0;
                    C[(long)(r0 + 8) * ldC + c0] = v2;
                }
                if (c0 + 1 < N) {
                    C[(long)r0 * ldC + c0 + 1] = v1;
                    C[(long)(r0 + 8) * ldC + c0 + 1] = v3;
                }
            }
        }
    }
}

// ----------------------------------------------------------------------------
// Single-pass fp16 tensor-core GEMM (coarse sims only) — unchanged
// ----------------------------------------------------------------------------
__global__ void __launch_bounds__(256) fgemm_kernel(
    const __half* __restrict__ A, const __half* __restrict__ B,
    float* __restrict__ C,
    int M, int N, int K, long zA, long zB, long zC)
{
    constexpr int BM = 128, BN = 128, NT = 4, ROWS = BM + BN;
    extern __shared__ __align__(16) __half fsmem[];

    const int bz = blockIdx.z;
    A += bz * zA; B += bz * zB; C += bz * zC;

    const int tid  = threadIdx.x;
    const int wid  = tid >> 5;
    const int lane = tid & 31;
    const int wm   = wid & 1;
    const int wn   = wid >> 1;
    const int qm   = lane >> 2;
    const int qk   = lane & 3;
    const int bm = blockIdx.y * BM;
    const int bn = blockIdx.x * BN;
    const uint32_t sbase = smem_u32(fsmem);

    float acc[4][NT][4];
#pragma unroll
    for (int mt = 0; mt < 4; mt++)
#pragma unroll
        for (int nt = 0; nt < NT; nt++)
#pragma unroll
            for (int r = 0; r < 4; r++) acc[mt][nt][r] = 0.f;

    auto loadStage = [&](int s, int k0) {
        const uint32_t p = sbase + (uint32_t)s * ROWS * 80;
#pragma unroll
        for (int c = tid; c < BM * 4; c += 256) {
            int row = c >> 2, kc = c & 3;
            long gofs = (long)(bm + row) * K + k0;
            CP_ASYNC16(p + row * 80 + kc * 16, (const char*)(A + gofs) + kc * 16);
        }
#pragma unroll
        for (int c = tid; c < BN * 4; c += 256) {
            int row = c >> 2, kc = c & 3;
            long gofs = (long)(bn + row) * K + k0;
            CP_ASYNC16(p + (BM + row) * 80 + kc * 16, (const char*)(B + gofs) + kc * 16);
        }
    };

    auto compute = [&](int s) {
        const uint32_t base = sbase + (uint32_t)s * ROWS * 80;
#pragma unroll
        for (int kc = 0; kc < 2; kc++) {
            uint32_t a[4][4], b[NT][2];
            const int arow = wm * 64 + (lane & 15);
            const uint32_t acol = kc * 32 + ((lane & 16) ? 16 : 0);
#pragma unroll
            for (int mt = 0; mt < 4; mt++) {
                uint32_t ro = (uint32_t)(arow + mt * 16) * 80 + acol;
                ldsm_x4(a[mt][0], a[mt][1], a[mt][2], a[mt][3], base + ro);
            }
            const int brow = BM + wn * 32 + (lane & 7) + ((lane & 16) ? 8 : 0);
            const uint32_t bcol = kc * 32 + ((lane & 8) ? 16 : 0);
#pragma unroll
            for (int np = 0; np < NT / 2; np++) {
                uint32_t ro = (uint32_t)(brow + np * 16) * 80 + bcol;
                ldsm_x4(b[2*np][0], b[2*np][1], b[2*np+1][0], b[2*np+1][1], base + ro);
            }
#pragma unroll
            for (int mt = 0; mt < 4; mt++)
#pragma unroll
                for (int nt = 0; nt < NT; nt++)
                    mma_f16(acc[mt][nt], a[mt][0], a[mt][1], a[mt][2], a[mt][3],
                            b[nt][0], b[nt][1]);
        }
    };

    const int niter = K >> 5;
    loadStage(0, 0); CP_COMMIT();
    for (int i = 0; i < niter; i++) {
        if (i + 1 < niter) { loadStage((i + 1) & 1, (i + 1) << 5); CP_COMMIT(); CP_WAIT(1); }
        else               { CP_WAIT(0); }
        __syncthreads();
        compute(i & 1);
        __syncthreads();
    }

#pragma unroll
    for (int mt = 0; mt < 4; mt++) {
        int r0 = bm + wm * 64 + mt * 16 + qm;
#pragma unroll
        for (int nt = 0; nt < NT; nt++) {
            int c0 = bn + wn * 32 + nt * 8 + qk * 2;
            C[(long)r0 * N + c0]           = acc[mt][nt][0];
            C[(long)r0 * N + c0 + 1]       = acc[mt][nt][1];
            C[(long)(r0 + 8) * N + c0]     = acc[mt][nt][2];
            C[(long)(r0 + 8) * N + c0 + 1] = acc[mt][nt][3];
        }
    }
}

// ----------------------------------------------------------------------------
// LayerNorm + fused splits (aux outputs optional)
// ----------------------------------------------------------------------------
__global__ void __launch_bounds__(256) ln_kernel(
    const float* __restrict__ x, const float* __restrict__ add,
    const float* __restrict__ g, const float* __restrict__ b,
    const float* __restrict__ qpos,
    float* __restrict__ out,
    __nv_bfloat16* __restrict__ ohi, __nv_bfloat16* __restrict__ olo,
    __nv_bfloat16* __restrict__ oqhi, __nv_bfloat16* __restrict__ oqlo,
    __half* __restrict__ oxf16)
{
    int row = blockIdx.x, tid = threadIdx.x;
    const float* xr = x + (long)row * D;
    float vals[3];
    float s = 0.f, sq = 0.f;
#pragma unroll
    for (int i = 0; i < 3; i++) {
        int c = tid + i * 256;
        float v = xr[c];
        if (add) v += add[(long)row * D + c];
        vals[i] = v; s += v; sq += v * v;
    }
    __shared__ float rs[256], rq[256];
    rs[tid] = s; rq[tid] = sq;
    __syncthreads();
    for (int o = 128; o > 0; o >>= 1) {
        if (tid < o) { rs[tid] += rs[tid + o]; rq[tid] += rq[tid + o]; }
        __syncthreads();
    }
    float mu = rs[0] * (1.f / D);
    float var = rq[0] * (1.f / D) - mu * mu;
    float rstd = rsqrtf(var + EPS);
#pragma unroll
    for (int i = 0; i < 3; i++) {
        int c = tid + i * 256;
        long o = (long)row * D + c;
        float v = (vals[i] - mu) * rstd * g[c] + b[c];
        out[o] = v;
        if (oxf16) oxf16[o] = __float2half_rn(v);
        __nv_bfloat16 h, l;
        if (ohi) {
            split1(v, h, l);
            ohi[o] = h; olo[o] = l;
        }
        if (oqhi) {
            split1(v + qpos[o], h, l);
            oqhi[o] = h; oqlo[o] = l;
        }
    }
}

// ----------------------------------------------------------------------------
// Top-32 via histogram threshold (unchanged)
// ----------------------------------------------------------------------------
__global__ void __launch_bounds__(256) topk_kernel(
    const float* __restrict__ sims, const float* __restrict__ minv,
    const float* __restrict__ x, const float* __restrict__ memory,
    int* __restrict__ idx_out)
{
    int row = blockIdx.x;
    int b = row >> 7;
    int tid = threadIdx.x;
    int warp = tid >> 5, lane = tid & 31;

    __shared__ float s[MNP];
    __shared__ float xrow[D];
    __shared__ int   hist[1024];
    __shared__ int   pcount[256];
    __shared__ int   cnt;
    __shared__ uint32_t s_tu;
    __shared__ int   cand[1024];
    __shared__ float cval[1024];

    for (int i = tid; i < MNP; i += 256)
        s[i] = sims[(long)row * MNP + i] * minv[b * MNP + i];
    for (int c = tid; c < D; c += 256)
        xrow[c] = x[(long)row * D + c];
    for (int i = tid; i < 1024; i += 256) hist[i] = 0;
    if (tid == 0) cnt = 0;
    __syncthreads();

    auto mapu = [](float f) -> uint32_t {
        uint32_t u = __float_as_uint(f);
        return (u & 0x80000000u) ? ~u : (u | 0x80000000u);
    };

    for (int i = tid; i < MNP; i += 256)
        atomicAdd(&hist[mapu(s[i]) >> 22], 1);
    __syncthreads();

    int local = hist[tid*4] + hist[tid*4+1] + hist[tid*4+2] + hist[tid*4+3];
    pcount[tid] = local;
    __syncthreads();
    for (int off = 1; off < 256; off <<= 1) {
        int v = (tid + off < 256) ? pcount[tid + off] : 0;
        __syncthreads();
        pcount[tid] += v;
        __syncthreads();
    }
    {
        int c0 = pcount[tid];
        int c1 = (tid + 1 < 256) ? pcount[tid + 1] : 0;
        if (c0 >= COVER && c1 < COVER) {
            int acc = c1;
            int chosen = tid * 4;
            for (int k = 3; k >= 0; k--) {
                acc += hist[tid*4 + k];
                if (acc >= COVER) { chosen = tid*4 + k; break; }
            }
            s_tu = (uint32_t)chosen << 22;
        }
    }
    __syncthreads();
    uint32_t tu = s_tu;

    for (int i = tid; i < MNP; i += 256) {
        if (mapu(s[i]) >= tu) {
            int p = atomicAdd(&cnt, 1);
            if (p < 1024) cand[p] = i;
        }
    }
    __syncthreads();
    int n = cnt < 1024 ? cnt : 1024;

    for (int j = warp; j < n; j += 8) {
        int ix = cand[j];
        const float* mr = memory + ((long)(b * MNP + ix)) * D;
        float acc = 0.f;
        for (int c = lane; c < D; c += 32) acc = fmaf(xrow[c], mr[c], acc);
#pragma unroll
        for (int o = 16; o > 0; o >>= 1) acc += __shfl_xor_sync(0xffffffffu, acc, o);
        if (lane == 0) cval[j] = acc * minv[b * MNP + ix];
    }
    __syncthreads();

    if (warp == 0) {
        for (int t = 0; t < TOPK; t++) {
            float v = -INFINITY; int myi = 0x7fffffff, myj = -1;
            for (int j = lane; j < n; j += 32) {
                float cv = cval[j];
                if (cv > v || (cv == v && cand[j] < myi)) { v = cv; myi = cand[j]; myj = j; }
            }
#pragma unroll
            for (int o = 16; o > 0; o >>= 1) {
                float ov = __shfl_xor_sync(0xffffffffu, v, o);
                int   oi = __shfl_xor_sync(0xffffffffu, myi, o);
                int   oj = __shfl_xor_sync(0xffffffffu, myj, o);
                if (ov > v || (ov == v && oi < myi)) { v = ov; myi = oi; myj = oj; }
            }
            if (lane == 0) {
                idx_out[row * TOPK + t] = myi;
                cval[myj] = -INFINITY;
            }
            __syncwarp();
        }
    }
}

// ----------------------------------------------------------------------------
// Fused cross-attention, single-pass online softmax: each gathered row is
// scored and aggregated in the same iteration (running max/sum/agg rescale).
// ----------------------------------------------------------------------------
__global__ void __launch_bounds__(128) xattn_kernel(
    const float* __restrict__ qf,
    const float* __restrict__ Z,
    const float* __restrict__ memory,
    const float* __restrict__ kpos,
    const float* __restrict__ l2b,
    const int*   __restrict__ idx,
    __nv_bfloat16* __restrict__ agghi,
    __nv_bfloat16* __restrict__ agglo)
{
    __shared__ __align__(16) float mrow[2][D];
    __shared__ __align__(16) float krow[2][D];
    __shared__ float qrow[D];
    __shared__ float qb[NH];
    __shared__ int   ids[TOPK];

    const int qi = blockIdx.x;
    const int b = qi >> 7;
    const int tid = threadIdx.x;
    const int warp = tid >> 5, lane = tid & 31;
    const int h0 = warp * 3;
    const uint32_t mbase = smem_u32(mrow);
    const uint32_t kbase = smem_u32(krow);

    for (int k = 0; k < 6; k++)
        qrow[tid + 128 * k] = qf[(long)qi * D + tid + 128 * k];
    if (tid < TOPK) ids[tid] = idx[qi * TOPK + tid];
    __syncthreads();

#pragma unroll
    for (int t = 0; t < 3; t++) {
        int h = h0 + t;
        float s = qrow[h * HD + lane] * l2b[h * HD + lane]
                + qrow[h * HD + 32 + lane] * l2b[h * HD + 32 + lane];
#pragma unroll
        for (int o = 16; o > 0; o >>= 1) s += __shfl_xor_sync(0xffffffffu, s, o);
        qb[h] = s;   // all lanes have s; redundant write is benign
    }

    float zreg[3][24];
#pragma unroll
    for (int t = 0; t < 3; t++) {
        const float* zp = Z + ((long)(h0 + t) * NTOK + qi) * D;
#pragma unroll
        for (int i = 0; i < 24; i++) zreg[t][i] = zp[lane + 32 * i];
    }

    float mx[3], ssum[3], A[3][24];
#pragma unroll
    for (int t = 0; t < 3; t++) {
        mx[t] = -INFINITY; ssum[t] = 0.f;
#pragma unroll
        for (int i = 0; i < 24; i++) A[t][i] = 0.f;
    }

    auto fetch_mk = [&](int buf, int j) {
        long base = ((long)(b * MNP + ids[j])) * D;
        for (int c = tid; c < 192; c += 128) {
            CP_ASYNC16(mbase + (uint32_t)(buf * D + c * 4) * 4, (const char*)(memory + base) + c * 16);
            CP_ASYNC16(kbase + (uint32_t)(buf * D + c * 4) * 4, (const char*)(kpos + base) + c * 16);
        }
    };

    fetch_mk(0, 0); CP_COMMIT();
    for (int j = 0; j < TOPK; j++) {
        int buf = j & 1;
        if (j + 1 < TOPK) { fetch_mk(buf ^ 1, j + 1); CP_COMMIT(); CP_WAIT(1); }
        else              { CP_WAIT(0); }
        __syncthreads();
#pragma unroll
        for (int t = 0; t < 3; t++) {
            float s = 0.f;
#pragma unroll
            for (int i = 0; i < 24; i++)
                s = fmaf(zreg[t][i], mrow[buf][lane + 32 * i] + krow[buf][lane + 32 * i], s);
#pragma unroll
            for (int o = 16; o > 0; o >>= 1) s += __shfl_xor_sync(0xffffffffu, s, o);
            s = (s + qb[h0 + t]) * 0.125f;
            float mn = fmaxf(mx[t], s);
            float scale = expf(mx[t] - mn);   // exp(-inf)=0 on first iter
            float e = expf(s - mn);
            ssum[t] = ssum[t] * scale + e;
#pragma unroll
            for (int i = 0; i < 24; i++)
                A[t][i] = fmaf(e, mrow[buf][lane + 32 * i], A[t][i] * scale);
            mx[t] = mn;
        }
        __syncthreads();
    }

#pragma unroll
    for (int t = 0; t < 3; t++) {
        float inv = 1.f / ssum[t];
        long o0 = ((long)(h0 + t) * NTOK + qi) * D;
#pragma unroll
        for (int i = 0; i < 24; i++) {
            __nv_bfloat16 h, l;
            split1(A[t][i] * inv, h, l);
            agghi[o0 + lane + 32 * i] = h;
            agglo[o0 + lane + 32 * i] = l;
        }
    }
}

// ----------------------------------------------------------------------------
// Self-attention: block per (batch, head) — unchanged
// ----------------------------------------------------------------------------
#define SA_SMEM ((128*64 + 128*65 + 128*65 + 4*128) * 4)

__global__ void __launch_bounds__(128) self_attn_kernel(
    const float* __restrict__ qk, const float* __restrict__ v,
    __nv_bfloat16* __restrict__ ohi, __nv_bfloat16* __restrict__ olo)
{
    extern __shared__ float ssm[];
    float* Qs = ssm;
    float* Ks = Qs + 128 * 64;
    float* Vs = Ks + 128 * 65;
    float* Ps = Vs + 128 * 65;

    const int bh = blockIdx.x;
    const int b = bh / NH, h = bh % NH;
    const int tid = threadIdx.x;
    const int warp = tid >> 5, lane = tid & 31;

    for (int i = tid; i < 128 * 16; i += 128) {
        int r = i >> 4, c4 = (i & 15) << 2;
        long tok = (long)(b * NP + r);
        float4 qv = *(const float4*)&qk[tok * 2 * D + h * HD + c4];
        float4 kv = *(const float4*)&qk[tok * 2 * D + D + h * HD + c4];
        float4 vv = *(const float4*)&v[tok * D + h * HD + c4];
        *(float4*)&Qs[r * 64 + c4] = qv;
        Ks[r * 65 + c4 + 0] = kv.x; Ks[r * 65 + c4 + 1] = kv.y;
        Ks[r * 65 + c4 + 2] = kv.z; Ks[r * 65 + c4 + 3] = kv.w;
        Vs[r * 65 + c4 + 0] = vv.x; Vs[r * 65 + c4 + 1] = vv.y;
        Vs[r * 65 + c4 + 2] = vv.z; Vs[r * 65 + c4 + 3] = vv.w;
    }
    __syncthreads();

    for (int qq = 0; qq < 32; qq++) {
        int qi = warp * 32 + qq;
        const float* qrow = &Qs[qi * 64];
        float s[4];
#pragma unroll
        for (int kk = 0; kk < 4; kk++) {
            int k = lane + kk * 32;
            const float* krow = &Ks[k * 65];
            float acc = 0.f;
#pragma unroll
            for (int d = 0; d < HD; d++) acc = fmaf(qrow[d], krow[d], acc);
            s[kk] = acc * 0.125f;
        }
        float m = fmaxf(fmaxf(s[0], s[1]), fmaxf(s[2], s[3]));
#pragma unroll
        for (int o = 16; o > 0; o >>= 1) m = fmaxf(m, __shfl_xor_sync(0xffffffffu, m, o));
        float e[4], sum = 0.f;
#pragma unroll
        for (int kk = 0; kk < 4; kk++) { e[kk] = expf(s[kk] - m); sum += e[kk]; }
#pragma unroll
        for (int o = 16; o > 0; o >>= 1) sum += __shfl_xor_sync(0xffffffffu, sum, o);
        float inv = 1.f / sum;
#pragma unroll
        for (int kk = 0; kk < 4; kk++) Ps[warp * 128 + lane + kk * 32] = e[kk] * inv;
        __syncwarp();

        float a0 = 0.f, a1 = 0.f;
#pragma unroll 8
        for (int k = 0; k < 128; k++) {
            float p = Ps[warp * 128 + k];
            a0 = fmaf(p, Vs[k * 65 + lane], a0);
            a1 = fmaf(p, Vs[k * 65 + lane + 32], a1);
        }
        long o = (long)(b * NP + qi) * D + h * HD + lane;
        __nv_bfloat16 hh, ll;
        split1(a0, hh, ll);
        ohi[o] = hh; olo[o] = ll;
        split1(a1, hh, ll);
        ohi[o + 32] = hh; olo[o + 32] = ll;
        __syncwarp();
    }
}

// ----------------------------------------------------------------------------
// BatchNorm stats (unchanged)
// ----------------------------------------------------------------------------
__global__ void __launch_bounds__(256) bn_stats_kernel(
    const float* __restrict__ x, const float* __restrict__ g,
    const float* __restrict__ b, float* __restrict__ scale,
    float* __restrict__ shift)
{
    int f = blockIdx.x, tid = threadIdx.x;
    float s = 0.f, sq = 0.f;
    for (int r = tid; r < NTOK; r += 256) {
        float v = x[(long)r * D + f];
        s += v; sq += v * v;
    }
    __shared__ float rs[256], rq[256];
    rs[tid] = s; rq[tid] = sq;
    __syncthreads();
    for (int o = 128; o > 0; o >>= 1) {
        if (tid < o) { rs[tid] += rs[tid + o]; rq[tid] += rq[tid + o]; }
        __syncthreads();
    }
    if (tid == 0) {
        float mu = rs[0] * (1.f / NTOK);
        float var = rq[0] * (1.f / NTOK) - mu * mu;
        float rstd = rsqrtf(var + EPS);
        float sc = rstd * g[f];
        scale[f] = sc;
        shift[f] = b[f] - mu * sc;
    }
}

// ----------------------------------------------------------------------------
// Host orchestration
// ----------------------------------------------------------------------------
#define SMEM128 (2 * 2 * 256 * 80)
#define SMEM64  (2 * 2 * 192 * 80)
#define SMEMF   (2 * 256 * 80)

extern "C" void kernel_launch(void* const* d_in, const int* in_sizes, int n_in,
                              void* d_out, int out_size)
{
    const float* tgt      = (const float*)d_in[0];
    const float* memory   = (const float*)d_in[1];
    const float* qpos     = (const float*)d_in[2];
    const float* kpos     = (const float*)d_in[3];
    const float* norm0_g  = (const float*)d_in[4];
    const float* norm0_b  = (const float*)d_in[5];
    const float* l1_w     = (const float*)d_in[6];
    const float* l1_b     = (const float*)d_in[7];
    const float* l2_w     = (const float*)d_in[8];
    const float* l2_b     = (const float*)d_in[9];
    const float* l3_w     = (const float*)d_in[10];
    const float* l3_b     = (const float*)d_in[11];
    const float* n1_g     = (const float*)d_in[12];
    const float* n1_b     = (const float*)d_in[13];
    const float* n2_g     = (const float*)d_in[14];
    const float* n2_b     = (const float*)d_in[15];
    const float* n3_g     = (const float*)d_in[16];
    const float* n3_b     = (const float*)d_in[17];
    const float* sa_in_w  = (const float*)d_in[18];
    const float* sa_in_b  = (const float*)d_in[19];
    const float* sa_out_w = (const float*)d_in[20];
    const float* sa_out_b = (const float*)d_in[21];
    const float* ff1_w    = (const float*)d_in[22];
    const float* ff1_b    = (const float*)d_in[23];
    const float* ff2_w    = (const float*)d_in[24];
    const float* ff2_b    = (const float*)d_in[25];
    const float* bn_g     = (const float*)d_in[26];
    const float* bn_b     = (const float*)d_in[27];
    const float* cls_w    = (const float*)d_in[28];

    float *x, *tmp, *q, *qk, *v, *attn, *Z, *sims, *minv, *bnsc, *bnsh;
    int* idx;
    __nv_bfloat16 *whi, *wlo, *w2th, *w2tl;
    __nv_bfloat16 *xhi, *xlo, *xqhi, *xqlo, *qhi, *qlo, *agghi, *agglo;
    __nv_bfloat16 *h1hi, *h1lo, *sahi, *salo, *cihi, *cilo;
    __half *mf16, *xf16;
    cudaGetSymbolAddress((void**)&x,    g_x);
    cudaGetSymbolAddress((void**)&tmp,  g_tmp);
    cudaGetSymbolAddress((void**)&q,    g_q);
    cudaGetSymbolAddress((void**)&qk,   g_qk);
    cudaGetSymbolAddress((void**)&v,    g_v);
    cudaGetSymbolAddress((void**)&attn, g_attn);
    cudaGetSymbolAddress((void**)&Z,    g_Z);
    cudaGetSymbolAddress((void**)&sims, g_sims);
    cudaGetSymbolAddress((void**)&idx,  g_idx);
    cudaGetSymbolAddress((void**)&minv, g_minv);
    cudaGetSymbolAddress((void**)&bnsc, g_bnscale);
    cudaGetSymbolAddress((void**)&bnsh, g_bnshift);
    cudaGetSymbolAddress((void**)&whi,  g_whi);
    cudaGetSymbolAddress((void**)&wlo,  g_wlo);
    cudaGetSymbolAddress((void**)&w2th, g_w2thi);
    cudaGetSymbolAddress((void**)&w2tl, g_w2tlo);
    cudaGetSymbolAddress((void**)&xhi,  g_xhi);
    cudaGetSymbolAddress((void**)&xlo,  g_xlo);
    cudaGetSymbolAddress((void**)&xqhi, g_xqhi);
    cudaGetSymbolAddress((void**)&xqlo, g_xqlo);
    cudaGetSymbolAddress((void**)&qhi,  g_qhi);
    cudaGetSymbolAddress((void**)&qlo,  g_qlo);
    cudaGetSymbolAddress((void**)&agghi, g_agghi);
    cudaGetSymbolAddress((void**)&agglo, g_agglo);
    cudaGetSymbolAddress((void**)&h1hi, g_h1hi);
    cudaGetSymbolAddress((void**)&h1lo, g_h1lo);
    cudaGetSymbolAddress((void**)&sahi, g_sahi);
    cudaGetSymbolAddress((void**)&salo, g_salo);
    cudaGetSymbolAddress((void**)&cihi, g_cihi);
    cudaGetSymbolAddress((void**)&cilo, g_cilo);
    cudaGetSymbolAddress((void**)&mf16, g_mf16);
    cudaGetSymbolAddress((void**)&xf16, g_xf16);

    cudaFuncSetAttribute(hgemm_kernel<128,0>, cudaFuncAttributeMaxDynamicSharedMemorySize, SMEM128);
    cudaFuncSetAttribute(hgemm_kernel<128,1>, cudaFuncAttributeMaxDynamicSharedMemorySize, SMEM128);
    cudaFuncSetAttribute(hgemm_kernel<64,0>,  cudaFuncAttributeMaxDynamicSharedMemorySize, SMEM64);
    cudaFuncSetAttribute(hgemm_kernel<64,3>,  cudaFuncAttributeMaxDynamicSharedMemorySize, SMEM64);
    cudaFuncSetAttribute(self_attn_kernel,    cudaFuncAttributeMaxDynamicSharedMemorySize, SA_SMEM);

    // ---- one fused weight split (7 segments, dst offsets == cumulative) ----
    {
        SplitJobs jobs;
        jobs.src[0] = l1_w;     jobs.cum[0] = OFF_L1;
        jobs.src[1] = l3_w;     jobs.cum[1] = OFF_L3;
        jobs.src[2] = sa_in_w;  jobs.cum[2] = OFF_SAIN;
        jobs.src[3] = sa_out_w; jobs.cum[3] = OFF_SAOUT;
        jobs.src[4] = ff1_w;    jobs.cum[4] = OFF_FF1;
        jobs.src[5] = ff2_w;    jobs.cum[5] = OFF_FF2;
        jobs.src[6] = cls_w;    jobs.cum[6] = OFF_CLS;
        jobs.cum[7] = WTOTAL;
        multi_split_kernel<<<8192, 256>>>(jobs, whi, wlo);
    }
    w2t_split_kernel<<<2048, 256>>>(l2_w, w2th, w2tl);
    convnorm_kernel<<<NMEM, 256>>>(memory, mf16, minv);

    ln_kernel<<<NTOK, 256>>>(tgt, nullptr, norm0_g, norm0_b, qpos,
                             x, xhi, xlo, xqhi, xqlo, xf16);

    for (int l = 0; l < NLAYERS; l++) {
        long wdd = (long)l * D * D;
        const __nv_bfloat16* l1h = whi + OFF_L1 + wdd;   const __nv_bfloat16* l1l = wlo + OFF_L1 + wdd;
        const __nv_bfloat16* l3h = whi + OFF_L3 + wdd;   const __nv_bfloat16* l3l = wlo + OFF_L3 + wdd;
        const __nv_bfloat16* sih = whi + OFF_SAIN + (long)l*3*D*D;
        const __nv_bfloat16* sil = wlo + OFF_SAIN + (long)l*3*D*D;
        const __nv_bfloat16* soh = whi + OFF_SAOUT + wdd;
        const __nv_bfloat16* sol = wlo + OFF_SAOUT + wdd;
        const __nv_bfloat16* f1h = whi + OFF_FF1 + (long)l*DFF*D;
        const __nv_bfloat16* f1l = wlo + OFF_FF1 + (long)l*DFF*D;
        const __nv_bfloat16* f2h = whi + OFF_FF2 + (long)l*D*DFF;
        const __nv_bfloat16* f2l = wlo + OFF_FF2 + (long)l*D*DFF;
        const __nv_bfloat16* w2h = w2th + (long)l*NH*D*HD;
        const __nv_bfloat16* w2l = w2tl + (long)l*NH*D*HD;
        const float* l1bb = l1_b + (long)l * D;
        const float* l2bb = l2_b + (long)l * D;
        const float* l3bb = l3_b + (long)l * D;
        const float* sab  = sa_in_b + (long)l * 3 * D;
        const float* sob  = sa_out_b + (long)l * D;
        const float* f1b  = ff1_b + (long)l * DFF;
        const float* f2b  = ff2_b + (long)l * D;
        const bool last = (l == NLAYERS - 1);

        fgemm_kernel<<<dim3(MNP/128, 1, BS), 256, SMEMF>>>(
            xf16, mf16, sims, NP, MNP, D,
            (long)NP*D, (long)MNP*D, (long)NP*MNP);

        topk_kernel<<<NTOK, 256>>>(sims, minv, x, memory, idx);

        hgemm_kernel<64,3><<<dim3(D/64, NTOK/128, 1), 256, SMEM64>>>(
            xqhi, xqlo, l1h, l1l, l1bb, q, qhi, qlo,
            NTOK, D, D, D, D, D, 0, 0, 0, 0);

        hgemm_kernel<128,0><<<dim3(D/128, NTOK/128, NH), 256, SMEM128>>>(
            qhi, qlo, w2h, w2l, nullptr, Z, nullptr, nullptr,
            NTOK, D, HD, D, HD, D,
            (long)HD, (long)D*HD, (long)NTOK*D, 0);

        xattn_kernel<<<NTOK, 128>>>(q, Z, memory, kpos, l2bb, idx, agghi, agglo);

        hgemm_kernel<64,0><<<dim3(1, NTOK/128, NH), 256, SMEM64>>>(
            agghi, agglo, l3h, l3l, l3bb, attn, nullptr, nullptr,
            NTOK, HD, D, D, D, D,
            (long)NTOK*D, (long)HD*D, (long)HD, (long)HD);

        ln_kernel<<<NTOK, 256>>>(x, attn, n1_g + (long)l * D, n1_b + (long)l * D,
                                 qpos, x, xhi, xlo, xqhi, xqlo, xf16);

        hgemm_kernel<128,0><<<dim3((2*D)/128, NTOK/128, 1), 256, SMEM128>>>(
            xqhi, xqlo, sih, sil, sab, qk, nullptr, nullptr,
            NTOK, 2*D, D, D, D, 2*D, 0, 0, 0, 0);
        hgemm_kernel<64,0><<<dim3(D/64, NTOK/128, 1), 256, SMEM64>>>(
            xhi, xlo, sih + (long)2*D*D, sil + (long)2*D*D, sab + 2*D,
            v, nullptr, nullptr, NTOK, D, D, D, D, D, 0, 0, 0, 0);

        self_attn_kernel<<<BS * NH, 128, SA_SMEM>>>(qk, v, sahi, salo);

        hgemm_kernel<64,0><<<dim3(D/64, NTOK/128, 1), 256, SMEM64>>>(
            sahi, salo, soh, sol, sob, tmp, nullptr, nullptr,
            NTOK, D, D, D, D, D, 0, 0, 0, 0);

        ln_kernel<<<NTOK, 256>>>(x, tmp, n2_g + (long)l * D, n2_b + (long)l * D,
                                 qpos, x, xhi, xlo, xqhi, xqlo, xf16);

        hgemm_kernel<128,1><<<dim3(DFF/128, NTOK/128, 1), 256, SMEM128>>>(
            xhi, xlo, f1h, f1l, f1b, nullptr, h1hi, h1lo,
            NTOK, DFF, D, D, D, DFF, 0, 0, 0, 0);
        hgemm_kernel<64,0><<<dim3(D/64, NTOK/128, 1), 256, SMEM64>>>(
            h1hi, h1lo, f2h, f2l, f2b, tmp, nullptr, nullptr,
            NTOK, D, DFF, DFF, DFF, D, 0, 0, 0, 0);

        // last LN of last layer: only fp32 x is consumed afterwards
        ln_kernel<<<NTOK, 256>>>(x, tmp, n3_g + (long)l * D, n3_b + (long)l * D,
                                 qpos, x,
                                 last ? nullptr : xhi, last ? nullptr : xlo,
                                 last ? nullptr : xqhi, last ? nullptr : xqlo,
                                 last ? nullptr : xf16);
    }

    bn_stats_kernel<<<D, 256>>>(x, bn_g, bn_b, bnsc, bnsh);
    split_affine_kernel<<<2048, 256>>>(x, bnsc, bnsh, cihi, cilo, (long)NTOK * D);

    float* out = (float*)d_out;
    long xsz = (long)NTOK * D;
    long csz = (long)NTOK * NC;

    if ((long)out_size >= xsz + csz) {
        cudaMemcpyAsync(out, x, sizeof(float) * xsz, cudaMemcpyDeviceToDevice, 0);
        hgemm_kernel<64,0><<<dim3((NC+63)/64, NTOK/128, 1), 256, SMEM64>>>(
            cihi, cilo, whi + OFF_CLS, wlo + OFF_CLS, nullptr,
            out + xsz, nullptr, nullptr, NTOK, NC, D, D, D, NC, 0, 0, 0, 0);
    } else if ((long)out_size == csz) {
        hgemm_kernel<64,0><<<dim3((NC+63)/64, NTOK/128, 1), 256, SMEM64>>>(
            cihi, cilo, whi + OFF_CLS, wlo + OFF_CLS, nullptr,
            out, nullptr, nullptr, NTOK, NC, D, D, D, NC, 0, 0, 0, 0);
    } else {
        cudaMemcpyAsync(out, x, sizeof(float) * ((long)out_size < xsz ? out_size : xsz),
                        cudaMemcpyDeviceToDevice, 0);
    }
}

// round 16
// speedup vs baseline: 2.9353x; 1.0530x over previous
#include <cuda_runtime.h>
#include <cuda_bf16.h>
#include <cuda_fp16.h>
#include <math.h>
#include <stdint.h>

#define BS   16
#define NP   128
#define MNP  2048
#define D    768
#define NH   12
#define HD   64
#define DFF  2048
#define NLAYERS 2
#define TOPK 32
#define COVER 48
#define NC   751
#define NTOK (BS*NP)
#define NMEM (BS*MNP)
#define EPS  1e-5f

// ----------------------------------------------------------------------------
// Scratch
// ----------------------------------------------------------------------------
__device__ float g_x   [NTOK*(long)D];
__device__ float g_tmp [NTOK*(long)D];
__device__ float g_q   [NTOK*(long)D];
__device__ float g_qk  [NTOK*(long)(2*D)];
__device__ float g_v   [NTOK*(long)D];
__device__ float g_attn[NTOK*(long)D];
__device__ float g_Z   [(long)NH*NTOK*D];
__device__ float g_sims[NTOK*(long)MNP];
__device__ int   g_idx [NTOK*TOPK];
__device__ float g_minv[NMEM];
__device__ float g_bnscale[D];
__device__ float g_bnshift[D];

#define OFF_L1    0L
#define OFF_L3    1179648L
#define OFF_SAIN  2359296L
#define OFF_SAOUT 5898240L
#define OFF_FF1   7077888L
#define OFF_FF2   10223616L
#define OFF_CLS   13369344L
#define WTOTAL    13946112L
__device__ __nv_bfloat16 g_whi[WTOTAL], g_wlo[WTOTAL];
__device__ __nv_bfloat16 g_w2thi[(long)NLAYERS*NH*D*HD], g_w2tlo[(long)NLAYERS*NH*D*HD];
__device__ __nv_bfloat16 g_xhi [NTOK*(long)D], g_xlo [NTOK*(long)D];
__device__ __nv_bfloat16 g_xqhi[NTOK*(long)D], g_xqlo[NTOK*(long)D];
__device__ __nv_bfloat16 g_qhi [NTOK*(long)D], g_qlo [NTOK*(long)D];
__device__ __nv_bfloat16 g_agghi[(long)NH*NTOK*D], g_agglo[(long)NH*NTOK*D];
__device__ __nv_bfloat16 g_h1hi[NTOK*(long)DFF], g_h1lo[NTOK*(long)DFF];
__device__ __nv_bfloat16 g_sahi[NTOK*(long)D], g_salo[NTOK*(long)D];
__device__ __nv_bfloat16 g_cihi[NTOK*(long)D], g_cilo[NTOK*(long)D];

__device__ __half g_mf16 [NMEM*(long)D];
__device__ __half g_xf16 [NTOK*(long)D];

// ----------------------------------------------------------------------------
// Helpers
// ----------------------------------------------------------------------------
__device__ __forceinline__ uint32_t smem_u32(const void* p) {
    uint32_t a;
    asm("{ .reg .u64 t; cvta.to.shared.u64 t, %1; cvt.u32.u64 %0, t; }"
        : "=r"(a) : "l"(p));
    return a;
}

#define CP_ASYNC16(dst, src) \
    asm volatile("cp.async.ca.shared.global [%0], [%1], 16;" \
                 :: "r"(dst), "l"(src) : "memory")
#define CP_COMMIT() asm volatile("cp.async.commit_group;" ::: "memory")
#define CP_WAIT(n)  asm volatile("cp.async.wait_group %0;" :: "n"(n) : "memory")

__device__ __forceinline__ void ldsm_x4(uint32_t& r0, uint32_t& r1,
                                        uint32_t& r2, uint32_t& r3, uint32_t addr)
{
    asm volatile("ldmatrix.sync.aligned.m8n8.x4.shared.b16 {%0,%1,%2,%3}, [%4];"
        : "=r"(r0), "=r"(r1), "=r"(r2), "=r"(r3) : "r"(addr));
}

__device__ __forceinline__ void mma_bf16(float c[4],
    uint32_t a0, uint32_t a1, uint32_t a2, uint32_t a3,
    uint32_t b0, uint32_t b1)
{
    asm("mma.sync.aligned.m16n8k16.row.col.f32.bf16.bf16.f32 "
        "{%0,%1,%2,%3}, {%4,%5,%6,%7}, {%8,%9}, {%0,%1,%2,%3};"
        : "+f"(c[0]), "+f"(c[1]), "+f"(c[2]), "+f"(c[3])
        : "r"(a0), "r"(a1), "r"(a2), "r"(a3), "r"(b0), "r"(b1));
}

__device__ __forceinline__ void mma_f16(float c[4],
    uint32_t a0, uint32_t a1, uint32_t a2, uint32_t a3,
    uint32_t b0, uint32_t b1)
{
    asm("mma.sync.aligned.m16n8k16.row.col.f32.f16.f16.f32 "
        "{%0,%1,%2,%3}, {%4,%5,%6,%7}, {%8,%9}, {%0,%1,%2,%3};"
        : "+f"(c[0]), "+f"(c[1]), "+f"(c[2]), "+f"(c[3])
        : "r"(a0), "r"(a1), "r"(a2), "r"(a3), "r"(b0), "r"(b1));
}

__device__ __forceinline__ void split1(float v, __nv_bfloat16& h, __nv_bfloat16& l) {
    __nv_bfloat16 hb = __float2bfloat16_rn(v);
    h = hb;
    l = __float2bfloat16_rn(v - __bfloat162float(hb));
}

// ----------------------------------------------------------------------------
// Fused multi-segment weight split
// ----------------------------------------------------------------------------
struct SplitJobs {
    const float* src[7];
    long cum[8];
};

__global__ void __launch_bounds__(256) multi_split_kernel(
    SplitJobs jobs, __nv_bfloat16* __restrict__ hi, __nv_bfloat16* __restrict__ lo)
{
    long total = jobs.cum[7];
    long i = blockIdx.x * 256L + threadIdx.x;
    long stride = (long)gridDim.x * 256;
    for (; i < total; i += stride) {
        int s = 0;
#pragma unroll
        for (int k = 1; k < 7; k++) if (i >= jobs.cum[k]) s = k;
        float v = jobs.src[s][i - jobs.cum[s]];
        __nv_bfloat16 h, l;
        split1(v, h, l);
        hi[i] = h; lo[i] = l;
    }
}

__global__ void __launch_bounds__(256) w2t_split_kernel(
    const float* __restrict__ l2w,
    __nv_bfloat16* __restrict__ hi, __nv_bfloat16* __restrict__ lo)
{
    long n = (long)NLAYERS * NH * D * HD;
    long i = blockIdx.x * 256L + threadIdx.x;
    long stride = (long)gridDim.x * 256;
    for (; i < n; i += stride) {
        int k = (int)(i & 63);
        long t = i >> 6;
        int nn = (int)(t % D);
        long t2 = t / D;
        int h = (int)(t2 % NH);
        int l = (int)(t2 / NH);
        float v = l2w[((long)l * D + h * HD + k) * D + nn];
        __nv_bfloat16 hh, ll;
        split1(v, hh, ll);
        hi[i] = hh; lo[i] = ll;
    }
}

__global__ void __launch_bounds__(256) convnorm_kernel(
    const float* __restrict__ m, __half* __restrict__ mf,
    float* __restrict__ minv)
{
    int row = blockIdx.x, tid = threadIdx.x;
    float s = 0.f;
#pragma unroll
    for (int i = 0; i < 3; i++) {
        long o = (long)row * D + tid + i * 256;
        float v = m[o];
        mf[o] = __float2half_rn(v);
        s += v * v;
    }
    __shared__ float rs[256];
    rs[tid] = s; __syncthreads();
    for (int o = 128; o > 0; o >>= 1) {
        if (tid < o) rs[tid] += rs[tid + o];
        __syncthreads();
    }
    if (tid == 0) minv[row] = rsqrtf(rs[0]);
}

__global__ void __launch_bounds__(256) split_affine_kernel(
    const float* __restrict__ src, const float* __restrict__ scale,
    const float* __restrict__ shift,
    __nv_bfloat16* __restrict__ hi, __nv_bfloat16* __restrict__ lo, long n)
{
    long i = blockIdx.x * 256L + threadIdx.x;
    long stride = (long)gridDim.x * 256;
    for (; i < n; i += stride) {
        int k = (int)(i % D);
        __nv_bfloat16 h, l;
        split1(src[i] * scale[k] + shift[k], h, l);
        hi[i] = h; lo[i] = l;
    }
}

// ----------------------------------------------------------------------------
// bf16x3 tensor-core GEMM (unchanged)
// ----------------------------------------------------------------------------
template<int BN, int EPI>
__global__ void __launch_bounds__(256) hgemm_kernel(
    const __nv_bfloat16* __restrict__ Ah, const __nv_bfloat16* __restrict__ Al,
    const __nv_bfloat16* __restrict__ Bh, const __nv_bfloat16* __restrict__ Bl,
    const float* __restrict__ bias,
    float* __restrict__ C,
    __nv_bfloat16* __restrict__ Chi, __nv_bfloat16* __restrict__ Clo,
    int M, int N, int K, int ldA, int ldB, int ldC,
    long zA, long zB, long zC, long zBias)
{
    constexpr int BM = 128;
    constexpr int NT = BN / 32;
    constexpr int ROWS = BM + BN;
    extern __shared__ __align__(16) __nv_bfloat16 smem[];

    const int bz = blockIdx.z;
    Ah += bz * zA; Al += bz * zA;
    Bh += bz * zB; Bl += bz * zB;
    if (bias) bias += bz * zBias;
    C  += bz * zC;
    if (EPI == 1 || EPI == 3) { Chi += bz * zC; Clo += bz * zC; }

    const int tid  = threadIdx.x;
    const int wid  = tid >> 5;
    const int lane = tid & 31;
    const int wm   = wid & 1;
    const int wn   = wid >> 1;
    const int qm   = lane >> 2;
    const int qk   = lane & 3;
    const int bm = blockIdx.y * BM;
    const int bn = blockIdx.x * BN;
    const uint32_t sbase = smem_u32(smem);

    float acc[4][NT][4];
#pragma unroll
    for (int mt = 0; mt < 4; mt++)
#pragma unroll
        for (int nt = 0; nt < NT; nt++)
#pragma unroll
            for (int r = 0; r < 4; r++) acc[mt][nt][r] = 0.f;

    auto loadStage = [&](int s, int k0) {
        const uint32_t pH = sbase + (uint32_t)(s * 2 + 0) * ROWS * 80;
        const uint32_t pL = sbase + (uint32_t)(s * 2 + 1) * ROWS * 80;
#pragma unroll
        for (int c = tid; c < BM * 4; c += 256) {
            int row = c >> 2, kc = c & 3;
            long gofs = (long)(bm + row) * ldA + k0;
            CP_ASYNC16(pH + row * 80 + kc * 16, (const char*)(Ah + gofs) + kc * 16);
            CP_ASYNC16(pL + row * 80 + kc * 16, (const char*)(Al + gofs) + kc * 16);
        }
#pragma unroll
        for (int c = tid; c < BN * 4; c += 256) {
            int row = c >> 2, kc = c & 3;
            int n = bn + row;
            uint32_t dh = pH + (BM + row) * 80 + kc * 16;
            uint32_t dl = pL + (BM + row) * 80 + kc * 16;
            if (n < N) {
                long gofs = (long)n * ldB + k0;
                CP_ASYNC16(dh, (const char*)(Bh + gofs) + kc * 16);
                CP_ASYNC16(dl, (const char*)(Bl + gofs) + kc * 16);
            } else {
                uint32_t z = 0;
                asm volatile("st.shared.v4.b32 [%0], {%1,%1,%1,%1};" :: "r"(dh), "r"(z) : "memory");
                asm volatile("st.shared.v4.b32 [%0], {%1,%1,%1,%1};" :: "r"(dl), "r"(z) : "memory");
            }
        }
    };

    auto compute = [&](int s) {
        const uint32_t baseH = sbase + (uint32_t)(s * 2 + 0) * ROWS * 80;
        const uint32_t baseL = sbase + (uint32_t)(s * 2 + 1) * ROWS * 80;
#pragma unroll
        for (int kc = 0; kc < 2; kc++) {
            uint32_t ah[4][4], al[4][4], bh[NT][2], bl[NT][2];
            const int arow = wm * 64 + (lane & 15);
            const uint32_t acol = kc * 32 + ((lane & 16) ? 16 : 0);
#pragma unroll
            for (int mt = 0; mt < 4; mt++) {
                uint32_t ro = (uint32_t)(arow + mt * 16) * 80 + acol;
                ldsm_x4(ah[mt][0], ah[mt][1], ah[mt][2], ah[mt][3], baseH + ro);
                ldsm_x4(al[mt][0], al[mt][1], al[mt][2], al[mt][3], baseL + ro);
            }
            const int brow = BM + wn * (BN / 4) + (lane & 7) + ((lane & 16) ? 8 : 0);
            const uint32_t bcol = kc * 32 + ((lane & 8) ? 16 : 0);
#pragma unroll
            for (int np = 0; np < NT / 2; np++) {
                uint32_t ro = (uint32_t)(brow + np * 16) * 80 + bcol;
                ldsm_x4(bh[2*np][0], bh[2*np][1], bh[2*np+1][0], bh[2*np+1][1], baseH + ro);
                ldsm_x4(bl[2*np][0], bl[2*np][1], bl[2*np+1][0], bl[2*np+1][1], baseL + ro);
            }
#pragma unroll
            for (int mt = 0; mt < 4; mt++)
#pragma unroll
                for (int nt = 0; nt < NT; nt++) {
                    mma_bf16(acc[mt][nt], ah[mt][0], ah[mt][1], ah[mt][2], ah[mt][3],
                             bh[nt][0], bh[nt][1]);
                    mma_bf16(acc[mt][nt], ah[mt][0], ah[mt][1], ah[mt][2], ah[mt][3],
                             bl[nt][0], bl[nt][1]);
                    mma_bf16(acc[mt][nt], al[mt][0], al[mt][1], al[mt][2], al[mt][3],
                             bh[nt][0], bh[nt][1]);
                }
        }
    };

    const int niter = K >> 5;
    loadStage(0, 0); CP_COMMIT();
    for (int i = 0; i < niter; i++) {
        if (i + 1 < niter) { loadStage((i + 1) & 1, (i + 1) << 5); CP_COMMIT(); CP_WAIT(1); }
        else               { CP_WAIT(0); }
        __syncthreads();
        compute(i & 1);
        __syncthreads();
    }

#pragma unroll
    for (int mt = 0; mt < 4; mt++) {
        int r0 = bm + wm * 64 + mt * 16 + qm;
#pragma unroll
        for (int nt = 0; nt < NT; nt++) {
            int c0 = bn + wn * (BN / 4) + nt * 8 + qk * 2;
            float v0 = acc[mt][nt][0], v1 = acc[mt][nt][1];
            float v2 = acc[mt][nt][2], v3 = acc[mt][nt][3];
            if (bias) {
                float b0 = (c0 < N) ? bias[c0] : 0.f;
                float b1 = (c0 + 1 < N) ? bias[c0 + 1] : 0.f;
                v0 += b0; v1 += b1; v2 += b0; v3 += b1;
            }
            if (EPI == 1) {
                v0 = 0.5f * v0 * (1.f + erff(v0 * 0.70710678118654752f));
                v1 = 0.5f * v1 * (1.f + erff(v1 * 0.70710678118654752f));
                v2 = 0.5f * v2 * (1.f + erff(v2 * 0.70710678118654752f));
                v3 = 0.5f * v3 * (1.f + erff(v3 * 0.70710678118654752f));
            }
            if (EPI == 1 || EPI == 3) {
                __nv_bfloat162 h2, l2;
                split1(v0, h2.x, l2.x); split1(v1, h2.y, l2.y);
                *(__nv_bfloat162*)(Chi + (long)r0 * ldC + c0) = h2;
                *(__nv_bfloat162*)(Clo + (long)r0 * ldC + c0) = l2;
                split1(v2, h2.x, l2.x); split1(v3, h2.y, l2.y);
                *(__nv_bfloat162*)(Chi + (long)(r0 + 8) * ldC + c0) = h2;
                *(__nv_bfloat162*)(Clo + (long)(r0 + 8) * ldC + c0) = l2;
            }
            if (EPI == 0 || EPI == 3) {
                if (c0 < N) {
                    C[(long)r0 * ldC + c0] = v0;
                    C[(long)(r0 + 8) * ldC + c0] = v2;
                }
                if (c0 + 1 < N) {
                    C[(long)r0 * ldC + c0 + 1] = v1;
                    C[(long)(r0 + 8) * ldC + c0 + 1] = v3;
                }
            }
        }
    }
}

// ----------------------------------------------------------------------------
// Single-pass fp16 tensor-core GEMM (coarse sims only) — unchanged
// ----------------------------------------------------------------------------
__global__ void __launch_bounds__(256) fgemm_kernel(
    const __half* __restrict__ A, const __half* __restrict__ B,
    float* __restrict__ C,
    int M, int N, int K, long zA, long zB, long zC)
{
    constexpr int BM = 128, BN = 128, NT = 4, ROWS = BM + BN;
    extern __shared__ __align__(16) __half fsmem[];

    const int bz = blockIdx.z;
    A += bz * zA; B += bz * zB; C += bz * zC;

    const int tid  = threadIdx.x;
    const int wid  = tid >> 5;
    const int lane = tid & 31;
    const int wm   = wid & 1;
    const int wn   = wid >> 1;
    const int qm   = lane >> 2;
    const int qk   = lane & 3;
    const int bm = blockIdx.y * BM;
    const int bn = blockIdx.x * BN;
    const uint32_t sbase = smem_u32(fsmem);

    float acc[4][NT][4];
#pragma unroll
    for (int mt = 0; mt < 4; mt++)
#pragma unroll
        for (int nt = 0; nt < NT; nt++)
#pragma unroll
            for (int r = 0; r < 4; r++) acc[mt][nt][r] = 0.f;

    auto loadStage = [&](int s, int k0) {
        const uint32_t p = sbase + (uint32_t)s * ROWS * 80;
#pragma unroll
        for (int c = tid; c < BM * 4; c += 256) {
            int row = c >> 2, kc = c & 3;
            long gofs = (long)(bm + row) * K + k0;
            CP_ASYNC16(p + row * 80 + kc * 16, (const char*)(A + gofs) + kc * 16);
        }
#pragma unroll
        for (int c = tid; c < BN * 4; c += 256) {
            int row = c >> 2, kc = c & 3;
            long gofs = (long)(bn + row) * K + k0;
            CP_ASYNC16(p + (BM + row) * 80 + kc * 16, (const char*)(B + gofs) + kc * 16);
        }
    };

    auto compute = [&](int s) {
        const uint32_t base = sbase + (uint32_t)s * ROWS * 80;
#pragma unroll
        for (int kc = 0; kc < 2; kc++) {
            uint32_t a[4][4], b[NT][2];
            const int arow = wm * 64 + (lane & 15);
            const uint32_t acol = kc * 32 + ((lane & 16) ? 16 : 0);
#pragma unroll
            for (int mt = 0; mt < 4; mt++) {
                uint32_t ro = (uint32_t)(arow + mt * 16) * 80 + acol;
                ldsm_x4(a[mt][0], a[mt][1], a[mt][2], a[mt][3], base + ro);
            }
            const int brow = BM + wn * 32 + (lane & 7) + ((lane & 16) ? 8 : 0);
            const uint32_t bcol = kc * 32 + ((lane & 8) ? 16 : 0);
#pragma unroll
            for (int np = 0; np < NT / 2; np++) {
                uint32_t ro = (uint32_t)(brow + np * 16) * 80 + bcol;
                ldsm_x4(b[2*np][0], b[2*np][1], b[2*np+1][0], b[2*np+1][1], base + ro);
            }
#pragma unroll
            for (int mt = 0; mt < 4; mt++)
#pragma unroll
                for (int nt = 0; nt < NT; nt++)
                    mma_f16(acc[mt][nt], a[mt][0], a[mt][1], a[mt][2], a[mt][3],
                            b[nt][0], b[nt][1]);
        }
    };

    const int niter = K >> 5;
    loadStage(0, 0); CP_COMMIT();
    for (int i = 0; i < niter; i++) {
        if (i + 1 < niter) { loadStage((i + 1) & 1, (i + 1) << 5); CP_COMMIT(); CP_WAIT(1); }
        else               { CP_WAIT(0); }
        __syncthreads();
        compute(i & 1);
        __syncthreads();
    }

#pragma unroll
    for (int mt = 0; mt < 4; mt++) {
        int r0 = bm + wm * 64 + mt * 16 + qm;
#pragma unroll
        for (int nt = 0; nt < NT; nt++) {
            int c0 = bn + wn * 32 + nt * 8 + qk * 2;
            C[(long)r0 * N + c0]           = acc[mt][nt][0];
            C[(long)r0 * N + c0 + 1]       = acc[mt][nt][1];
            C[(long)(r0 + 8) * N + c0]     = acc[mt][nt][2];
            C[(long)(r0 + 8) * N + c0 + 1] = acc[mt][nt][3];
        }
    }
}

// ----------------------------------------------------------------------------
// LayerNorm + fused splits (aux outputs optional)
// ----------------------------------------------------------------------------
__global__ void __launch_bounds__(256) ln_kernel(
    const float* __restrict__ x, const float* __restrict__ add,
    const float* __restrict__ g, const float* __restrict__ b,
    const float* __restrict__ qpos,
    float* __restrict__ out,
    __nv_bfloat16* __restrict__ ohi, __nv_bfloat16* __restrict__ olo,
    __nv_bfloat16* __restrict__ oqhi, __nv_bfloat16* __restrict__ oqlo,
    __half* __restrict__ oxf16)
{
    int row = blockIdx.x, tid = threadIdx.x;
    const float* xr = x + (long)row * D;
    float vals[3];
    float s = 0.f, sq = 0.f;
#pragma unroll
    for (int i = 0; i < 3; i++) {
        int c = tid + i * 256;
        float v = xr[c];
        if (add) v += add[(long)row * D + c];
        vals[i] = v; s += v; sq += v * v;
    }
    __shared__ float rs[256], rq[256];
    rs[tid] = s; rq[tid] = sq;
    __syncthreads();
    for (int o = 128; o > 0; o >>= 1) {
        if (tid < o) { rs[tid] += rs[tid + o]; rq[tid] += rq[tid + o]; }
        __syncthreads();
    }
    float mu = rs[0] * (1.f / D);
    float var = rq[0] * (1.f / D) - mu * mu;
    float rstd = rsqrtf(var + EPS);
#pragma unroll
    for (int i = 0; i < 3; i++) {
        int c = tid + i * 256;
        long o = (long)row * D + c;
        float v = (vals[i] - mu) * rstd * g[c] + b[c];
        out[o] = v;
        if (oxf16) oxf16[o] = __float2half_rn(v);
        __nv_bfloat16 h, l;
        if (ohi) {
            split1(v, h, l);
            ohi[o] = h; olo[o] = l;
        }
        if (oqhi) {
            split1(v + qpos[o], h, l);
            oqhi[o] = h; oqlo[o] = l;
        }
    }
}

// ----------------------------------------------------------------------------
// Top-32 via histogram threshold (unchanged)
// ----------------------------------------------------------------------------
__global__ void __launch_bounds__(256) topk_kernel(
    const float* __restrict__ sims, const float* __restrict__ minv,
    const float* __restrict__ x, const float* __restrict__ memory,
    int* __restrict__ idx_out)
{
    int row = blockIdx.x;
    int b = row >> 7;
    int tid = threadIdx.x;
    int warp = tid >> 5, lane = tid & 31;

    __shared__ float s[MNP];
    __shared__ float xrow[D];
    __shared__ int   hist[1024];
    __shared__ int   pcount[256];
    __shared__ int   cnt;
    __shared__ uint32_t s_tu;
    __shared__ int   cand[1024];
    __shared__ float cval[1024];

    for (int i = tid; i < MNP; i += 256)
        s[i] = sims[(long)row * MNP + i] * minv[b * MNP + i];
    for (int c = tid; c < D; c += 256)
        xrow[c] = x[(long)row * D + c];
    for (int i = tid; i < 1024; i += 256) hist[i] = 0;
    if (tid == 0) cnt = 0;
    __syncthreads();

    auto mapu = [](float f) -> uint32_t {
        uint32_t u = __float_as_uint(f);
        return (u & 0x80000000u) ? ~u : (u | 0x80000000u);
    };

    for (int i = tid; i < MNP; i += 256)
        atomicAdd(&hist[mapu(s[i]) >> 22], 1);
    __syncthreads();

    int local = hist[tid*4] + hist[tid*4+1] + hist[tid*4+2] + hist[tid*4+3];
    pcount[tid] = local;
    __syncthreads();
    for (int off = 1; off < 256; off <<= 1) {
        int v = (tid + off < 256) ? pcount[tid + off] : 0;
        __syncthreads();
        pcount[tid] += v;
        __syncthreads();
    }
    {
        int c0 = pcount[tid];
        int c1 = (tid + 1 < 256) ? pcount[tid + 1] : 0;
        if (c0 >= COVER && c1 < COVER) {
            int acc = c1;
            int chosen = tid * 4;
            for (int k = 3; k >= 0; k--) {
                acc += hist[tid*4 + k];
                if (acc >= COVER) { chosen = tid*4 + k; break; }
            }
            s_tu = (uint32_t)chosen << 22;
        }
    }
    __syncthreads();
    uint32_t tu = s_tu;

    for (int i = tid; i < MNP; i += 256) {
        if (mapu(s[i]) >= tu) {
            int p = atomicAdd(&cnt, 1);
            if (p < 1024) cand[p] = i;
        }
    }
    __syncthreads();
    int n = cnt < 1024 ? cnt : 1024;

    for (int j = warp; j < n; j += 8) {
        int ix = cand[j];
        const float* mr = memory + ((long)(b * MNP + ix)) * D;
        float acc = 0.f;
        for (int c = lane; c < D; c += 32) acc = fmaf(xrow[c], mr[c], acc);
#pragma unroll
        for (int o = 16; o > 0; o >>= 1) acc += __shfl_xor_sync(0xffffffffu, acc, o);
        if (lane == 0) cval[j] = acc * minv[b * MNP + ix];
    }
    __syncthreads();

    if (warp == 0) {
        for (int t = 0; t < TOPK; t++) {
            float v = -INFINITY; int myi = 0x7fffffff, myj = -1;
            for (int j = lane; j < n; j += 32) {
                float cv = cval[j];
                if (cv > v || (cv == v && cand[j] < myi)) { v = cv; myi = cand[j]; myj = j; }
            }
#pragma unroll
            for (int o = 16; o > 0; o >>= 1) {
                float ov = __shfl_xor_sync(0xffffffffu, v, o);
                int   oi = __shfl_xor_sync(0xffffffffu, myi, o);
                int   oj = __shfl_xor_sync(0xffffffffu, myj, o);
                if (ov > v || (ov == v && oi < myi)) { v = ov; myi = oi; myj = oj; }
            }
            if (lane == 0) {
                idx_out[row * TOPK + t] = myi;
                cval[myj] = -INFINITY;
            }
            __syncwarp();
        }
    }
}

// ----------------------------------------------------------------------------
// Fused cross-attention, single-pass online softmax (unchanged)
// ----------------------------------------------------------------------------
__global__ void __launch_bounds__(128) xattn_kernel(
    const float* __restrict__ qf,
    const float* __restrict__ Z,
    const float* __restrict__ memory,
    const float* __restrict__ kpos,
    const float* __restrict__ l2b,
    const int*   __restrict__ idx,
    __nv_bfloat16* __restrict__ agghi,
    __nv_bfloat16* __restrict__ agglo)
{
    __shared__ __align__(16) float mrow[2][D];
    __shared__ __align__(16) float krow[2][D];
    __shared__ float qrow[D];
    __shared__ float qb[NH];
    __shared__ int   ids[TOPK];

    const int qi = blockIdx.x;
    const int b = qi >> 7;
    const int tid = threadIdx.x;
    const int warp = tid >> 5, lane = tid & 31;
    const int h0 = warp * 3;
    const uint32_t mbase = smem_u32(mrow);
    const uint32_t kbase = smem_u32(krow);

    for (int k = 0; k < 6; k++)
        qrow[tid + 128 * k] = qf[(long)qi * D + tid + 128 * k];
    if (tid < TOPK) ids[tid] = idx[qi * TOPK + tid];
    __syncthreads();

#pragma unroll
    for (int t = 0; t < 3; t++) {
        int h = h0 + t;
        float s = qrow[h * HD + lane] * l2b[h * HD + lane]
                + qrow[h * HD + 32 + lane] * l2b[h * HD + 32 + lane];
#pragma unroll
        for (int o = 16; o > 0; o >>= 1) s += __shfl_xor_sync(0xffffffffu, s, o);
        qb[h] = s;
    }

    float zreg[3][24];
#pragma unroll
    for (int t = 0; t < 3; t++) {
        const float* zp = Z + ((long)(h0 + t) * NTOK + qi) * D;
#pragma unroll
        for (int i = 0; i < 24; i++) zreg[t][i] = zp[lane + 32 * i];
    }

    float mx[3], ssum[3], A[3][24];
#pragma unroll
    for (int t = 0; t < 3; t++) {
        mx[t] = -INFINITY; ssum[t] = 0.f;
#pragma unroll
        for (int i = 0; i < 24; i++) A[t][i] = 0.f;
    }

    auto fetch_mk = [&](int buf, int j) {
        long base = ((long)(b * MNP + ids[j])) * D;
        for (int c = tid; c < 192; c += 128) {
            CP_ASYNC16(mbase + (uint32_t)(buf * D + c * 4) * 4, (const char*)(memory + base) + c * 16);
            CP_ASYNC16(kbase + (uint32_t)(buf * D + c * 4) * 4, (const char*)(kpos + base) + c * 16);
        }
    };

    fetch_mk(0, 0); CP_COMMIT();
    for (int j = 0; j < TOPK; j++) {
        int buf = j & 1;
        if (j + 1 < TOPK) { fetch_mk(buf ^ 1, j + 1); CP_COMMIT(); CP_WAIT(1); }
        else              { CP_WAIT(0); }
        __syncthreads();
#pragma unroll
        for (int t = 0; t < 3; t++) {
            float s = 0.f;
#pragma unroll
            for (int i = 0; i < 24; i++)
                s = fmaf(zreg[t][i], mrow[buf][lane + 32 * i] + krow[buf][lane + 32 * i], s);
#pragma unroll
            for (int o = 16; o > 0; o >>= 1) s += __shfl_xor_sync(0xffffffffu, s, o);
            s = (s + qb[h0 + t]) * 0.125f;
            float mn = fmaxf(mx[t], s);
            float scale = expf(mx[t] - mn);
            float e = expf(s - mn);
            ssum[t] = ssum[t] * scale + e;
#pragma unroll
            for (int i = 0; i < 24; i++)
                A[t][i] = fmaf(e, mrow[buf][lane + 32 * i], A[t][i] * scale);
            mx[t] = mn;
        }
        __syncthreads();
    }

#pragma unroll
    for (int t = 0; t < 3; t++) {
        float inv = 1.f / ssum[t];
        long o0 = ((long)(h0 + t) * NTOK + qi) * D;
#pragma unroll
        for (int i = 0; i < 24; i++) {
            __nv_bfloat16 h, l;
            split1(A[t][i] * inv, h, l);
            agghi[o0 + lane + 32 * i] = h;
            agglo[o0 + lane + 32 * i] = l;
        }
    }
}

// ----------------------------------------------------------------------------
// Self-attention: block per (batch, head) — unchanged
// ----------------------------------------------------------------------------
#define SA_SMEM ((128*64 + 128*65 + 128*65 + 4*128) * 4)

__global__ void __launch_bounds__(128) self_attn_kernel(
    const float* __restrict__ qk, const float* __restrict__ v,
    __nv_bfloat16* __restrict__ ohi, __nv_bfloat16* __restrict__ olo)
{
    extern __shared__ float ssm[];
    float* Qs = ssm;
    float* Ks = Qs + 128 * 64;
    float* Vs = Ks + 128 * 65;
    float* Ps = Vs + 128 * 65;

    const int bh = blockIdx.x;
    const int b = bh / NH, h = bh % NH;
    const int tid = threadIdx.x;
    const int warp = tid >> 5, lane = tid & 31;

    for (int i = tid; i < 128 * 16; i += 128) {
        int r = i >> 4, c4 = (i & 15) << 2;
        long tok = (long)(b * NP + r);
        float4 qv = *(const float4*)&qk[tok * 2 * D + h * HD + c4];
        float4 kv = *(const float4*)&qk[tok * 2 * D + D + h * HD + c4];
        float4 vv = *(const float4*)&v[tok * D + h * HD + c4];
        *(float4*)&Qs[r * 64 + c4] = qv;
        Ks[r * 65 + c4 + 0] = kv.x; Ks[r * 65 + c4 + 1] = kv.y;
        Ks[r * 65 + c4 + 2] = kv.z; Ks[r * 65 + c4 + 3] = kv.w;
        Vs[r * 65 + c4 + 0] = vv.x; Vs[r * 65 + c4 + 1] = vv.y;
        Vs[r * 65 + c4 + 2] = vv.z; Vs[r * 65 + c4 + 3] = vv.w;
    }
    __syncthreads();

    for (int qq = 0; qq < 32; qq++) {
        int qi = warp * 32 + qq;
        const float* qrow = &Qs[qi * 64];
        float s[4];
#pragma unroll
        for (int kk = 0; kk < 4; kk++) {
            int k = lane + kk * 32;
            const float* krow = &Ks[k * 65];
            float acc = 0.f;
#pragma unroll
            for (int d = 0; d < HD; d++) acc = fmaf(qrow[d], krow[d], acc);
            s[kk] = acc * 0.125f;
        }
        float m = fmaxf(fmaxf(s[0], s[1]), fmaxf(s[2], s[3]));
#pragma unroll
        for (int o = 16; o > 0; o >>= 1) m = fmaxf(m, __shfl_xor_sync(0xffffffffu, m, o));
        float e[4], sum = 0.f;
#pragma unroll
        for (int kk = 0; kk < 4; kk++) { e[kk] = expf(s[kk] - m); sum += e[kk]; }
#pragma unroll
        for (int o = 16; o > 0; o >>= 1) sum += __shfl_xor_sync(0xffffffffu, sum, o);
        float inv = 1.f / sum;
#pragma unroll
        for (int kk = 0; kk < 4; kk++) Ps[warp * 128 + lane + kk * 32] = e[kk] * inv;
        __syncwarp();

        float a0 = 0.f, a1 = 0.f;
#pragma unroll 8
        for (int k = 0; k < 128; k++) {
            float p = Ps[warp * 128 + k];
            a0 = fmaf(p, Vs[k * 65 + lane], a0);
            a1 = fmaf(p, Vs[k * 65 + lane + 32], a1);
        }
        long o = (long)(b * NP + qi) * D + h * HD + lane;
        __nv_bfloat16 hh, ll;
        split1(a0, hh, ll);
        ohi[o] = hh; olo[o] = ll;
        split1(a1, hh, ll);
        ohi[o + 32] = hh; olo[o + 32] = ll;
        __syncwarp();
    }
}

// ----------------------------------------------------------------------------
// BatchNorm stats (unchanged)
// ----------------------------------------------------------------------------
__global__ void __launch_bounds__(256) bn_stats_kernel(
    const float* __restrict__ x, const float* __restrict__ g,
    const float* __restrict__ b, float* __restrict__ scale,
    float* __restrict__ shift)
{
    int f = blockIdx.x, tid = threadIdx.x;
    float s = 0.f, sq = 0.f;
    for (int r = tid; r < NTOK; r += 256) {
        float v = x[(long)r * D + f];
        s += v; sq += v * v;
    }
    __shared__ float rs[256], rq[256];
    rs[tid] = s; rq[tid] = sq;
    __syncthreads();
    for (int o = 128; o > 0; o >>= 1) {
        if (tid < o) { rs[tid] += rs[tid + o]; rq[tid] += rq[tid + o]; }
        __syncthreads();
    }
    if (tid == 0) {
        float mu = rs[0] * (1.f / NTOK);
        float var = rq[0] * (1.f / NTOK) - mu * mu;
        float rstd = rsqrtf(var + EPS);
        float sc = rstd * g[f];
        scale[f] = sc;
        shift[f] = b[f] - mu * sc;
    }
}

// ----------------------------------------------------------------------------
// Host orchestration — two-stream overlap (capture-safe event fork/join)
// ----------------------------------------------------------------------------
#define SMEM128 (2 * 2 * 256 * 80)
#define SMEM64  (2 * 2 * 192 * 80)
#define SMEMF   (2 * 256 * 80)

extern "C" void kernel_launch(void* const* d_in, const int* in_sizes, int n_in,
                              void* d_out, int out_size)
{
    const float* tgt      = (const float*)d_in[0];
    const float* memory   = (const float*)d_in[1];
    const float* qpos     = (const float*)d_in[2];
    const float* kpos     = (const float*)d_in[3];
    const float* norm0_g  = (const float*)d_in[4];
    const float* norm0_b  = (const float*)d_in[5];
    const float* l1_w     = (const float*)d_in[6];
    const float* l1_b     = (const float*)d_in[7];
    const float* l2_w     = (const float*)d_in[8];
    const float* l2_b     = (const float*)d_in[9];
    const float* l3_w     = (const float*)d_in[10];
    const float* l3_b     = (const float*)d_in[11];
    const float* n1_g     = (const float*)d_in[12];
    const float* n1_b     = (const float*)d_in[13];
    const float* n2_g     = (const float*)d_in[14];
    const float* n2_b     = (const float*)d_in[15];
    const float* n3_g     = (const float*)d_in[16];
    const float* n3_b     = (const float*)d_in[17];
    const float* sa_in_w  = (const float*)d_in[18];
    const float* sa_in_b  = (const float*)d_in[19];
    const float* sa_out_w = (const float*)d_in[20];
    const float* sa_out_b = (const float*)d_in[21];
    const float* ff1_w    = (const float*)d_in[22];
    const float* ff1_b    = (const float*)d_in[23];
    const float* ff2_w    = (const float*)d_in[24];
    const float* ff2_b    = (const float*)d_in[25];
    const float* bn_g     = (const float*)d_in[26];
    const float* bn_b     = (const float*)d_in[27];
    const float* cls_w    = (const float*)d_in[28];

    float *x, *tmp, *q, *qk, *v, *attn, *Z, *sims, *minv, *bnsc, *bnsh;
    int* idx;
    __nv_bfloat16 *whi, *wlo, *w2th, *w2tl;
    __nv_bfloat16 *xhi, *xlo, *xqhi, *xqlo, *qhi, *qlo, *agghi, *agglo;
    __nv_bfloat16 *h1hi, *h1lo, *sahi, *salo, *cihi, *cilo;
    __half *mf16, *xf16;
    cudaGetSymbolAddress((void**)&x,    g_x);
    cudaGetSymbolAddress((void**)&tmp,  g_tmp);
    cudaGetSymbolAddress((void**)&q,    g_q);
    cudaGetSymbolAddress((void**)&qk,   g_qk);
    cudaGetSymbolAddress((void**)&v,    g_v);
    cudaGetSymbolAddress((void**)&attn, g_attn);
    cudaGetSymbolAddress((void**)&Z,    g_Z);
    cudaGetSymbolAddress((void**)&sims, g_sims);
    cudaGetSymbolAddress((void**)&idx,  g_idx);
    cudaGetSymbolAddress((void**)&minv, g_minv);
    cudaGetSymbolAddress((void**)&bnsc, g_bnscale);
    cudaGetSymbolAddress((void**)&bnsh, g_bnshift);
    cudaGetSymbolAddress((void**)&whi,  g_whi);
    cudaGetSymbolAddress((void**)&wlo,  g_wlo);
    cudaGetSymbolAddress((void**)&w2th, g_w2thi);
    cudaGetSymbolAddress((void**)&w2tl, g_w2tlo);
    cudaGetSymbolAddress((void**)&xhi,  g_xhi);
    cudaGetSymbolAddress((void**)&xlo,  g_xlo);
    cudaGetSymbolAddress((void**)&xqhi, g_xqhi);
    cudaGetSymbolAddress((void**)&xqlo, g_xqlo);
    cudaGetSymbolAddress((void**)&qhi,  g_qhi);
    cudaGetSymbolAddress((void**)&qlo,  g_qlo);
    cudaGetSymbolAddress((void**)&agghi, g_agghi);
    cudaGetSymbolAddress((void**)&agglo, g_agglo);
    cudaGetSymbolAddress((void**)&h1hi, g_h1hi);
    cudaGetSymbolAddress((void**)&h1lo, g_h1lo);
    cudaGetSymbolAddress((void**)&sahi, g_sahi);
    cudaGetSymbolAddress((void**)&salo, g_salo);
    cudaGetSymbolAddress((void**)&cihi, g_cihi);
    cudaGetSymbolAddress((void**)&cilo, g_cilo);
    cudaGetSymbolAddress((void**)&mf16, g_mf16);
    cudaGetSymbolAddress((void**)&xf16, g_xf16);

    cudaFuncSetAttribute(hgemm_kernel<128,0>, cudaFuncAttributeMaxDynamicSharedMemorySize, SMEM128);
    cudaFuncSetAttribute(hgemm_kernel<128,1>, cudaFuncAttributeMaxDynamicSharedMemorySize, SMEM128);
    cudaFuncSetAttribute(hgemm_kernel<64,0>,  cudaFuncAttributeMaxDynamicSharedMemorySize, SMEM64);
    cudaFuncSetAttribute(hgemm_kernel<64,3>,  cudaFuncAttributeMaxDynamicSharedMemorySize, SMEM64);
    cudaFuncSetAttribute(self_attn_kernel,    cudaFuncAttributeMaxDynamicSharedMemorySize, SA_SMEM);

    // Side stream + events: created once (first call is the non-captured
    // correctness run); reused by the capture call. No device memory involved.
    static cudaStream_t sB = (cudaStream_t)0;
    static cudaEvent_t  ev[12];
    static bool inited = false;
    if (!inited) {
        if (cudaStreamCreateWithFlags(&sB, cudaStreamNonBlocking) != cudaSuccess)
            sB = (cudaStream_t)0;   // fallback: everything serial on stream 0
        for (int i = 0; i < 12; i++)
            cudaEventCreateWithFlags(&ev[i], cudaEventDisableTiming);
        inited = true;
    }
    cudaStream_t s0 = (cudaStream_t)0;

    // ---- preprocessing: fork {w2t, convnorm} onto sB ----
    cudaEventRecord(ev[0], s0);
    cudaStreamWaitEvent(sB, ev[0], 0);

    {
        SplitJobs jobs;
        jobs.src[0] = l1_w;     jobs.cum[0] = OFF_L1;
        jobs.src[1] = l3_w;     jobs.cum[1] = OFF_L3;
        jobs.src[2] = sa_in_w;  jobs.cum[2] = OFF_SAIN;
        jobs.src[3] = sa_out_w; jobs.cum[3] = OFF_SAOUT;
        jobs.src[4] = ff1_w;    jobs.cum[4] = OFF_FF1;
        jobs.src[5] = ff2_w;    jobs.cum[5] = OFF_FF2;
        jobs.src[6] = cls_w;    jobs.cum[6] = OFF_CLS;
        jobs.cum[7] = WTOTAL;
        multi_split_kernel<<<8192, 256, 0, s0>>>(jobs, whi, wlo);
    }
    w2t_split_kernel<<<2048, 256, 0, sB>>>(l2_w, w2th, w2tl);
    convnorm_kernel<<<NMEM, 256, 0, sB>>>(memory, mf16, minv);
    cudaEventRecord(ev[1], sB);   // w2t + convnorm done

    ln_kernel<<<NTOK, 256, 0, s0>>>(tgt, nullptr, norm0_g, norm0_b, qpos,
                                    x, xhi, xlo, xqhi, xqlo, xf16);

    for (int l = 0; l < NLAYERS; l++) {
        long wdd = (long)l * D * D;
        const __nv_bfloat16* l1h = whi + OFF_L1 + wdd;   const __nv_bfloat16* l1l = wlo + OFF_L1 + wdd;
        const __nv_bfloat16* l3h = whi + OFF_L3 + wdd;   const __nv_bfloat16* l3l = wlo + OFF_L3 + wdd;
        const __nv_bfloat16* sih = whi + OFF_SAIN + (long)l*3*D*D;
        const __nv_bfloat16* sil = wlo + OFF_SAIN + (long)l*3*D*D;
        const __nv_bfloat16* soh = whi + OFF_SAOUT + wdd;
        const __nv_bfloat16* sol = wlo + OFF_SAOUT + wdd;
        const __nv_bfloat16* f1h = whi + OFF_FF1 + (long)l*DFF*D;
        const __nv_bfloat16* f1l = wlo + OFF_FF1 + (long)l*DFF*D;
        const __nv_bfloat16* f2h = whi + OFF_FF2 + (long)l*D*DFF;
        const __nv_bfloat16* f2l = wlo + OFF_FF2 + (long)l*D*DFF;
        const __nv_bfloat16* w2h = w2th + (long)l*NH*D*HD;
        const __nv_bfloat16* w2l = w2tl + (long)l*NH*D*HD;
        const float* l1bb = l1_b + (long)l * D;
        const float* l2bb = l2_b + (long)l * D;
        const float* l3bb = l3_b + (long)l * D;
        const float* sab  = sa_in_b + (long)l * 3 * D;
        const float* sob  = sa_out_b + (long)l * D;
        const float* f1b  = ff1_b + (long)l * DFF;
        const float* f2b  = ff2_b + (long)l * D;
        const bool last = (l == NLAYERS - 1);
        cudaEvent_t eA = ev[2 + l*4], eB = ev[3 + l*4], eC = ev[4 + l*4], eD = ev[5 + l*4];

        // fork: {sims, topk} on sB  ∥  {qproj, Z} on s0
        cudaEventRecord(eA, s0);             // x / xf16 / xq splits ready
        cudaStreamWaitEvent(sB, eA, 0);
        fgemm_kernel<<<dim3(MNP/128, 1, BS), 256, SMEMF, sB>>>(
            xf16, mf16, sims, NP, MNP, D,
            (long)NP*D, (long)MNP*D, (long)NP*MNP);
        topk_kernel<<<NTOK, 256, 0, sB>>>(sims, minv, x, memory, idx);
        cudaEventRecord(eB, sB);

        hgemm_kernel<64,3><<<dim3(D/64, NTOK/128, 1), 256, SMEM64, s0>>>(
            xqhi, xqlo, l1h, l1l, l1bb, q, qhi, qlo,
            NTOK, D, D, D, D, D, 0, 0, 0, 0);

        if (l == 0) cudaStreamWaitEvent(s0, ev[1], 0);   // w2t ready
        hgemm_kernel<128,0><<<dim3(D/128, NTOK/128, NH), 256, SMEM128, s0>>>(
            qhi, qlo, w2h, w2l, nullptr, Z, nullptr, nullptr,
            NTOK, D, HD, D, HD, D,
            (long)HD, (long)D*HD, (long)NTOK*D, 0);

        cudaStreamWaitEvent(s0, eB, 0);      // join: idx ready
        xattn_kernel<<<NTOK, 128, 0, s0>>>(q, Z, memory, kpos, l2bb, idx, agghi, agglo);

        hgemm_kernel<64,0><<<dim3(1, NTOK/128, NH), 256, SMEM64, s0>>>(
            agghi, agglo, l3h, l3l, l3bb, attn, nullptr, nullptr,
            NTOK, HD, D, D, D, D,
            (long)NTOK*D, (long)HD*D, (long)HD, (long)HD);

        ln_kernel<<<NTOK, 256, 0, s0>>>(x, attn, n1_g + (long)l * D, n1_b + (long)l * D,
                                        qpos, x, xhi, xlo, xqhi, xqlo, xf16);

        // fork: v projection on sB ∥ qk projection on s0
        cudaEventRecord(eC, s0);
        cudaStreamWaitEvent(sB, eC, 0);
        hgemm_kernel<64,0><<<dim3(D/64, NTOK/128, 1), 256, SMEM64, sB>>>(
            xhi, xlo, sih + (long)2*D*D, sil + (long)2*D*D, sab + 2*D,
            v, nullptr, nullptr, NTOK, D, D, D, D, D, 0, 0, 0, 0);
        cudaEventRecord(eD, sB);

        hgemm_kernel<128,0><<<dim3((2*D)/128, NTOK/128, 1), 256, SMEM128, s0>>>(
            xqhi, xqlo, sih, sil, sab, qk, nullptr, nullptr,
            NTOK, 2*D, D, D, D, 2*D, 0, 0, 0, 0);

        cudaStreamWaitEvent(s0, eD, 0);      // join: v ready
        self_attn_kernel<<<BS * NH, 128, SA_SMEM, s0>>>(qk, v, sahi, salo);

        hgemm_kernel<64,0><<<dim3(D/64, NTOK/128, 1), 256, SMEM64, s0>>>(
            sahi, salo, soh, sol, sob, tmp, nullptr, nullptr,
            NTOK, D, D, D, D, D, 0, 0, 0, 0);

        ln_kernel<<<NTOK, 256, 0, s0>>>(x, tmp, n2_g + (long)l * D, n2_b + (long)l * D,
                                        qpos, x, xhi, xlo, xqhi, xqlo, xf16);

        hgemm_kernel<128,1><<<dim3(DFF/128, NTOK/128, 1), 256, SMEM128, s0>>>(
            xhi, xlo, f1h, f1l, f1b, nullptr, h1hi, h1lo,
            NTOK, DFF, D, D, D, DFF, 0, 0, 0, 0);
        hgemm_kernel<64,0><<<dim3(D/64, NTOK/128, 1), 256, SMEM64, s0>>>(
            h1hi, h1lo, f2h, f2l, f2b, tmp, nullptr, nullptr,
            NTOK, D, DFF, DFF, DFF, D, 0, 0, 0, 0);

        ln_kernel<<<NTOK, 256, 0, s0>>>(x, tmp, n3_g + (long)l * D, n3_b + (long)l * D,
                                        qpos, x,
                                        last ? nullptr : xhi, last ? nullptr : xlo,
                                        last ? nullptr : xqhi, last ? nullptr : xqlo,
                                        last ? nullptr : xf16);
    }

    bn_stats_kernel<<<D, 256, 0, s0>>>(x, bn_g, bn_b, bnsc, bnsh);
    split_affine_kernel<<<2048, 256, 0, s0>>>(x, bnsc, bnsh, cihi, cilo, (long)NTOK * D);

    float* out = (float*)d_out;
    long xsz = (long)NTOK * D;
    long csz = (long)NTOK * NC;

    if ((long)out_size >= xsz + csz) {
        cudaMemcpyAsync(out, x, sizeof(float) * xsz, cudaMemcpyDeviceToDevice, s0);
        hgemm_kernel<64,0><<<dim3((NC+63)/64, NTOK/128, 1), 256, SMEM64, s0>>>(
            cihi, cilo, whi + OFF_CLS, wlo + OFF_CLS, nullptr,
            out + xsz, nullptr, nullptr, NTOK, NC, D, D, D, NC, 0, 0, 0, 0);
    } else if ((long)out_size == csz) {
        hgemm_kernel<64,0><<<dim3((NC+63)/64, NTOK/128, 1), 256, SMEM64, s0>>>(
            cihi, cilo, whi + OFF_CLS, wlo + OFF_CLS, nullptr,
            out, nullptr, nullptr, NTOK, NC, D, D, D, NC, 0, 0, 0, 0);
    } else {
        cudaMemcpyAsync(out, x, sizeof(float) * ((long)out_size < xsz ? out_size : xsz),
                        cudaMemcpyDeviceToDevice, s0);
    }
}

// round 17
// speedup vs baseline: 2.9744x; 1.0133x over previous
#include <cuda_runtime.h>
#include <cuda_bf16.h>
#include <cuda_fp16.h>
#include <math.h>
#include <stdint.h>

#define BS   16
#define NP   128
#define MNP  2048
#define D    768
#define NH   12
#define HD   64
#define DFF  2048
#define NLAYERS 2
#define TOPK 32
#define COVER 48
#define NC   751
#define NTOK (BS*NP)
#define NMEM (BS*MNP)
#define EPS  1e-5f

// ----------------------------------------------------------------------------
// Scratch
// ----------------------------------------------------------------------------
__device__ float g_x   [NTOK*(long)D];
__device__ float g_tmp [NTOK*(long)D];
__device__ float g_q   [NTOK*(long)D];
__device__ float g_qk  [NTOK*(long)(2*D)];
__device__ float g_v   [NTOK*(long)D];
__device__ float g_attn[NTOK*(long)D];
__device__ float g_Z   [(long)NH*NTOK*D];
__device__ float g_sims[NTOK*(long)MNP];
__device__ int   g_idx [NTOK*TOPK];
__device__ float g_minv[NMEM];
__device__ float g_bnscale[D];
__device__ float g_bnshift[D];

#define OFF_L1    0L
#define OFF_L3    1179648L
#define OFF_SAIN  2359296L
#define OFF_SAOUT 5898240L
#define OFF_FF1   7077888L
#define OFF_FF2   10223616L
#define OFF_CLS   13369344L
#define WTOTAL    13946112L
__device__ __nv_bfloat16 g_whi[WTOTAL], g_wlo[WTOTAL];
__device__ __nv_bfloat16 g_w2thi[(long)NLAYERS*NH*D*HD], g_w2tlo[(long)NLAYERS*NH*D*HD];
__device__ __nv_bfloat16 g_xhi [NTOK*(long)D], g_xlo [NTOK*(long)D];
__device__ __nv_bfloat16 g_xqhi[NTOK*(long)D], g_xqlo[NTOK*(long)D];
__device__ __nv_bfloat16 g_qhi [NTOK*(long)D], g_qlo [NTOK*(long)D];
__device__ __nv_bfloat16 g_agghi[(long)NH*NTOK*D], g_agglo[(long)NH*NTOK*D];
__device__ __nv_bfloat16 g_h1hi[NTOK*(long)DFF], g_h1lo[NTOK*(long)DFF];
__device__ __nv_bfloat16 g_sahi[NTOK*(long)D], g_salo[NTOK*(long)D];
__device__ __nv_bfloat16 g_cihi[NTOK*(long)D], g_cilo[NTOK*(long)D];

__device__ __half g_mf16 [NMEM*(long)D];
__device__ __half g_xf16 [NTOK*(long)D];

// ----------------------------------------------------------------------------
// Helpers
// ----------------------------------------------------------------------------
__device__ __forceinline__ uint32_t smem_u32(const void* p) {
    uint32_t a;
    asm("{ .reg .u64 t; cvta.to.shared.u64 t, %1; cvt.u32.u64 %0, t; }"
        : "=r"(a) : "l"(p));
    return a;
}

#define CP_ASYNC16(dst, src) \
    asm volatile("cp.async.ca.shared.global [%0], [%1], 16;" \
                 :: "r"(dst), "l"(src) : "memory")
#define CP_COMMIT() asm volatile("cp.async.commit_group;" ::: "memory")
#define CP_WAIT(n)  asm volatile("cp.async.wait_group %0;" :: "n"(n) : "memory")

__device__ __forceinline__ void ldsm_x4(uint32_t& r0, uint32_t& r1,
                                        uint32_t& r2, uint32_t& r3, uint32_t addr)
{
    asm volatile("ldmatrix.sync.aligned.m8n8.x4.shared.b16 {%0,%1,%2,%3}, [%4];"
        : "=r"(r0), "=r"(r1), "=r"(r2), "=r"(r3) : "r"(addr));
}

__device__ __forceinline__ void mma_bf16(float c[4],
    uint32_t a0, uint32_t a1, uint32_t a2, uint32_t a3,
    uint32_t b0, uint32_t b1)
{
    asm("mma.sync.aligned.m16n8k16.row.col.f32.bf16.bf16.f32 "
        "{%0,%1,%2,%3}, {%4,%5,%6,%7}, {%8,%9}, {%0,%1,%2,%3};"
        : "+f"(c[0]), "+f"(c[1]), "+f"(c[2]), "+f"(c[3])
        : "r"(a0), "r"(a1), "r"(a2), "r"(a3), "r"(b0), "r"(b1));
}

__device__ __forceinline__ void mma_f16(float c[4],
    uint32_t a0, uint32_t a1, uint32_t a2, uint32_t a3,
    uint32_t b0, uint32_t b1)
{
    asm("mma.sync.aligned.m16n8k16.row.col.f32.f16.f16.f32 "
        "{%0,%1,%2,%3}, {%4,%5,%6,%7}, {%8,%9}, {%0,%1,%2,%3};"
        : "+f"(c[0]), "+f"(c[1]), "+f"(c[2]), "+f"(c[3])
        : "r"(a0), "r"(a1), "r"(a2), "r"(a3), "r"(b0), "r"(b1));
}

__device__ __forceinline__ void split1(float v, __nv_bfloat16& h, __nv_bfloat16& l) {
    __nv_bfloat16 hb = __float2bfloat16_rn(v);
    h = hb;
    l = __float2bfloat16_rn(v - __bfloat162float(hb));
}

// pack two splits into bf162 pair
__device__ __forceinline__ void split2(float a, float b,
    __nv_bfloat162& hp, __nv_bfloat162& lp)
{
    split1(a, hp.x, lp.x);
    split1(b, hp.y, lp.y);
}

// ----------------------------------------------------------------------------
// Fused multi-segment weight split (pair-vectorized; all offsets even)
// ----------------------------------------------------------------------------
struct SplitJobs {
    const float* src[7];
    long cum[8];
};

__global__ void __launch_bounds__(256) multi_split_kernel(
    SplitJobs jobs, __nv_bfloat16* __restrict__ hi, __nv_bfloat16* __restrict__ lo)
{
    long totalp = jobs.cum[7] >> 1;
    long i = blockIdx.x * 256L + threadIdx.x;
    long stride = (long)gridDim.x * 256;
    __nv_bfloat162* hi2 = (__nv_bfloat162*)hi;
    __nv_bfloat162* lo2 = (__nv_bfloat162*)lo;
    for (; i < totalp; i += stride) {
        long e = i << 1;
        int s = 0;
#pragma unroll
        for (int k = 1; k < 7; k++) if (e >= jobs.cum[k]) s = k;
        const float2* sp = (const float2*)jobs.src[s];
        float2 v = sp[(e - jobs.cum[s]) >> 1];
        __nv_bfloat162 hp, lp;
        split2(v.x, v.y, hp, lp);
        hi2[i] = hp; lo2[i] = lp;
    }
}

// W2 transpose-split (pair over k; pairs stay within one (l,h,nn) group)
__global__ void __launch_bounds__(256) w2t_split_kernel(
    const float* __restrict__ l2w,
    __nv_bfloat16* __restrict__ hi, __nv_bfloat16* __restrict__ lo)
{
    long np = ((long)NLAYERS * NH * D * HD) >> 1;
    long i = blockIdx.x * 256L + threadIdx.x;
    long stride = (long)gridDim.x * 256;
    __nv_bfloat162* hi2 = (__nv_bfloat162*)hi;
    __nv_bfloat162* lo2 = (__nv_bfloat162*)lo;
    for (; i < np; i += stride) {
        int k2 = (int)(i & 31);
        long t = i >> 5;
        int nn = (int)(t % D);
        long t2 = t / D;
        int h = (int)(t2 % NH);
        int l = (int)(t2 / NH);
        long r0 = ((long)l * D + h * HD + 2 * k2) * D + nn;
        float v0 = l2w[r0];
        float v1 = l2w[r0 + D];
        __nv_bfloat162 hp, lp;
        split2(v0, v1, hp, lp);
        hi2[i] = hp; lo2[i] = lp;
    }
}

// memory -> fp16 copy + row inverse norms, pair-vectorized.
__global__ void __launch_bounds__(256) convnorm_kernel(
    const float* __restrict__ m, __half* __restrict__ mf,
    float* __restrict__ minv)
{
    int row = blockIdx.x, tid = threadIdx.x;
    const float2* mr = (const float2*)(m + (long)row * D);
    __half2* mf2 = (__half2*)(mf + (long)row * D);
    float s = 0.f;
#pragma unroll
    for (int i = 0; i < 2; i++) {
        int p = tid + i * 256;
        if (p < 384) {
            float2 v = mr[p];
            mf2[p] = __floats2half2_rn(v.x, v.y);
            s += v.x * v.x + v.y * v.y;
        }
    }
    __shared__ float rs[256];
    rs[tid] = s; __syncthreads();
    for (int o = 128; o > 0; o >>= 1) {
        if (tid < o) rs[tid] += rs[tid + o];
        __syncthreads();
    }
    if (tid == 0) minv[row] = rsqrtf(rs[0]);
}

__global__ void __launch_bounds__(256) split_affine_kernel(
    const float* __restrict__ src, const float* __restrict__ scale,
    const float* __restrict__ shift,
    __nv_bfloat16* __restrict__ hi, __nv_bfloat16* __restrict__ lo, long n)
{
    long np = n >> 1;
    long i = blockIdx.x * 256L + threadIdx.x;
    long stride = (long)gridDim.x * 256;
    const float2* s2 = (const float2*)src;
    const float2* sc2 = (const float2*)scale;
    const float2* sh2 = (const float2*)shift;
    __nv_bfloat162* hi2 = (__nv_bfloat162*)hi;
    __nv_bfloat162* lo2 = (__nv_bfloat162*)lo;
    for (; i < np; i += stride) {
        int kp = (int)(i % (D / 2));
        float2 v = s2[i], sc = sc2[kp], sh = sh2[kp];
        __nv_bfloat162 hp, lp;
        split2(v.x * sc.x + sh.x, v.y * sc.y + sh.y, hp, lp);
        hi2[i] = hp; lo2[i] = lp;
    }
}

// ----------------------------------------------------------------------------
// bf16x3 tensor-core GEMM (unchanged)
// ----------------------------------------------------------------------------
template<int BN, int EPI>
__global__ void __launch_bounds__(256) hgemm_kernel(
    const __nv_bfloat16* __restrict__ Ah, const __nv_bfloat16* __restrict__ Al,
    const __nv_bfloat16* __restrict__ Bh, const __nv_bfloat16* __restrict__ Bl,
    const float* __restrict__ bias,
    float* __restrict__ C,
    __nv_bfloat16* __restrict__ Chi, __nv_bfloat16* __restrict__ Clo,
    int M, int N, int K, int ldA, int ldB, int ldC,
    long zA, long zB, long zC, long zBias)
{
    constexpr int BM = 128;
    constexpr int NT = BN / 32;
    constexpr int ROWS = BM + BN;
    extern __shared__ __align__(16) __nv_bfloat16 smem[];

    const int bz = blockIdx.z;
    Ah += bz * zA; Al += bz * zA;
    Bh += bz * zB; Bl += bz * zB;
    if (bias) bias += bz * zBias;
    C  += bz * zC;
    if (EPI == 1 || EPI == 3) { Chi += bz * zC; Clo += bz * zC; }

    const int tid  = threadIdx.x;
    const int wid  = tid >> 5;
    const int lane = tid & 31;
    const int wm   = wid & 1;
    const int wn   = wid >> 1;
    const int qm   = lane >> 2;
    const int qk   = lane & 3;
    const int bm = blockIdx.y * BM;
    const int bn = blockIdx.x * BN;
    const uint32_t sbase = smem_u32(smem);

    float acc[4][NT][4];
#pragma unroll
    for (int mt = 0; mt < 4; mt++)
#pragma unroll
        for (int nt = 0; nt < NT; nt++)
#pragma unroll
            for (int r = 0; r < 4; r++) acc[mt][nt][r] = 0.f;

    auto loadStage = [&](int s, int k0) {
        const uint32_t pH = sbase + (uint32_t)(s * 2 + 0) * ROWS * 80;
        const uint32_t pL = sbase + (uint32_t)(s * 2 + 1) * ROWS * 80;
#pragma unroll
        for (int c = tid; c < BM * 4; c += 256) {
            int row = c >> 2, kc = c & 3;
            long gofs = (long)(bm + row) * ldA + k0;
            CP_ASYNC16(pH + row * 80 + kc * 16, (const char*)(Ah + gofs) + kc * 16);
            CP_ASYNC16(pL + row * 80 + kc * 16, (const char*)(Al + gofs) + kc * 16);
        }
#pragma unroll
        for (int c = tid; c < BN * 4; c += 256) {
            int row = c >> 2, kc = c & 3;
            int n = bn + row;
            uint32_t dh = pH + (BM + row) * 80 + kc * 16;
            uint32_t dl = pL + (BM + row) * 80 + kc * 16;
            if (n < N) {
                long gofs = (long)n * ldB + k0;
                CP_ASYNC16(dh, (const char*)(Bh + gofs) + kc * 16);
                CP_ASYNC16(dl, (const char*)(Bl + gofs) + kc * 16);
            } else {
                uint32_t z = 0;
                asm volatile("st.shared.v4.b32 [%0], {%1,%1,%1,%1};" :: "r"(dh), "r"(z) : "memory");
                asm volatile("st.shared.v4.b32 [%0], {%1,%1,%1,%1};" :: "r"(dl), "r"(z) : "memory");
            }
        }
    };

    auto compute = [&](int s) {
        const uint32_t baseH = sbase + (uint32_t)(s * 2 + 0) * ROWS * 80;
        const uint32_t baseL = sbase + (uint32_t)(s * 2 + 1) * ROWS * 80;
#pragma unroll
        for (int kc = 0; kc < 2; kc++) {
            uint32_t ah[4][4], al[4][4], bh[NT][2], bl[NT][2];
            const int arow = wm * 64 + (lane & 15);
            const uint32_t acol = kc * 32 + ((lane & 16) ? 16 : 0);
#pragma unroll
            for (int mt = 0; mt < 4; mt++) {
                uint32_t ro = (uint32_t)(arow + mt * 16) * 80 + acol;
                ldsm_x4(ah[mt][0], ah[mt][1], ah[mt][2], ah[mt][3], baseH + ro);
                ldsm_x4(al[mt][0], al[mt][1], al[mt][2], al[mt][3], baseL + ro);
            }
            const int brow = BM + wn * (BN / 4) + (lane & 7) + ((lane & 16) ? 8 : 0);
            const uint32_t bcol = kc * 32 + ((lane & 8) ? 16 : 0);
#pragma unroll
            for (int np = 0; np < NT / 2; np++) {
                uint32_t ro = (uint32_t)(brow + np * 16) * 80 + bcol;
                ldsm_x4(bh[2*np][0], bh[2*np][1], bh[2*np+1][0], bh[2*np+1][1], baseH + ro);
                ldsm_x4(bl[2*np][0], bl[2*np][1], bl[2*np+1][0], bl[2*np+1][1], baseL + ro);
            }
#pragma unroll
            for (int mt = 0; mt < 4; mt++)
#pragma unroll
                for (int nt = 0; nt < NT; nt++) {
                    mma_bf16(acc[mt][nt], ah[mt][0], ah[mt][1], ah[mt][2], ah[mt][3],
                             bh[nt][0], bh[nt][1]);
                    mma_bf16(acc[mt][nt], ah[mt][0], ah[mt][1], ah[mt][2], ah[mt][3],
                             bl[nt][0], bl[nt][1]);
                    mma_bf16(acc[mt][nt], al[mt][0], al[mt][1], al[mt][2], al[mt][3],
                             bh[nt][0], bh[nt][1]);
                }
        }
    };

    const int niter = K >> 5;
    loadStage(0, 0); CP_COMMIT();
    for (int i = 0; i < niter; i++) {
        if (i + 1 < niter) { loadStage((i + 1) & 1, (i + 1) << 5); CP_COMMIT(); CP_WAIT(1); }
        else               { CP_WAIT(0); }
        __syncthreads();
        compute(i & 1);
        __syncthreads();
    }

#pragma unroll
    for (int mt = 0; mt < 4; mt++) {
        int r0 = bm + wm * 64 + mt * 16 + qm;
#pragma unroll
        for (int nt = 0; nt < NT; nt++) {
            int c0 = bn + wn * (BN / 4) + nt * 8 + qk * 2;
            float v0 = acc[mt][nt][0], v1 = acc[mt][nt][1];
            float v2 = acc[mt][nt][2], v3 = acc[mt][nt][3];
            if (bias) {
                float b0 = (c0 < N) ? bias[c0] : 0.f;
                float b1 = (c0 + 1 < N) ? bias[c0 + 1] : 0.f;
                v0 += b0; v1 += b1; v2 += b0; v3 += b1;
            }
            if (EPI == 1) {
                v0 = 0.5f * v0 * (1.f + erff(v0 * 0.70710678118654752f));
                v1 = 0.5f * v1 * (1.f + erff(v1 * 0.70710678118654752f));
                v2 = 0.5f * v2 * (1.f + erff(v2 * 0.70710678118654752f));
                v3 = 0.5f * v3 * (1.f + erff(v3 * 0.70710678118654752f));
            }
            if (EPI == 1 || EPI == 3) {
                __nv_bfloat162 h2, l2;
                split2(v0, v1, h2, l2);
                *(__nv_bfloat162*)(Chi + (long)r0 * ldC + c0) = h2;
                *(__nv_bfloat162*)(Clo + (long)r0 * ldC + c0) = l2;
                split2(v2, v3, h2, l2);
                *(__nv_bfloat162*)(Chi + (long)(r0 + 8) * ldC + c0) = h2;
                *(__nv_bfloat162*)(Clo + (long)(r0 + 8) * ldC + c0) = l2;
            }
            if (EPI == 0 || EPI == 3) {
                if (c0 < N) {
                    C[(long)r0 * ldC + c0] = v0;
                    C[(long)(r0 + 8) * ldC + c0] = v2;
                }
                if (c0 + 1 < N) {
                    C[(long)r0 * ldC + c0 + 1] = v1;
                    C[(long)(r0 + 8) * ldC + c0 + 1] = v3;
                }
            }
        }
    }
}

// ----------------------------------------------------------------------------
// Single-pass fp16 tensor-core GEMM (coarse sims only) — unchanged
// ----------------------------------------------------------------------------
__global__ void __launch_bounds__(256) fgemm_kernel(
    const __half* __restrict__ A, const __half* __restrict__ B,
    float* __restrict__ C,
    int M, int N, int K, long zA, long zB, long zC)
{
    constexpr int BM = 128, BN = 128, NT = 4, ROWS = BM + BN;
    extern __shared__ __align__(16) __half fsmem[];

    const int bz = blockIdx.z;
    A += bz * zA; B += bz * zB; C += bz * zC;

    const int tid  = threadIdx.x;
    const int wid  = tid >> 5;
    const int lane = tid & 31;
    const int wm   = wid & 1;
    const int wn   = wid >> 1;
    const int qm   = lane >> 2;
    const int qk   = lane & 3;
    const int bm = blockIdx.y * BM;
    const int bn = blockIdx.x * BN;
    const uint32_t sbase = smem_u32(fsmem);

    float acc[4][NT][4];
#pragma unroll
    for (int mt = 0; mt < 4; mt++)
#pragma unroll
        for (int nt = 0; nt < NT; nt++)
#pragma unroll
            for (int r = 0; r < 4; r++) acc[mt][nt][r] = 0.f;

    auto loadStage = [&](int s, int k0) {
        const uint32_t p = sbase + (uint32_t)s * ROWS * 80;
#pragma unroll
        for (int c = tid; c < BM * 4; c += 256) {
            int row = c >> 2, kc = c & 3;
            long gofs = (long)(bm + row) * K + k0;
            CP_ASYNC16(p + row * 80 + kc * 16, (const char*)(A + gofs) + kc * 16);
        }
#pragma unroll
        for (int c = tid; c < BN * 4; c += 256) {
            int row = c >> 2, kc = c & 3;
            long gofs = (long)(bn + row) * K + k0;
            CP_ASYNC16(p + (BM + row) * 80 + kc * 16, (const char*)(B + gofs) + kc * 16);
        }
    };

    auto compute = [&](int s) {
        const uint32_t base = sbase + (uint32_t)s * ROWS * 80;
#pragma unroll
        for (int kc = 0; kc < 2; kc++) {
            uint32_t a[4][4], b[NT][2];
            const int arow = wm * 64 + (lane & 15);
            const uint32_t acol = kc * 32 + ((lane & 16) ? 16 : 0);
#pragma unroll
            for (int mt = 0; mt < 4; mt++) {
                uint32_t ro = (uint32_t)(arow + mt * 16) * 80 + acol;
                ldsm_x4(a[mt][0], a[mt][1], a[mt][2], a[mt][3], base + ro);
            }
            const int brow = BM + wn * 32 + (lane & 7) + ((lane & 16) ? 8 : 0);
            const uint32_t bcol = kc * 32 + ((lane & 8) ? 16 : 0);
#pragma unroll
            for (int np = 0; np < NT / 2; np++) {
                uint32_t ro = (uint32_t)(brow + np * 16) * 80 + bcol;
                ldsm_x4(b[2*np][0], b[2*np][1], b[2*np+1][0], b[2*np+1][1], base + ro);
            }
#pragma unroll
            for (int mt = 0; mt < 4; mt++)
#pragma unroll
                for (int nt = 0; nt < NT; nt++)
                    mma_f16(acc[mt][nt], a[mt][0], a[mt][1], a[mt][2], a[mt][3],
                            b[nt][0], b[nt][1]);
        }
    };

    const int niter = K >> 5;
    loadStage(0, 0); CP_COMMIT();
    for (int i = 0; i < niter; i++) {
        if (i + 1 < niter) { loadStage((i + 1) & 1, (i + 1) << 5); CP_COMMIT(); CP_WAIT(1); }
        else               { CP_WAIT(0); }
        __syncthreads();
        compute(i & 1);
        __syncthreads();
    }

#pragma unroll
    for (int mt = 0; mt < 4; mt++) {
        int r0 = bm + wm * 64 + mt * 16 + qm;
#pragma unroll
        for (int nt = 0; nt < NT; nt++) {
            int c0 = bn + wn * 32 + nt * 8 + qk * 2;
            C[(long)r0 * N + c0]           = acc[mt][nt][0];
            C[(long)r0 * N + c0 + 1]       = acc[mt][nt][1];
            C[(long)(r0 + 8) * N + c0]     = acc[mt][nt][2];
            C[(long)(r0 + 8) * N + c0 + 1] = acc[mt][nt][3];
        }
    }
}

// ----------------------------------------------------------------------------
// LayerNorm + fused splits, pair-vectorized (float2 in, bf162/half2 out)
// ----------------------------------------------------------------------------
__global__ void __launch_bounds__(256) ln_kernel(
    const float* __restrict__ x, const float* __restrict__ add,
    const float* __restrict__ g, const float* __restrict__ b,
    const float* __restrict__ qpos,
    float* __restrict__ out,
    __nv_bfloat16* __restrict__ ohi, __nv_bfloat16* __restrict__ olo,
    __nv_bfloat16* __restrict__ oqhi, __nv_bfloat16* __restrict__ oqlo,
    __half* __restrict__ oxf16)
{
    int row = blockIdx.x, tid = threadIdx.x;
    const float2* xr = (const float2*)(x + (long)row * D);
    const float2* ar = add ? (const float2*)(add + (long)row * D) : nullptr;
    float2 vals[2];
    float s = 0.f, sq = 0.f;
#pragma unroll
    for (int i = 0; i < 2; i++) {
        int p = tid + i * 256;
        if (p < D / 2) {
            float2 v = xr[p];
            if (ar) { float2 a = ar[p]; v.x += a.x; v.y += a.y; }
            vals[i] = v;
            s += v.x + v.y;
            sq += v.x * v.x + v.y * v.y;
        }
    }
    __shared__ float rs[256], rq[256];
    rs[tid] = s; rq[tid] = sq;
    __syncthreads();
    for (int o = 128; o > 0; o >>= 1) {
        if (tid < o) { rs[tid] += rs[tid + o]; rq[tid] += rq[tid + o]; }
        __syncthreads();
    }
    float mu = rs[0] * (1.f / D);
    float var = rq[0] * (1.f / D) - mu * mu;
    float rstd = rsqrtf(var + EPS);

    const float2* g2 = (const float2*)g;
    const float2* b2 = (const float2*)b;
    const float2* q2 = (const float2*)(qpos + (long)row * D);
    float2* out2 = (float2*)(out + (long)row * D);
    __half2* xf2 = oxf16 ? (__half2*)(oxf16 + (long)row * D) : nullptr;
    __nv_bfloat162* oh2 = ohi ? (__nv_bfloat162*)(ohi + (long)row * D) : nullptr;
    __nv_bfloat162* ol2 = ohi ? (__nv_bfloat162*)(olo + (long)row * D) : nullptr;
    __nv_bfloat162* qh2 = oqhi ? (__nv_bfloat162*)(oqhi + (long)row * D) : nullptr;
    __nv_bfloat162* ql2 = oqhi ? (__nv_bfloat162*)(oqlo + (long)row * D) : nullptr;

#pragma unroll
    for (int i = 0; i < 2; i++) {
        int p = tid + i * 256;
        if (p < D / 2) {
            float2 gg = g2[p], bb = b2[p];
            float v0 = (vals[i].x - mu) * rstd * gg.x + bb.x;
            float v1 = (vals[i].y - mu) * rstd * gg.y + bb.y;
            out2[p] = make_float2(v0, v1);
            if (xf2) xf2[p] = __floats2half2_rn(v0, v1);
            __nv_bfloat162 hp, lp;
            if (oh2) {
                split2(v0, v1, hp, lp);
                oh2[p] = hp; ol2[p] = lp;
            }
            if (qh2) {
                float2 qq = q2[p];
                split2(v0 + qq.x, v1 + qq.y, hp, lp);
                qh2[p] = hp; ql2[p] = lp;
            }
        }
    }
}

// ----------------------------------------------------------------------------
// Top-32 via histogram threshold (unchanged)
// ----------------------------------------------------------------------------
__global__ void __launch_bounds__(256) topk_kernel(
    const float* __restrict__ sims, const float* __restrict__ minv,
    const float* __restrict__ x, const float* __restrict__ memory,
    int* __restrict__ idx_out)
{
    int row = blockIdx.x;
    int b = row >> 7;
    int tid = threadIdx.x;
    int warp = tid >> 5, lane = tid & 31;

    __shared__ float s[MNP];
    __shared__ float xrow[D];
    __shared__ int   hist[1024];
    __shared__ int   pcount[256];
    __shared__ int   cnt;
    __shared__ uint32_t s_tu;
    __shared__ int   cand[1024];
    __shared__ float cval[1024];

    for (int i = tid; i < MNP; i += 256)
        s[i] = sims[(long)row * MNP + i] * minv[b * MNP + i];
    for (int c = tid; c < D; c += 256)
        xrow[c] = x[(long)row * D + c];
    for (int i = tid; i < 1024; i += 256) hist[i] = 0;
    if (tid == 0) cnt = 0;
    __syncthreads();

    auto mapu = [](float f) -> uint32_t {
        uint32_t u = __float_as_uint(f);
        return (u & 0x80000000u) ? ~u : (u | 0x80000000u);
    };

    for (int i = tid; i < MNP; i += 256)
        atomicAdd(&hist[mapu(s[i]) >> 22], 1);
    __syncthreads();

    int local = hist[tid*4] + hist[tid*4+1] + hist[tid*4+2] + hist[tid*4+3];
    pcount[tid] = local;
    __syncthreads();
    for (int off = 1; off < 256; off <<= 1) {
        int v = (tid + off < 256) ? pcount[tid + off] : 0;
        __syncthreads();
        pcount[tid] += v;
        __syncthreads();
    }
    {
        int c0 = pcount[tid];
        int c1 = (tid + 1 < 256) ? pcount[tid + 1] : 0;
        if (c0 >= COVER && c1 < COVER) {
            int acc = c1;
            int chosen = tid * 4;
            for (int k = 3; k >= 0; k--) {
                acc += hist[tid*4 + k];
                if (acc >= COVER) { chosen = tid*4 + k; break; }
            }
            s_tu = (uint32_t)chosen << 22;
        }
    }
    __syncthreads();
    uint32_t tu = s_tu;

    for (int i = tid; i < MNP; i += 256) {
        if (mapu(s[i]) >= tu) {
            int p = atomicAdd(&cnt, 1);
            if (p < 1024) cand[p] = i;
        }
    }
    __syncthreads();
    int n = cnt < 1024 ? cnt : 1024;

    for (int j = warp; j < n; j += 8) {
        int ix = cand[j];
        const float* mr = memory + ((long)(b * MNP + ix)) * D;
        float acc = 0.f;
        for (int c = lane; c < D; c += 32) acc = fmaf(xrow[c], mr[c], acc);
#pragma unroll
        for (int o = 16; o > 0; o >>= 1) acc += __shfl_xor_sync(0xffffffffu, acc, o);
        if (lane == 0) cval[j] = acc * minv[b * MNP + ix];
    }
    __syncthreads();

    if (warp == 0) {
        for (int t = 0; t < TOPK; t++) {
            float v = -INFINITY; int myi = 0x7fffffff, myj = -1;
            for (int j = lane; j < n; j += 32) {
                float cv = cval[j];
                if (cv > v || (cv == v && cand[j] < myi)) { v = cv; myi = cand[j]; myj = j; }
            }
#pragma unroll
            for (int o = 16; o > 0; o >>= 1) {
                float ov = __shfl_xor_sync(0xffffffffu, v, o);
                int   oi = __shfl_xor_sync(0xffffffffu, myi, o);
                int   oj = __shfl_xor_sync(0xffffffffu, myj, o);
                if (ov > v || (ov == v && oi < myi)) { v = ov; myi = oi; myj = oj; }
            }
            if (lane == 0) {
                idx_out[row * TOPK + t] = myi;
                cval[myj] = -INFINITY;
            }
            __syncwarp();
        }
    }
}

// ----------------------------------------------------------------------------
// Fused cross-attention, single-pass online softmax, paired columns:
// lane owns columns (2*lane + 64*j, +1) for j=0..11 -> float2/bf162 traffic.
// ----------------------------------------------------------------------------
__global__ void __launch_bounds__(128) xattn_kernel(
    const float* __restrict__ qf,
    const float* __restrict__ Z,
    const float* __restrict__ memory,
    const float* __restrict__ kpos,
    const float* __restrict__ l2b,
    const int*   __restrict__ idx,
    __nv_bfloat16* __restrict__ agghi,
    __nv_bfloat16* __restrict__ agglo)
{
    __shared__ __align__(16) float mrow[2][D];
    __shared__ __align__(16) float krow[2][D];
    __shared__ float qrow[D];
    __shared__ float qb[NH];
    __shared__ int   ids[TOPK];

    const int qi = blockIdx.x;
    const int b = qi >> 7;
    const int tid = threadIdx.x;
    const int warp = tid >> 5, lane = tid & 31;
    const int h0 = warp * 3;
    const uint32_t mbase = smem_u32(mrow);
    const uint32_t kbase = smem_u32(krow);

    for (int k = 0; k < 6; k++)
        qrow[tid + 128 * k] = qf[(long)qi * D + tid + 128 * k];
    if (tid < TOPK) ids[tid] = idx[qi * TOPK + tid];
    __syncthreads();

#pragma unroll
    for (int t = 0; t < 3; t++) {
        int h = h0 + t;
        float s = qrow[h * HD + lane] * l2b[h * HD + lane]
                + qrow[h * HD + 32 + lane] * l2b[h * HD + 32 + lane];
#pragma unroll
        for (int o = 16; o > 0; o >>= 1) s += __shfl_xor_sync(0xffffffffu, s, o);
        qb[h] = s;
    }

    // Z pairs: lane owns float2 index lane + 32*j (cols 2*lane+64*j, +1)
    float2 zreg[3][12];
#pragma unroll
    for (int t = 0; t < 3; t++) {
        const float2* zp = (const float2*)(Z + ((long)(h0 + t) * NTOK + qi) * D);
#pragma unroll
        for (int j = 0; j < 12; j++) zreg[t][j] = zp[lane + 32 * j];
    }

    float mx[3], ssum[3];
    float2 A[3][12];
#pragma unroll
    for (int t = 0; t < 3; t++) {
        mx[t] = -INFINITY; ssum[t] = 0.f;
#pragma unroll
        for (int j = 0; j < 12; j++) A[t][j] = make_float2(0.f, 0.f);
    }

    auto fetch_mk = [&](int buf, int j) {
        long base = ((long)(b * MNP + ids[j])) * D;
        for (int c = tid; c < 192; c += 128) {
            CP_ASYNC16(mbase + (uint32_t)(buf * D + c * 4) * 4, (const char*)(memory + base) + c * 16);
            CP_ASYNC16(kbase + (uint32_t)(buf * D + c * 4) * 4, (const char*)(kpos + base) + c * 16);
        }
    };

    fetch_mk(0, 0); CP_COMMIT();
    for (int j = 0; j < TOPK; j++) {
        int buf = j & 1;
        if (j + 1 < TOPK) { fetch_mk(buf ^ 1, j + 1); CP_COMMIT(); CP_WAIT(1); }
        else              { CP_WAIT(0); }
        __syncthreads();
        const float2* m2 = (const float2*)mrow[buf];
        const float2* k2 = (const float2*)krow[buf];
#pragma unroll
        for (int t = 0; t < 3; t++) {
            float s = 0.f;
#pragma unroll
            for (int i = 0; i < 12; i++) {
                float2 mm = m2[lane + 32 * i];
                float2 kk = k2[lane + 32 * i];
                s = fmaf(zreg[t][i].x, mm.x + kk.x, s);
                s = fmaf(zreg[t][i].y, mm.y + kk.y, s);
            }
#pragma unroll
            for (int o = 16; o > 0; o >>= 1) s += __shfl_xor_sync(0xffffffffu, s, o);
            s = (s + qb[h0 + t]) * 0.125f;
            float mn = fmaxf(mx[t], s);
            float scale = expf(mx[t] - mn);
            float e = expf(s - mn);
            ssum[t] = ssum[t] * scale + e;
#pragma unroll
            for (int i = 0; i < 12; i++) {
                float2 mm = m2[lane + 32 * i];
                A[t][i].x = fmaf(e, mm.x, A[t][i].x * scale);
                A[t][i].y = fmaf(e, mm.y, A[t][i].y * scale);
            }
            mx[t] = mn;
        }
        __syncthreads();
    }

#pragma unroll
    for (int t = 0; t < 3; t++) {
        float inv = 1.f / ssum[t];
        long o0 = ((long)(h0 + t) * NTOK + qi) * D;
        __nv_bfloat162* oh = (__nv_bfloat162*)(agghi + o0);
        __nv_bfloat162* ol = (__nv_bfloat162*)(agglo + o0);
#pragma unroll
        for (int i = 0; i < 12; i++) {
            __nv_bfloat162 hp, lp;
            split2(A[t][i].x * inv, A[t][i].y * inv, hp, lp);
            oh[lane + 32 * i] = hp;
            ol[lane + 32 * i] = lp;
        }
    }
}

// ----------------------------------------------------------------------------
// Self-attention: block per (batch, head) — V pitch 64 + float2, paired dims.
// ----------------------------------------------------------------------------
#define SA_SMEM ((128*64 + 128*65 + 128*64 + 4*128) * 4)

__global__ void __launch_bounds__(128) self_attn_kernel(
    const float* __restrict__ qk, const float* __restrict__ v,
    __nv_bfloat16* __restrict__ ohi, __nv_bfloat16* __restrict__ olo)
{
    extern __shared__ float ssm[];
    float* Qs = ssm;                      // [128][64]
    float* Ks = Qs + 128 * 64;            // [128][65]
    float* Vs = Ks + 128 * 65;            // [128][64] (float2 access)
    float* Ps = Vs + 128 * 64;            // [4][128]

    const int bh = blockIdx.x;
    const int b = bh / NH, h = bh % NH;
    const int tid = threadIdx.x;
    const int warp = tid >> 5, lane = tid & 31;

    for (int i = tid; i < 128 * 16; i += 128) {
        int r = i >> 4, c4 = (i & 15) << 2;
        long tok = (long)(b * NP + r);
        float4 qv = *(const float4*)&qk[tok * 2 * D + h * HD + c4];
        float4 kv = *(const float4*)&qk[tok * 2 * D + D + h * HD + c4];
        float4 vv = *(const float4*)&v[tok * D + h * HD + c4];
        *(float4*)&Qs[r * 64 + c4] = qv;
        Ks[r * 65 + c4 + 0] = kv.x; Ks[r * 65 + c4 + 1] = kv.y;
        Ks[r * 65 + c4 + 2] = kv.z; Ks[r * 65 + c4 + 3] = kv.w;
        *(float4*)&Vs[r * 64 + c4] = vv;
    }
    __syncthreads();

    for (int qq = 0; qq < 32; qq++) {
        int qi = warp * 32 + qq;
        const float* qrow = &Qs[qi * 64];
        float s[4];
#pragma unroll
        for (int kk = 0; kk < 4; kk++) {
            int k = lane + kk * 32;
            const float* krow = &Ks[k * 65];
            float acc = 0.f;
#pragma unroll
            for (int d = 0; d < HD; d++) acc = fmaf(qrow[d], krow[d], acc);
            s[kk] = acc * 0.125f;
        }
        float m = fmaxf(fmaxf(s[0], s[1]), fmaxf(s[2], s[3]));
#pragma unroll
        for (int o = 16; o > 0; o >>= 1) m = fmaxf(m, __shfl_xor_sync(0xffffffffu, m, o));
        float e[4], sum = 0.f;
#pragma unroll
        for (int kk = 0; kk < 4; kk++) { e[kk] = expf(s[kk] - m); sum += e[kk]; }
#pragma unroll
        for (int o = 16; o > 0; o >>= 1) sum += __shfl_xor_sync(0xffffffffu, sum, o);
        float inv = 1.f / sum;
#pragma unroll
        for (int kk = 0; kk < 4; kk++) Ps[warp * 128 + lane + kk * 32] = e[kk] * inv;
        __syncwarp();

        // lane owns dims (2*lane, 2*lane+1) via float2
        float2 a = make_float2(0.f, 0.f);
        const float2* V2 = (const float2*)Vs;
#pragma unroll 8
        for (int k = 0; k < 128; k++) {
            float p = Ps[warp * 128 + k];
            float2 vv = V2[k * 32 + lane];
            a.x = fmaf(p, vv.x, a.x);
            a.y = fmaf(p, vv.y, a.y);
        }
        long o = (long)(b * NP + qi) * D + h * HD + 2 * lane;
        __nv_bfloat162 hp, lp;
        split2(a.x, a.y, hp, lp);
        *(__nv_bfloat162*)(ohi + o) = hp;
        *(__nv_bfloat162*)(olo + o) = lp;
        __syncwarp();
    }
}

// ----------------------------------------------------------------------------
// BatchNorm stats (unchanged)
// ----------------------------------------------------------------------------
__global__ void __launch_bounds__(256) bn_stats_kernel(
    const float* __restrict__ x, const float* __restrict__ g,
    const float* __restrict__ b, float* __restrict__ scale,
    float* __restrict__ shift)
{
    int f = blockIdx.x, tid = threadIdx.x;
    float s = 0.f, sq = 0.f;
    for (int r = tid; r < NTOK; r += 256) {
        float v = x[(long)r * D + f];
        s += v; sq += v * v;
    }
    __shared__ float rs[256], rq[256];
    rs[tid] = s; rq[tid] = sq;
    __syncthreads();
    for (int o = 128; o > 0; o >>= 1) {
        if (tid < o) { rs[tid] += rs[tid + o]; rq[tid] += rq[tid + o]; }
        __syncthreads();
    }
    if (tid == 0) {
        float mu = rs[0] * (1.f / NTOK);
        float var = rq[0] * (1.f / NTOK) - mu * mu;
        float rstd = rsqrtf(var + EPS);
        float sc = rstd * g[f];
        scale[f] = sc;
        shift[f] = b[f] - mu * sc;
    }
}

// ----------------------------------------------------------------------------
// Host orchestration — two-stream overlap (capture-safe event fork/join)
// ----------------------------------------------------------------------------
#define SMEM128 (2 * 2 * 256 * 80)
#define SMEM64  (2 * 2 * 192 * 80)
#define SMEMF   (2 * 256 * 80)

extern "C" void kernel_launch(void* const* d_in, const int* in_sizes, int n_in,
                              void* d_out, int out_size)
{
    const float* tgt      = (const float*)d_in[0];
    const float* memory   = (const float*)d_in[1];
    const float* qpos     = (const float*)d_in[2];
    const float* kpos     = (const float*)d_in[3];
    const float* norm0_g  = (const float*)d_in[4];
    const float* norm0_b  = (const float*)d_in[5];
    const float* l1_w     = (const float*)d_in[6];
    const float* l1_b     = (const float*)d_in[7];
    const float* l2_w     = (const float*)d_in[8];
    const float* l2_b     = (const float*)d_in[9];
    const float* l3_w     = (const float*)d_in[10];
    const float* l3_b     = (const float*)d_in[11];
    const float* n1_g     = (const float*)d_in[12];
    const float* n1_b     = (const float*)d_in[13];
    const float* n2_g     = (const float*)d_in[14];
    const float* n2_b     = (const float*)d_in[15];
    const float* n3_g     = (const float*)d_in[16];
    const float* n3_b     = (const float*)d_in[17];
    const float* sa_in_w  = (const float*)d_in[18];
    const float* sa_in_b  = (const float*)d_in[19];
    const float* sa_out_w = (const float*)d_in[20];
    const float* sa_out_b = (const float*)d_in[21];
    const float* ff1_w    = (const float*)d_in[22];
    const float* ff1_b    = (const float*)d_in[23];
    const float* ff2_w    = (const float*)d_in[24];
    const float* ff2_b    = (const float*)d_in[25];
    const float* bn_g     = (const float*)d_in[26];
    const float* bn_b     = (const float*)d_in[27];
    const float* cls_w    = (const float*)d_in[28];

    float *x, *tmp, *q, *qk, *v, *attn, *Z, *sims, *minv, *bnsc, *bnsh;
    int* idx;
    __nv_bfloat16 *whi, *wlo, *w2th, *w2tl;
    __nv_bfloat16 *xhi, *xlo, *xqhi, *xqlo, *qhi, *qlo, *agghi, *agglo;
    __nv_bfloat16 *h1hi, *h1lo, *sahi, *salo, *cihi, *cilo;
    __half *mf16, *xf16;
    cudaGetSymbolAddress((void**)&x,    g_x);
    cudaGetSymbolAddress((void**)&tmp,  g_tmp);
    cudaGetSymbolAddress((void**)&q,    g_q);
    cudaGetSymbolAddress((void**)&qk,   g_qk);
    cudaGetSymbolAddress((void**)&v,    g_v);
    cudaGetSymbolAddress((void**)&attn, g_attn);
    cudaGetSymbolAddress((void**)&Z,    g_Z);
    cudaGetSymbolAddress((void**)&sims, g_sims);
    cudaGetSymbolAddress((void**)&idx,  g_idx);
    cudaGetSymbolAddress((void**)&minv, g_minv);
    cudaGetSymbolAddress((void**)&bnsc, g_bnscale);
    cudaGetSymbolAddress((void**)&bnsh, g_bnshift);
    cudaGetSymbolAddress((void**)&whi,  g_whi);
    cudaGetSymbolAddress((void**)&wlo,  g_wlo);
    cudaGetSymbolAddress((void**)&w2th, g_w2thi);
    cudaGetSymbolAddress((void**)&w2tl, g_w2tlo);
    cudaGetSymbolAddress((void**)&xhi,  g_xhi);
    cudaGetSymbolAddress((void**)&xlo,  g_xlo);
    cudaGetSymbolAddress((void**)&xqhi, g_xqhi);
    cudaGetSymbolAddress((void**)&xqlo, g_xqlo);
    cudaGetSymbolAddress((void**)&qhi,  g_qhi);
    cudaGetSymbolAddress((void**)&qlo,  g_qlo);
    cudaGetSymbolAddress((void**)&agghi, g_agghi);
    cudaGetSymbolAddress((void**)&agglo, g_agglo);
    cudaGetSymbolAddress((void**)&h1hi, g_h1hi);
    cudaGetSymbolAddress((void**)&h1lo, g_h1lo);
    cudaGetSymbolAddress((void**)&sahi, g_sahi);
    cudaGetSymbolAddress((void**)&salo, g_salo);
    cudaGetSymbolAddress((void**)&cihi, g_cihi);
    cudaGetSymbolAddress((void**)&cilo, g_cilo);
    cudaGetSymbolAddress((void**)&mf16, g_mf16);
    cudaGetSymbolAddress((void**)&xf16, g_xf16);

    cudaFuncSetAttribute(hgemm_kernel<128,0>, cudaFuncAttributeMaxDynamicSharedMemorySize, SMEM128);
    cudaFuncSetAttribute(hgemm_kernel<128,1>, cudaFuncAttributeMaxDynamicSharedMemorySize, SMEM128);
    cudaFuncSetAttribute(hgemm_kernel<64,0>,  cudaFuncAttributeMaxDynamicSharedMemorySize, SMEM64);
    cudaFuncSetAttribute(hgemm_kernel<64,3>,  cudaFuncAttributeMaxDynamicSharedMemorySize, SMEM64);
    cudaFuncSetAttribute(self_attn_kernel,    cudaFuncAttributeMaxDynamicSharedMemorySize, SA_SMEM);

    static cudaStream_t sB = (cudaStream_t)0;
    static cudaEvent_t  ev[14];
    static bool inited = false;
    if (!inited) {
        if (cudaStreamCreateWithFlags(&sB, cudaStreamNonBlocking) != cudaSuccess)
            sB = (cudaStream_t)0;
        for (int i = 0; i < 14; i++)
            cudaEventCreateWithFlags(&ev[i], cudaEventDisableTiming);
        inited = true;
    }
    cudaStream_t s0 = (cudaStream_t)0;

    // ---- preprocessing: fork {w2t, convnorm} onto sB ----
    cudaEventRecord(ev[0], s0);
    cudaStreamWaitEvent(sB, ev[0], 0);

    {
        SplitJobs jobs;
        jobs.src[0] = l1_w;     jobs.cum[0] = OFF_L1;
        jobs.src[1] = l3_w;     jobs.cum[1] = OFF_L3;
        jobs.src[2] = sa_in_w;  jobs.cum[2] = OFF_SAIN;
        jobs.src[3] = sa_out_w; jobs.cum[3] = OFF_SAOUT;
        jobs.src[4] = ff1_w;    jobs.cum[4] = OFF_FF1;
        jobs.src[5] = ff2_w;    jobs.cum[5] = OFF_FF2;
        jobs.src[6] = cls_w;    jobs.cum[6] = OFF_CLS;
        jobs.cum[7] = WTOTAL;
        multi_split_kernel<<<4096, 256, 0, s0>>>(jobs, whi, wlo);
    }
    w2t_split_kernel<<<1024, 256, 0, sB>>>(l2_w, w2th, w2tl);
    convnorm_kernel<<<NMEM, 256, 0, sB>>>(memory, mf16, minv);
    cudaEventRecord(ev[1], sB);

    ln_kernel<<<NTOK, 256, 0, s0>>>(tgt, nullptr, norm0_g, norm0_b, qpos,
                                    x, xhi, xlo, xqhi, xqlo, xf16);

    for (int l = 0; l < NLAYERS; l++) {
        long wdd = (long)l * D * D;
        const __nv_bfloat16* l1h = whi + OFF_L1 + wdd;   const __nv_bfloat16* l1l = wlo + OFF_L1 + wdd;
        const __nv_bfloat16* l3h = whi + OFF_L3 + wdd;   const __nv_bfloat16* l3l = wlo + OFF_L3 + wdd;
        const __nv_bfloat16* sih = whi + OFF_SAIN + (long)l*3*D*D;
        const __nv_bfloat16* sil = wlo + OFF_SAIN + (long)l*3*D*D;
        const __nv_bfloat16* soh = whi + OFF_SAOUT + wdd;
        const __nv_bfloat16* sol = wlo + OFF_SAOUT + wdd;
        const __nv_bfloat16* f1h = whi + OFF_FF1 + (long)l*DFF*D;
        const __nv_bfloat16* f1l = wlo + OFF_FF1 + (long)l*DFF*D;
        const __nv_bfloat16* f2h = whi + OFF_FF2 + (long)l*D*DFF;
        const __nv_bfloat16* f2l = wlo + OFF_FF2 + (long)l*D*DFF;
        const __nv_bfloat16* w2h = w2th + (long)l*NH*D*HD;
        const __nv_bfloat16* w2l = w2tl + (long)l*NH*D*HD;
        const float* l1bb = l1_b + (long)l * D;
        const float* l2bb = l2_b + (long)l * D;
        const float* l3bb = l3_b + (long)l * D;
        const float* sab  = sa_in_b + (long)l * 3 * D;
        const float* sob  = sa_out_b + (long)l * D;
        const float* f1b  = ff1_b + (long)l * DFF;
        const float* f2b  = ff2_b + (long)l * D;
        const bool last = (l == NLAYERS - 1);
        cudaEvent_t eA = ev[2 + l*4], eB = ev[3 + l*4], eC = ev[4 + l*4], eD = ev[5 + l*4];

        cudaEventRecord(eA, s0);
        cudaStreamWaitEvent(sB, eA, 0);
        fgemm_kernel<<<dim3(MNP/128, 1, BS), 256, SMEMF, sB>>>(
            xf16, mf16, sims, NP, MNP, D,
            (long)NP*D, (long)MNP*D, (long)NP*MNP);
        topk_kernel<<<NTOK, 256, 0, sB>>>(sims, minv, x, memory, idx);
        cudaEventRecord(eB, sB);

        hgemm_kernel<64,3><<<dim3(D/64, NTOK/128, 1), 256, SMEM64, s0>>>(
            xqhi, xqlo, l1h, l1l, l1bb, q, qhi, qlo,
            NTOK, D, D, D, D, D, 0, 0, 0, 0);

        if (l == 0) cudaStreamWaitEvent(s0, ev[1], 0);
        hgemm_kernel<128,0><<<dim3(D/128, NTOK/128, NH), 256, SMEM128, s0>>>(
            qhi, qlo, w2h, w2l, nullptr, Z, nullptr, nullptr,
            NTOK, D, HD, D, HD, D,
            (long)HD, (long)D*HD, (long)NTOK*D, 0);

        cudaStreamWaitEvent(s0, eB, 0);
        xattn_kernel<<<NTOK, 128, 0, s0>>>(q, Z, memory, kpos, l2bb, idx, agghi, agglo);

        hgemm_kernel<64,0><<<dim3(1, NTOK/128, NH), 256, SMEM64, s0>>>(
            agghi, agglo, l3h, l3l, l3bb, attn, nullptr, nullptr,
            NTOK, HD, D, D, D, D,
            (long)NTOK*D, (long)HD*D, (long)HD, (long)HD);

        ln_kernel<<<NTOK, 256, 0, s0>>>(x, attn, n1_g + (long)l * D, n1_b + (long)l * D,
                                        qpos, x, xhi, xlo, xqhi, xqlo, xf16);

        cudaEventRecord(eC, s0);
        cudaStreamWaitEvent(sB, eC, 0);
        hgemm_kernel<64,0><<<dim3(D/64, NTOK/128, 1), 256, SMEM64, sB>>>(
            xhi, xlo, sih + (long)2*D*D, sil + (long)2*D*D, sab + 2*D,
            v, nullptr, nullptr, NTOK, D, D, D, D, D, 0, 0, 0, 0);
        cudaEventRecord(eD, sB);

        hgemm_kernel<128,0><<<dim3((2*D)/128, NTOK/128, 1), 256, SMEM128, s0>>>(
            xqhi, xqlo, sih, sil, sab, qk, nullptr, nullptr,
            NTOK, 2*D, D, D, D, 2*D, 0, 0, 0, 0);

        cudaStreamWaitEvent(s0, eD, 0);
        self_attn_kernel<<<BS * NH, 128, SA_SMEM, s0>>>(qk, v, sahi, salo);

        hgemm_kernel<64,0><<<dim3(D/64, NTOK/128, 1), 256, SMEM64, s0>>>(
            sahi, salo, soh, sol, sob, tmp, nullptr, nullptr,
            NTOK, D, D, D, D, D, 0, 0, 0, 0);

        ln_kernel<<<NTOK, 256, 0, s0>>>(x, tmp, n2_g + (long)l * D, n2_b + (long)l * D,
                                        qpos, x, xhi, xlo, xqhi, xqlo, xf16);

        hgemm_kernel<128,1><<<dim3(DFF/128, NTOK/128, 1), 256, SMEM128, s0>>>(
            xhi, xlo, f1h, f1l, f1b, nullptr, h1hi, h1lo,
            NTOK, DFF, D, D, D, DFF, 0, 0, 0, 0);
        hgemm_kernel<64,0><<<dim3(D/64, NTOK/128, 1), 256, SMEM64, s0>>>(
            h1hi, h1lo, f2h, f2l, f2b, tmp, nullptr, nullptr,
            NTOK, D, DFF, DFF, DFF, D, 0, 0, 0, 0);

        ln_kernel<<<NTOK, 256, 0, s0>>>(x, tmp, n3_g + (long)l * D, n3_b + (long)l * D,
                                        qpos, x,
                                        last ? nullptr : xhi, last ? nullptr : xlo,
                                        last ? nullptr : xqhi, last ? nullptr : xqlo,
                                        last ? nullptr : xf16);
    }

    // Epilogue: x memcpy overlapped on sB with bn/cls chain on s0
    float* out = (float*)d_out;
    long xsz = (long)NTOK * D;
    long csz = (long)NTOK * NC;

    cudaEventRecord(ev[10], s0);    // x final
    bn_stats_kernel<<<D, 256, 0, s0>>>(x, bn_g, bn_b, bnsc, bnsh);
    split_affine_kernel<<<2048, 256, 0, s0>>>(x, bnsc, bnsh, cihi, cilo, (long)NTOK * D);

    if ((long)out_size >= xsz + csz) {
        cudaStreamWaitEvent(sB, ev[10], 0);
        cudaMemcpyAsync(out, x, sizeof(float) * xsz, cudaMemcpyDeviceToDevice, sB);
        cudaEventRecord(ev[11], sB);
        hgemm_kernel<64,0><<<dim3((NC+63)/64, NTOK/128, 1), 256, SMEM64, s0>>>(
            cihi, cilo, whi + OFF_CLS, wlo + OFF_CLS, nullptr,
            out + xsz, nullptr, nullptr, NTOK, NC, D, D, D, NC, 0, 0, 0, 0);
        cudaStreamWaitEvent(s0, ev[11], 0);
    } else if ((long)out_size == csz) {
        hgemm_kernel<64,0><<<dim3((NC+63)/64, NTOK/128, 1), 256, SMEM64, s0>>>(
            cihi, cilo, whi + OFF_CLS, wlo + OFF_CLS, nullptr,
            out, nullptr, nullptr, NTOK, NC, D, D, D, NC, 0, 0, 0, 0);
    } else {
        cudaMemcpyAsync(out, x, sizeof(float) * ((long)out_size < xsz ? out_size : xsz),
                        cudaMemcpyDeviceToDevice, s0);
    }
}